// round 1
// baseline (speedup 1.0000x reference)
#include <cuda_runtime.h>
#include <math.h>
#include <stdint.h>

#define D_MODEL 2048
#define SEQ     1024
#define N_HEADS 32
#define HEAD_DIM 64
#define ABLOCK  64
#define NB      (SEQ/ABLOCK)   // 16
#define D_FFN   8192
#define VOCAB   50257
#define NEXP    4

// ---------------- scratch (static __device__, allowed) ----------------
__device__ float g_x  [SEQ*D_MODEL];
__device__ float g_q  [SEQ*D_MODEL];
__device__ float g_k  [SEQ*D_MODEL];
__device__ float g_v  [SEQ*D_MODEL];
__device__ float g_att[SEQ*D_MODEL];
__device__ float g_y  [SEQ*D_MODEL];
__device__ float g_h1 [SEQ*D_FFN];
__device__ float g_h3 [SEQ*D_FFN];
__device__ float g_moe[SEQ*D_MODEL];
__device__ float g_wts[NEXP*SEQ];
__device__ float g_var[SEQ];

// ---------------- embedding ----------------
__global__ void embed_kernel(const int* __restrict__ tok,
                             const float* __restrict__ emb,
                             float* __restrict__ x) {
    int t = blockIdx.x;
    int tk = tok[t];
    for (int d = threadIdx.x; d < D_MODEL; d += 256)
        x[(size_t)t*D_MODEL + d] = emb[(size_t)tk*D_MODEL + d];
}

// ---------------- NT GEMM: C[m,n] = sum_k A[m,k]*B[n,k] ----------------
// residual != null : C = acc + residual   (same layout as C)
// rowScale != null : C += rowScale[m] * acc   (C must be pre-initialized)
__global__ void __launch_bounds__(256, 2) gemm_nt(
    const float* __restrict__ A, const float* __restrict__ B,
    float* __restrict__ C, int M, int N, int K,
    const float* __restrict__ residual, const float* __restrict__ rowScale)
{
    __shared__ float As[16][132];
    __shared__ float Bs[16][132];
    const int tid = threadIdx.x;
    const int m0 = blockIdx.y * 128;
    const int n0 = blockIdx.x * 128;
    const int tx = tid & 15, ty = tid >> 4;

    float acc[8][8];
    #pragma unroll
    for (int i = 0; i < 8; i++)
        #pragma unroll
        for (int j = 0; j < 8; j++) acc[i][j] = 0.f;

    for (int k0 = 0; k0 < K; k0 += 16) {
        #pragma unroll
        for (int i = 0; i < 2; i++) {
            int v   = tid + i*256;
            int row = v >> 2;
            int kq  = (v & 3) << 2;
            float4 a = *(const float4*)(A + (size_t)(m0+row)*K + k0 + kq);
            As[kq+0][row] = a.x; As[kq+1][row] = a.y;
            As[kq+2][row] = a.z; As[kq+3][row] = a.w;
            float4 b = make_float4(0.f, 0.f, 0.f, 0.f);
            if (n0 + row < N)
                b = *(const float4*)(B + (size_t)(n0+row)*K + k0 + kq);
            Bs[kq+0][row] = b.x; Bs[kq+1][row] = b.y;
            Bs[kq+2][row] = b.z; Bs[kq+3][row] = b.w;
        }
        __syncthreads();
        #pragma unroll
        for (int kk = 0; kk < 16; kk++) {
            float ar[8], br[8];
            #pragma unroll
            for (int i = 0; i < 8; i++) ar[i] = As[kk][ty*8+i];
            #pragma unroll
            for (int j = 0; j < 8; j++) br[j] = Bs[kk][tx*8+j];
            #pragma unroll
            for (int i = 0; i < 8; i++)
                #pragma unroll
                for (int j = 0; j < 8; j++)
                    acc[i][j] = fmaf(ar[i], br[j], acc[i][j]);
        }
        __syncthreads();
    }

    #pragma unroll
    for (int i = 0; i < 8; i++) {
        int m = m0 + ty*8 + i;
        #pragma unroll
        for (int j = 0; j < 8; j++) {
            int n = n0 + tx*8 + j;
            if (n < N) {
                size_t idx = (size_t)m * N + n;
                float val = acc[i][j];
                if (residual) val += residual[idx];
                if (rowScale) C[idx] += rowScale[m] * val;
                else          C[idx] = val;
            }
        }
    }
}

// ---------------- RoPE (in place on q and k) ----------------
__global__ void rope_kernel(float* __restrict__ q, float* __restrict__ k) {
    int t = blockIdx.x, h = blockIdx.y, i = threadIdx.x;   // i = pair 0..31
    float inv = powf(10000.f, -((float)(2*i)) / 64.f);
    float ang = (float)t * inv;
    float s, c;
    sincosf(ang, &s, &c);
    size_t base = (size_t)t*D_MODEL + h*HEAD_DIM + 2*i;
    float q0 = q[base], q1 = q[base+1];
    q[base]   = q0*c - q1*s;
    q[base+1] = q0*s + q1*c;
    float k0 = k[base], k1 = k[base+1];
    k[base]   = k0*c - k1*s;
    k[base+1] = k0*s + k1*c;
}

// ---------------- blocked attention (per-key-block max, exact ref semantics) ----------------
#define ATTN_SMEM (4 * 64 * 65 * 4)
__global__ void __launch_bounds__(256) attn_kernel(
    const float* __restrict__ q, const float* __restrict__ k,
    const float* __restrict__ v, float* __restrict__ o)
{
    extern __shared__ float sm[];
    float* Qs = sm;              // 64 x 65
    float* Ks = Qs + 64*65;
    float* Vs = Ks + 64*65;
    float* Ps = Vs + 64*65;
    const int ib = blockIdx.x, h = blockIdx.y;
    const int tid = threadIdx.x;
    const int qr  = tid >> 2;        // query row 0..63
    const int c0  = (tid & 3) * 16;  // 16-col segment

    for (int idx = tid; idx < 64*64; idx += 256) {
        int r = idx >> 6, c = idx & 63;
        Qs[r*65 + c] = q[(size_t)(ib*64+r)*D_MODEL + h*HEAD_DIM + c];
    }

    float accO[16];
    #pragma unroll
    for (int i = 0; i < 16; i++) accO[i] = 0.f;
    float den = 0.f;

    for (int jb = 0; jb <= ib; jb++) {
        __syncthreads();
        for (int idx = tid; idx < 64*64; idx += 256) {
            int r = idx >> 6, c = idx & 63;
            Ks[r*65 + c] = k[(size_t)(jb*64+r)*D_MODEL + h*HEAD_DIM + c];
            Vs[r*65 + c] = v[(size_t)(jb*64+r)*D_MODEL + h*HEAD_DIM + c];
        }
        __syncthreads();

        float s[16];
        float mx = -1e30f;
        #pragma unroll
        for (int cc = 0; cc < 16; cc++) {
            int c = c0 + cc;
            float dot = 0.f;
            #pragma unroll
            for (int d = 0; d < 64; d++)
                dot = fmaf(Qs[qr*65 + d], Ks[c*65 + d], dot);
            dot *= 0.125f;                       // hd^-0.5
            if (jb == ib && c > qr) dot = -1e30f; // triu mask on diag block
            s[cc] = dot;
            mx = fmaxf(mx, dot);
        }
        // per-(block,row) max across the 4-thread quad
        mx = fmaxf(mx, __shfl_xor_sync(0xffffffffu, mx, 1));
        mx = fmaxf(mx, __shfl_xor_sync(0xffffffffu, mx, 2));

        #pragma unroll
        for (int cc = 0; cc < 16; cc++) {
            float p = expf(s[cc] - mx);
            Ps[qr*65 + c0 + cc] = p;
            den += p;
        }
        __syncthreads();

        #pragma unroll 8
        for (int kk = 0; kk < 64; kk++) {
            float pv = Ps[qr*65 + kk];
            #pragma unroll
            for (int d = 0; d < 16; d++)
                accO[d] = fmaf(pv, Vs[kk*65 + c0 + d], accO[d]);
        }
    }

    den += __shfl_xor_sync(0xffffffffu, den, 1);
    den += __shfl_xor_sync(0xffffffffu, den, 2);
    float invd = 1.f / (den + 1e-6f);
    #pragma unroll
    for (int d = 0; d < 16; d++)
        o[(size_t)(ib*64+qr)*D_MODEL + h*HEAD_DIM + c0 + d] = accO[d] * invd;
}

// ---------------- layernorm (optional residual add), two-pass ----------------
__global__ void __launch_bounds__(256) ln_kernel(
    const float* __restrict__ in, const float* __restrict__ res,
    const float* __restrict__ g, const float* __restrict__ b,
    float* __restrict__ out)
{
    __shared__ float red[256];
    int t = blockIdx.x, tid = threadIdx.x;
    float v[8];
    float sum = 0.f;
    #pragma unroll
    for (int i = 0; i < 8; i++) {
        int d = i*256 + tid;
        float x = in[(size_t)t*D_MODEL + d];
        if (res) x += res[(size_t)t*D_MODEL + d];
        v[i] = x; sum += x;
    }
    red[tid] = sum; __syncthreads();
    for (int s = 128; s > 0; s >>= 1) { if (tid < s) red[tid] += red[tid+s]; __syncthreads(); }
    float mu = red[0] / D_MODEL;
    __syncthreads();
    float sq = 0.f;
    #pragma unroll
    for (int i = 0; i < 8; i++) { float d0 = v[i] - mu; sq += d0*d0; }
    red[tid] = sq; __syncthreads();
    for (int s = 128; s > 0; s >>= 1) { if (tid < s) red[tid] += red[tid+s]; __syncthreads(); }
    float rstd = rsqrtf(red[0] / D_MODEL + 1e-5f);
    #pragma unroll
    for (int i = 0; i < 8; i++) {
        int d = i*256 + tid;
        out[(size_t)t*D_MODEL + d] = (v[i] - mu) * rstd * g[d] + b[d];
    }
}

// ---------------- MoE gate: softmax -> top2 -> renorm + per-token logit variance ----------------
__global__ void __launch_bounds__(128) gate_kernel(
    const float* __restrict__ x, const float* __restrict__ gw,
    float* __restrict__ wts, float* __restrict__ varr)
{
    __shared__ float red[128];
    __shared__ float logit[4];
    int t = blockIdx.x, tid = threadIdx.x;
    float p[4] = {0.f, 0.f, 0.f, 0.f};
    for (int d = tid; d < D_MODEL; d += 128) {
        float xv = x[(size_t)t*D_MODEL + d];
        #pragma unroll
        for (int e = 0; e < 4; e++)
            p[e] = fmaf(xv, gw[e*D_MODEL + d], p[e]);
    }
    for (int e = 0; e < 4; e++) {
        red[tid] = p[e]; __syncthreads();
        for (int s = 64; s > 0; s >>= 1) { if (tid < s) red[tid] += red[tid+s]; __syncthreads(); }
        if (tid == 0) logit[e] = red[0];
        __syncthreads();
    }
    if (tid == 0) {
        float l[4] = {logit[0], logit[1], logit[2], logit[3]};
        float mx = fmaxf(fmaxf(l[0], l[1]), fmaxf(l[2], l[3]));
        float ex[4], ssum = 0.f;
        for (int e = 0; e < 4; e++) { ex[e] = expf(l[e] - mx); ssum += ex[e]; }
        float pr[4];
        for (int e = 0; e < 4; e++) pr[e] = ex[e] / ssum;
        int b1 = 0;
        for (int e = 1; e < 4; e++) if (pr[e] > pr[b1]) b1 = e;
        int b2 = -1;
        for (int e = 0; e < 4; e++) { if (e == b1) continue; if (b2 < 0 || pr[e] > pr[b2]) b2 = e; }
        float s2 = pr[b1] + pr[b2];
        float wv[4] = {0.f, 0.f, 0.f, 0.f};
        wv[b1] = pr[b1] / s2; wv[b2] = pr[b2] / s2;
        for (int e = 0; e < 4; e++) wts[e*SEQ + t] = wv[e];
        float mu = (l[0]+l[1]+l[2]+l[3]) * 0.25f;
        float va = ((l[0]-mu)*(l[0]-mu) + (l[1]-mu)*(l[1]-mu) +
                    (l[2]-mu)*(l[2]-mu) + (l[3]-mu)*(l[3]-mu)) / 3.f;  // ddof=1
        varr[t] = va;
    }
}

__global__ void aux_kernel(const float* __restrict__ varr, float* __restrict__ out) {
    __shared__ float red[256];
    int tid = threadIdx.x;
    float s = 0.f;
    for (int i = tid; i < SEQ; i += 256) s += varr[i];
    red[tid] = s; __syncthreads();
    for (int st = 128; st > 0; st >>= 1) { if (tid < st) red[tid] += red[tid+st]; __syncthreads(); }
    if (tid == 0) out[0] = red[0] / (float)SEQ;
}

__global__ void silu_mul_kernel(float* __restrict__ h1, const float* __restrict__ h3, int n) {
    int i = blockIdx.x * 256 + threadIdx.x;
    if (i < n) {
        float a = h1[i];
        float sig = 1.f / (1.f + expf(-a));
        h1[i] = a * sig * h3[i];
    }
}

__global__ void zero_kernel(float* __restrict__ p, int n) {
    int i = blockIdx.x * 256 + threadIdx.x;
    if (i < n) p[i] = 0.f;
}

// ---------------- driver ----------------
extern "C" void kernel_launch(void* const* d_in, const int* in_sizes, int n_in,
                              void* d_out, int out_size) {
    const int*   tokens = (const int*)  d_in[0];
    const float* emb    = (const float*)d_in[1];
    const float* wq     = (const float*)d_in[2];
    const float* wk     = (const float*)d_in[3];
    const float* wv     = (const float*)d_in[4];
    const float* wo     = (const float*)d_in[5];
    const float* ln1g   = (const float*)d_in[6];
    const float* ln1b   = (const float*)d_in[7];
    const float* gatew  = (const float*)d_in[8];
    const float* w1     = (const float*)d_in[9];
    const float* w2     = (const float*)d_in[10];
    const float* w3     = (const float*)d_in[11];
    const float* ln2g   = (const float*)d_in[12];
    const float* ln2b   = (const float*)d_in[13];
    const float* fing   = (const float*)d_in[14];
    const float* finb   = (const float*)d_in[15];
    const float* headw  = (const float*)d_in[16];
    float* out = (float*)d_out;

    float *x, *q, *k, *v, *att, *y, *h1, *h3, *moe, *wts, *varr;
    cudaGetSymbolAddress((void**)&x,    g_x);
    cudaGetSymbolAddress((void**)&q,    g_q);
    cudaGetSymbolAddress((void**)&k,    g_k);
    cudaGetSymbolAddress((void**)&v,    g_v);
    cudaGetSymbolAddress((void**)&att,  g_att);
    cudaGetSymbolAddress((void**)&y,    g_y);
    cudaGetSymbolAddress((void**)&h1,   g_h1);
    cudaGetSymbolAddress((void**)&h3,   g_h3);
    cudaGetSymbolAddress((void**)&moe,  g_moe);
    cudaGetSymbolAddress((void**)&wts,  g_wts);
    cudaGetSymbolAddress((void**)&varr, g_var);

    cudaFuncSetAttribute(attn_kernel, cudaFuncAttributeMaxDynamicSharedMemorySize, ATTN_SMEM);

    // 1) x = emb[tokens]
    embed_kernel<<<SEQ, 256>>>(tokens, emb, x);

    // 2) q,k,v projections
    dim3 g2048(D_MODEL/128, SEQ/128);
    gemm_nt<<<g2048, 256>>>(x, wq, q, SEQ, D_MODEL, D_MODEL, nullptr, nullptr);
    gemm_nt<<<g2048, 256>>>(x, wk, k, SEQ, D_MODEL, D_MODEL, nullptr, nullptr);
    gemm_nt<<<g2048, 256>>>(x, wv, v, SEQ, D_MODEL, D_MODEL, nullptr, nullptr);

    // 3) RoPE
    rope_kernel<<<dim3(SEQ, N_HEADS), 32>>>(q, k);

    // 4) blocked attention
    attn_kernel<<<dim3(NB, N_HEADS), 256, ATTN_SMEM>>>(q, k, v, att);

    // 5) output projection + residual:  y = att @ wo^T + x
    gemm_nt<<<g2048, 256>>>(att, wo, y, SEQ, D_MODEL, D_MODEL, x, nullptr);

    // 6) x = LN1(y)
    ln_kernel<<<SEQ, 256>>>(y, nullptr, ln1g, ln1b, x);

    // 7) gate: weights (transposed [e][t]) + per-token logit variance
    gate_kernel<<<SEQ, 128>>>(x, gatew, wts, varr);

    // 8) MoE: dense experts, weighted accumulate into moe
    zero_kernel<<<(SEQ*D_MODEL + 255)/256, 256>>>(moe, SEQ*D_MODEL);
    dim3 gffn(D_FFN/128, SEQ/128);
    for (int e = 0; e < NEXP; e++) {
        const float* w1e = w1 + (size_t)e * D_FFN * D_MODEL;
        const float* w3e = w3 + (size_t)e * D_FFN * D_MODEL;
        const float* w2e = w2 + (size_t)e * D_MODEL * D_FFN;
        gemm_nt<<<gffn, 256>>>(x, w1e, h1, SEQ, D_FFN, D_MODEL, nullptr, nullptr);
        gemm_nt<<<gffn, 256>>>(x, w3e, h3, SEQ, D_FFN, D_MODEL, nullptr, nullptr);
        silu_mul_kernel<<<(SEQ*D_FFN + 255)/256, 256>>>(h1, h3, SEQ*D_FFN);
        gemm_nt<<<g2048, 256>>>(h1, w2e, moe, SEQ, D_MODEL, D_FFN, nullptr, wts + e*SEQ);
    }

    // 9) y = LN2(moe + x);  x = LNfin(y)
    ln_kernel<<<SEQ, 256>>>(moe, x, ln2g, ln2b, y);
    ln_kernel<<<SEQ, 256>>>(y, nullptr, fing, finb, x);

    // 10) logits = x @ head_w^T  -> d_out
    dim3 ghead((VOCAB + 127)/128, SEQ/128);
    gemm_nt<<<ghead, 256>>>(x, headw, out, SEQ, VOCAB, D_MODEL, nullptr, nullptr);

    // 11) aux = mean_t var(logits_t, ddof=1) -> last output element
    long long nlog = (long long)SEQ * VOCAB;
    if ((long long)out_size > nlog)
        aux_kernel<<<1, 256>>>(varr, out + nlog);
}

// round 4
// speedup vs baseline: 2.3862x; 2.3862x over previous
#include <cuda_runtime.h>
#include <cuda_bf16.h>
#include <math.h>
#include <stdint.h>

#define D_MODEL 2048
#define SEQ     1024
#define N_HEADS 32
#define HEAD_DIM 64
#define NB      (SEQ/64)
#define D_FFN   8192
#define VOCAB   50257
#define NEXP    4

// ---------------- scratch ----------------
__device__ float g_x  [SEQ*D_MODEL];
__device__ float g_q  [SEQ*D_MODEL];
__device__ float g_k  [SEQ*D_MODEL];
__device__ float g_v  [SEQ*D_MODEL];
__device__ float g_att[SEQ*D_MODEL];
__device__ float g_y  [SEQ*D_MODEL];
__device__ float g_h1 [SEQ*D_FFN];
__device__ float g_h3 [SEQ*D_FFN];
__device__ float g_moe[SEQ*D_MODEL];
__device__ float g_wts[NEXP*SEQ];
__device__ float g_var[SEQ];

// bf16 split scratch
__device__ __nv_bfloat16 g_ah[SEQ*D_MODEL];     // A-operand (d_model acts)
__device__ __nv_bfloat16 g_al[SEQ*D_MODEL];
__device__ __nv_bfloat16 g_ch[SEQ*D_FFN];       // A-operand (ffn acts)
__device__ __nv_bfloat16 g_cl[SEQ*D_FFN];
__device__ __nv_bfloat16 g_bh[(size_t)VOCAB*D_MODEL];   // B-operand (weights, max = head)
__device__ __nv_bfloat16 g_bl[(size_t)VOCAB*D_MODEL];

// ---------------- PTX helpers (sm_80-compatible only) ----------------
__device__ __forceinline__ uint32_t smem_u32(const void* p) {
    uint32_t a;
    asm("{ .reg .u64 t; cvta.to.shared.u64 t, %1; cvt.u32.u64 %0, t; }" : "=r"(a) : "l"(p));
    return a;
}
__device__ __forceinline__ void cp_async16(uint32_t dst, const void* src, int src_bytes) {
    asm volatile("cp.async.cg.shared.global [%0], [%1], 16, %2;\n"
                 :: "r"(dst), "l"(src), "r"(src_bytes) : "memory");
}
#define CP_COMMIT() asm volatile("cp.async.commit_group;\n" ::: "memory")

__device__ __forceinline__ void ldsm_x4(uint32_t& r0, uint32_t& r1, uint32_t& r2, uint32_t& r3,
                                        uint32_t addr) {
    asm volatile("ldmatrix.sync.aligned.m8n8.x4.shared.b16 {%0,%1,%2,%3}, [%4];"
                 : "=r"(r0), "=r"(r1), "=r"(r2), "=r"(r3) : "r"(addr));
}
__device__ __forceinline__ void mma_bf16(float* c, const uint32_t* a, const uint32_t* b) {
    asm volatile(
        "mma.sync.aligned.m16n8k16.row.col.f32.bf16.bf16.f32 "
        "{%0,%1,%2,%3}, {%4,%5,%6,%7}, {%8,%9}, {%0,%1,%2,%3};"
        : "+f"(c[0]), "+f"(c[1]), "+f"(c[2]), "+f"(c[3])
        : "r"(a[0]), "r"(a[1]), "r"(a[2]), "r"(a[3]), "r"(b[0]), "r"(b[1]));
}

// ---------------- fp32 -> (bf16 hi, bf16 lo) split ----------------
__global__ void __launch_bounds__(256) split_kernel(
    const float* __restrict__ in, __nv_bfloat16* __restrict__ hi,
    __nv_bfloat16* __restrict__ lo, int n4)
{
    int i = blockIdx.x * 256 + threadIdx.x;
    if (i >= n4) return;
    float4 v = ((const float4*)in)[i];
    __nv_bfloat16 h0 = __float2bfloat16(v.x);
    __nv_bfloat16 h1 = __float2bfloat16(v.y);
    __nv_bfloat16 h2 = __float2bfloat16(v.z);
    __nv_bfloat16 h3 = __float2bfloat16(v.w);
    __nv_bfloat162 hh0; hh0.x = h0; hh0.y = h1;
    __nv_bfloat162 hh1; hh1.x = h2; hh1.y = h3;
    __nv_bfloat162 ll0, ll1;
    ll0.x = __float2bfloat16(v.x - __bfloat162float(h0));
    ll0.y = __float2bfloat16(v.y - __bfloat162float(h1));
    ll1.x = __float2bfloat16(v.z - __bfloat162float(h2));
    ll1.y = __float2bfloat16(v.w - __bfloat162float(h3));
    ((__nv_bfloat162*)hi)[i*2]   = hh0;
    ((__nv_bfloat162*)hi)[i*2+1] = hh1;
    ((__nv_bfloat162*)lo)[i*2]   = ll0;
    ((__nv_bfloat162*)lo)[i*2+1] = ll1;
}

// ---------------- bf16x3 tensor-core NT GEMM ----------------
// C[m,n] = sum_k A[m,k] * B[n,k],  A = Ah+Al, B = Bh+Bl (bf16 pairs)
// 128x128 CTA tile, BK=32, 8 warps (4x2), warp tile 32x64, 5-stage cp.async.
// smem row layout (128B per logical row): chunks 0-3 = hi k0..31, chunks 4-7 = lo k0..31.
#define NSTG 5
#define GEMM_SMEM (NSTG * 2 * 128 * 128)

__global__ void __launch_bounds__(256, 1) gemm_tc(
    const __nv_bfloat16* __restrict__ Ah, const __nv_bfloat16* __restrict__ Al,
    const __nv_bfloat16* __restrict__ Bh, const __nv_bfloat16* __restrict__ Bl,
    float* __restrict__ C, int M, int N, int K,
    const float* __restrict__ residual, const float* __restrict__ rowScale)
{
    extern __shared__ char smem[];
    const uint32_t sb = smem_u32(smem);
    const int tid = threadIdx.x;
    const int wid = tid >> 5, lid = tid & 31;
    const int wm  = wid >> 1, wn = wid & 1;
    const int m0  = blockIdx.y * 128;
    const int n0  = blockIdx.x * 128;

    constexpr int STAGE = 2 * 128 * 128;

    float acc[2][8][4];
    #pragma unroll
    for (int i = 0; i < 2; i++)
        #pragma unroll
        for (int j = 0; j < 8; j++)
            #pragma unroll
            for (int t = 0; t < 4; t++) acc[i][j][t] = 0.f;

    const int iters = K >> 5;

    auto fill = [&](int stage, int kit) {
        const int k0 = kit << 5;
        const uint32_t abase = sb + stage * STAGE;
        const uint32_t bbase = abase + 128 * 128;
        #pragma unroll
        for (int i = 0; i < 4; i++) {
            int idx = tid + i * 256;
            int r = idx >> 3, c = idx & 7;
            uint32_t dst = abase + r * 128 + ((c ^ (r & 7)) << 4);
            const __nv_bfloat16* src = (c < 4)
                ? Ah + (size_t)(m0 + r) * K + k0 + c * 8
                : Al + (size_t)(m0 + r) * K + k0 + (c - 4) * 8;
            cp_async16(dst, src, 16);
        }
        #pragma unroll
        for (int i = 0; i < 4; i++) {
            int idx = tid + i * 256;
            int r = idx >> 3, c = idx & 7;
            uint32_t dst = bbase + r * 128 + ((c ^ (r & 7)) << 4);
            int rg = n0 + r;
            int rc = rg < N ? rg : (N - 1);
            const __nv_bfloat16* src = (c < 4)
                ? Bh + (size_t)rc * K + k0 + c * 8
                : Bl + (size_t)rc * K + k0 + (c - 4) * 8;
            cp_async16(dst, src, rg < N ? 16 : 0);
        }
        CP_COMMIT();
    };

    #pragma unroll
    for (int s = 0; s < NSTG - 1; s++) fill(s, s);

    const int grp = lid >> 3;
    const int rin = lid & 7;

    for (int i = 0; i < iters; i++) {
        const int s = i % NSTG;
        asm volatile("cp.async.wait_group %0;\n" :: "n"(NSTG - 2));
        __syncthreads();

        if (i + NSTG - 1 < iters) fill((i + NSTG - 1) % NSTG, i + NSTG - 1);
        else CP_COMMIT();

        const uint32_t abase = sb + s * STAGE;
        const uint32_t bbase = abase + 128 * 128;

        #pragma unroll
        for (int g = 0; g < 2; g++) {        // two k16 groups per 32-K stage
            uint32_t ah[2][4], al[2][4], bh[8][2], bl[8][2];
            #pragma unroll
            for (int mt = 0; mt < 2; mt++) {
                int row = wm * 32 + mt * 16 + (grp & 1) * 8 + rin;
                int kch = 2 * g + (grp >> 1);
                uint32_t ad = abase + row * 128 + ((kch ^ (row & 7)) << 4);
                ldsm_x4(ah[mt][0], ah[mt][1], ah[mt][2], ah[mt][3], ad);
                int kcl = 4 + 2 * g + (grp >> 1);
                uint32_t adl = abase + row * 128 + ((kcl ^ (row & 7)) << 4);
                ldsm_x4(al[mt][0], al[mt][1], al[mt][2], al[mt][3], adl);
            }
            #pragma unroll
            for (int p = 0; p < 4; p++) {
                int tile = 2 * p + (grp >> 1);
                int row  = wn * 64 + tile * 8 + rin;
                int kch  = 2 * g + (grp & 1);
                uint32_t bd = bbase + row * 128 + ((kch ^ (row & 7)) << 4);
                ldsm_x4(bh[2*p][0], bh[2*p][1], bh[2*p+1][0], bh[2*p+1][1], bd);
                int kcl  = 4 + 2 * g + (grp & 1);
                uint32_t bdl = bbase + row * 128 + ((kcl ^ (row & 7)) << 4);
                ldsm_x4(bl[2*p][0], bl[2*p][1], bl[2*p+1][0], bl[2*p+1][1], bdl);
            }
            #pragma unroll
            for (int mt = 0; mt < 2; mt++)
                #pragma unroll
                for (int nt = 0; nt < 8; nt++) {
                    mma_bf16(acc[mt][nt], ah[mt], bh[nt]);
                    mma_bf16(acc[mt][nt], ah[mt], bl[nt]);
                    mma_bf16(acc[mt][nt], al[mt], bh[nt]);
                }
        }
        __syncthreads();
    }

    // epilogue
    #pragma unroll
    for (int mt = 0; mt < 2; mt++) {
        #pragma unroll
        for (int nt = 0; nt < 8; nt++) {
            int row = m0 + wm * 32 + mt * 16 + (lid >> 2);
            int col = n0 + wn * 64 + nt * 8 + (lid & 3) * 2;
            #pragma unroll
            for (int h = 0; h < 2; h++) {
                int m = row + h * 8;
                float v0 = acc[mt][nt][h * 2 + 0];
                float v1 = acc[mt][nt][h * 2 + 1];
                size_t idx = (size_t)m * N + col;
                if (residual) {
                    if (col     < N) v0 += residual[idx];
                    if (col + 1 < N) v1 += residual[idx + 1];
                }
                if (rowScale) {
                    float w = rowScale[m];
                    if (col     < N) C[idx]     += w * v0;
                    if (col + 1 < N) C[idx + 1] += w * v1;
                } else {
                    if (col     < N) C[idx]     = v0;
                    if (col + 1 < N) C[idx + 1] = v1;
                }
            }
        }
    }
}

// ---------------- embedding ----------------
__global__ void embed_kernel(const int* __restrict__ tok,
                             const float* __restrict__ emb,
                             float* __restrict__ x) {
    int t = blockIdx.x;
    int tk = tok[t];
    for (int d = threadIdx.x; d < D_MODEL; d += 256)
        x[(size_t)t*D_MODEL + d] = emb[(size_t)tk*D_MODEL + d];
}

// ---------------- RoPE ----------------
__global__ void rope_kernel(float* __restrict__ q, float* __restrict__ k) {
    int t = blockIdx.x, h = blockIdx.y, i = threadIdx.x;
    float inv = powf(10000.f, -((float)(2*i)) / 64.f);
    float ang = (float)t * inv;
    float s, c;
    sincosf(ang, &s, &c);
    size_t base = (size_t)t*D_MODEL + h*HEAD_DIM + 2*i;
    float q0 = q[base], q1 = q[base+1];
    q[base]   = q0*c - q1*s;
    q[base+1] = q0*s + q1*c;
    float k0 = k[base], k1 = k[base+1];
    k[base]   = k0*c - k1*s;
    k[base+1] = k0*s + k1*c;
}

// ---------------- blocked attention (exact ref semantics) ----------------
#define ATTN_SMEM (4 * 64 * 65 * 4)
__global__ void __launch_bounds__(256) attn_kernel(
    const float* __restrict__ q, const float* __restrict__ k,
    const float* __restrict__ v, float* __restrict__ o)
{
    extern __shared__ float sm[];
    float* Qs = sm;
    float* Ks = Qs + 64*65;
    float* Vs = Ks + 64*65;
    float* Ps = Vs + 64*65;
    const int ib = blockIdx.x, h = blockIdx.y;
    const int tid = threadIdx.x;
    const int qr  = tid >> 2;
    const int c0  = (tid & 3) * 16;

    for (int idx = tid; idx < 64*64; idx += 256) {
        int r = idx >> 6, c = idx & 63;
        Qs[r*65 + c] = q[(size_t)(ib*64+r)*D_MODEL + h*HEAD_DIM + c];
    }

    float accO[16];
    #pragma unroll
    for (int i = 0; i < 16; i++) accO[i] = 0.f;
    float den = 0.f;

    for (int jb = 0; jb <= ib; jb++) {
        __syncthreads();
        for (int idx = tid; idx < 64*64; idx += 256) {
            int r = idx >> 6, c = idx & 63;
            Ks[r*65 + c] = k[(size_t)(jb*64+r)*D_MODEL + h*HEAD_DIM + c];
            Vs[r*65 + c] = v[(size_t)(jb*64+r)*D_MODEL + h*HEAD_DIM + c];
        }
        __syncthreads();

        float s[16];
        float mx = -1e30f;
        #pragma unroll
        for (int cc = 0; cc < 16; cc++) {
            int c = c0 + cc;
            float dot = 0.f;
            #pragma unroll
            for (int d = 0; d < 64; d++)
                dot = fmaf(Qs[qr*65 + d], Ks[c*65 + d], dot);
            dot *= 0.125f;
            if (jb == ib && c > qr) dot = -1e30f;
            s[cc] = dot;
            mx = fmaxf(mx, dot);
        }
        mx = fmaxf(mx, __shfl_xor_sync(0xffffffffu, mx, 1));
        mx = fmaxf(mx, __shfl_xor_sync(0xffffffffu, mx, 2));

        #pragma unroll
        for (int cc = 0; cc < 16; cc++) {
            float p = expf(s[cc] - mx);
            Ps[qr*65 + c0 + cc] = p;
            den += p;
        }
        __syncthreads();

        #pragma unroll 8
        for (int kk = 0; kk < 64; kk++) {
            float pv = Ps[qr*65 + kk];
            #pragma unroll
            for (int d = 0; d < 16; d++)
                accO[d] = fmaf(pv, Vs[kk*65 + c0 + d], accO[d]);
        }
    }

    den += __shfl_xor_sync(0xffffffffu, den, 1);
    den += __shfl_xor_sync(0xffffffffu, den, 2);
    float invd = 1.f / (den + 1e-6f);
    #pragma unroll
    for (int d = 0; d < 16; d++)
        o[(size_t)(ib*64+qr)*D_MODEL + h*HEAD_DIM + c0 + d] = accO[d] * invd;
}

// ---------------- layernorm ----------------
__global__ void __launch_bounds__(256) ln_kernel(
    const float* __restrict__ in, const float* __restrict__ res,
    const float* __restrict__ g, const float* __restrict__ b,
    float* __restrict__ out)
{
    __shared__ float red[256];
    int t = blockIdx.x, tid = threadIdx.x;
    float v[8];
    float sum = 0.f;
    #pragma unroll
    for (int i = 0; i < 8; i++) {
        int d = i*256 + tid;
        float x = in[(size_t)t*D_MODEL + d];
        if (res) x += res[(size_t)t*D_MODEL + d];
        v[i] = x; sum += x;
    }
    red[tid] = sum; __syncthreads();
    for (int s = 128; s > 0; s >>= 1) { if (tid < s) red[tid] += red[tid+s]; __syncthreads(); }
    float mu = red[0] / D_MODEL;
    __syncthreads();
    float sq = 0.f;
    #pragma unroll
    for (int i = 0; i < 8; i++) { float d0 = v[i] - mu; sq += d0*d0; }
    red[tid] = sq; __syncthreads();
    for (int s = 128; s > 0; s >>= 1) { if (tid < s) red[tid] += red[tid+s]; __syncthreads(); }
    float rstd = rsqrtf(red[0] / D_MODEL + 1e-5f);
    #pragma unroll
    for (int i = 0; i < 8; i++) {
        int d = i*256 + tid;
        out[(size_t)t*D_MODEL + d] = (v[i] - mu) * rstd * g[d] + b[d];
    }
}

// ---------------- MoE gate ----------------
__global__ void __launch_bounds__(128) gate_kernel(
    const float* __restrict__ x, const float* __restrict__ gw,
    float* __restrict__ wts, float* __restrict__ varr)
{
    __shared__ float red[128];
    __shared__ float logit[4];
    int t = blockIdx.x, tid = threadIdx.x;
    float p[4] = {0.f, 0.f, 0.f, 0.f};
    for (int d = tid; d < D_MODEL; d += 128) {
        float xv = x[(size_t)t*D_MODEL + d];
        #pragma unroll
        for (int e = 0; e < 4; e++)
            p[e] = fmaf(xv, gw[e*D_MODEL + d], p[e]);
    }
    for (int e = 0; e < 4; e++) {
        red[tid] = p[e]; __syncthreads();
        for (int s = 64; s > 0; s >>= 1) { if (tid < s) red[tid] += red[tid+s]; __syncthreads(); }
        if (tid == 0) logit[e] = red[0];
        __syncthreads();
    }
    if (tid == 0) {
        float l[4] = {logit[0], logit[1], logit[2], logit[3]};
        float mx = fmaxf(fmaxf(l[0], l[1]), fmaxf(l[2], l[3]));
        float ex[4], ssum = 0.f;
        for (int e = 0; e < 4; e++) { ex[e] = expf(l[e] - mx); ssum += ex[e]; }
        float pr[4];
        for (int e = 0; e < 4; e++) pr[e] = ex[e] / ssum;
        int b1 = 0;
        for (int e = 1; e < 4; e++) if (pr[e] > pr[b1]) b1 = e;
        int b2 = -1;
        for (int e = 0; e < 4; e++) { if (e == b1) continue; if (b2 < 0 || pr[e] > pr[b2]) b2 = e; }
        float s2 = pr[b1] + pr[b2];
        float wv[4] = {0.f, 0.f, 0.f, 0.f};
        wv[b1] = pr[b1] / s2; wv[b2] = pr[b2] / s2;
        for (int e = 0; e < 4; e++) wts[e*SEQ + t] = wv[e];
        float mu = (l[0]+l[1]+l[2]+l[3]) * 0.25f;
        float va = ((l[0]-mu)*(l[0]-mu) + (l[1]-mu)*(l[1]-mu) +
                    (l[2]-mu)*(l[2]-mu) + (l[3]-mu)*(l[3]-mu)) / 3.f;
        varr[t] = va;
    }
}

__global__ void aux_kernel(const float* __restrict__ varr, float* __restrict__ out) {
    __shared__ float red[256];
    int tid = threadIdx.x;
    float s = 0.f;
    for (int i = tid; i < SEQ; i += 256) s += varr[i];
    red[tid] = s; __syncthreads();
    for (int st = 128; st > 0; st >>= 1) { if (tid < st) red[tid] += red[tid+st]; __syncthreads(); }
    if (tid == 0) out[0] = red[0] / (float)SEQ;
}

__global__ void silu_mul_kernel(float* __restrict__ h1, const float* __restrict__ h3, int n) {
    int i = blockIdx.x * 256 + threadIdx.x;
    if (i < n) {
        float a = h1[i];
        float sig = 1.f / (1.f + expf(-a));
        h1[i] = a * sig * h3[i];
    }
}

__global__ void zero_kernel(float* __restrict__ p, int n) {
    int i = blockIdx.x * 256 + threadIdx.x;
    if (i < n) p[i] = 0.f;
}

// ---------------- driver ----------------
static inline void split(const float* src, __nv_bfloat16* hi, __nv_bfloat16* lo, long long n) {
    int n4 = (int)(n / 4);
    split_kernel<<<(n4 + 255)/256, 256>>>(src, hi, lo, n4);
}

extern "C" void kernel_launch(void* const* d_in, const int* in_sizes, int n_in,
                              void* d_out, int out_size) {
    const int*   tokens = (const int*)  d_in[0];
    const float* emb    = (const float*)d_in[1];
    const float* wq     = (const float*)d_in[2];
    const float* wk     = (const float*)d_in[3];
    const float* wv     = (const float*)d_in[4];
    const float* wo     = (const float*)d_in[5];
    const float* ln1g   = (const float*)d_in[6];
    const float* ln1b   = (const float*)d_in[7];
    const float* gatew  = (const float*)d_in[8];
    const float* w1     = (const float*)d_in[9];
    const float* w2     = (const float*)d_in[10];
    const float* w3     = (const float*)d_in[11];
    const float* ln2g   = (const float*)d_in[12];
    const float* ln2b   = (const float*)d_in[13];
    const float* fing   = (const float*)d_in[14];
    const float* finb   = (const float*)d_in[15];
    const float* headw  = (const float*)d_in[16];
    float* out = (float*)d_out;

    float *x, *q, *k, *v, *att, *y, *h1, *h3, *moe, *wts, *varr;
    __nv_bfloat16 *ah, *al, *ch, *cl, *bh, *bl;
    cudaGetSymbolAddress((void**)&x,    g_x);
    cudaGetSymbolAddress((void**)&q,    g_q);
    cudaGetSymbolAddress((void**)&k,    g_k);
    cudaGetSymbolAddress((void**)&v,    g_v);
    cudaGetSymbolAddress((void**)&att,  g_att);
    cudaGetSymbolAddress((void**)&y,    g_y);
    cudaGetSymbolAddress((void**)&h1,   g_h1);
    cudaGetSymbolAddress((void**)&h3,   g_h3);
    cudaGetSymbolAddress((void**)&moe,  g_moe);
    cudaGetSymbolAddress((void**)&wts,  g_wts);
    cudaGetSymbolAddress((void**)&varr, g_var);
    cudaGetSymbolAddress((void**)&ah,   g_ah);
    cudaGetSymbolAddress((void**)&al,   g_al);
    cudaGetSymbolAddress((void**)&ch,   g_ch);
    cudaGetSymbolAddress((void**)&cl,   g_cl);
    cudaGetSymbolAddress((void**)&bh,   g_bh);
    cudaGetSymbolAddress((void**)&bl,   g_bl);

    cudaFuncSetAttribute(attn_kernel, cudaFuncAttributeMaxDynamicSharedMemorySize, ATTN_SMEM);
    cudaFuncSetAttribute(gemm_tc, cudaFuncAttributeMaxDynamicSharedMemorySize, GEMM_SMEM);

    // 1) embed + split x
    embed_kernel<<<SEQ, 256>>>(tokens, emb, x);
    split(x, ah, al, (long long)SEQ * D_MODEL);

    // 2) q,k,v projections
    dim3 gA(D_MODEL/128, SEQ/128);
    split(wq, bh, bl, (long long)D_MODEL * D_MODEL);
    gemm_tc<<<gA, 256, GEMM_SMEM>>>(ah, al, bh, bl, q, SEQ, D_MODEL, D_MODEL, nullptr, nullptr);
    split(wk, bh, bl, (long long)D_MODEL * D_MODEL);
    gemm_tc<<<gA, 256, GEMM_SMEM>>>(ah, al, bh, bl, k, SEQ, D_MODEL, D_MODEL, nullptr, nullptr);
    split(wv, bh, bl, (long long)D_MODEL * D_MODEL);
    gemm_tc<<<gA, 256, GEMM_SMEM>>>(ah, al, bh, bl, v, SEQ, D_MODEL, D_MODEL, nullptr, nullptr);

    // 3) RoPE
    rope_kernel<<<dim3(SEQ, N_HEADS), 32>>>(q, k);

    // 4) attention
    attn_kernel<<<dim3(NB, N_HEADS), 256, ATTN_SMEM>>>(q, k, v, att);

    // 5) output proj + residual
    split(att, ah, al, (long long)SEQ * D_MODEL);
    split(wo, bh, bl, (long long)D_MODEL * D_MODEL);
    gemm_tc<<<gA, 256, GEMM_SMEM>>>(ah, al, bh, bl, y, SEQ, D_MODEL, D_MODEL, x, nullptr);

    // 6) LN1 -> x, split for MoE up-projections
    ln_kernel<<<SEQ, 256>>>(y, nullptr, ln1g, ln1b, x);
    split(x, ah, al, (long long)SEQ * D_MODEL);

    // 7) gate
    gate_kernel<<<SEQ, 128>>>(x, gatew, wts, varr);

    // 8) MoE
    zero_kernel<<<(SEQ*D_MODEL + 255)/256, 256>>>(moe, SEQ*D_MODEL);
    dim3 gF(D_FFN/128, SEQ/128);
    for (int e = 0; e < NEXP; e++) {
        const float* w1e = w1 + (size_t)e * D_FFN * D_MODEL;
        const float* w3e = w3 + (size_t)e * D_FFN * D_MODEL;
        const float* w2e = w2 + (size_t)e * D_MODEL * D_FFN;
        split(w1e, bh, bl, (long long)D_FFN * D_MODEL);
        gemm_tc<<<gF, 256, GEMM_SMEM>>>(ah, al, bh, bl, h1, SEQ, D_FFN, D_MODEL, nullptr, nullptr);
        split(w3e, bh, bl, (long long)D_FFN * D_MODEL);
        gemm_tc<<<gF, 256, GEMM_SMEM>>>(ah, al, bh, bl, h3, SEQ, D_FFN, D_MODEL, nullptr, nullptr);
        silu_mul_kernel<<<(SEQ*D_FFN + 255)/256, 256>>>(h1, h3, SEQ*D_FFN);
        split(h1, ch, cl, (long long)SEQ * D_FFN);
        split(w2e, bh, bl, (long long)D_MODEL * D_FFN);
        gemm_tc<<<gA, 256, GEMM_SMEM>>>(ch, cl, bh, bl, moe, SEQ, D_MODEL, D_FFN, nullptr, wts + e*SEQ);
    }

    // 9) LN2 + final LN
    ln_kernel<<<SEQ, 256>>>(moe, x, ln2g, ln2b, y);
    ln_kernel<<<SEQ, 256>>>(y, nullptr, fing, finb, x);

    // 10) head
    split(x, ah, al, (long long)SEQ * D_MODEL);
    split(headw, bh, bl, (long long)VOCAB * D_MODEL);
    dim3 gH((VOCAB + 127)/128, SEQ/128);
    gemm_tc<<<gH, 256, GEMM_SMEM>>>(ah, al, bh, bl, out, SEQ, VOCAB, D_MODEL, nullptr, nullptr);

    // 11) aux
    long long nlog = (long long)SEQ * VOCAB;
    if ((long long)out_size > nlog)
        aux_kernel<<<1, 256>>>(varr, out + nlog);
}

// round 5
// speedup vs baseline: 2.8826x; 1.2080x over previous
#include <cuda_runtime.h>
#include <cuda_bf16.h>
#include <math.h>
#include <stdint.h>

#define D_MODEL 2048
#define SEQ     1024
#define N_HEADS 32
#define HEAD_DIM 64
#define NB      (SEQ/64)
#define D_FFN   8192
#define VOCAB   50257
#define NEXP    4

// ---------------- scratch ----------------
__device__ float g_x  [SEQ*D_MODEL];
__device__ float g_q  [SEQ*D_MODEL];
__device__ float g_k  [SEQ*D_MODEL];
__device__ float g_v  [SEQ*D_MODEL];
__device__ float g_att[SEQ*D_MODEL];
__device__ float g_y  [SEQ*D_MODEL];
__device__ float g_h1 [SEQ*D_FFN];
__device__ float g_h3 [SEQ*D_FFN];
__device__ float g_moe[SEQ*D_MODEL];
__device__ float g_wts[NEXP*SEQ];
__device__ float g_var[SEQ];

// routing
__device__ int   g_cnt[NEXP];
__device__ int   g_ridx[NEXP*SEQ];
__device__ float g_rwt [NEXP*SEQ];

// bf16 split scratch
__device__ __nv_bfloat16 g_ah[SEQ*D_MODEL];
__device__ __nv_bfloat16 g_al[SEQ*D_MODEL];
__device__ __nv_bfloat16 g_gxh[SEQ*D_MODEL];    // gathered per-expert rows
__device__ __nv_bfloat16 g_gxl[SEQ*D_MODEL];
__device__ __nv_bfloat16 g_ch[SEQ*D_FFN];
__device__ __nv_bfloat16 g_cl[SEQ*D_FFN];
__device__ __nv_bfloat16 g_bh[(size_t)VOCAB*D_MODEL];
__device__ __nv_bfloat16 g_bl[(size_t)VOCAB*D_MODEL];

// ---------------- PTX helpers ----------------
__device__ __forceinline__ uint32_t smem_u32(const void* p) {
    uint32_t a;
    asm("{ .reg .u64 t; cvta.to.shared.u64 t, %1; cvt.u32.u64 %0, t; }" : "=r"(a) : "l"(p));
    return a;
}
__device__ __forceinline__ void cp_async16(uint32_t dst, const void* src, int src_bytes) {
    asm volatile("cp.async.cg.shared.global [%0], [%1], 16, %2;\n"
                 :: "r"(dst), "l"(src), "r"(src_bytes) : "memory");
}
#define CP_COMMIT() asm volatile("cp.async.commit_group;\n" ::: "memory")

__device__ __forceinline__ void ldsm_x4(uint32_t& r0, uint32_t& r1, uint32_t& r2, uint32_t& r3,
                                        uint32_t addr) {
    asm volatile("ldmatrix.sync.aligned.m8n8.x4.shared.b16 {%0,%1,%2,%3}, [%4];"
                 : "=r"(r0), "=r"(r1), "=r"(r2), "=r"(r3) : "r"(addr));
}
__device__ __forceinline__ void mma_bf16(float* c, const uint32_t* a, const uint32_t* b) {
    asm volatile(
        "mma.sync.aligned.m16n8k16.row.col.f32.bf16.bf16.f32 "
        "{%0,%1,%2,%3}, {%4,%5,%6,%7}, {%8,%9}, {%0,%1,%2,%3};"
        : "+f"(c[0]), "+f"(c[1]), "+f"(c[2]), "+f"(c[3])
        : "r"(a[0]), "r"(a[1]), "r"(a[2]), "r"(a[3]), "r"(b[0]), "r"(b[1]));
}

// ---------------- fp32 -> (bf16 hi, bf16 lo) split ----------------
__global__ void __launch_bounds__(256) split_kernel(
    const float* __restrict__ in, __nv_bfloat16* __restrict__ hi,
    __nv_bfloat16* __restrict__ lo, int n4)
{
    int i = blockIdx.x * 256 + threadIdx.x;
    if (i >= n4) return;
    float4 v = ((const float4*)in)[i];
    __nv_bfloat16 h0 = __float2bfloat16(v.x);
    __nv_bfloat16 h1 = __float2bfloat16(v.y);
    __nv_bfloat16 h2 = __float2bfloat16(v.z);
    __nv_bfloat16 h3 = __float2bfloat16(v.w);
    __nv_bfloat162 hh0; hh0.x = h0; hh0.y = h1;
    __nv_bfloat162 hh1; hh1.x = h2; hh1.y = h3;
    __nv_bfloat162 ll0, ll1;
    ll0.x = __float2bfloat16(v.x - __bfloat162float(h0));
    ll0.y = __float2bfloat16(v.y - __bfloat162float(h1));
    ll1.x = __float2bfloat16(v.z - __bfloat162float(h2));
    ll1.y = __float2bfloat16(v.w - __bfloat162float(h3));
    ((__nv_bfloat162*)hi)[i*2]   = hh0;
    ((__nv_bfloat162*)hi)[i*2+1] = hh1;
    ((__nv_bfloat162*)lo)[i*2]   = ll0;
    ((__nv_bfloat162*)lo)[i*2+1] = ll1;
}

// ================= bf16x3 GEMM core (shared by both variants) =================
#define NSTG 5
#define GEMM_SMEM (NSTG * 2 * 128 * 128)

// MODE 0: C[m,n] = val (+residual)        (M compile-known via value, rows full)
// MODE 1: routed: M from *Mptr, plain store to C (row stride N)
// MODE 2: routed: M from *Mptr, atomicAdd(C[idx[m]*N+n], rwt[m]*val)
template<int MODE>
__global__ void __launch_bounds__(256, 1) gemm_tc(
    const __nv_bfloat16* __restrict__ Ah, const __nv_bfloat16* __restrict__ Al,
    const __nv_bfloat16* __restrict__ Bh, const __nv_bfloat16* __restrict__ Bl,
    float* __restrict__ C, int M_in, int N, int K,
    const float* __restrict__ residual,
    const int* __restrict__ Mptr, const int* __restrict__ ridx,
    const float* __restrict__ rwt)
{
    int M = M_in;
    if (MODE != 0) {
        M = *Mptr;
        if ((int)blockIdx.y * 128 >= M) return;
    }
    extern __shared__ char smem[];
    const uint32_t sb = smem_u32(smem);
    const int tid = threadIdx.x;
    const int wid = tid >> 5, lid = tid & 31;
    const int wm  = wid >> 1, wn = wid & 1;
    const int m0  = blockIdx.y * 128;
    const int n0  = blockIdx.x * 128;

    constexpr int STAGE = 2 * 128 * 128;

    float acc[2][8][4];
    #pragma unroll
    for (int i = 0; i < 2; i++)
        #pragma unroll
        for (int j = 0; j < 8; j++)
            #pragma unroll
            for (int t = 0; t < 4; t++) acc[i][j][t] = 0.f;

    const int iters = K >> 5;

    auto fill = [&](int stage, int kit) {
        const int k0 = kit << 5;
        const uint32_t abase = sb + stage * STAGE;
        const uint32_t bbase = abase + 128 * 128;
        #pragma unroll
        for (int i = 0; i < 4; i++) {
            int idx = tid + i * 256;
            int r = idx >> 3, c = idx & 7;
            int rg = m0 + r;
            if (MODE != 0) rg = rg < M ? rg : (M - 1);
            uint32_t dst = abase + r * 128 + ((c ^ (r & 7)) << 4);
            const __nv_bfloat16* src = (c < 4)
                ? Ah + (size_t)rg * K + k0 + c * 8
                : Al + (size_t)rg * K + k0 + (c - 4) * 8;
            cp_async16(dst, src, 16);
        }
        #pragma unroll
        for (int i = 0; i < 4; i++) {
            int idx = tid + i * 256;
            int r = idx >> 3, c = idx & 7;
            uint32_t dst = bbase + r * 128 + ((c ^ (r & 7)) << 4);
            int rg = n0 + r;
            int rc = rg < N ? rg : (N - 1);
            const __nv_bfloat16* src = (c < 4)
                ? Bh + (size_t)rc * K + k0 + c * 8
                : Bl + (size_t)rc * K + k0 + (c - 4) * 8;
            cp_async16(dst, src, rg < N ? 16 : 0);
        }
        CP_COMMIT();
    };

    #pragma unroll
    for (int s = 0; s < NSTG - 1; s++) fill(s, s);

    const int grp = lid >> 3;
    const int rin = lid & 7;

    for (int i = 0; i < iters; i++) {
        const int s = i % NSTG;
        asm volatile("cp.async.wait_group %0;\n" :: "n"(NSTG - 2));
        __syncthreads();

        if (i + NSTG - 1 < iters) fill((i + NSTG - 1) % NSTG, i + NSTG - 1);
        else CP_COMMIT();

        const uint32_t abase = sb + s * STAGE;
        const uint32_t bbase = abase + 128 * 128;

        #pragma unroll
        for (int g = 0; g < 2; g++) {
            uint32_t ah[2][4], al[2][4], bh[8][2], bl[8][2];
            #pragma unroll
            for (int mt = 0; mt < 2; mt++) {
                int row = wm * 32 + mt * 16 + (grp & 1) * 8 + rin;
                int kch = 2 * g + (grp >> 1);
                uint32_t ad = abase + row * 128 + ((kch ^ (row & 7)) << 4);
                ldsm_x4(ah[mt][0], ah[mt][1], ah[mt][2], ah[mt][3], ad);
                int kcl = 4 + 2 * g + (grp >> 1);
                uint32_t adl = abase + row * 128 + ((kcl ^ (row & 7)) << 4);
                ldsm_x4(al[mt][0], al[mt][1], al[mt][2], al[mt][3], adl);
            }
            #pragma unroll
            for (int p = 0; p < 4; p++) {
                int tile = 2 * p + (grp >> 1);
                int row  = wn * 64 + tile * 8 + rin;
                int kch  = 2 * g + (grp & 1);
                uint32_t bd = bbase + row * 128 + ((kch ^ (row & 7)) << 4);
                ldsm_x4(bh[2*p][0], bh[2*p][1], bh[2*p+1][0], bh[2*p+1][1], bd);
                int kcl  = 4 + 2 * g + (grp & 1);
                uint32_t bdl = bbase + row * 128 + ((kcl ^ (row & 7)) << 4);
                ldsm_x4(bl[2*p][0], bl[2*p][1], bl[2*p+1][0], bl[2*p+1][1], bdl);
            }
            #pragma unroll
            for (int mt = 0; mt < 2; mt++)
                #pragma unroll
                for (int nt = 0; nt < 8; nt++) {
                    mma_bf16(acc[mt][nt], ah[mt], bh[nt]);
                    mma_bf16(acc[mt][nt], ah[mt], bl[nt]);
                    mma_bf16(acc[mt][nt], al[mt], bh[nt]);
                }
        }
        __syncthreads();
    }

    // epilogue
    #pragma unroll
    for (int mt = 0; mt < 2; mt++) {
        #pragma unroll
        for (int nt = 0; nt < 8; nt++) {
            int rbase = m0 + wm * 32 + mt * 16 + (lid >> 2);
            int col = n0 + wn * 64 + nt * 8 + (lid & 3) * 2;
            #pragma unroll
            for (int h = 0; h < 2; h++) {
                int m = rbase + h * 8;
                float v0 = acc[mt][nt][h * 2 + 0];
                float v1 = acc[mt][nt][h * 2 + 1];
                if (MODE == 0) {
                    size_t idx = (size_t)m * N + col;
                    if (residual) {
                        if (col     < N) v0 += residual[idx];
                        if (col + 1 < N) v1 += residual[idx + 1];
                    }
                    if (col     < N) C[idx]     = v0;
                    if (col + 1 < N) C[idx + 1] = v1;
                } else if (MODE == 1) {
                    if (m < M) {
                        size_t idx = (size_t)m * N + col;
                        C[idx]     = v0;
                        C[idx + 1] = v1;
                    }
                } else {
                    if (m < M) {
                        int tok = ridx[m];
                        float w = rwt[m];
                        size_t idx = (size_t)tok * N + col;
                        atomicAdd(&C[idx],     w * v0);
                        atomicAdd(&C[idx + 1], w * v1);
                    }
                }
            }
        }
    }
}

// ---------------- embedding ----------------
__global__ void embed_kernel(const int* __restrict__ tok,
                             const float* __restrict__ emb,
                             float* __restrict__ x) {
    int t = blockIdx.x;
    int tk = tok[t];
    for (int d = threadIdx.x; d < D_MODEL; d += 256)
        x[(size_t)t*D_MODEL + d] = emb[(size_t)tk*D_MODEL + d];
}

// ---------------- RoPE ----------------
__global__ void rope_kernel(float* __restrict__ q, float* __restrict__ k) {
    int t = blockIdx.x, h = blockIdx.y, i = threadIdx.x;
    float inv = powf(10000.f, -((float)(2*i)) / 64.f);
    float ang = (float)t * inv;
    float s, c;
    sincosf(ang, &s, &c);
    size_t base = (size_t)t*D_MODEL + h*HEAD_DIM + 2*i;
    float q0 = q[base], q1 = q[base+1];
    q[base]   = q0*c - q1*s;
    q[base+1] = q0*s + q1*c;
    float k0 = k[base], k1 = k[base+1];
    k[base]   = k0*c - k1*s;
    k[base+1] = k0*s + k1*c;
}

// ---------------- blocked attention (exact ref semantics) ----------------
#define ATTN_SMEM (4 * 64 * 65 * 4)
__global__ void __launch_bounds__(256) attn_kernel(
    const float* __restrict__ q, const float* __restrict__ k,
    const float* __restrict__ v, float* __restrict__ o)
{
    extern __shared__ float sm[];
    float* Qs = sm;
    float* Ks = Qs + 64*65;
    float* Vs = Ks + 64*65;
    float* Ps = Vs + 64*65;
    const int ib = blockIdx.x, h = blockIdx.y;
    const int tid = threadIdx.x;
    const int qr  = tid >> 2;
    const int c0  = (tid & 3) * 16;

    for (int idx = tid; idx < 64*64; idx += 256) {
        int r = idx >> 6, c = idx & 63;
        Qs[r*65 + c] = q[(size_t)(ib*64+r)*D_MODEL + h*HEAD_DIM + c];
    }

    float accO[16];
    #pragma unroll
    for (int i = 0; i < 16; i++) accO[i] = 0.f;
    float den = 0.f;

    for (int jb = 0; jb <= ib; jb++) {
        __syncthreads();
        for (int idx = tid; idx < 64*64; idx += 256) {
            int r = idx >> 6, c = idx & 63;
            Ks[r*65 + c] = k[(size_t)(jb*64+r)*D_MODEL + h*HEAD_DIM + c];
            Vs[r*65 + c] = v[(size_t)(jb*64+r)*D_MODEL + h*HEAD_DIM + c];
        }
        __syncthreads();

        float s[16];
        float mx = -1e30f;
        #pragma unroll
        for (int cc = 0; cc < 16; cc++) {
            int c = c0 + cc;
            float dot = 0.f;
            #pragma unroll
            for (int d = 0; d < 64; d++)
                dot = fmaf(Qs[qr*65 + d], Ks[c*65 + d], dot);
            dot *= 0.125f;
            if (jb == ib && c > qr) dot = -1e30f;
            s[cc] = dot;
            mx = fmaxf(mx, dot);
        }
        mx = fmaxf(mx, __shfl_xor_sync(0xffffffffu, mx, 1));
        mx = fmaxf(mx, __shfl_xor_sync(0xffffffffu, mx, 2));

        #pragma unroll
        for (int cc = 0; cc < 16; cc++) {
            float p = expf(s[cc] - mx);
            Ps[qr*65 + c0 + cc] = p;
            den += p;
        }
        __syncthreads();

        #pragma unroll 8
        for (int kk = 0; kk < 64; kk++) {
            float pv = Ps[qr*65 + kk];
            #pragma unroll
            for (int d = 0; d < 16; d++)
                accO[d] = fmaf(pv, Vs[kk*65 + c0 + d], accO[d]);
        }
    }

    den += __shfl_xor_sync(0xffffffffu, den, 1);
    den += __shfl_xor_sync(0xffffffffu, den, 2);
    float invd = 1.f / (den + 1e-6f);
    #pragma unroll
    for (int d = 0; d < 16; d++)
        o[(size_t)(ib*64+qr)*D_MODEL + h*HEAD_DIM + c0 + d] = accO[d] * invd;
}

// ---------------- layernorm ----------------
__global__ void __launch_bounds__(256) ln_kernel(
    const float* __restrict__ in, const float* __restrict__ res,
    const float* __restrict__ g, const float* __restrict__ b,
    float* __restrict__ out)
{
    __shared__ float red[256];
    int t = blockIdx.x, tid = threadIdx.x;
    float v[8];
    float sum = 0.f;
    #pragma unroll
    for (int i = 0; i < 8; i++) {
        int d = i*256 + tid;
        float x = in[(size_t)t*D_MODEL + d];
        if (res) x += res[(size_t)t*D_MODEL + d];
        v[i] = x; sum += x;
    }
    red[tid] = sum; __syncthreads();
    for (int s = 128; s > 0; s >>= 1) { if (tid < s) red[tid] += red[tid+s]; __syncthreads(); }
    float mu = red[0] / D_MODEL;
    __syncthreads();
    float sq = 0.f;
    #pragma unroll
    for (int i = 0; i < 8; i++) { float d0 = v[i] - mu; sq += d0*d0; }
    red[tid] = sq; __syncthreads();
    for (int s = 128; s > 0; s >>= 1) { if (tid < s) red[tid] += red[tid+s]; __syncthreads(); }
    float rstd = rsqrtf(red[0] / D_MODEL + 1e-5f);
    #pragma unroll
    for (int i = 0; i < 8; i++) {
        int d = i*256 + tid;
        out[(size_t)t*D_MODEL + d] = (v[i] - mu) * rstd * g[d] + b[d];
    }
}

// ---------------- MoE gate ----------------
__global__ void __launch_bounds__(128) gate_kernel(
    const float* __restrict__ x, const float* __restrict__ gw,
    float* __restrict__ wts, float* __restrict__ varr)
{
    __shared__ float red[128];
    __shared__ float logit[4];
    int t = blockIdx.x, tid = threadIdx.x;
    float p[4] = {0.f, 0.f, 0.f, 0.f};
    for (int d = tid; d < D_MODEL; d += 128) {
        float xv = x[(size_t)t*D_MODEL + d];
        #pragma unroll
        for (int e = 0; e < 4; e++)
            p[e] = fmaf(xv, gw[e*D_MODEL + d], p[e]);
    }
    for (int e = 0; e < 4; e++) {
        red[tid] = p[e]; __syncthreads();
        for (int s = 64; s > 0; s >>= 1) { if (tid < s) red[tid] += red[tid+s]; __syncthreads(); }
        if (tid == 0) logit[e] = red[0];
        __syncthreads();
    }
    if (tid == 0) {
        float l[4] = {logit[0], logit[1], logit[2], logit[3]};
        float mx = fmaxf(fmaxf(l[0], l[1]), fmaxf(l[2], l[3]));
        float ex[4], ssum = 0.f;
        for (int e = 0; e < 4; e++) { ex[e] = expf(l[e] - mx); ssum += ex[e]; }
        float pr[4];
        for (int e = 0; e < 4; e++) pr[e] = ex[e] / ssum;
        int b1 = 0;
        for (int e = 1; e < 4; e++) if (pr[e] > pr[b1]) b1 = e;
        int b2 = -1;
        for (int e = 0; e < 4; e++) { if (e == b1) continue; if (b2 < 0 || pr[e] > pr[b2]) b2 = e; }
        float s2 = pr[b1] + pr[b2];
        float wv[4] = {0.f, 0.f, 0.f, 0.f};
        wv[b1] = pr[b1] / s2; wv[b2] = pr[b2] / s2;
        for (int e = 0; e < 4; e++) wts[e*SEQ + t] = wv[e];
        float mu = (l[0]+l[1]+l[2]+l[3]) * 0.25f;
        float va = ((l[0]-mu)*(l[0]-mu) + (l[1]-mu)*(l[1]-mu) +
                    (l[2]-mu)*(l[2]-mu) + (l[3]-mu)*(l[3]-mu)) / 3.f;
        varr[t] = va;
    }
}

// ---------------- routing: deterministic compaction (prefix scan) ----------------
__global__ void __launch_bounds__(1024) compact_kernel(
    const float* __restrict__ wts, int* __restrict__ cnt,
    int* __restrict__ ridx, float* __restrict__ rwt)
{
    __shared__ int sc[1024];
    int e = blockIdx.x, t = threadIdx.x;
    float w = wts[e*SEQ + t];
    int flag = (w != 0.f) ? 1 : 0;
    sc[t] = flag;
    __syncthreads();
    for (int off = 1; off < 1024; off <<= 1) {
        int v = (t >= off) ? sc[t - off] : 0;
        __syncthreads();
        sc[t] += v;
        __syncthreads();
    }
    if (flag) {
        int pos = sc[t] - 1;
        ridx[e*SEQ + pos] = t;
        rwt [e*SEQ + pos] = w;
    }
    if (t == 1023) cnt[e] = sc[1023];
}

// gather split-bf16 rows into contiguous per-expert buffers
__global__ void __launch_bounds__(256) gather_kernel(
    const __nv_bfloat16* __restrict__ ah, const __nv_bfloat16* __restrict__ al,
    const int* __restrict__ ridx, const int* __restrict__ cnt,
    __nv_bfloat16* __restrict__ gh, __nv_bfloat16* __restrict__ gl)
{
    int row = blockIdx.x;
    if (row >= *cnt) return;
    int tok = ridx[row];
    const uint4* sh = (const uint4*)(ah + (size_t)tok*D_MODEL);
    const uint4* sl = (const uint4*)(al + (size_t)tok*D_MODEL);
    uint4* dh = (uint4*)(gh + (size_t)row*D_MODEL);
    uint4* dl = (uint4*)(gl + (size_t)row*D_MODEL);
    int c = threadIdx.x;      // exactly 256 16B chunks per 2048-bf16 row
    dh[c] = sh[c];
    dl[c] = sl[c];
}

// fused silu(h1)*h3 -> split bf16 (routed rows)
__global__ void __launch_bounds__(256) silu_split_kernel(
    const float* __restrict__ h1, const float* __restrict__ h3,
    const int* __restrict__ cnt,
    __nv_bfloat16* __restrict__ ch, __nv_bfloat16* __restrict__ cl)
{
    int row = blockIdx.x;
    if (row >= *cnt) return;
    size_t base = (size_t)row * D_FFN;
    for (int c = threadIdx.x; c < D_FFN; c += 256) {
        float a = h1[base + c];
        float v = a / (1.f + expf(-a)) * h3[base + c];
        __nv_bfloat16 hi = __float2bfloat16(v);
        ch[base + c] = hi;
        cl[base + c] = __float2bfloat16(v - __bfloat162float(hi));
    }
}

__global__ void aux_kernel(const float* __restrict__ varr, float* __restrict__ out) {
    __shared__ float red[256];
    int tid = threadIdx.x;
    float s = 0.f;
    for (int i = tid; i < SEQ; i += 256) s += varr[i];
    red[tid] = s; __syncthreads();
    for (int st = 128; st > 0; st >>= 1) { if (tid < st) red[tid] += red[tid+st]; __syncthreads(); }
    if (tid == 0) out[0] = red[0] / (float)SEQ;
}

__global__ void zero_kernel(float* __restrict__ p, int n) {
    int i = blockIdx.x * 256 + threadIdx.x;
    if (i < n) p[i] = 0.f;
}

// ---------------- driver ----------------
static inline void split(const float* src, __nv_bfloat16* hi, __nv_bfloat16* lo, long long n) {
    int n4 = (int)(n / 4);
    split_kernel<<<(n4 + 255)/256, 256>>>(src, hi, lo, n4);
}

extern "C" void kernel_launch(void* const* d_in, const int* in_sizes, int n_in,
                              void* d_out, int out_size) {
    const int*   tokens = (const int*)  d_in[0];
    const float* emb    = (const float*)d_in[1];
    const float* wq     = (const float*)d_in[2];
    const float* wk     = (const float*)d_in[3];
    const float* wv     = (const float*)d_in[4];
    const float* wo     = (const float*)d_in[5];
    const float* ln1g   = (const float*)d_in[6];
    const float* ln1b   = (const float*)d_in[7];
    const float* gatew  = (const float*)d_in[8];
    const float* w1     = (const float*)d_in[9];
    const float* w2     = (const float*)d_in[10];
    const float* w3     = (const float*)d_in[11];
    const float* ln2g   = (const float*)d_in[12];
    const float* ln2b   = (const float*)d_in[13];
    const float* fing   = (const float*)d_in[14];
    const float* finb   = (const float*)d_in[15];
    const float* headw  = (const float*)d_in[16];
    float* out = (float*)d_out;

    float *x, *q, *k, *v, *att, *y, *h1, *h3, *moe, *wts, *varr, *rwt;
    int *cnt, *ridx;
    __nv_bfloat16 *ah, *al, *gxh, *gxl, *ch, *cl, *bh, *bl;
    cudaGetSymbolAddress((void**)&x,    g_x);
    cudaGetSymbolAddress((void**)&q,    g_q);
    cudaGetSymbolAddress((void**)&k,    g_k);
    cudaGetSymbolAddress((void**)&v,    g_v);
    cudaGetSymbolAddress((void**)&att,  g_att);
    cudaGetSymbolAddress((void**)&y,    g_y);
    cudaGetSymbolAddress((void**)&h1,   g_h1);
    cudaGetSymbolAddress((void**)&h3,   g_h3);
    cudaGetSymbolAddress((void**)&moe,  g_moe);
    cudaGetSymbolAddress((void**)&wts,  g_wts);
    cudaGetSymbolAddress((void**)&varr, g_var);
    cudaGetSymbolAddress((void**)&cnt,  g_cnt);
    cudaGetSymbolAddress((void**)&ridx, g_ridx);
    cudaGetSymbolAddress((void**)&rwt,  g_rwt);
    cudaGetSymbolAddress((void**)&ah,   g_ah);
    cudaGetSymbolAddress((void**)&al,   g_al);
    cudaGetSymbolAddress((void**)&gxh,  g_gxh);
    cudaGetSymbolAddress((void**)&gxl,  g_gxl);
    cudaGetSymbolAddress((void**)&ch,   g_ch);
    cudaGetSymbolAddress((void**)&cl,   g_cl);
    cudaGetSymbolAddress((void**)&bh,   g_bh);
    cudaGetSymbolAddress((void**)&bl,   g_bl);

    cudaFuncSetAttribute(attn_kernel, cudaFuncAttributeMaxDynamicSharedMemorySize, ATTN_SMEM);
    cudaFuncSetAttribute(gemm_tc<0>, cudaFuncAttributeMaxDynamicSharedMemorySize, GEMM_SMEM);
    cudaFuncSetAttribute(gemm_tc<1>, cudaFuncAttributeMaxDynamicSharedMemorySize, GEMM_SMEM);
    cudaFuncSetAttribute(gemm_tc<2>, cudaFuncAttributeMaxDynamicSharedMemorySize, GEMM_SMEM);

    // 1) embed + split x
    embed_kernel<<<SEQ, 256>>>(tokens, emb, x);
    split(x, ah, al, (long long)SEQ * D_MODEL);

    // 2) q,k,v projections
    dim3 gA(D_MODEL/128, SEQ/128);
    split(wq, bh, bl, (long long)D_MODEL * D_MODEL);
    gemm_tc<0><<<gA, 256, GEMM_SMEM>>>(ah, al, bh, bl, q, SEQ, D_MODEL, D_MODEL, nullptr, nullptr, nullptr, nullptr);
    split(wk, bh, bl, (long long)D_MODEL * D_MODEL);
    gemm_tc<0><<<gA, 256, GEMM_SMEM>>>(ah, al, bh, bl, k, SEQ, D_MODEL, D_MODEL, nullptr, nullptr, nullptr, nullptr);
    split(wv, bh, bl, (long long)D_MODEL * D_MODEL);
    gemm_tc<0><<<gA, 256, GEMM_SMEM>>>(ah, al, bh, bl, v, SEQ, D_MODEL, D_MODEL, nullptr, nullptr, nullptr, nullptr);

    // 3) RoPE
    rope_kernel<<<dim3(SEQ, N_HEADS), 32>>>(q, k);

    // 4) attention
    attn_kernel<<<dim3(NB, N_HEADS), 256, ATTN_SMEM>>>(q, k, v, att);

    // 5) output proj + residual
    split(att, ah, al, (long long)SEQ * D_MODEL);
    split(wo, bh, bl, (long long)D_MODEL * D_MODEL);
    gemm_tc<0><<<gA, 256, GEMM_SMEM>>>(ah, al, bh, bl, y, SEQ, D_MODEL, D_MODEL, x, nullptr, nullptr, nullptr);

    // 6) LN1 -> x, split for MoE
    ln_kernel<<<SEQ, 256>>>(y, nullptr, ln1g, ln1b, x);
    split(x, ah, al, (long long)SEQ * D_MODEL);

    // 7) gate + deterministic routing
    gate_kernel<<<SEQ, 128>>>(x, gatew, wts, varr);
    compact_kernel<<<NEXP, 1024>>>(wts, cnt, ridx, rwt);

    // 8) MoE: routed experts
    zero_kernel<<<(SEQ*D_MODEL + 255)/256, 256>>>(moe, SEQ*D_MODEL);
    dim3 gF(D_FFN/128, SEQ/128);
    for (int e = 0; e < NEXP; e++) {
        const float* w1e = w1 + (size_t)e * D_FFN * D_MODEL;
        const float* w3e = w3 + (size_t)e * D_FFN * D_MODEL;
        const float* w2e = w2 + (size_t)e * D_MODEL * D_FFN;
        const int*   ce  = cnt + e;
        const int*   ie  = ridx + e * SEQ;
        const float* we  = rwt + e * SEQ;

        gather_kernel<<<SEQ, 256>>>(ah, al, ie, ce, gxh, gxl);
        split(w1e, bh, bl, (long long)D_FFN * D_MODEL);
        gemm_tc<1><<<gF, 256, GEMM_SMEM>>>(gxh, gxl, bh, bl, h1, 0, D_FFN, D_MODEL, nullptr, ce, nullptr, nullptr);
        split(w3e, bh, bl, (long long)D_FFN * D_MODEL);
        gemm_tc<1><<<gF, 256, GEMM_SMEM>>>(gxh, gxl, bh, bl, h3, 0, D_FFN, D_MODEL, nullptr, ce, nullptr, nullptr);
        silu_split_kernel<<<SEQ, 256>>>(h1, h3, ce, ch, cl);
        split(w2e, bh, bl, (long long)D_MODEL * D_FFN);
        gemm_tc<2><<<gA, 256, GEMM_SMEM>>>(ch, cl, bh, bl, moe, 0, D_MODEL, D_FFN, nullptr, ce, ie, we);
    }

    // 9) LN2 + final LN
    ln_kernel<<<SEQ, 256>>>(moe, x, ln2g, ln2b, y);
    ln_kernel<<<SEQ, 256>>>(y, nullptr, fing, finb, x);

    // 10) head
    split(x, ah, al, (long long)SEQ * D_MODEL);
    split(headw, bh, bl, (long long)VOCAB * D_MODEL);
    dim3 gH((VOCAB + 127)/128, SEQ/128);
    gemm_tc<0><<<gH, 256, GEMM_SMEM>>>(ah, al, bh, bl, out, SEQ, VOCAB, D_MODEL, nullptr, nullptr, nullptr, nullptr);

    // 11) aux
    long long nlog = (long long)SEQ * VOCAB;
    if ((long long)out_size > nlog)
        aux_kernel<<<1, 256>>>(varr, out + nlog);
}

// round 6
// speedup vs baseline: 3.3011x; 1.1452x over previous
#include <cuda_runtime.h>
#include <cuda_bf16.h>
#include <math.h>
#include <stdint.h>

#define D_MODEL 2048
#define SEQ     1024
#define N_HEADS 32
#define HEAD_DIM 64
#define NB      (SEQ/64)
#define D_FFN   8192
#define VOCAB   50257
#define NEXP    4
#define QKV_STRIDE (3*D_MODEL)

// ---------------- scratch ----------------
__device__ float g_x  [SEQ*D_MODEL];
__device__ float g_qkv[SEQ*3*D_MODEL];
__device__ float g_att[SEQ*D_MODEL];
__device__ float g_y  [SEQ*D_MODEL];
__device__ float g_h13[SEQ*2*D_FFN];
__device__ float g_moe[SEQ*D_MODEL];
__device__ float g_wts[NEXP*SEQ];
__device__ float g_var[SEQ];

// routing
__device__ int   g_cnt[NEXP];
__device__ int   g_ridx[NEXP*SEQ];
__device__ float g_rwt [NEXP*SEQ];

// bf16 split scratch
__device__ __nv_bfloat16 g_ah[SEQ*D_MODEL];
__device__ __nv_bfloat16 g_al[SEQ*D_MODEL];
__device__ __nv_bfloat16 g_gxh[SEQ*D_MODEL];
__device__ __nv_bfloat16 g_gxl[SEQ*D_MODEL];
__device__ __nv_bfloat16 g_ch[SEQ*D_FFN];
__device__ __nv_bfloat16 g_cl[SEQ*D_FFN];
__device__ __nv_bfloat16 g_bh[(size_t)2*D_FFN*D_MODEL];  // weights (max: w1+w3 = 33.5M)
__device__ __nv_bfloat16 g_bl[(size_t)2*D_FFN*D_MODEL];

// ---------------- PTX helpers ----------------
__device__ __forceinline__ uint32_t smem_u32(const void* p) {
    uint32_t a;
    asm("{ .reg .u64 t; cvta.to.shared.u64 t, %1; cvt.u32.u64 %0, t; }" : "=r"(a) : "l"(p));
    return a;
}
__device__ __forceinline__ void cp_async16(uint32_t dst, const void* src, int src_bytes) {
    asm volatile("cp.async.cg.shared.global [%0], [%1], 16, %2;\n"
                 :: "r"(dst), "l"(src), "r"(src_bytes) : "memory");
}
#define CP_COMMIT() asm volatile("cp.async.commit_group;\n" ::: "memory")

__device__ __forceinline__ void ldsm_x4(uint32_t& r0, uint32_t& r1, uint32_t& r2, uint32_t& r3,
                                        uint32_t addr) {
    asm volatile("ldmatrix.sync.aligned.m8n8.x4.shared.b16 {%0,%1,%2,%3}, [%4];"
                 : "=r"(r0), "=r"(r1), "=r"(r2), "=r"(r3) : "r"(addr));
}
__device__ __forceinline__ void mma_bf16(float* c, const uint32_t* a, const uint32_t* b) {
    asm volatile(
        "mma.sync.aligned.m16n8k16.row.col.f32.bf16.bf16.f32 "
        "{%0,%1,%2,%3}, {%4,%5,%6,%7}, {%8,%9}, {%0,%1,%2,%3};"
        : "+f"(c[0]), "+f"(c[1]), "+f"(c[2]), "+f"(c[3])
        : "r"(a[0]), "r"(a[1]), "r"(a[2]), "r"(a[3]), "r"(b[0]), "r"(b[1]));
}
__device__ __forceinline__ void mma_tf32(float* c, const uint32_t* a, const uint32_t* b) {
    asm volatile(
        "mma.sync.aligned.m16n8k8.row.col.f32.tf32.tf32.f32 "
        "{%0,%1,%2,%3}, {%4,%5,%6,%7}, {%8,%9}, {%0,%1,%2,%3};"
        : "+f"(c[0]), "+f"(c[1]), "+f"(c[2]), "+f"(c[3])
        : "r"(a[0]), "r"(a[1]), "r"(a[2]), "r"(a[3]), "r"(b[0]), "r"(b[1]));
}

// ---------------- fp32 -> (bf16 hi, bf16 lo) split ----------------
__global__ void __launch_bounds__(256) split_kernel(
    const float* __restrict__ in, __nv_bfloat16* __restrict__ hi,
    __nv_bfloat16* __restrict__ lo, int n4)
{
    int i = blockIdx.x * 256 + threadIdx.x;
    if (i >= n4) return;
    float4 v = ((const float4*)in)[i];
    __nv_bfloat16 h0 = __float2bfloat16(v.x);
    __nv_bfloat16 h1 = __float2bfloat16(v.y);
    __nv_bfloat16 h2 = __float2bfloat16(v.z);
    __nv_bfloat16 h3 = __float2bfloat16(v.w);
    __nv_bfloat162 hh0; hh0.x = h0; hh0.y = h1;
    __nv_bfloat162 hh1; hh1.x = h2; hh1.y = h3;
    __nv_bfloat162 ll0, ll1;
    ll0.x = __float2bfloat16(v.x - __bfloat162float(h0));
    ll0.y = __float2bfloat16(v.y - __bfloat162float(h1));
    ll1.x = __float2bfloat16(v.z - __bfloat162float(h2));
    ll1.y = __float2bfloat16(v.w - __bfloat162float(h3));
    ((__nv_bfloat162*)hi)[i*2]   = hh0;
    ((__nv_bfloat162*)hi)[i*2+1] = hh1;
    ((__nv_bfloat162*)lo)[i*2]   = ll0;
    ((__nv_bfloat162*)lo)[i*2+1] = ll1;
}

// ================= bf16x3 GEMM =================
#define NSTG 5
#define GEMM_SMEM (NSTG * 2 * 128 * 128)

// MODE 0: C[m,n] = val (+residual)
// MODE 1: routed rows: M from *Mptr, plain store
// MODE 2: routed rows: M from *Mptr, atomicAdd(C[ridx[m]*N+n], rwt[m]*val)
template<int MODE>
__global__ void __launch_bounds__(256, 1) gemm_tc(
    const __nv_bfloat16* __restrict__ Ah, const __nv_bfloat16* __restrict__ Al,
    const __nv_bfloat16* __restrict__ Bh, const __nv_bfloat16* __restrict__ Bl,
    float* __restrict__ C, int M_in, int N, int K,
    const float* __restrict__ residual,
    const int* __restrict__ Mptr, const int* __restrict__ ridx,
    const float* __restrict__ rwt)
{
    int M = M_in;
    if (MODE != 0) {
        M = *Mptr;
        if ((int)blockIdx.y * 128 >= M) return;
    }
    extern __shared__ char smem[];
    const uint32_t sb = smem_u32(smem);
    const int tid = threadIdx.x;
    const int wid = tid >> 5, lid = tid & 31;
    const int wm  = wid >> 1, wn = wid & 1;
    const int m0  = blockIdx.y * 128;
    const int n0  = blockIdx.x * 128;

    constexpr int STAGE = 2 * 128 * 128;

    float acc[2][8][4];
    #pragma unroll
    for (int i = 0; i < 2; i++)
        #pragma unroll
        for (int j = 0; j < 8; j++)
            #pragma unroll
            for (int t = 0; t < 4; t++) acc[i][j][t] = 0.f;

    const int iters = K >> 5;

    auto fill = [&](int stage, int kit) {
        const int k0 = kit << 5;
        const uint32_t abase = sb + stage * STAGE;
        const uint32_t bbase = abase + 128 * 128;
        #pragma unroll
        for (int i = 0; i < 4; i++) {
            int idx = tid + i * 256;
            int r = idx >> 3, c = idx & 7;
            int rg = m0 + r;
            if (MODE != 0) rg = rg < M ? rg : (M - 1);
            uint32_t dst = abase + r * 128 + ((c ^ (r & 7)) << 4);
            const __nv_bfloat16* src = (c < 4)
                ? Ah + (size_t)rg * K + k0 + c * 8
                : Al + (size_t)rg * K + k0 + (c - 4) * 8;
            cp_async16(dst, src, 16);
        }
        #pragma unroll
        for (int i = 0; i < 4; i++) {
            int idx = tid + i * 256;
            int r = idx >> 3, c = idx & 7;
            uint32_t dst = bbase + r * 128 + ((c ^ (r & 7)) << 4);
            int rg = n0 + r;
            int rc = rg < N ? rg : (N - 1);
            const __nv_bfloat16* src = (c < 4)
                ? Bh + (size_t)rc * K + k0 + c * 8
                : Bl + (size_t)rc * K + k0 + (c - 4) * 8;
            cp_async16(dst, src, rg < N ? 16 : 0);
        }
        CP_COMMIT();
    };

    #pragma unroll
    for (int s = 0; s < NSTG - 1; s++) fill(s, s);

    const int grp = lid >> 3;
    const int rin = lid & 7;

    for (int i = 0; i < iters; i++) {
        const int s = i % NSTG;
        asm volatile("cp.async.wait_group %0;\n" :: "n"(NSTG - 2));
        __syncthreads();   // single barrier per iter (orders prior reads + data ready)

        if (i + NSTG - 1 < iters) fill((i + NSTG - 1) % NSTG, i + NSTG - 1);
        else CP_COMMIT();

        const uint32_t abase = sb + s * STAGE;
        const uint32_t bbase = abase + 128 * 128;

        #pragma unroll
        for (int g = 0; g < 2; g++) {
            uint32_t ah[2][4], al[2][4], bh[8][2], bl[8][2];
            #pragma unroll
            for (int mt = 0; mt < 2; mt++) {
                int row = wm * 32 + mt * 16 + (grp & 1) * 8 + rin;
                int kch = 2 * g + (grp >> 1);
                uint32_t ad = abase + row * 128 + ((kch ^ (row & 7)) << 4);
                ldsm_x4(ah[mt][0], ah[mt][1], ah[mt][2], ah[mt][3], ad);
                int kcl = 4 + 2 * g + (grp >> 1);
                uint32_t adl = abase + row * 128 + ((kcl ^ (row & 7)) << 4);
                ldsm_x4(al[mt][0], al[mt][1], al[mt][2], al[mt][3], adl);
            }
            #pragma unroll
            for (int p = 0; p < 4; p++) {
                int tile = 2 * p + (grp >> 1);
                int row  = wn * 64 + tile * 8 + rin;
                int kch  = 2 * g + (grp & 1);
                uint32_t bd = bbase + row * 128 + ((kch ^ (row & 7)) << 4);
                ldsm_x4(bh[2*p][0], bh[2*p][1], bh[2*p+1][0], bh[2*p+1][1], bd);
                int kcl  = 4 + 2 * g + (grp & 1);
                uint32_t bdl = bbase + row * 128 + ((kcl ^ (row & 7)) << 4);
                ldsm_x4(bl[2*p][0], bl[2*p][1], bl[2*p+1][0], bl[2*p+1][1], bdl);
            }
            #pragma unroll
            for (int mt = 0; mt < 2; mt++)
                #pragma unroll
                for (int nt = 0; nt < 8; nt++) {
                    mma_bf16(acc[mt][nt], ah[mt], bh[nt]);
                    mma_bf16(acc[mt][nt], ah[mt], bl[nt]);
                    mma_bf16(acc[mt][nt], al[mt], bh[nt]);
                }
        }
        // no bottom barrier: top-of-next-iter barrier provides the ordering
    }

    #pragma unroll
    for (int mt = 0; mt < 2; mt++) {
        #pragma unroll
        for (int nt = 0; nt < 8; nt++) {
            int rbase = m0 + wm * 32 + mt * 16 + (lid >> 2);
            int col = n0 + wn * 64 + nt * 8 + (lid & 3) * 2;
            #pragma unroll
            for (int h = 0; h < 2; h++) {
                int m = rbase + h * 8;
                float v0 = acc[mt][nt][h * 2 + 0];
                float v1 = acc[mt][nt][h * 2 + 1];
                if (MODE == 0) {
                    size_t idx = (size_t)m * N + col;
                    if (residual) {
                        if (col     < N) v0 += residual[idx];
                        if (col + 1 < N) v1 += residual[idx + 1];
                    }
                    if (col     < N) C[idx]     = v0;
                    if (col + 1 < N) C[idx + 1] = v1;
                } else if (MODE == 1) {
                    if (m < M) {
                        size_t idx = (size_t)m * N + col;
                        C[idx]     = v0;
                        C[idx + 1] = v1;
                    }
                } else {
                    if (m < M) {
                        int tok = ridx[m];
                        float w = rwt[m];
                        size_t idx = (size_t)tok * N + col;
                        atomicAdd(&C[idx],     w * v0);
                        atomicAdd(&C[idx + 1], w * v1);
                    }
                }
            }
        }
    }
}

// ================= tf32 single-pass GEMM (head) =================
__global__ void __launch_bounds__(256, 1) gemm_tf32(
    const float* __restrict__ A, const float* __restrict__ B,
    float* __restrict__ C, int M, int N, int K)
{
    extern __shared__ char smem[];
    const uint32_t sb = smem_u32(smem);
    const int tid = threadIdx.x;
    const int wid = tid >> 5, lid = tid & 31;
    const int wm  = wid >> 1, wn = wid & 1;
    const int m0  = blockIdx.y * 128;
    const int n0  = blockIdx.x * 128;

    constexpr int STAGE = 2 * 128 * 128;

    float acc[2][8][4];
    #pragma unroll
    for (int i = 0; i < 2; i++)
        #pragma unroll
        for (int j = 0; j < 8; j++)
            #pragma unroll
            for (int t = 0; t < 4; t++) acc[i][j][t] = 0.f;

    const int iters = K >> 5;

    auto fill = [&](int stage, int kit) {
        const int k0 = kit << 5;
        const uint32_t abase = sb + stage * STAGE;
        const uint32_t bbase = abase + 128 * 128;
        #pragma unroll
        for (int i = 0; i < 4; i++) {
            int idx = tid + i * 256;
            int r = idx >> 3, c = idx & 7;
            uint32_t dst = abase + r * 128 + ((c ^ (r & 7)) << 4);
            cp_async16(dst, A + (size_t)(m0 + r) * K + k0 + c * 4, 16);
        }
        #pragma unroll
        for (int i = 0; i < 4; i++) {
            int idx = tid + i * 256;
            int r = idx >> 3, c = idx & 7;
            uint32_t dst = bbase + r * 128 + ((c ^ (r & 7)) << 4);
            int rg = n0 + r;
            int rc = rg < N ? rg : (N - 1);
            cp_async16(dst, B + (size_t)rc * K + k0 + c * 4, rg < N ? 16 : 0);
        }
        CP_COMMIT();
    };

    #pragma unroll
    for (int s = 0; s < NSTG - 1; s++) fill(s, s);

    const int grp = lid >> 3;
    const int rin = lid & 7;

    for (int i = 0; i < iters; i++) {
        const int s = i % NSTG;
        asm volatile("cp.async.wait_group %0;\n" :: "n"(NSTG - 2));
        __syncthreads();

        if (i + NSTG - 1 < iters) fill((i + NSTG - 1) % NSTG, i + NSTG - 1);
        else CP_COMMIT();

        const uint32_t abase = sb + s * STAGE;
        const uint32_t bbase = abase + 128 * 128;

        #pragma unroll
        for (int k8 = 0; k8 < 4; k8++) {
            uint32_t a[2][4], b[8][2];
            #pragma unroll
            for (int mt = 0; mt < 2; mt++) {
                int row = wm * 32 + mt * 16 + (grp & 1) * 8 + rin;
                int kc  = k8 * 2 + (grp >> 1);
                uint32_t addr = abase + row * 128 + ((kc ^ (row & 7)) << 4);
                ldsm_x4(a[mt][0], a[mt][1], a[mt][2], a[mt][3], addr);
            }
            #pragma unroll
            for (int p = 0; p < 4; p++) {
                int tile = 2 * p + (grp >> 1);
                int row  = wn * 64 + tile * 8 + rin;
                int kc   = k8 * 2 + (grp & 1);
                uint32_t addr = bbase + row * 128 + ((kc ^ (row & 7)) << 4);
                ldsm_x4(b[2*p][0], b[2*p][1], b[2*p+1][0], b[2*p+1][1], addr);
            }
            #pragma unroll
            for (int mt = 0; mt < 2; mt++)
                #pragma unroll
                for (int nt = 0; nt < 8; nt++)
                    mma_tf32(acc[mt][nt], a[mt], b[nt]);
        }
    }

    #pragma unroll
    for (int mt = 0; mt < 2; mt++) {
        #pragma unroll
        for (int nt = 0; nt < 8; nt++) {
            int rbase = m0 + wm * 32 + mt * 16 + (lid >> 2);
            int col = n0 + wn * 64 + nt * 8 + (lid & 3) * 2;
            #pragma unroll
            for (int h = 0; h < 2; h++) {
                int m = rbase + h * 8;
                size_t idx = (size_t)m * N + col;
                if (col     < N) C[idx]     = acc[mt][nt][h * 2 + 0];
                if (col + 1 < N) C[idx + 1] = acc[mt][nt][h * 2 + 1];
            }
        }
    }
}

// ---------------- embedding ----------------
__global__ void embed_kernel(const int* __restrict__ tok,
                             const float* __restrict__ emb,
                             float* __restrict__ x) {
    int t = blockIdx.x;
    int tk = tok[t];
    for (int d = threadIdx.x; d < D_MODEL; d += 256)
        x[(size_t)t*D_MODEL + d] = emb[(size_t)tk*D_MODEL + d];
}

// ---------------- RoPE (on strided qkv buffer) ----------------
__global__ void rope_kernel(float* __restrict__ qkv) {
    int t = blockIdx.x, h = blockIdx.y, i = threadIdx.x;
    float inv = powf(10000.f, -((float)(2*i)) / 64.f);
    float ang = (float)t * inv;
    float s, c;
    sincosf(ang, &s, &c);
    size_t base = (size_t)t*QKV_STRIDE + h*HEAD_DIM + 2*i;
    float q0 = qkv[base], q1 = qkv[base+1];
    qkv[base]   = q0*c - q1*s;
    qkv[base+1] = q0*s + q1*c;
    size_t kb = base + D_MODEL;
    float k0 = qkv[kb], k1 = qkv[kb+1];
    qkv[kb]   = k0*c - k1*s;
    qkv[kb+1] = k0*s + k1*c;
}

// ---------------- blocked attention (exact ref semantics) ----------------
#define ATTN_SMEM (4 * 64 * 65 * 4)
__global__ void __launch_bounds__(256) attn_kernel(
    const float* __restrict__ qkv, float* __restrict__ o)
{
    extern __shared__ float sm[];
    float* Qs = sm;
    float* Ks = Qs + 64*65;
    float* Vs = Ks + 64*65;
    float* Ps = Vs + 64*65;
    const int ib = blockIdx.x, h = blockIdx.y;
    const int tid = threadIdx.x;
    const int qr  = tid >> 2;
    const int c0  = (tid & 3) * 16;

    for (int idx = tid; idx < 64*64; idx += 256) {
        int r = idx >> 6, c = idx & 63;
        Qs[r*65 + c] = qkv[(size_t)(ib*64+r)*QKV_STRIDE + h*HEAD_DIM + c];
    }

    float accO[16];
    #pragma unroll
    for (int i = 0; i < 16; i++) accO[i] = 0.f;
    float den = 0.f;

    for (int jb = 0; jb <= ib; jb++) {
        __syncthreads();
        for (int idx = tid; idx < 64*64; idx += 256) {
            int r = idx >> 6, c = idx & 63;
            size_t base = (size_t)(jb*64+r)*QKV_STRIDE + h*HEAD_DIM + c;
            Ks[r*65 + c] = qkv[base + D_MODEL];
            Vs[r*65 + c] = qkv[base + 2*D_MODEL];
        }
        __syncthreads();

        float s[16];
        float mx = -1e30f;
        #pragma unroll
        for (int cc = 0; cc < 16; cc++) {
            int c = c0 + cc;
            float dot = 0.f;
            #pragma unroll
            for (int d = 0; d < 64; d++)
                dot = fmaf(Qs[qr*65 + d], Ks[c*65 + d], dot);
            dot *= 0.125f;
            if (jb == ib && c > qr) dot = -1e30f;
            s[cc] = dot;
            mx = fmaxf(mx, dot);
        }
        mx = fmaxf(mx, __shfl_xor_sync(0xffffffffu, mx, 1));
        mx = fmaxf(mx, __shfl_xor_sync(0xffffffffu, mx, 2));

        #pragma unroll
        for (int cc = 0; cc < 16; cc++) {
            float p = expf(s[cc] - mx);
            Ps[qr*65 + c0 + cc] = p;
            den += p;
        }
        __syncthreads();

        #pragma unroll 8
        for (int kk = 0; kk < 64; kk++) {
            float pv = Ps[qr*65 + kk];
            #pragma unroll
            for (int d = 0; d < 16; d++)
                accO[d] = fmaf(pv, Vs[kk*65 + c0 + d], accO[d]);
        }
    }

    den += __shfl_xor_sync(0xffffffffu, den, 1);
    den += __shfl_xor_sync(0xffffffffu, den, 2);
    float invd = 1.f / (den + 1e-6f);
    #pragma unroll
    for (int d = 0; d < 16; d++)
        o[(size_t)(ib*64+qr)*D_MODEL + h*HEAD_DIM + c0 + d] = accO[d] * invd;
}

// ---------------- layernorm ----------------
__global__ void __launch_bounds__(256) ln_kernel(
    const float* __restrict__ in, const float* __restrict__ res,
    const float* __restrict__ g, const float* __restrict__ b,
    float* __restrict__ out)
{
    __shared__ float red[256];
    int t = blockIdx.x, tid = threadIdx.x;
    float v[8];
    float sum = 0.f;
    #pragma unroll
    for (int i = 0; i < 8; i++) {
        int d = i*256 + tid;
        float x = in[(size_t)t*D_MODEL + d];
        if (res) x += res[(size_t)t*D_MODEL + d];
        v[i] = x; sum += x;
    }
    red[tid] = sum; __syncthreads();
    for (int s = 128; s > 0; s >>= 1) { if (tid < s) red[tid] += red[tid+s]; __syncthreads(); }
    float mu = red[0] / D_MODEL;
    __syncthreads();
    float sq = 0.f;
    #pragma unroll
    for (int i = 0; i < 8; i++) { float d0 = v[i] - mu; sq += d0*d0; }
    red[tid] = sq; __syncthreads();
    for (int s = 128; s > 0; s >>= 1) { if (tid < s) red[tid] += red[tid+s]; __syncthreads(); }
    float rstd = rsqrtf(red[0] / D_MODEL + 1e-5f);
    #pragma unroll
    for (int i = 0; i < 8; i++) {
        int d = i*256 + tid;
        out[(size_t)t*D_MODEL + d] = (v[i] - mu) * rstd * g[d] + b[d];
    }
}

// ---------------- MoE gate ----------------
__global__ void __launch_bounds__(128) gate_kernel(
    const float* __restrict__ x, const float* __restrict__ gw,
    float* __restrict__ wts, float* __restrict__ varr)
{
    __shared__ float red[128];
    __shared__ float logit[4];
    int t = blockIdx.x, tid = threadIdx.x;
    float p[4] = {0.f, 0.f, 0.f, 0.f};
    for (int d = tid; d < D_MODEL; d += 128) {
        float xv = x[(size_t)t*D_MODEL + d];
        #pragma unroll
        for (int e = 0; e < 4; e++)
            p[e] = fmaf(xv, gw[e*D_MODEL + d], p[e]);
    }
    for (int e = 0; e < 4; e++) {
        red[tid] = p[e]; __syncthreads();
        for (int s = 64; s > 0; s >>= 1) { if (tid < s) red[tid] += red[tid+s]; __syncthreads(); }
        if (tid == 0) logit[e] = red[0];
        __syncthreads();
    }
    if (tid == 0) {
        float l[4] = {logit[0], logit[1], logit[2], logit[3]};
        float mx = fmaxf(fmaxf(l[0], l[1]), fmaxf(l[2], l[3]));
        float ex[4], ssum = 0.f;
        for (int e = 0; e < 4; e++) { ex[e] = expf(l[e] - mx); ssum += ex[e]; }
        float pr[4];
        for (int e = 0; e < 4; e++) pr[e] = ex[e] / ssum;
        int b1 = 0;
        for (int e = 1; e < 4; e++) if (pr[e] > pr[b1]) b1 = e;
        int b2 = -1;
        for (int e = 0; e < 4; e++) { if (e == b1) continue; if (b2 < 0 || pr[e] > pr[b2]) b2 = e; }
        float s2 = pr[b1] + pr[b2];
        float wv[4] = {0.f, 0.f, 0.f, 0.f};
        wv[b1] = pr[b1] / s2; wv[b2] = pr[b2] / s2;
        for (int e = 0; e < 4; e++) wts[e*SEQ + t] = wv[e];
        float mu = (l[0]+l[1]+l[2]+l[3]) * 0.25f;
        float va = ((l[0]-mu)*(l[0]-mu) + (l[1]-mu)*(l[1]-mu) +
                    (l[2]-mu)*(l[2]-mu) + (l[3]-mu)*(l[3]-mu)) / 3.f;
        varr[t] = va;
    }
}

// ---------------- routing compaction ----------------
__global__ void __launch_bounds__(1024) compact_kernel(
    const float* __restrict__ wts, int* __restrict__ cnt,
    int* __restrict__ ridx, float* __restrict__ rwt)
{
    __shared__ int sc[1024];
    int e = blockIdx.x, t = threadIdx.x;
    float w = wts[e*SEQ + t];
    int flag = (w != 0.f) ? 1 : 0;
    sc[t] = flag;
    __syncthreads();
    for (int off = 1; off < 1024; off <<= 1) {
        int v = (t >= off) ? sc[t - off] : 0;
        __syncthreads();
        sc[t] += v;
        __syncthreads();
    }
    if (flag) {
        int pos = sc[t] - 1;
        ridx[e*SEQ + pos] = t;
        rwt [e*SEQ + pos] = w;
    }
    if (t == 1023) cnt[e] = sc[1023];
}

__global__ void __launch_bounds__(256) gather_kernel(
    const __nv_bfloat16* __restrict__ ah, const __nv_bfloat16* __restrict__ al,
    const int* __restrict__ ridx, const int* __restrict__ cnt,
    __nv_bfloat16* __restrict__ gh, __nv_bfloat16* __restrict__ gl)
{
    int row = blockIdx.x;
    if (row >= *cnt) return;
    int tok = ridx[row];
    const uint4* sh = (const uint4*)(ah + (size_t)tok*D_MODEL);
    const uint4* sl = (const uint4*)(al + (size_t)tok*D_MODEL);
    uint4* dh = (uint4*)(gh + (size_t)row*D_MODEL);
    uint4* dl = (uint4*)(gl + (size_t)row*D_MODEL);
    int c = threadIdx.x;
    dh[c] = sh[c];
    dl[c] = sl[c];
}

// fused silu(h1)*h3 -> split bf16 (h13 = [rows][2*D_FFN], h1 cols 0..8191, h3 cols 8192..)
__global__ void __launch_bounds__(256) silu_split_kernel(
    const float* __restrict__ h13, const int* __restrict__ cnt,
    __nv_bfloat16* __restrict__ ch, __nv_bfloat16* __restrict__ cl)
{
    int row = blockIdx.x;
    if (row >= *cnt) return;
    size_t src = (size_t)row * (2*D_FFN);
    size_t dst = (size_t)row * D_FFN;
    for (int c = threadIdx.x; c < D_FFN; c += 256) {
        float a = h13[src + c];
        float v = a / (1.f + expf(-a)) * h13[src + D_FFN + c];
        __nv_bfloat16 hi = __float2bfloat16(v);
        ch[dst + c] = hi;
        cl[dst + c] = __float2bfloat16(v - __bfloat162float(hi));
    }
}

__global__ void aux_kernel(const float* __restrict__ varr, float* __restrict__ out) {
    __shared__ float red[256];
    int tid = threadIdx.x;
    float s = 0.f;
    for (int i = tid; i < SEQ; i += 256) s += varr[i];
    red[tid] = s; __syncthreads();
    for (int st = 128; st > 0; st >>= 1) { if (tid < st) red[tid] += red[tid+st]; __syncthreads(); }
    if (tid == 0) out[0] = red[0] / (float)SEQ;
}

__global__ void zero_kernel(float* __restrict__ p, int n) {
    int i = blockIdx.x * 256 + threadIdx.x;
    if (i < n) p[i] = 0.f;
}

// ---------------- driver ----------------
static inline void split(const float* src, __nv_bfloat16* hi, __nv_bfloat16* lo, long long n) {
    int n4 = (int)(n / 4);
    split_kernel<<<(n4 + 255)/256, 256>>>(src, hi, lo, n4);
}

extern "C" void kernel_launch(void* const* d_in, const int* in_sizes, int n_in,
                              void* d_out, int out_size) {
    const int*   tokens = (const int*)  d_in[0];
    const float* emb    = (const float*)d_in[1];
    const float* wq     = (const float*)d_in[2];
    const float* wk     = (const float*)d_in[3];
    const float* wv     = (const float*)d_in[4];
    const float* wo     = (const float*)d_in[5];
    const float* ln1g   = (const float*)d_in[6];
    const float* ln1b   = (const float*)d_in[7];
    const float* gatew  = (const float*)d_in[8];
    const float* w1     = (const float*)d_in[9];
    const float* w2     = (const float*)d_in[10];
    const float* w3     = (const float*)d_in[11];
    const float* ln2g   = (const float*)d_in[12];
    const float* ln2b   = (const float*)d_in[13];
    const float* fing   = (const float*)d_in[14];
    const float* finb   = (const float*)d_in[15];
    const float* headw  = (const float*)d_in[16];
    float* out = (float*)d_out;

    float *x, *qkv, *att, *y, *h13, *moe, *wts, *varr, *rwt;
    int *cnt, *ridx;
    __nv_bfloat16 *ah, *al, *gxh, *gxl, *ch, *cl, *bh, *bl;
    cudaGetSymbolAddress((void**)&x,    g_x);
    cudaGetSymbolAddress((void**)&qkv,  g_qkv);
    cudaGetSymbolAddress((void**)&att,  g_att);
    cudaGetSymbolAddress((void**)&y,    g_y);
    cudaGetSymbolAddress((void**)&h13,  g_h13);
    cudaGetSymbolAddress((void**)&moe,  g_moe);
    cudaGetSymbolAddress((void**)&wts,  g_wts);
    cudaGetSymbolAddress((void**)&varr, g_var);
    cudaGetSymbolAddress((void**)&cnt,  g_cnt);
    cudaGetSymbolAddress((void**)&ridx, g_ridx);
    cudaGetSymbolAddress((void**)&rwt,  g_rwt);
    cudaGetSymbolAddress((void**)&ah,   g_ah);
    cudaGetSymbolAddress((void**)&al,   g_al);
    cudaGetSymbolAddress((void**)&gxh,  g_gxh);
    cudaGetSymbolAddress((void**)&gxl,  g_gxl);
    cudaGetSymbolAddress((void**)&ch,   g_ch);
    cudaGetSymbolAddress((void**)&cl,   g_cl);
    cudaGetSymbolAddress((void**)&bh,   g_bh);
    cudaGetSymbolAddress((void**)&bl,   g_bl);

    cudaFuncSetAttribute(attn_kernel, cudaFuncAttributeMaxDynamicSharedMemorySize, ATTN_SMEM);
    cudaFuncSetAttribute(gemm_tc<0>, cudaFuncAttributeMaxDynamicSharedMemorySize, GEMM_SMEM);
    cudaFuncSetAttribute(gemm_tc<1>, cudaFuncAttributeMaxDynamicSharedMemorySize, GEMM_SMEM);
    cudaFuncSetAttribute(gemm_tc<2>, cudaFuncAttributeMaxDynamicSharedMemorySize, GEMM_SMEM);
    cudaFuncSetAttribute(gemm_tf32, cudaFuncAttributeMaxDynamicSharedMemorySize, GEMM_SMEM);

    const long long DD = (long long)D_MODEL * D_MODEL;

    // 1) embed + split x
    embed_kernel<<<SEQ, 256>>>(tokens, emb, x);
    split(x, ah, al, (long long)SEQ * D_MODEL);

    // 2) fused QKV: B = [wq;wk;wv], N=6144
    split(wq, bh,        bl,        DD);
    split(wk, bh + DD,   bl + DD,   DD);
    split(wv, bh + 2*DD, bl + 2*DD, DD);
    dim3 gQKV(3*D_MODEL/128, SEQ/128);
    gemm_tc<0><<<gQKV, 256, GEMM_SMEM>>>(ah, al, bh, bl, qkv, SEQ, 3*D_MODEL, D_MODEL,
                                         nullptr, nullptr, nullptr, nullptr);

    // 3) RoPE + attention
    rope_kernel<<<dim3(SEQ, N_HEADS), 32>>>(qkv);
    attn_kernel<<<dim3(NB, N_HEADS), 256, ATTN_SMEM>>>(qkv, att);

    // 4) output proj + residual
    dim3 gA(D_MODEL/128, SEQ/128);
    split(att, ah, al, (long long)SEQ * D_MODEL);
    split(wo, bh, bl, DD);
    gemm_tc<0><<<gA, 256, GEMM_SMEM>>>(ah, al, bh, bl, y, SEQ, D_MODEL, D_MODEL,
                                       x, nullptr, nullptr, nullptr);

    // 5) LN1 -> x, split for MoE
    ln_kernel<<<SEQ, 256>>>(y, nullptr, ln1g, ln1b, x);
    split(x, ah, al, (long long)SEQ * D_MODEL);

    // 6) gate + routing
    gate_kernel<<<SEQ, 128>>>(x, gatew, wts, varr);
    compact_kernel<<<NEXP, 1024>>>(wts, cnt, ridx, rwt);

    // 7) MoE
    zero_kernel<<<(SEQ*D_MODEL + 255)/256, 256>>>(moe, SEQ*D_MODEL);
    const long long FD = (long long)D_FFN * D_MODEL;
    dim3 gUp(2*D_FFN/128, SEQ/128);
    for (int e = 0; e < NEXP; e++) {
        const float* w1e = w1 + (size_t)e * FD;
        const float* w3e = w3 + (size_t)e * FD;
        const float* w2e = w2 + (size_t)e * FD;
        const int*   ce  = cnt + e;
        const int*   ie  = ridx + e * SEQ;
        const float* we  = rwt + e * SEQ;

        gather_kernel<<<SEQ, 256>>>(ah, al, ie, ce, gxh, gxl);
        split(w1e, bh,      bl,      FD);
        split(w3e, bh + FD, bl + FD, FD);
        gemm_tc<1><<<gUp, 256, GEMM_SMEM>>>(gxh, gxl, bh, bl, h13, 0, 2*D_FFN, D_MODEL,
                                            nullptr, ce, nullptr, nullptr);
        silu_split_kernel<<<SEQ, 256>>>(h13, ce, ch, cl);
        split(w2e, bh, bl, FD);
        gemm_tc<2><<<gA, 256, GEMM_SMEM>>>(ch, cl, bh, bl, moe, 0, D_MODEL, D_FFN,
                                           nullptr, ce, ie, we);
    }

    // 8) LN2 + final LN
    ln_kernel<<<SEQ, 256>>>(moe, x, ln2g, ln2b, y);
    ln_kernel<<<SEQ, 256>>>(y, nullptr, fing, finb, x);

    // 9) head: tf32 single-pass, fp32 operands (no splits)
    dim3 gH((VOCAB + 127)/128, SEQ/128);
    gemm_tf32<<<gH, 256, GEMM_SMEM>>>(x, headw, out, SEQ, VOCAB, D_MODEL);

    // 10) aux
    long long nlog = (long long)SEQ * VOCAB;
    if ((long long)out_size > nlog)
        aux_kernel<<<1, 256>>>(varr, out + nlog);
}

// round 7
// speedup vs baseline: 3.4012x; 1.0303x over previous
#include <cuda_runtime.h>
#include <cuda_bf16.h>
#include <math.h>
#include <stdint.h>

#define D_MODEL 2048
#define SEQ     1024
#define N_HEADS 32
#define HEAD_DIM 64
#define NB      (SEQ/64)
#define D_FFN   8192
#define VOCAB   50257
#define NEXP    4
#define QKV_STRIDE (3*D_MODEL)

// ---------------- scratch ----------------
__device__ float g_x  [SEQ*D_MODEL];
__device__ float g_qkv[SEQ*3*D_MODEL];
__device__ float g_att[SEQ*D_MODEL];
__device__ float g_y  [SEQ*D_MODEL];
__device__ float g_h13[SEQ*2*D_FFN];
__device__ float g_moe[SEQ*D_MODEL];
__device__ float g_wts[NEXP*SEQ];
__device__ float g_var[SEQ];

// routing
__device__ int   g_cnt[NEXP];
__device__ int   g_ridx[NEXP*SEQ];
__device__ float g_rwt [NEXP*SEQ];

// bf16 split scratch
__device__ __nv_bfloat16 g_ah[SEQ*D_MODEL];
__device__ __nv_bfloat16 g_al[SEQ*D_MODEL];
__device__ __nv_bfloat16 g_gxh[SEQ*D_MODEL];
__device__ __nv_bfloat16 g_gxl[SEQ*D_MODEL];
__device__ __nv_bfloat16 g_ch[SEQ*D_FFN];
__device__ __nv_bfloat16 g_cl[SEQ*D_FFN];
__device__ __nv_bfloat16 g_bh[(size_t)2*D_FFN*D_MODEL];
__device__ __nv_bfloat16 g_bl[(size_t)2*D_FFN*D_MODEL];

// ---------------- PTX helpers ----------------
__device__ __forceinline__ uint32_t smem_u32(const void* p) {
    uint32_t a;
    asm("{ .reg .u64 t; cvta.to.shared.u64 t, %1; cvt.u32.u64 %0, t; }" : "=r"(a) : "l"(p));
    return a;
}
__device__ __forceinline__ void cp_async16(uint32_t dst, const void* src, int src_bytes) {
    asm volatile("cp.async.cg.shared.global [%0], [%1], 16, %2;\n"
                 :: "r"(dst), "l"(src), "r"(src_bytes) : "memory");
}
#define CP_COMMIT() asm volatile("cp.async.commit_group;\n" ::: "memory")

__device__ __forceinline__ void ldsm_x4(uint32_t& r0, uint32_t& r1, uint32_t& r2, uint32_t& r3,
                                        uint32_t addr) {
    asm volatile("ldmatrix.sync.aligned.m8n8.x4.shared.b16 {%0,%1,%2,%3}, [%4];"
                 : "=r"(r0), "=r"(r1), "=r"(r2), "=r"(r3) : "r"(addr));
}
__device__ __forceinline__ void mma_bf16(float* c, const uint32_t* a, const uint32_t* b) {
    asm volatile(
        "mma.sync.aligned.m16n8k16.row.col.f32.bf16.bf16.f32 "
        "{%0,%1,%2,%3}, {%4,%5,%6,%7}, {%8,%9}, {%0,%1,%2,%3};"
        : "+f"(c[0]), "+f"(c[1]), "+f"(c[2]), "+f"(c[3])
        : "r"(a[0]), "r"(a[1]), "r"(a[2]), "r"(a[3]), "r"(b[0]), "r"(b[1]));
}
__device__ __forceinline__ void mma_tf32(float* c, const uint32_t* a, const uint32_t* b) {
    asm volatile(
        "mma.sync.aligned.m16n8k8.row.col.f32.tf32.tf32.f32 "
        "{%0,%1,%2,%3}, {%4,%5,%6,%7}, {%8,%9}, {%0,%1,%2,%3};"
        : "+f"(c[0]), "+f"(c[1]), "+f"(c[2]), "+f"(c[3])
        : "r"(a[0]), "r"(a[1]), "r"(a[2]), "r"(a[3]), "r"(b[0]), "r"(b[1]));
}

// ---------------- fp32 -> (bf16 hi, bf16 lo) split ----------------
__global__ void __launch_bounds__(256) split_kernel(
    const float* __restrict__ in, __nv_bfloat16* __restrict__ hi,
    __nv_bfloat16* __restrict__ lo, int n4)
{
    int i = blockIdx.x * 256 + threadIdx.x;
    if (i >= n4) return;
    float4 v = ((const float4*)in)[i];
    __nv_bfloat16 h0 = __float2bfloat16(v.x);
    __nv_bfloat16 h1 = __float2bfloat16(v.y);
    __nv_bfloat16 h2 = __float2bfloat16(v.z);
    __nv_bfloat16 h3 = __float2bfloat16(v.w);
    __nv_bfloat162 hh0; hh0.x = h0; hh0.y = h1;
    __nv_bfloat162 hh1; hh1.x = h2; hh1.y = h3;
    __nv_bfloat162 ll0, ll1;
    ll0.x = __float2bfloat16(v.x - __bfloat162float(h0));
    ll0.y = __float2bfloat16(v.y - __bfloat162float(h1));
    ll1.x = __float2bfloat16(v.z - __bfloat162float(h2));
    ll1.y = __float2bfloat16(v.w - __bfloat162float(h3));
    ((__nv_bfloat162*)hi)[i*2]   = hh0;
    ((__nv_bfloat162*)hi)[i*2+1] = hh1;
    ((__nv_bfloat162*)lo)[i*2]   = ll0;
    ((__nv_bfloat162*)lo)[i*2+1] = ll1;
}

// ================= bf16x3 GEMM: CTA 128x256, 8 warps (2Mx4N), warp 64x64 =================
#define NSTG 4
#define A_BYTES (128*128)
#define B_BYTES (256*128)
#define STAGE_B (A_BYTES + B_BYTES)
#define GEMM_SMEM (NSTG * STAGE_B)   // 196608

// MODE 0: C[m,n] = val (+residual)
// MODE 1: routed rows: M from *Mptr, plain store
// MODE 2: routed rows: M from *Mptr, atomicAdd(C[ridx[m]*N+n], rwt[m]*val); split-K over gridDim.z
template<int MODE>
__global__ void __launch_bounds__(256, 1) gemm_tc(
    const __nv_bfloat16* __restrict__ Ah, const __nv_bfloat16* __restrict__ Al,
    const __nv_bfloat16* __restrict__ Bh, const __nv_bfloat16* __restrict__ Bl,
    float* __restrict__ C, int M_in, int N, int K,
    const float* __restrict__ residual,
    const int* __restrict__ Mptr, const int* __restrict__ ridx,
    const float* __restrict__ rwt)
{
    int M = M_in;
    if (MODE != 0) {
        M = *Mptr;
        if ((int)blockIdx.y * 128 >= M) return;
    }
    extern __shared__ char smem[];
    const uint32_t sb = smem_u32(smem);
    const int tid = threadIdx.x;
    const int wid = tid >> 5, lid = tid & 31;
    const int wm  = wid >> 2, wn = wid & 3;      // warp grid 2(M) x 4(N)
    const int m0  = blockIdx.y * 128;
    const int n0  = blockIdx.x * 256;

    const int Kc    = K / (int)gridDim.z;        // split-K chunk (gridDim.z==1 for MODE 0/1)
    const int kbase = (int)blockIdx.z * Kc;

    float acc[4][8][4];
    #pragma unroll
    for (int i = 0; i < 4; i++)
        #pragma unroll
        for (int j = 0; j < 8; j++)
            #pragma unroll
            for (int t = 0; t < 4; t++) acc[i][j][t] = 0.f;

    const int iters = Kc >> 5;

    auto fill = [&](int stage, int kit) {
        const int k0 = kbase + (kit << 5);
        const uint32_t abase = sb + stage * STAGE_B;
        const uint32_t bbase = abase + A_BYTES;
        #pragma unroll
        for (int i = 0; i < 4; i++) {            // A: 128 rows x 8 chunks
            int idx = tid + i * 256;
            int r = idx >> 3, c = idx & 7;
            int rg = m0 + r;
            if (MODE != 0) rg = rg < M ? rg : (M - 1);
            uint32_t dst = abase + r * 128 + ((c ^ (r & 7)) << 4);
            const __nv_bfloat16* src = (c < 4)
                ? Ah + (size_t)rg * K + k0 + c * 8
                : Al + (size_t)rg * K + k0 + (c - 4) * 8;
            cp_async16(dst, src, 16);
        }
        #pragma unroll
        for (int i = 0; i < 8; i++) {            // B: 256 rows x 8 chunks
            int idx = tid + i * 256;
            int r = idx >> 3, c = idx & 7;
            uint32_t dst = bbase + r * 128 + ((c ^ (r & 7)) << 4);
            int rg = n0 + r;
            int rc = rg < N ? rg : (N - 1);
            const __nv_bfloat16* src = (c < 4)
                ? Bh + (size_t)rc * K + k0 + c * 8
                : Bl + (size_t)rc * K + k0 + (c - 4) * 8;
            cp_async16(dst, src, rg < N ? 16 : 0);
        }
        CP_COMMIT();
    };

    #pragma unroll
    for (int s = 0; s < NSTG - 1; s++) fill(s, s);

    const int grp = lid >> 3;
    const int rin = lid & 7;

    for (int i = 0; i < iters; i++) {
        const int s = i % NSTG;
        asm volatile("cp.async.wait_group %0;\n" :: "n"(NSTG - 2));
        __syncthreads();

        if (i + NSTG - 1 < iters) fill((i + NSTG - 1) % NSTG, i + NSTG - 1);
        else CP_COMMIT();

        const uint32_t abase = sb + s * STAGE_B;
        const uint32_t bbase = abase + A_BYTES;

        #pragma unroll
        for (int g = 0; g < 2; g++) {
            uint32_t ah[4][4], bh[8][2];
            // A hi + B hi
            #pragma unroll
            for (int mt = 0; mt < 4; mt++) {
                int row = wm * 64 + mt * 16 + (grp & 1) * 8 + rin;
                int kch = 2 * g + (grp >> 1);
                uint32_t ad = abase + row * 128 + ((kch ^ (row & 7)) << 4);
                ldsm_x4(ah[mt][0], ah[mt][1], ah[mt][2], ah[mt][3], ad);
            }
            #pragma unroll
            for (int p = 0; p < 4; p++) {
                int tile = 2 * p + (grp >> 1);
                int row  = wn * 64 + tile * 8 + rin;
                int kch  = 2 * g + (grp & 1);
                uint32_t bd = bbase + row * 128 + ((kch ^ (row & 7)) << 4);
                ldsm_x4(bh[2*p][0], bh[2*p][1], bh[2*p+1][0], bh[2*p+1][1], bd);
            }
            #pragma unroll
            for (int mt = 0; mt < 4; mt++)
                #pragma unroll
                for (int nt = 0; nt < 8; nt++)
                    mma_bf16(acc[mt][nt], ah[mt], bh[nt]);
            // A lo x B hi
            {
                uint32_t al[4][4];
                #pragma unroll
                for (int mt = 0; mt < 4; mt++) {
                    int row = wm * 64 + mt * 16 + (grp & 1) * 8 + rin;
                    int kcl = 4 + 2 * g + (grp >> 1);
                    uint32_t adl = abase + row * 128 + ((kcl ^ (row & 7)) << 4);
                    ldsm_x4(al[mt][0], al[mt][1], al[mt][2], al[mt][3], adl);
                }
                #pragma unroll
                for (int mt = 0; mt < 4; mt++)
                    #pragma unroll
                    for (int nt = 0; nt < 8; nt++)
                        mma_bf16(acc[mt][nt], al[mt], bh[nt]);
            }
            // A hi x B lo
            {
                uint32_t bl[8][2];
                #pragma unroll
                for (int p = 0; p < 4; p++) {
                    int tile = 2 * p + (grp >> 1);
                    int row  = wn * 64 + tile * 8 + rin;
                    int kcl  = 4 + 2 * g + (grp & 1);
                    uint32_t bdl = bbase + row * 128 + ((kcl ^ (row & 7)) << 4);
                    ldsm_x4(bl[2*p][0], bl[2*p][1], bl[2*p+1][0], bl[2*p+1][1], bdl);
                }
                #pragma unroll
                for (int mt = 0; mt < 4; mt++)
                    #pragma unroll
                    for (int nt = 0; nt < 8; nt++)
                        mma_bf16(acc[mt][nt], ah[mt], bl[nt]);
            }
        }
    }

    #pragma unroll
    for (int mt = 0; mt < 4; mt++) {
        #pragma unroll
        for (int nt = 0; nt < 8; nt++) {
            int rbase = m0 + wm * 64 + mt * 16 + (lid >> 2);
            int col = n0 + wn * 64 + nt * 8 + (lid & 3) * 2;
            #pragma unroll
            for (int h = 0; h < 2; h++) {
                int m = rbase + h * 8;
                float v0 = acc[mt][nt][h * 2 + 0];
                float v1 = acc[mt][nt][h * 2 + 1];
                if (MODE == 0) {
                    size_t idx = (size_t)m * N + col;
                    if (residual) {
                        if (col     < N) v0 += residual[idx];
                        if (col + 1 < N) v1 += residual[idx + 1];
                    }
                    if (col     < N) C[idx]     = v0;
                    if (col + 1 < N) C[idx + 1] = v1;
                } else if (MODE == 1) {
                    if (m < M) {
                        size_t idx = (size_t)m * N + col;
                        C[idx]     = v0;
                        C[idx + 1] = v1;
                    }
                } else {
                    if (m < M) {
                        int tok = ridx[m];
                        float w = rwt[m];
                        size_t idx = (size_t)tok * N + col;
                        atomicAdd(&C[idx],     w * v0);
                        atomicAdd(&C[idx + 1], w * v1);
                    }
                }
            }
        }
    }
}

// ================= tf32 single-pass GEMM (head), same tiling =================
__global__ void __launch_bounds__(256, 1) gemm_tf32(
    const float* __restrict__ A, const float* __restrict__ B,
    float* __restrict__ C, int M, int N, int K)
{
    extern __shared__ char smem[];
    const uint32_t sb = smem_u32(smem);
    const int tid = threadIdx.x;
    const int wid = tid >> 5, lid = tid & 31;
    const int wm  = wid >> 2, wn = wid & 3;
    const int m0  = blockIdx.y * 128;
    const int n0  = blockIdx.x * 256;

    float acc[4][8][4];
    #pragma unroll
    for (int i = 0; i < 4; i++)
        #pragma unroll
        for (int j = 0; j < 8; j++)
            #pragma unroll
            for (int t = 0; t < 4; t++) acc[i][j][t] = 0.f;

    const int iters = K >> 5;

    auto fill = [&](int stage, int kit) {
        const int k0 = kit << 5;
        const uint32_t abase = sb + stage * STAGE_B;
        const uint32_t bbase = abase + A_BYTES;
        #pragma unroll
        for (int i = 0; i < 4; i++) {
            int idx = tid + i * 256;
            int r = idx >> 3, c = idx & 7;
            uint32_t dst = abase + r * 128 + ((c ^ (r & 7)) << 4);
            cp_async16(dst, A + (size_t)(m0 + r) * K + k0 + c * 4, 16);
        }
        #pragma unroll
        for (int i = 0; i < 8; i++) {
            int idx = tid + i * 256;
            int r = idx >> 3, c = idx & 7;
            uint32_t dst = bbase + r * 128 + ((c ^ (r & 7)) << 4);
            int rg = n0 + r;
            int rc = rg < N ? rg : (N - 1);
            cp_async16(dst, B + (size_t)rc * K + k0 + c * 4, rg < N ? 16 : 0);
        }
        CP_COMMIT();
    };

    #pragma unroll
    for (int s = 0; s < NSTG - 1; s++) fill(s, s);

    const int grp = lid >> 3;
    const int rin = lid & 7;

    for (int i = 0; i < iters; i++) {
        const int s = i % NSTG;
        asm volatile("cp.async.wait_group %0;\n" :: "n"(NSTG - 2));
        __syncthreads();

        if (i + NSTG - 1 < iters) fill((i + NSTG - 1) % NSTG, i + NSTG - 1);
        else CP_COMMIT();

        const uint32_t abase = sb + s * STAGE_B;
        const uint32_t bbase = abase + A_BYTES;

        #pragma unroll
        for (int k8 = 0; k8 < 4; k8++) {
            uint32_t a[4][4], b[8][2];
            #pragma unroll
            for (int mt = 0; mt < 4; mt++) {
                int row = wm * 64 + mt * 16 + (grp & 1) * 8 + rin;
                int kc  = k8 * 2 + (grp >> 1);
                uint32_t addr = abase + row * 128 + ((kc ^ (row & 7)) << 4);
                ldsm_x4(a[mt][0], a[mt][1], a[mt][2], a[mt][3], addr);
            }
            #pragma unroll
            for (int p = 0; p < 4; p++) {
                int tile = 2 * p + (grp >> 1);
                int row  = wn * 64 + tile * 8 + rin;
                int kc   = k8 * 2 + (grp & 1);
                uint32_t addr = bbase + row * 128 + ((kc ^ (row & 7)) << 4);
                ldsm_x4(b[2*p][0], b[2*p][1], b[2*p+1][0], b[2*p+1][1], addr);
            }
            #pragma unroll
            for (int mt = 0; mt < 4; mt++)
                #pragma unroll
                for (int nt = 0; nt < 8; nt++)
                    mma_tf32(acc[mt][nt], a[mt], b[nt]);
        }
    }

    #pragma unroll
    for (int mt = 0; mt < 4; mt++) {
        #pragma unroll
        for (int nt = 0; nt < 8; nt++) {
            int rbase = m0 + wm * 64 + mt * 16 + (lid >> 2);
            int col = n0 + wn * 64 + nt * 8 + (lid & 3) * 2;
            #pragma unroll
            for (int h = 0; h < 2; h++) {
                int m = rbase + h * 8;
                size_t idx = (size_t)m * N + col;
                if (col     < N) C[idx]     = acc[mt][nt][h * 2 + 0];
                if (col + 1 < N) C[idx + 1] = acc[mt][nt][h * 2 + 1];
            }
        }
    }
}

// ---------------- embedding ----------------
__global__ void embed_kernel(const int* __restrict__ tok,
                             const float* __restrict__ emb,
                             float* __restrict__ x) {
    int t = blockIdx.x;
    int tk = tok[t];
    for (int d = threadIdx.x; d < D_MODEL; d += 256)
        x[(size_t)t*D_MODEL + d] = emb[(size_t)tk*D_MODEL + d];
}

// ---------------- RoPE ----------------
__global__ void rope_kernel(float* __restrict__ qkv) {
    int t = blockIdx.x, h = blockIdx.y, i = threadIdx.x;
    float inv = powf(10000.f, -((float)(2*i)) / 64.f);
    float ang = (float)t * inv;
    float s, c;
    sincosf(ang, &s, &c);
    size_t base = (size_t)t*QKV_STRIDE + h*HEAD_DIM + 2*i;
    float q0 = qkv[base], q1 = qkv[base+1];
    qkv[base]   = q0*c - q1*s;
    qkv[base+1] = q0*s + q1*c;
    size_t kb = base + D_MODEL;
    float k0 = qkv[kb], k1 = qkv[kb+1];
    qkv[kb]   = k0*c - k1*s;
    qkv[kb+1] = k0*s + k1*c;
}

// ---------------- blocked attention (exact ref semantics) ----------------
#define ATTN_SMEM (4 * 64 * 65 * 4)
__global__ void __launch_bounds__(256) attn_kernel(
    const float* __restrict__ qkv, float* __restrict__ o)
{
    extern __shared__ float sm[];
    float* Qs = sm;
    float* Ks = Qs + 64*65;
    float* Vs = Ks + 64*65;
    float* Ps = Vs + 64*65;
    const int ib = blockIdx.x, h = blockIdx.y;
    const int tid = threadIdx.x;
    const int qr  = tid >> 2;
    const int c0  = (tid & 3) * 16;

    for (int idx = tid; idx < 64*64; idx += 256) {
        int r = idx >> 6, c = idx & 63;
        Qs[r*65 + c] = qkv[(size_t)(ib*64+r)*QKV_STRIDE + h*HEAD_DIM + c];
    }

    float accO[16];
    #pragma unroll
    for (int i = 0; i < 16; i++) accO[i] = 0.f;
    float den = 0.f;

    for (int jb = 0; jb <= ib; jb++) {
        __syncthreads();
        for (int idx = tid; idx < 64*64; idx += 256) {
            int r = idx >> 6, c = idx & 63;
            size_t base = (size_t)(jb*64+r)*QKV_STRIDE + h*HEAD_DIM + c;
            Ks[r*65 + c] = qkv[base + D_MODEL];
            Vs[r*65 + c] = qkv[base + 2*D_MODEL];
        }
        __syncthreads();

        float s[16];
        float mx = -1e30f;
        #pragma unroll
        for (int cc = 0; cc < 16; cc++) {
            int c = c0 + cc;
            float dot = 0.f;
            #pragma unroll
            for (int d = 0; d < 64; d++)
                dot = fmaf(Qs[qr*65 + d], Ks[c*65 + d], dot);
            dot *= 0.125f;
            if (jb == ib && c > qr) dot = -1e30f;
            s[cc] = dot;
            mx = fmaxf(mx, dot);
        }
        mx = fmaxf(mx, __shfl_xor_sync(0xffffffffu, mx, 1));
        mx = fmaxf(mx, __shfl_xor_sync(0xffffffffu, mx, 2));

        #pragma unroll
        for (int cc = 0; cc < 16; cc++) {
            float p = expf(s[cc] - mx);
            Ps[qr*65 + c0 + cc] = p;
            den += p;
        }
        __syncthreads();

        #pragma unroll 8
        for (int kk = 0; kk < 64; kk++) {
            float pv = Ps[qr*65 + kk];
            #pragma unroll
            for (int d = 0; d < 16; d++)
                accO[d] = fmaf(pv, Vs[kk*65 + c0 + d], accO[d]);
        }
    }

    den += __shfl_xor_sync(0xffffffffu, den, 1);
    den += __shfl_xor_sync(0xffffffffu, den, 2);
    float invd = 1.f / (den + 1e-6f);
    #pragma unroll
    for (int d = 0; d < 16; d++)
        o[(size_t)(ib*64+qr)*D_MODEL + h*HEAD_DIM + c0 + d] = accO[d] * invd;
}

// ---------------- layernorm ----------------
__global__ void __launch_bounds__(256) ln_kernel(
    const float* __restrict__ in, const float* __restrict__ res,
    const float* __restrict__ g, const float* __restrict__ b,
    float* __restrict__ out)
{
    __shared__ float red[256];
    int t = blockIdx.x, tid = threadIdx.x;
    float v[8];
    float sum = 0.f;
    #pragma unroll
    for (int i = 0; i < 8; i++) {
        int d = i*256 + tid;
        float x = in[(size_t)t*D_MODEL + d];
        if (res) x += res[(size_t)t*D_MODEL + d];
        v[i] = x; sum += x;
    }
    red[tid] = sum; __syncthreads();
    for (int s = 128; s > 0; s >>= 1) { if (tid < s) red[tid] += red[tid+s]; __syncthreads(); }
    float mu = red[0] / D_MODEL;
    __syncthreads();
    float sq = 0.f;
    #pragma unroll
    for (int i = 0; i < 8; i++) { float d0 = v[i] - mu; sq += d0*d0; }
    red[tid] = sq; __syncthreads();
    for (int s = 128; s > 0; s >>= 1) { if (tid < s) red[tid] += red[tid+s]; __syncthreads(); }
    float rstd = rsqrtf(red[0] / D_MODEL + 1e-5f);
    #pragma unroll
    for (int i = 0; i < 8; i++) {
        int d = i*256 + tid;
        out[(size_t)t*D_MODEL + d] = (v[i] - mu) * rstd * g[d] + b[d];
    }
}

// ---------------- MoE gate ----------------
__global__ void __launch_bounds__(128) gate_kernel(
    const float* __restrict__ x, const float* __restrict__ gw,
    float* __restrict__ wts, float* __restrict__ varr)
{
    __shared__ float red[128];
    __shared__ float logit[4];
    int t = blockIdx.x, tid = threadIdx.x;
    float p[4] = {0.f, 0.f, 0.f, 0.f};
    for (int d = tid; d < D_MODEL; d += 128) {
        float xv = x[(size_t)t*D_MODEL + d];
        #pragma unroll
        for (int e = 0; e < 4; e++)
            p[e] = fmaf(xv, gw[e*D_MODEL + d], p[e]);
    }
    for (int e = 0; e < 4; e++) {
        red[tid] = p[e]; __syncthreads();
        for (int s = 64; s > 0; s >>= 1) { if (tid < s) red[tid] += red[tid+s]; __syncthreads(); }
        if (tid == 0) logit[e] = red[0];
        __syncthreads();
    }
    if (tid == 0) {
        float l[4] = {logit[0], logit[1], logit[2], logit[3]};
        float mx = fmaxf(fmaxf(l[0], l[1]), fmaxf(l[2], l[3]));
        float ex[4], ssum = 0.f;
        for (int e = 0; e < 4; e++) { ex[e] = expf(l[e] - mx); ssum += ex[e]; }
        float pr[4];
        for (int e = 0; e < 4; e++) pr[e] = ex[e] / ssum;
        int b1 = 0;
        for (int e = 1; e < 4; e++) if (pr[e] > pr[b1]) b1 = e;
        int b2 = -1;
        for (int e = 0; e < 4; e++) { if (e == b1) continue; if (b2 < 0 || pr[e] > pr[b2]) b2 = e; }
        float s2 = pr[b1] + pr[b2];
        float wv[4] = {0.f, 0.f, 0.f, 0.f};
        wv[b1] = pr[b1] / s2; wv[b2] = pr[b2] / s2;
        for (int e = 0; e < 4; e++) wts[e*SEQ + t] = wv[e];
        float mu = (l[0]+l[1]+l[2]+l[3]) * 0.25f;
        float va = ((l[0]-mu)*(l[0]-mu) + (l[1]-mu)*(l[1]-mu) +
                    (l[2]-mu)*(l[2]-mu) + (l[3]-mu)*(l[3]-mu)) / 3.f;
        varr[t] = va;
    }
}

// ---------------- routing compaction ----------------
__global__ void __launch_bounds__(1024) compact_kernel(
    const float* __restrict__ wts, int* __restrict__ cnt,
    int* __restrict__ ridx, float* __restrict__ rwt)
{
    __shared__ int sc[1024];
    int e = blockIdx.x, t = threadIdx.x;
    float w = wts[e*SEQ + t];
    int flag = (w != 0.f) ? 1 : 0;
    sc[t] = flag;
    __syncthreads();
    for (int off = 1; off < 1024; off <<= 1) {
        int v = (t >= off) ? sc[t - off] : 0;
        __syncthreads();
        sc[t] += v;
        __syncthreads();
    }
    if (flag) {
        int pos = sc[t] - 1;
        ridx[e*SEQ + pos] = t;
        rwt [e*SEQ + pos] = w;
    }
    if (t == 1023) cnt[e] = sc[1023];
}

__global__ void __launch_bounds__(256) gather_kernel(
    const __nv_bfloat16* __restrict__ ah, const __nv_bfloat16* __restrict__ al,
    const int* __restrict__ ridx, const int* __restrict__ cnt,
    __nv_bfloat16* __restrict__ gh, __nv_bfloat16* __restrict__ gl)
{
    int row = blockIdx.x;
    if (row >= *cnt) return;
    int tok = ridx[row];
    const uint4* sh = (const uint4*)(ah + (size_t)tok*D_MODEL);
    const uint4* sl = (const uint4*)(al + (size_t)tok*D_MODEL);
    uint4* dh = (uint4*)(gh + (size_t)row*D_MODEL);
    uint4* dl = (uint4*)(gl + (size_t)row*D_MODEL);
    int c = threadIdx.x;
    dh[c] = sh[c];
    dl[c] = sl[c];
}

// fused silu(h1)*h3 -> split bf16
__global__ void __launch_bounds__(256) silu_split_kernel(
    const float* __restrict__ h13, const int* __restrict__ cnt,
    __nv_bfloat16* __restrict__ ch, __nv_bfloat16* __restrict__ cl)
{
    int row = blockIdx.x;
    if (row >= *cnt) return;
    size_t src = (size_t)row * (2*D_FFN);
    size_t dst = (size_t)row * D_FFN;
    for (int c = threadIdx.x; c < D_FFN; c += 256) {
        float a = h13[src + c];
        float v = a / (1.f + expf(-a)) * h13[src + D_FFN + c];
        __nv_bfloat16 hi = __float2bfloat16(v);
        ch[dst + c] = hi;
        cl[dst + c] = __float2bfloat16(v - __bfloat162float(hi));
    }
}

__global__ void aux_kernel(const float* __restrict__ varr, float* __restrict__ out) {
    __shared__ float red[256];
    int tid = threadIdx.x;
    float s = 0.f;
    for (int i = tid; i < SEQ; i += 256) s += varr[i];
    red[tid] = s; __syncthreads();
    for (int st = 128; st > 0; st >>= 1) { if (tid < st) red[tid] += red[tid+st]; __syncthreads(); }
    if (tid == 0) out[0] = red[0] / (float)SEQ;
}

__global__ void zero_kernel(float* __restrict__ p, int n) {
    int i = blockIdx.x * 256 + threadIdx.x;
    if (i < n) p[i] = 0.f;
}

// ---------------- driver ----------------
static inline void split(const float* src, __nv_bfloat16* hi, __nv_bfloat16* lo, long long n) {
    int n4 = (int)(n / 4);
    split_kernel<<<(n4 + 255)/256, 256>>>(src, hi, lo, n4);
}

extern "C" void kernel_launch(void* const* d_in, const int* in_sizes, int n_in,
                              void* d_out, int out_size) {
    const int*   tokens = (const int*)  d_in[0];
    const float* emb    = (const float*)d_in[1];
    const float* wq     = (const float*)d_in[2];
    const float* wk     = (const float*)d_in[3];
    const float* wv     = (const float*)d_in[4];
    const float* wo     = (const float*)d_in[5];
    const float* ln1g   = (const float*)d_in[6];
    const float* ln1b   = (const float*)d_in[7];
    const float* gatew  = (const float*)d_in[8];
    const float* w1     = (const float*)d_in[9];
    const float* w2     = (const float*)d_in[10];
    const float* w3     = (const float*)d_in[11];
    const float* ln2g   = (const float*)d_in[12];
    const float* ln2b   = (const float*)d_in[13];
    const float* fing   = (const float*)d_in[14];
    const float* finb   = (const float*)d_in[15];
    const float* headw  = (const float*)d_in[16];
    float* out = (float*)d_out;

    float *x, *qkv, *att, *y, *h13, *moe, *wts, *varr, *rwt;
    int *cnt, *ridx;
    __nv_bfloat16 *ah, *al, *gxh, *gxl, *ch, *cl, *bh, *bl;
    cudaGetSymbolAddress((void**)&x,    g_x);
    cudaGetSymbolAddress((void**)&qkv,  g_qkv);
    cudaGetSymbolAddress((void**)&att,  g_att);
    cudaGetSymbolAddress((void**)&y,    g_y);
    cudaGetSymbolAddress((void**)&h13,  g_h13);
    cudaGetSymbolAddress((void**)&moe,  g_moe);
    cudaGetSymbolAddress((void**)&wts,  g_wts);
    cudaGetSymbolAddress((void**)&varr, g_var);
    cudaGetSymbolAddress((void**)&cnt,  g_cnt);
    cudaGetSymbolAddress((void**)&ridx, g_ridx);
    cudaGetSymbolAddress((void**)&rwt,  g_rwt);
    cudaGetSymbolAddress((void**)&ah,   g_ah);
    cudaGetSymbolAddress((void**)&al,   g_al);
    cudaGetSymbolAddress((void**)&gxh,  g_gxh);
    cudaGetSymbolAddress((void**)&gxl,  g_gxl);
    cudaGetSymbolAddress((void**)&ch,   g_ch);
    cudaGetSymbolAddress((void**)&cl,   g_cl);
    cudaGetSymbolAddress((void**)&bh,   g_bh);
    cudaGetSymbolAddress((void**)&bl,   g_bl);

    cudaFuncSetAttribute(attn_kernel, cudaFuncAttributeMaxDynamicSharedMemorySize, ATTN_SMEM);
    cudaFuncSetAttribute(gemm_tc<0>, cudaFuncAttributeMaxDynamicSharedMemorySize, GEMM_SMEM);
    cudaFuncSetAttribute(gemm_tc<1>, cudaFuncAttributeMaxDynamicSharedMemorySize, GEMM_SMEM);
    cudaFuncSetAttribute(gemm_tc<2>, cudaFuncAttributeMaxDynamicSharedMemorySize, GEMM_SMEM);
    cudaFuncSetAttribute(gemm_tf32, cudaFuncAttributeMaxDynamicSharedMemorySize, GEMM_SMEM);

    const long long DD = (long long)D_MODEL * D_MODEL;

    // 1) embed + split x
    embed_kernel<<<SEQ, 256>>>(tokens, emb, x);
    split(x, ah, al, (long long)SEQ * D_MODEL);

    // 2) fused QKV (N=6144)
    split(wq, bh,        bl,        DD);
    split(wk, bh + DD,   bl + DD,   DD);
    split(wv, bh + 2*DD, bl + 2*DD, DD);
    dim3 gQKV(3*D_MODEL/256, SEQ/128);
    gemm_tc<0><<<gQKV, 256, GEMM_SMEM>>>(ah, al, bh, bl, qkv, SEQ, 3*D_MODEL, D_MODEL,
                                         nullptr, nullptr, nullptr, nullptr);

    // 3) RoPE + attention
    rope_kernel<<<dim3(SEQ, N_HEADS), 32>>>(qkv);
    attn_kernel<<<dim3(NB, N_HEADS), 256, ATTN_SMEM>>>(qkv, att);

    // 4) output proj + residual
    dim3 gA(D_MODEL/256, SEQ/128);
    split(att, ah, al, (long long)SEQ * D_MODEL);
    split(wo, bh, bl, DD);
    gemm_tc<0><<<gA, 256, GEMM_SMEM>>>(ah, al, bh, bl, y, SEQ, D_MODEL, D_MODEL,
                                       x, nullptr, nullptr, nullptr);

    // 5) LN1 -> x, split for MoE
    ln_kernel<<<SEQ, 256>>>(y, nullptr, ln1g, ln1b, x);
    split(x, ah, al, (long long)SEQ * D_MODEL);

    // 6) gate + routing
    gate_kernel<<<SEQ, 128>>>(x, gatew, wts, varr);
    compact_kernel<<<NEXP, 1024>>>(wts, cnt, ridx, rwt);

    // 7) MoE
    zero_kernel<<<(SEQ*D_MODEL + 255)/256, 256>>>(moe, SEQ*D_MODEL);
    const long long FD = (long long)D_FFN * D_MODEL;
    dim3 gUp(2*D_FFN/256, SEQ/128);
    dim3 gDn(D_MODEL/256, SEQ/128, 4);        // split-K x4
    for (int e = 0; e < NEXP; e++) {
        const float* w1e = w1 + (size_t)e * FD;
        const float* w3e = w3 + (size_t)e * FD;
        const float* w2e = w2 + (size_t)e * FD;
        const int*   ce  = cnt + e;
        const int*   ie  = ridx + e * SEQ;
        const float* we  = rwt + e * SEQ;

        gather_kernel<<<SEQ, 256>>>(ah, al, ie, ce, gxh, gxl);
        split(w1e, bh,      bl,      FD);
        split(w3e, bh + FD, bl + FD, FD);
        gemm_tc<1><<<gUp, 256, GEMM_SMEM>>>(gxh, gxl, bh, bl, h13, 0, 2*D_FFN, D_MODEL,
                                            nullptr, ce, nullptr, nullptr);
        silu_split_kernel<<<SEQ, 256>>>(h13, ce, ch, cl);
        split(w2e, bh, bl, FD);
        gemm_tc<2><<<gDn, 256, GEMM_SMEM>>>(ch, cl, bh, bl, moe, 0, D_MODEL, D_FFN,
                                            nullptr, ce, ie, we);
    }

    // 8) LN2 + final LN
    ln_kernel<<<SEQ, 256>>>(moe, x, ln2g, ln2b, y);
    ln_kernel<<<SEQ, 256>>>(y, nullptr, fing, finb, x);

    // 9) head (tf32 single-pass)
    dim3 gH((VOCAB + 255)/256, SEQ/128);
    gemm_tf32<<<gH, 256, GEMM_SMEM>>>(x, headw, out, SEQ, VOCAB, D_MODEL);

    // 10) aux
    long long nlog = (long long)SEQ * VOCAB;
    if ((long long)out_size > nlog)
        aux_kernel<<<1, 256>>>(varr, out + nlog);
}

// round 8
// speedup vs baseline: 3.6271x; 1.0664x over previous
#include <cuda_runtime.h>
#include <cuda_bf16.h>
#include <math.h>
#include <stdint.h>

#define D_MODEL 2048
#define SEQ     1024
#define N_HEADS 32
#define HEAD_DIM 64
#define NB      (SEQ/64)
#define D_FFN   8192
#define VOCAB   50257
#define NEXP    4
#define QKV_STRIDE (3*D_MODEL)

// ---------------- scratch ----------------
__device__ float g_x  [SEQ*D_MODEL];
__device__ float g_qkv[SEQ*3*D_MODEL];
__device__ float g_att[SEQ*D_MODEL];
__device__ float g_y  [SEQ*D_MODEL];
__device__ float g_h13[SEQ*2*D_FFN];
__device__ float g_moe[SEQ*D_MODEL];
__device__ float g_wts[NEXP*SEQ];
__device__ float g_var[SEQ];

// routing
__device__ int   g_cnt[NEXP];
__device__ int   g_ridx[NEXP*SEQ];
__device__ float g_rwt [NEXP*SEQ];

// bf16 split scratch (activations only now)
__device__ __nv_bfloat16 g_ah[SEQ*D_MODEL];
__device__ __nv_bfloat16 g_al[SEQ*D_MODEL];
__device__ __nv_bfloat16 g_gxh[SEQ*D_MODEL];
__device__ __nv_bfloat16 g_gxl[SEQ*D_MODEL];
__device__ __nv_bfloat16 g_ch[SEQ*D_FFN];
__device__ __nv_bfloat16 g_cl[SEQ*D_FFN];

// ---------------- PTX helpers ----------------
__device__ __forceinline__ uint32_t smem_u32(const void* p) {
    uint32_t a;
    asm("{ .reg .u64 t; cvta.to.shared.u64 t, %1; cvt.u32.u64 %0, t; }" : "=r"(a) : "l"(p));
    return a;
}
__device__ __forceinline__ void cp_async16(uint32_t dst, const void* src, int src_bytes) {
    asm volatile("cp.async.cg.shared.global [%0], [%1], 16, %2;\n"
                 :: "r"(dst), "l"(src), "r"(src_bytes) : "memory");
}
#define CP_COMMIT() asm volatile("cp.async.commit_group;\n" ::: "memory")

#define STS128(addr, a, b, c, d) \
    asm volatile("st.shared.v4.b32 [%0], {%1,%2,%3,%4};" \
                 :: "r"(addr), "r"(a), "r"(b), "r"(c), "r"(d) : "memory")

__device__ __forceinline__ void ldsm_x4(uint32_t& r0, uint32_t& r1, uint32_t& r2, uint32_t& r3,
                                        uint32_t addr) {
    asm volatile("ldmatrix.sync.aligned.m8n8.x4.shared.b16 {%0,%1,%2,%3}, [%4];"
                 : "=r"(r0), "=r"(r1), "=r"(r2), "=r"(r3) : "r"(addr));
}
__device__ __forceinline__ void mma_bf16(float* c, const uint32_t* a, const uint32_t* b) {
    asm volatile(
        "mma.sync.aligned.m16n8k16.row.col.f32.bf16.bf16.f32 "
        "{%0,%1,%2,%3}, {%4,%5,%6,%7}, {%8,%9}, {%0,%1,%2,%3};"
        : "+f"(c[0]), "+f"(c[1]), "+f"(c[2]), "+f"(c[3])
        : "r"(a[0]), "r"(a[1]), "r"(a[2]), "r"(a[3]), "r"(b[0]), "r"(b[1]));
}
__device__ __forceinline__ void mma_tf32(float* c, const uint32_t* a, const uint32_t* b) {
    asm volatile(
        "mma.sync.aligned.m16n8k8.row.col.f32.tf32.tf32.f32 "
        "{%0,%1,%2,%3}, {%4,%5,%6,%7}, {%8,%9}, {%0,%1,%2,%3};"
        : "+f"(c[0]), "+f"(c[1]), "+f"(c[2]), "+f"(c[3])
        : "r"(a[0]), "r"(a[1]), "r"(a[2]), "r"(a[3]), "r"(b[0]), "r"(b[1]));
}

__device__ __forceinline__ uint32_t pack_hi2(float a, float b) {
    __nv_bfloat162 t;
    t.x = __float2bfloat16(a); t.y = __float2bfloat16(b);
    return *(uint32_t*)&t;
}
__device__ __forceinline__ uint32_t pack_lo2(float a, float b) {
    __nv_bfloat16 ha = __float2bfloat16(a), hb = __float2bfloat16(b);
    __nv_bfloat162 t;
    t.x = __float2bfloat16(a - __bfloat162float(ha));
    t.y = __float2bfloat16(b - __bfloat162float(hb));
    return *(uint32_t*)&t;
}

// ---------------- fp32 -> (bf16 hi, bf16 lo) split (activations only) ----------------
__global__ void __launch_bounds__(256) split_kernel(
    const float* __restrict__ in, __nv_bfloat16* __restrict__ hi,
    __nv_bfloat16* __restrict__ lo, int n4)
{
    int i = blockIdx.x * 256 + threadIdx.x;
    if (i >= n4) return;
    float4 v = ((const float4*)in)[i];
    uint32_t h0 = pack_hi2(v.x, v.y), h1 = pack_hi2(v.z, v.w);
    uint32_t l0 = pack_lo2(v.x, v.y), l1 = pack_lo2(v.z, v.w);
    ((uint32_t*)hi)[i*2]   = h0;
    ((uint32_t*)hi)[i*2+1] = h1;
    ((uint32_t*)lo)[i*2]   = l0;
    ((uint32_t*)lo)[i*2+1] = l1;
}

// ================= bf16x3 GEMM: CTA 128x256, 8 warps (2Mx4N), warp 64x64 =================
// A: pre-split bf16 (hi/lo arrays), cp.async pipeline.
// B: fp32 weights read directly, converted to bf16 hi/lo in registers, STS to smem.
//    B rows select among up to 3 base pointers: row < rPB -> B0, < 2*rPB -> B1, else B2.
#define NSTG_TC 3
#define A_BYTES (128*128)
#define B_BYTES (256*128)
#define STAGE_B (A_BYTES + B_BYTES)
#define GEMM_SMEM_TC (NSTG_TC * STAGE_B)   // 147456
#define NSTG_TF 4
#define GEMM_SMEM_TF (NSTG_TF * STAGE_B)   // 196608

// MODE 0: C[m,n] = val (+residual)
// MODE 1: routed rows: M from *Mptr, plain store
// MODE 2: routed rows: M from *Mptr, atomicAdd(C[ridx[m]*N+n], rwt[m]*val); split-K via gridDim.z
template<int MODE>
__global__ void __launch_bounds__(256, 1) gemm_tc(
    const __nv_bfloat16* __restrict__ Ah, const __nv_bfloat16* __restrict__ Al,
    const float* __restrict__ B0, const float* __restrict__ B1, const float* __restrict__ B2,
    int rPB,
    float* __restrict__ C, int M_in, int N, int K,
    const float* __restrict__ residual,
    const int* __restrict__ Mptr, const int* __restrict__ ridx,
    const float* __restrict__ rwt)
{
    int M = M_in;
    if (MODE != 0) {
        M = *Mptr;
        if ((int)blockIdx.y * 128 >= M) return;
    }
    extern __shared__ char smem[];
    const uint32_t sb = smem_u32(smem);
    const int tid = threadIdx.x;
    const int wid = tid >> 5, lid = tid & 31;
    const int wm  = wid >> 2, wn = wid & 3;
    const int m0  = blockIdx.y * 128;
    const int n0  = blockIdx.x * 256;

    const int Kc    = K / (int)gridDim.z;
    const int kbase = (int)blockIdx.z * Kc;

    float acc[4][8][4];
    #pragma unroll
    for (int i = 0; i < 4; i++)
        #pragma unroll
        for (int j = 0; j < 8; j++)
            #pragma unroll
            for (int t = 0; t < 4; t++) acc[i][j][t] = 0.f;

    const int iters = Kc >> 5;

    auto fillA = [&](int stage, int kit) {
        const int k0 = kbase + (kit << 5);
        const uint32_t abase = sb + stage * STAGE_B;
        #pragma unroll
        for (int i = 0; i < 4; i++) {
            int idx = tid + i * 256;
            int r = idx >> 3, c = idx & 7;
            int rg = m0 + r;
            if (MODE != 0) rg = rg < M ? rg : (M - 1);
            uint32_t dst = abase + r * 128 + ((c ^ (r & 7)) << 4);
            const __nv_bfloat16* src = (c < 4)
                ? Ah + (size_t)rg * K + k0 + c * 8
                : Al + (size_t)rg * K + k0 + (c - 4) * 8;
            cp_async16(dst, src, 16);
        }
        CP_COMMIT();
    };

    auto ldgB = [&](float4* breg, int kit) {
        const int k0 = kbase + (kit << 5);
        #pragma unroll
        for (int i = 0; i < 4; i++) {
            int idx = tid + i * 256;
            int r = idx >> 2, c2 = idx & 3;
            int rg = n0 + r;
            int rc = rg < N ? rg : (N - 1);
            const float* Bp; int rr;
            if (rc < rPB)           { Bp = B0; rr = rc; }
            else if (rc < 2 * rPB)  { Bp = B1; rr = rc - rPB; }
            else                    { Bp = B2; rr = rc - 2 * rPB; }
            const float4* s4 = (const float4*)(Bp + (size_t)rr * K + k0 + c2 * 8);
            breg[i*2]     = s4[0];
            breg[i*2 + 1] = s4[1];
        }
    };

    auto stsB = [&](const float4* breg, int stage) {
        const uint32_t bbase = sb + stage * STAGE_B + A_BYTES;
        #pragma unroll
        for (int i = 0; i < 4; i++) {
            int idx = tid + i * 256;
            int r = idx >> 2, c2 = idx & 3;
            float4 v0 = breg[i*2], v1 = breg[i*2 + 1];
            uint32_t h0 = pack_hi2(v0.x, v0.y), h1 = pack_hi2(v0.z, v0.w);
            uint32_t h2 = pack_hi2(v1.x, v1.y), h3 = pack_hi2(v1.z, v1.w);
            uint32_t l0 = pack_lo2(v0.x, v0.y), l1 = pack_lo2(v0.z, v0.w);
            uint32_t l2 = pack_lo2(v1.x, v1.y), l3 = pack_lo2(v1.z, v1.w);
            uint32_t ha = bbase + r * 128 + ((c2 ^ (r & 7)) << 4);
            uint32_t la = bbase + r * 128 + (((c2 + 4) ^ (r & 7)) << 4);
            STS128(ha, h0, h1, h2, h3);
            STS128(la, l0, l1, l2, l3);
        }
    };

    // prologue: stages 0..NSTG_TC-2
    {
        float4 pb[8];
        #pragma unroll
        for (int s = 0; s < NSTG_TC - 1; s++) {
            fillA(s, s);
            ldgB(pb, s);
            stsB(pb, s);
        }
    }

    const int grp = lid >> 3;
    const int rin = lid & 7;
    float4 breg[8];

    for (int i = 0; i < iters; i++) {
        const int s = i % NSTG_TC;
        const bool pre = (i + NSTG_TC - 1 < iters);
        if (pre) ldgB(breg, i + NSTG_TC - 1);

        asm volatile("cp.async.wait_group %0;\n" :: "n"(NSTG_TC - 2));
        __syncthreads();

        if (pre) fillA((i + NSTG_TC - 1) % NSTG_TC, i + NSTG_TC - 1);
        else CP_COMMIT();

        const uint32_t abase = sb + s * STAGE_B;
        const uint32_t bbase = abase + A_BYTES;

        #pragma unroll
        for (int g = 0; g < 2; g++) {
            uint32_t ah[4][4], bh[8][2];
            #pragma unroll
            for (int mt = 0; mt < 4; mt++) {
                int row = wm * 64 + mt * 16 + (grp & 1) * 8 + rin;
                int kch = 2 * g + (grp >> 1);
                uint32_t ad = abase + row * 128 + ((kch ^ (row & 7)) << 4);
                ldsm_x4(ah[mt][0], ah[mt][1], ah[mt][2], ah[mt][3], ad);
            }
            #pragma unroll
            for (int p = 0; p < 4; p++) {
                int tile = 2 * p + (grp >> 1);
                int row  = wn * 64 + tile * 8 + rin;
                int kch  = 2 * g + (grp & 1);
                uint32_t bd = bbase + row * 128 + ((kch ^ (row & 7)) << 4);
                ldsm_x4(bh[2*p][0], bh[2*p][1], bh[2*p+1][0], bh[2*p+1][1], bd);
            }
            #pragma unroll
            for (int mt = 0; mt < 4; mt++)
                #pragma unroll
                for (int nt = 0; nt < 8; nt++)
                    mma_bf16(acc[mt][nt], ah[mt], bh[nt]);
            {
                uint32_t al[4][4];
                #pragma unroll
                for (int mt = 0; mt < 4; mt++) {
                    int row = wm * 64 + mt * 16 + (grp & 1) * 8 + rin;
                    int kcl = 4 + 2 * g + (grp >> 1);
                    uint32_t adl = abase + row * 128 + ((kcl ^ (row & 7)) << 4);
                    ldsm_x4(al[mt][0], al[mt][1], al[mt][2], al[mt][3], adl);
                }
                #pragma unroll
                for (int mt = 0; mt < 4; mt++)
                    #pragma unroll
                    for (int nt = 0; nt < 8; nt++)
                        mma_bf16(acc[mt][nt], al[mt], bh[nt]);
            }
            {
                uint32_t bl[8][2];
                #pragma unroll
                for (int p = 0; p < 4; p++) {
                    int tile = 2 * p + (grp >> 1);
                    int row  = wn * 64 + tile * 8 + rin;
                    int kcl  = 4 + 2 * g + (grp & 1);
                    uint32_t bdl = bbase + row * 128 + ((kcl ^ (row & 7)) << 4);
                    ldsm_x4(bl[2*p][0], bl[2*p][1], bl[2*p+1][0], bl[2*p+1][1], bdl);
                }
                #pragma unroll
                for (int mt = 0; mt < 4; mt++)
                    #pragma unroll
                    for (int nt = 0; nt < 8; nt++)
                        mma_bf16(acc[mt][nt], ah[mt], bl[nt]);
            }
        }

        if (pre) stsB(breg, (i + NSTG_TC - 1) % NSTG_TC);
    }

    #pragma unroll
    for (int mt = 0; mt < 4; mt++) {
        #pragma unroll
        for (int nt = 0; nt < 8; nt++) {
            int rbase = m0 + wm * 64 + mt * 16 + (lid >> 2);
            int col = n0 + wn * 64 + nt * 8 + (lid & 3) * 2;
            #pragma unroll
            for (int h = 0; h < 2; h++) {
                int m = rbase + h * 8;
                float v0 = acc[mt][nt][h * 2 + 0];
                float v1 = acc[mt][nt][h * 2 + 1];
                if (MODE == 0) {
                    size_t idx = (size_t)m * N + col;
                    if (residual) {
                        if (col     < N) v0 += residual[idx];
                        if (col + 1 < N) v1 += residual[idx + 1];
                    }
                    if (col     < N) C[idx]     = v0;
                    if (col + 1 < N) C[idx + 1] = v1;
                } else if (MODE == 1) {
                    if (m < M) {
                        size_t idx = (size_t)m * N + col;
                        C[idx]     = v0;
                        C[idx + 1] = v1;
                    }
                } else {
                    if (m < M) {
                        int tok = ridx[m];
                        float w = rwt[m];
                        size_t idx = (size_t)tok * N + col;
                        atomicAdd(&C[idx],     w * v0);
                        atomicAdd(&C[idx + 1], w * v1);
                    }
                }
            }
        }
    }
}

// ================= tf32 single-pass GEMM (head) =================
__global__ void __launch_bounds__(256, 1) gemm_tf32(
    const float* __restrict__ A, const float* __restrict__ B,
    float* __restrict__ C, int M, int N, int K)
{
    extern __shared__ char smem[];
    const uint32_t sb = smem_u32(smem);
    const int tid = threadIdx.x;
    const int wid = tid >> 5, lid = tid & 31;
    const int wm  = wid >> 2, wn = wid & 3;
    const int m0  = blockIdx.y * 128;
    const int n0  = blockIdx.x * 256;

    float acc[4][8][4];
    #pragma unroll
    for (int i = 0; i < 4; i++)
        #pragma unroll
        for (int j = 0; j < 8; j++)
            #pragma unroll
            for (int t = 0; t < 4; t++) acc[i][j][t] = 0.f;

    const int iters = K >> 5;

    auto fill = [&](int stage, int kit) {
        const int k0 = kit << 5;
        const uint32_t abase = sb + stage * STAGE_B;
        const uint32_t bbase = abase + A_BYTES;
        #pragma unroll
        for (int i = 0; i < 4; i++) {
            int idx = tid + i * 256;
            int r = idx >> 3, c = idx & 7;
            uint32_t dst = abase + r * 128 + ((c ^ (r & 7)) << 4);
            cp_async16(dst, A + (size_t)(m0 + r) * K + k0 + c * 4, 16);
        }
        #pragma unroll
        for (int i = 0; i < 8; i++) {
            int idx = tid + i * 256;
            int r = idx >> 3, c = idx & 7;
            uint32_t dst = bbase + r * 128 + ((c ^ (r & 7)) << 4);
            int rg = n0 + r;
            int rc = rg < N ? rg : (N - 1);
            cp_async16(dst, B + (size_t)rc * K + k0 + c * 4, rg < N ? 16 : 0);
        }
        CP_COMMIT();
    };

    #pragma unroll
    for (int s = 0; s < NSTG_TF - 1; s++) fill(s, s);

    const int grp = lid >> 3;
    const int rin = lid & 7;

    for (int i = 0; i < iters; i++) {
        const int s = i % NSTG_TF;
        asm volatile("cp.async.wait_group %0;\n" :: "n"(NSTG_TF - 2));
        __syncthreads();

        if (i + NSTG_TF - 1 < iters) fill((i + NSTG_TF - 1) % NSTG_TF, i + NSTG_TF - 1);
        else CP_COMMIT();

        const uint32_t abase = sb + s * STAGE_B;
        const uint32_t bbase = abase + A_BYTES;

        #pragma unroll
        for (int k8 = 0; k8 < 4; k8++) {
            uint32_t a[4][4], b[8][2];
            #pragma unroll
            for (int mt = 0; mt < 4; mt++) {
                int row = wm * 64 + mt * 16 + (grp & 1) * 8 + rin;
                int kc  = k8 * 2 + (grp >> 1);
                uint32_t addr = abase + row * 128 + ((kc ^ (row & 7)) << 4);
                ldsm_x4(a[mt][0], a[mt][1], a[mt][2], a[mt][3], addr);
            }
            #pragma unroll
            for (int p = 0; p < 4; p++) {
                int tile = 2 * p + (grp >> 1);
                int row  = wn * 64 + tile * 8 + rin;
                int kc   = k8 * 2 + (grp & 1);
                uint32_t addr = bbase + row * 128 + ((kc ^ (row & 7)) << 4);
                ldsm_x4(b[2*p][0], b[2*p][1], b[2*p+1][0], b[2*p+1][1], addr);
            }
            #pragma unroll
            for (int mt = 0; mt < 4; mt++)
                #pragma unroll
                for (int nt = 0; nt < 8; nt++)
                    mma_tf32(acc[mt][nt], a[mt], b[nt]);
        }
    }

    #pragma unroll
    for (int mt = 0; mt < 4; mt++) {
        #pragma unroll
        for (int nt = 0; nt < 8; nt++) {
            int rbase = m0 + wm * 64 + mt * 16 + (lid >> 2);
            int col = n0 + wn * 64 + nt * 8 + (lid & 3) * 2;
            #pragma unroll
            for (int h = 0; h < 2; h++) {
                int m = rbase + h * 8;
                size_t idx = (size_t)m * N + col;
                if (col     < N) C[idx]     = acc[mt][nt][h * 2 + 0];
                if (col + 1 < N) C[idx + 1] = acc[mt][nt][h * 2 + 1];
            }
        }
    }
}

// ---------------- embedding ----------------
__global__ void embed_kernel(const int* __restrict__ tok,
                             const float* __restrict__ emb,
                             float* __restrict__ x) {
    int t = blockIdx.x;
    int tk = tok[t];
    for (int d = threadIdx.x; d < D_MODEL; d += 256)
        x[(size_t)t*D_MODEL + d] = emb[(size_t)tk*D_MODEL + d];
}

// ---------------- RoPE ----------------
__global__ void rope_kernel(float* __restrict__ qkv) {
    int t = blockIdx.x, h = blockIdx.y, i = threadIdx.x;
    float inv = powf(10000.f, -((float)(2*i)) / 64.f);
    float ang = (float)t * inv;
    float s, c;
    sincosf(ang, &s, &c);
    size_t base = (size_t)t*QKV_STRIDE + h*HEAD_DIM + 2*i;
    float q0 = qkv[base], q1 = qkv[base+1];
    qkv[base]   = q0*c - q1*s;
    qkv[base+1] = q0*s + q1*c;
    size_t kb = base + D_MODEL;
    float k0 = qkv[kb], k1 = qkv[kb+1];
    qkv[kb]   = k0*c - k1*s;
    qkv[kb+1] = k0*s + k1*c;
}

// ---------------- blocked attention (exact ref semantics) ----------------
#define ATTN_SMEM (4 * 64 * 65 * 4)
__global__ void __launch_bounds__(256) attn_kernel(
    const float* __restrict__ qkv, float* __restrict__ o)
{
    extern __shared__ float sm[];
    float* Qs = sm;
    float* Ks = Qs + 64*65;
    float* Vs = Ks + 64*65;
    float* Ps = Vs + 64*65;
    const int ib = blockIdx.x, h = blockIdx.y;
    const int tid = threadIdx.x;
    const int qr  = tid >> 2;
    const int c0  = (tid & 3) * 16;

    for (int idx = tid; idx < 64*64; idx += 256) {
        int r = idx >> 6, c = idx & 63;
        Qs[r*65 + c] = qkv[(size_t)(ib*64+r)*QKV_STRIDE + h*HEAD_DIM + c];
    }

    float accO[16];
    #pragma unroll
    for (int i = 0; i < 16; i++) accO[i] = 0.f;
    float den = 0.f;

    for (int jb = 0; jb <= ib; jb++) {
        __syncthreads();
        for (int idx = tid; idx < 64*64; idx += 256) {
            int r = idx >> 6, c = idx & 63;
            size_t base = (size_t)(jb*64+r)*QKV_STRIDE + h*HEAD_DIM + c;
            Ks[r*65 + c] = qkv[base + D_MODEL];
            Vs[r*65 + c] = qkv[base + 2*D_MODEL];
        }
        __syncthreads();

        float s[16];
        float mx = -1e30f;
        #pragma unroll
        for (int cc = 0; cc < 16; cc++) {
            int c = c0 + cc;
            float dot = 0.f;
            #pragma unroll
            for (int d = 0; d < 64; d++)
                dot = fmaf(Qs[qr*65 + d], Ks[c*65 + d], dot);
            dot *= 0.125f;
            if (jb == ib && c > qr) dot = -1e30f;
            s[cc] = dot;
            mx = fmaxf(mx, dot);
        }
        mx = fmaxf(mx, __shfl_xor_sync(0xffffffffu, mx, 1));
        mx = fmaxf(mx, __shfl_xor_sync(0xffffffffu, mx, 2));

        #pragma unroll
        for (int cc = 0; cc < 16; cc++) {
            float p = expf(s[cc] - mx);
            Ps[qr*65 + c0 + cc] = p;
            den += p;
        }
        __syncthreads();

        #pragma unroll 8
        for (int kk = 0; kk < 64; kk++) {
            float pv = Ps[qr*65 + kk];
            #pragma unroll
            for (int d = 0; d < 16; d++)
                accO[d] = fmaf(pv, Vs[kk*65 + c0 + d], accO[d]);
        }
    }

    den += __shfl_xor_sync(0xffffffffu, den, 1);
    den += __shfl_xor_sync(0xffffffffu, den, 2);
    float invd = 1.f / (den + 1e-6f);
    #pragma unroll
    for (int d = 0; d < 16; d++)
        o[(size_t)(ib*64+qr)*D_MODEL + h*HEAD_DIM + c0 + d] = accO[d] * invd;
}

// ---------------- layernorm ----------------
__global__ void __launch_bounds__(256) ln_kernel(
    const float* __restrict__ in, const float* __restrict__ res,
    const float* __restrict__ g, const float* __restrict__ b,
    float* __restrict__ out)
{
    __shared__ float red[256];
    int t = blockIdx.x, tid = threadIdx.x;
    float v[8];
    float sum = 0.f;
    #pragma unroll
    for (int i = 0; i < 8; i++) {
        int d = i*256 + tid;
        float x = in[(size_t)t*D_MODEL + d];
        if (res) x += res[(size_t)t*D_MODEL + d];
        v[i] = x; sum += x;
    }
    red[tid] = sum; __syncthreads();
    for (int s = 128; s > 0; s >>= 1) { if (tid < s) red[tid] += red[tid+s]; __syncthreads(); }
    float mu = red[0] / D_MODEL;
    __syncthreads();
    float sq = 0.f;
    #pragma unroll
    for (int i = 0; i < 8; i++) { float d0 = v[i] - mu; sq += d0*d0; }
    red[tid] = sq; __syncthreads();
    for (int s = 128; s > 0; s >>= 1) { if (tid < s) red[tid] += red[tid+s]; __syncthreads(); }
    float rstd = rsqrtf(red[0] / D_MODEL + 1e-5f);
    #pragma unroll
    for (int i = 0; i < 8; i++) {
        int d = i*256 + tid;
        out[(size_t)t*D_MODEL + d] = (v[i] - mu) * rstd * g[d] + b[d];
    }
}

// ---------------- MoE gate ----------------
__global__ void __launch_bounds__(128) gate_kernel(
    const float* __restrict__ x, const float* __restrict__ gw,
    float* __restrict__ wts, float* __restrict__ varr)
{
    __shared__ float red[128];
    __shared__ float logit[4];
    int t = blockIdx.x, tid = threadIdx.x;
    float p[4] = {0.f, 0.f, 0.f, 0.f};
    for (int d = tid; d < D_MODEL; d += 128) {
        float xv = x[(size_t)t*D_MODEL + d];
        #pragma unroll
        for (int e = 0; e < 4; e++)
            p[e] = fmaf(xv, gw[e*D_MODEL + d], p[e]);
    }
    for (int e = 0; e < 4; e++) {
        red[tid] = p[e]; __syncthreads();
        for (int s = 64; s > 0; s >>= 1) { if (tid < s) red[tid] += red[tid+s]; __syncthreads(); }
        if (tid == 0) logit[e] = red[0];
        __syncthreads();
    }
    if (tid == 0) {
        float l[4] = {logit[0], logit[1], logit[2], logit[3]};
        float mx = fmaxf(fmaxf(l[0], l[1]), fmaxf(l[2], l[3]));
        float ex[4], ssum = 0.f;
        for (int e = 0; e < 4; e++) { ex[e] = expf(l[e] - mx); ssum += ex[e]; }
        float pr[4];
        for (int e = 0; e < 4; e++) pr[e] = ex[e] / ssum;
        int b1 = 0;
        for (int e = 1; e < 4; e++) if (pr[e] > pr[b1]) b1 = e;
        int b2 = -1;
        for (int e = 0; e < 4; e++) { if (e == b1) continue; if (b2 < 0 || pr[e] > pr[b2]) b2 = e; }
        float s2 = pr[b1] + pr[b2];
        float wv[4] = {0.f, 0.f, 0.f, 0.f};
        wv[b1] = pr[b1] / s2; wv[b2] = pr[b2] / s2;
        for (int e = 0; e < 4; e++) wts[e*SEQ + t] = wv[e];
        float mu = (l[0]+l[1]+l[2]+l[3]) * 0.25f;
        float va = ((l[0]-mu)*(l[0]-mu) + (l[1]-mu)*(l[1]-mu) +
                    (l[2]-mu)*(l[2]-mu) + (l[3]-mu)*(l[3]-mu)) / 3.f;
        varr[t] = va;
    }
}

// ---------------- routing compaction ----------------
__global__ void __launch_bounds__(1024) compact_kernel(
    const float* __restrict__ wts, int* __restrict__ cnt,
    int* __restrict__ ridx, float* __restrict__ rwt)
{
    __shared__ int sc[1024];
    int e = blockIdx.x, t = threadIdx.x;
    float w = wts[e*SEQ + t];
    int flag = (w != 0.f) ? 1 : 0;
    sc[t] = flag;
    __syncthreads();
    for (int off = 1; off < 1024; off <<= 1) {
        int v = (t >= off) ? sc[t - off] : 0;
        __syncthreads();
        sc[t] += v;
        __syncthreads();
    }
    if (flag) {
        int pos = sc[t] - 1;
        ridx[e*SEQ + pos] = t;
        rwt [e*SEQ + pos] = w;
    }
    if (t == 1023) cnt[e] = sc[1023];
}

__global__ void __launch_bounds__(256) gather_kernel(
    const __nv_bfloat16* __restrict__ ah, const __nv_bfloat16* __restrict__ al,
    const int* __restrict__ ridx, const int* __restrict__ cnt,
    __nv_bfloat16* __restrict__ gh, __nv_bfloat16* __restrict__ gl)
{
    int row = blockIdx.x;
    if (row >= *cnt) return;
    int tok = ridx[row];
    const uint4* sh = (const uint4*)(ah + (size_t)tok*D_MODEL);
    const uint4* sl = (const uint4*)(al + (size_t)tok*D_MODEL);
    uint4* dh = (uint4*)(gh + (size_t)row*D_MODEL);
    uint4* dl = (uint4*)(gl + (size_t)row*D_MODEL);
    int c = threadIdx.x;
    dh[c] = sh[c];
    dl[c] = sl[c];
}

// fused silu(h1)*h3 -> split bf16
__global__ void __launch_bounds__(256) silu_split_kernel(
    const float* __restrict__ h13, const int* __restrict__ cnt,
    __nv_bfloat16* __restrict__ ch, __nv_bfloat16* __restrict__ cl)
{
    int row = blockIdx.x;
    if (row >= *cnt) return;
    size_t src = (size_t)row * (2*D_FFN);
    size_t dst = (size_t)row * D_FFN;
    for (int c = threadIdx.x; c < D_FFN; c += 256) {
        float a = h13[src + c];
        float v = a / (1.f + expf(-a)) * h13[src + D_FFN + c];
        __nv_bfloat16 hi = __float2bfloat16(v);
        ch[dst + c] = hi;
        cl[dst + c] = __float2bfloat16(v - __bfloat162float(hi));
    }
}

__global__ void aux_kernel(const float* __restrict__ varr, float* __restrict__ out) {
    __shared__ float red[256];
    int tid = threadIdx.x;
    float s = 0.f;
    for (int i = tid; i < SEQ; i += 256) s += varr[i];
    red[tid] = s; __syncthreads();
    for (int st = 128; st > 0; st >>= 1) { if (tid < st) red[tid] += red[tid+st]; __syncthreads(); }
    if (tid == 0) out[0] = red[0] / (float)SEQ;
}

__global__ void zero_kernel(float* __restrict__ p, int n) {
    int i = blockIdx.x * 256 + threadIdx.x;
    if (i < n) p[i] = 0.f;
}

// ---------------- driver ----------------
static inline void split(const float* src, __nv_bfloat16* hi, __nv_bfloat16* lo, long long n) {
    int n4 = (int)(n / 4);
    split_kernel<<<(n4 + 255)/256, 256>>>(src, hi, lo, n4);
}

extern "C" void kernel_launch(void* const* d_in, const int* in_sizes, int n_in,
                              void* d_out, int out_size) {
    const int*   tokens = (const int*)  d_in[0];
    const float* emb    = (const float*)d_in[1];
    const float* wq     = (const float*)d_in[2];
    const float* wk     = (const float*)d_in[3];
    const float* wv     = (const float*)d_in[4];
    const float* wo     = (const float*)d_in[5];
    const float* ln1g   = (const float*)d_in[6];
    const float* ln1b   = (const float*)d_in[7];
    const float* gatew  = (const float*)d_in[8];
    const float* w1     = (const float*)d_in[9];
    const float* w2     = (const float*)d_in[10];
    const float* w3     = (const float*)d_in[11];
    const float* ln2g   = (const float*)d_in[12];
    const float* ln2b   = (const float*)d_in[13];
    const float* fing   = (const float*)d_in[14];
    const float* finb   = (const float*)d_in[15];
    const float* headw  = (const float*)d_in[16];
    float* out = (float*)d_out;

    float *x, *qkv, *att, *y, *h13, *moe, *wts, *varr, *rwt;
    int *cnt, *ridx;
    __nv_bfloat16 *ah, *al, *gxh, *gxl, *ch, *cl;
    cudaGetSymbolAddress((void**)&x,    g_x);
    cudaGetSymbolAddress((void**)&qkv,  g_qkv);
    cudaGetSymbolAddress((void**)&att,  g_att);
    cudaGetSymbolAddress((void**)&y,    g_y);
    cudaGetSymbolAddress((void**)&h13,  g_h13);
    cudaGetSymbolAddress((void**)&moe,  g_moe);
    cudaGetSymbolAddress((void**)&wts,  g_wts);
    cudaGetSymbolAddress((void**)&varr, g_var);
    cudaGetSymbolAddress((void**)&cnt,  g_cnt);
    cudaGetSymbolAddress((void**)&ridx, g_ridx);
    cudaGetSymbolAddress((void**)&rwt,  g_rwt);
    cudaGetSymbolAddress((void**)&ah,   g_ah);
    cudaGetSymbolAddress((void**)&al,   g_al);
    cudaGetSymbolAddress((void**)&gxh,  g_gxh);
    cudaGetSymbolAddress((void**)&gxl,  g_gxl);
    cudaGetSymbolAddress((void**)&ch,   g_ch);
    cudaGetSymbolAddress((void**)&cl,   g_cl);

    cudaFuncSetAttribute(attn_kernel, cudaFuncAttributeMaxDynamicSharedMemorySize, ATTN_SMEM);
    cudaFuncSetAttribute(gemm_tc<0>, cudaFuncAttributeMaxDynamicSharedMemorySize, GEMM_SMEM_TC);
    cudaFuncSetAttribute(gemm_tc<1>, cudaFuncAttributeMaxDynamicSharedMemorySize, GEMM_SMEM_TC);
    cudaFuncSetAttribute(gemm_tc<2>, cudaFuncAttributeMaxDynamicSharedMemorySize, GEMM_SMEM_TC);
    cudaFuncSetAttribute(gemm_tf32, cudaFuncAttributeMaxDynamicSharedMemorySize, GEMM_SMEM_TF);

    // 1) embed + split x
    embed_kernel<<<SEQ, 256>>>(tokens, emb, x);
    split(x, ah, al, (long long)SEQ * D_MODEL);

    // 2) fused QKV (N=6144) — weights fp32 direct
    dim3 gQKV(3*D_MODEL/256, SEQ/128);
    gemm_tc<0><<<gQKV, 256, GEMM_SMEM_TC>>>(ah, al, wq, wk, wv, D_MODEL,
                                            qkv, SEQ, 3*D_MODEL, D_MODEL,
                                            nullptr, nullptr, nullptr, nullptr);

    // 3) RoPE + attention
    rope_kernel<<<dim3(SEQ, N_HEADS), 32>>>(qkv);
    attn_kernel<<<dim3(NB, N_HEADS), 256, ATTN_SMEM>>>(qkv, att);

    // 4) output proj + residual — wo fp32 direct
    dim3 gA(D_MODEL/256, SEQ/128);
    split(att, ah, al, (long long)SEQ * D_MODEL);
    gemm_tc<0><<<gA, 256, GEMM_SMEM_TC>>>(ah, al, wo, wo, wo, D_MODEL,
                                          y, SEQ, D_MODEL, D_MODEL,
                                          x, nullptr, nullptr, nullptr);

    // 5) LN1 -> x, split for MoE
    ln_kernel<<<SEQ, 256>>>(y, nullptr, ln1g, ln1b, x);
    split(x, ah, al, (long long)SEQ * D_MODEL);

    // 6) gate + routing
    gate_kernel<<<SEQ, 128>>>(x, gatew, wts, varr);
    compact_kernel<<<NEXP, 1024>>>(wts, cnt, ridx, rwt);

    // 7) MoE — weights fp32 direct
    zero_kernel<<<(SEQ*D_MODEL + 255)/256, 256>>>(moe, SEQ*D_MODEL);
    const long long FD = (long long)D_FFN * D_MODEL;
    dim3 gUp(2*D_FFN/256, SEQ/128);
    dim3 gDn(D_MODEL/256, SEQ/128, 4);        // split-K x4
    for (int e = 0; e < NEXP; e++) {
        const float* w1e = w1 + (size_t)e * FD;
        const float* w3e = w3 + (size_t)e * FD;
        const float* w2e = w2 + (size_t)e * FD;
        const int*   ce  = cnt + e;
        const int*   ie  = ridx + e * SEQ;
        const float* we  = rwt + e * SEQ;

        gather_kernel<<<SEQ, 256>>>(ah, al, ie, ce, gxh, gxl);
        gemm_tc<1><<<gUp, 256, GEMM_SMEM_TC>>>(gxh, gxl, w1e, w3e, w3e, D_FFN,
                                               h13, 0, 2*D_FFN, D_MODEL,
                                               nullptr, ce, nullptr, nullptr);
        silu_split_kernel<<<SEQ, 256>>>(h13, ce, ch, cl);
        gemm_tc<2><<<gDn, 256, GEMM_SMEM_TC>>>(ch, cl, w2e, w2e, w2e, D_MODEL,
                                               moe, 0, D_MODEL, D_FFN,
                                               nullptr, ce, ie, we);
    }

    // 8) LN2 + final LN
    ln_kernel<<<SEQ, 256>>>(moe, x, ln2g, ln2b, y);
    ln_kernel<<<SEQ, 256>>>(y, nullptr, fing, finb, x);

    // 9) head (tf32 single-pass, fp32 operands)
    dim3 gH((VOCAB + 255)/256, SEQ/128);
    gemm_tf32<<<gH, 256, GEMM_SMEM_TF>>>(x, headw, out, SEQ, VOCAB, D_MODEL);

    // 10) aux
    long long nlog = (long long)SEQ * VOCAB;
    if ((long long)out_size > nlog)
        aux_kernel<<<1, 256>>>(varr, out + nlog);
}

// round 9
// speedup vs baseline: 4.1828x; 1.1532x over previous
#include <cuda_runtime.h>
#include <cuda_bf16.h>
#include <math.h>
#include <stdint.h>

#define D_MODEL 2048
#define SEQ     1024
#define N_HEADS 32
#define HEAD_DIM 64
#define NB      (SEQ/64)
#define D_FFN   8192
#define VOCAB   50257
#define NEXP    4
#define QKV_STRIDE (3*D_MODEL)

// ---------------- scratch ----------------
__device__ float g_x  [SEQ*D_MODEL];
__device__ float g_qkv[SEQ*3*D_MODEL];
__device__ float g_att[SEQ*D_MODEL];
__device__ float g_y  [SEQ*D_MODEL];
__device__ float g_h13[(size_t)NEXP*SEQ*2*D_FFN];
__device__ float g_moe[SEQ*D_MODEL];
__device__ float g_wts[NEXP*SEQ];
__device__ float g_var[SEQ];

// routing
__device__ int   g_cnt[NEXP];
__device__ int   g_ridx[NEXP*SEQ];
__device__ float g_rwt [NEXP*SEQ];

// bf16 split scratch (activations only)
__device__ __nv_bfloat16 g_ah[SEQ*D_MODEL];
__device__ __nv_bfloat16 g_al[SEQ*D_MODEL];
__device__ __nv_bfloat16 g_ch[(size_t)NEXP*SEQ*D_FFN];
__device__ __nv_bfloat16 g_cl[(size_t)NEXP*SEQ*D_FFN];

// ---------------- PTX helpers ----------------
__device__ __forceinline__ uint32_t smem_u32(const void* p) {
    uint32_t a;
    asm("{ .reg .u64 t; cvta.to.shared.u64 t, %1; cvt.u32.u64 %0, t; }" : "=r"(a) : "l"(p));
    return a;
}
__device__ __forceinline__ void cp_async16(uint32_t dst, const void* src, int src_bytes) {
    asm volatile("cp.async.cg.shared.global [%0], [%1], 16, %2;\n"
                 :: "r"(dst), "l"(src), "r"(src_bytes) : "memory");
}
#define CP_COMMIT() asm volatile("cp.async.commit_group;\n" ::: "memory")

#define STS128(addr, a, b, c, d) \
    asm volatile("st.shared.v4.b32 [%0], {%1,%2,%3,%4};" \
                 :: "r"(addr), "r"(a), "r"(b), "r"(c), "r"(d) : "memory")

__device__ __forceinline__ void ldsm_x4(uint32_t& r0, uint32_t& r1, uint32_t& r2, uint32_t& r3,
                                        uint32_t addr) {
    asm volatile("ldmatrix.sync.aligned.m8n8.x4.shared.b16 {%0,%1,%2,%3}, [%4];"
                 : "=r"(r0), "=r"(r1), "=r"(r2), "=r"(r3) : "r"(addr));
}
__device__ __forceinline__ void mma_bf16(float* c, const uint32_t* a, const uint32_t* b) {
    asm volatile(
        "mma.sync.aligned.m16n8k16.row.col.f32.bf16.bf16.f32 "
        "{%0,%1,%2,%3}, {%4,%5,%6,%7}, {%8,%9}, {%0,%1,%2,%3};"
        : "+f"(c[0]), "+f"(c[1]), "+f"(c[2]), "+f"(c[3])
        : "r"(a[0]), "r"(a[1]), "r"(a[2]), "r"(a[3]), "r"(b[0]), "r"(b[1]));
}
__device__ __forceinline__ void mma_tf32(float* c, const uint32_t* a, const uint32_t* b) {
    asm volatile(
        "mma.sync.aligned.m16n8k8.row.col.f32.tf32.tf32.f32 "
        "{%0,%1,%2,%3}, {%4,%5,%6,%7}, {%8,%9}, {%0,%1,%2,%3};"
        : "+f"(c[0]), "+f"(c[1]), "+f"(c[2]), "+f"(c[3])
        : "r"(a[0]), "r"(a[1]), "r"(a[2]), "r"(a[3]), "r"(b[0]), "r"(b[1]));
}

__device__ __forceinline__ void split2(float a, float b, uint32_t& hi, uint32_t& lo) {
    __nv_bfloat16 ha = __float2bfloat16(a), hb = __float2bfloat16(b);
    __nv_bfloat162 h; h.x = ha; h.y = hb;
    __nv_bfloat162 l;
    l.x = __float2bfloat16(a - __bfloat162float(ha));
    l.y = __float2bfloat16(b - __bfloat162float(hb));
    hi = *(uint32_t*)&h;
    lo = *(uint32_t*)&l;
}

// ---------------- fp32 -> (bf16 hi, bf16 lo) split (activations) ----------------
__global__ void __launch_bounds__(256) split_kernel(
    const float* __restrict__ in, __nv_bfloat16* __restrict__ hi,
    __nv_bfloat16* __restrict__ lo, int n4)
{
    int i = blockIdx.x * 256 + threadIdx.x;
    if (i >= n4) return;
    float4 v = ((const float4*)in)[i];
    uint32_t h0, h1, l0, l1;
    split2(v.x, v.y, h0, l0);
    split2(v.z, v.w, h1, l1);
    ((uint32_t*)hi)[i*2]   = h0;
    ((uint32_t*)hi)[i*2+1] = h1;
    ((uint32_t*)lo)[i*2]   = l0;
    ((uint32_t*)lo)[i*2+1] = l1;
}

// ================= bf16x3 GEMM: CTA 128x256, 8 warps (2Mx4N), warp 64x64 =================
// A: pre-split bf16 hi/lo, cp.async pipeline (token-indirect in MODE 1).
// B: fp32 weights read directly, converted to bf16 hi/lo in regs, STS.
#define NSTG_TC 3
#define A_BYTES (128*128)
#define B_BYTES (256*128)
#define STAGE_B (A_BYTES + B_BYTES)
#define GEMM_SMEM_TC (NSTG_TC * STAGE_B)   // 147456
#define NSTG_TF 4
#define GEMM_SMEM_TF (NSTG_TF * STAGE_B)   // 196608

// MODE 0: dense. C[m,n]=val(+residual). B rows: <rPB->B0, <2rPB->B1, else B2.
// MODE 1: expert-batched up. e=blockIdx.z. M=cnt[e]. A rows via ridx[e]. B rows: <rPB->B0+e*sB else B1+e*sB.
//         C = Cbase + e*sC, plain store.
// MODE 2: expert-batched down + split-K4. e=z>>2, ks=z&3. A = Ah+e*sA (compacted). B=B0+e*sB.
//         atomicAdd(C[ridx[e][m]*N+n], rwt[e][m]*val).
template<int MODE>
__global__ void __launch_bounds__(256, 1) gemm_tc(
    const __nv_bfloat16* __restrict__ Ah, const __nv_bfloat16* __restrict__ Al,
    const float* __restrict__ B0, const float* __restrict__ B1, const float* __restrict__ B2,
    int rPB,
    float* __restrict__ C, int M_in, int N, int K,
    const float* __restrict__ residual,
    const int* __restrict__ cntArr, const int* __restrict__ ridxAll,
    const float* __restrict__ rwtAll,
    long long sA, long long sB, long long sC)
{
    const int tid = threadIdx.x;
    const int m0  = blockIdx.y * 128;
    const int n0  = blockIdx.x * 256;

    int M = M_in;
    int e = 0, kbase = 0, Kc = K;
    const int* ridx = ridxAll;
    const float* rwt = rwtAll;
    const float* b0p = B0; const float* b1p = B1; const float* b2p = B2;
    const __nv_bfloat16* ahp = Ah; const __nv_bfloat16* alp = Al;
    float* Cp = C;

    if (MODE == 1) {
        e = blockIdx.z;
        M = cntArr[e];
        if (m0 >= M) return;
        ridx = ridxAll + e * SEQ;
        b0p = B0 + (size_t)e * sB;
        b1p = B1 + (size_t)e * sB;
        Cp  = C + (size_t)e * sC;
    } else if (MODE == 2) {
        e = blockIdx.z >> 2;
        int ks = blockIdx.z & 3;
        M = cntArr[e];
        if (m0 >= M) return;
        ridx = ridxAll + e * SEQ;
        rwt  = rwtAll + e * SEQ;
        ahp = Ah + (size_t)e * sA;
        alp = Al + (size_t)e * sA;
        b0p = B0 + (size_t)e * sB;
        Kc = K >> 2;
        kbase = ks * Kc;
    }

    // per-thread A row sources (4 rows per thread across the fill)
    int arow[4];
    #pragma unroll
    for (int i = 0; i < 4; i++) {
        int r = (tid + i * 256) >> 3;
        int rg = m0 + r;
        if (MODE == 0)      arow[i] = rg;
        else {
            rg = rg < M ? rg : (M - 1);
            arow[i] = (MODE == 1) ? ridx[rg] : rg;
        }
    }

    extern __shared__ char smem[];
    const uint32_t sb = smem_u32(smem);
    const int wid = tid >> 5, lid = tid & 31;
    const int wm  = wid >> 2, wn = wid & 3;

    float acc[4][8][4];
    #pragma unroll
    for (int i = 0; i < 4; i++)
        #pragma unroll
        for (int j = 0; j < 8; j++)
            #pragma unroll
            for (int t = 0; t < 4; t++) acc[i][j][t] = 0.f;

    const int iters = Kc >> 5;

    auto fillA = [&](int stage, int kit) {
        const int k0 = kbase + (kit << 5);
        const uint32_t abase = sb + stage * STAGE_B;
        #pragma unroll
        for (int i = 0; i < 4; i++) {
            int idx = tid + i * 256;
            int r = idx >> 3, c = idx & 7;
            uint32_t dst = abase + r * 128 + ((c ^ (r & 7)) << 4);
            const __nv_bfloat16* src = (c < 4)
                ? ahp + (size_t)arow[i] * K + k0 + c * 8
                : alp + (size_t)arow[i] * K + k0 + (c - 4) * 8;
            cp_async16(dst, src, 16);
        }
        CP_COMMIT();
    };

    auto ldgB = [&](float4* breg, int kit) {
        const int k0 = kbase + (kit << 5);
        #pragma unroll
        for (int i = 0; i < 4; i++) {
            int idx = tid + i * 256;
            int r = idx >> 2, c2 = idx & 3;
            int rg = n0 + r;
            int rc = rg < N ? rg : (N - 1);
            const float* Bp; int rr;
            if (MODE == 2)          { Bp = b0p; rr = rc; }
            else if (rc < rPB)      { Bp = b0p; rr = rc; }
            else if (MODE == 1 || rc < 2 * rPB) { Bp = b1p; rr = rc - rPB; }
            else                    { Bp = b2p; rr = rc - 2 * rPB; }
            const float4* s4 = (const float4*)(Bp + (size_t)rr * K + k0 + c2 * 8);
            breg[i*2]     = s4[0];
            breg[i*2 + 1] = s4[1];
        }
    };

    auto stsB = [&](const float4* breg, int stage) {
        const uint32_t bbase = sb + stage * STAGE_B + A_BYTES;
        #pragma unroll
        for (int i = 0; i < 4; i++) {
            int idx = tid + i * 256;
            int r = idx >> 2, c2 = idx & 3;
            float4 v0 = breg[i*2], v1 = breg[i*2 + 1];
            uint32_t h0, h1, h2, h3, l0, l1, l2, l3;
            split2(v0.x, v0.y, h0, l0);
            split2(v0.z, v0.w, h1, l1);
            split2(v1.x, v1.y, h2, l2);
            split2(v1.z, v1.w, h3, l3);
            uint32_t ha = bbase + r * 128 + ((c2 ^ (r & 7)) << 4);
            uint32_t la = bbase + r * 128 + (((c2 + 4) ^ (r & 7)) << 4);
            STS128(ha, h0, h1, h2, h3);
            STS128(la, l0, l1, l2, l3);
        }
    };

    {
        float4 pb[8];
        #pragma unroll
        for (int s = 0; s < NSTG_TC - 1; s++) {
            fillA(s, s);
            ldgB(pb, s);
            stsB(pb, s);
        }
    }

    const int grp = lid >> 3;
    const int rin = lid & 7;
    float4 breg[8];

    for (int i = 0; i < iters; i++) {
        const int s = i % NSTG_TC;
        const bool pre = (i + NSTG_TC - 1 < iters);
        if (pre) ldgB(breg, i + NSTG_TC - 1);

        asm volatile("cp.async.wait_group %0;\n" :: "n"(NSTG_TC - 2));
        __syncthreads();

        if (pre) fillA((i + NSTG_TC - 1) % NSTG_TC, i + NSTG_TC - 1);
        else CP_COMMIT();

        const uint32_t abase = sb + s * STAGE_B;
        const uint32_t bbase = abase + A_BYTES;

        #pragma unroll
        for (int g = 0; g < 2; g++) {
            uint32_t ah[4][4], bh[8][2];
            #pragma unroll
            for (int mt = 0; mt < 4; mt++) {
                int row = wm * 64 + mt * 16 + (grp & 1) * 8 + rin;
                int kch = 2 * g + (grp >> 1);
                uint32_t ad = abase + row * 128 + ((kch ^ (row & 7)) << 4);
                ldsm_x4(ah[mt][0], ah[mt][1], ah[mt][2], ah[mt][3], ad);
            }
            #pragma unroll
            for (int p = 0; p < 4; p++) {
                int tile = 2 * p + (grp >> 1);
                int row  = wn * 64 + tile * 8 + rin;
                int kch  = 2 * g + (grp & 1);
                uint32_t bd = bbase + row * 128 + ((kch ^ (row & 7)) << 4);
                ldsm_x4(bh[2*p][0], bh[2*p][1], bh[2*p+1][0], bh[2*p+1][1], bd);
            }
            #pragma unroll
            for (int mt = 0; mt < 4; mt++)
                #pragma unroll
                for (int nt = 0; nt < 8; nt++)
                    mma_bf16(acc[mt][nt], ah[mt], bh[nt]);
            {
                uint32_t al[4][4];
                #pragma unroll
                for (int mt = 0; mt < 4; mt++) {
                    int row = wm * 64 + mt * 16 + (grp & 1) * 8 + rin;
                    int kcl = 4 + 2 * g + (grp >> 1);
                    uint32_t adl = abase + row * 128 + ((kcl ^ (row & 7)) << 4);
                    ldsm_x4(al[mt][0], al[mt][1], al[mt][2], al[mt][3], adl);
                }
                #pragma unroll
                for (int mt = 0; mt < 4; mt++)
                    #pragma unroll
                    for (int nt = 0; nt < 8; nt++)
                        mma_bf16(acc[mt][nt], al[mt], bh[nt]);
            }
            {
                uint32_t bl[8][2];
                #pragma unroll
                for (int p = 0; p < 4; p++) {
                    int tile = 2 * p + (grp >> 1);
                    int row  = wn * 64 + tile * 8 + rin;
                    int kcl  = 4 + 2 * g + (grp & 1);
                    uint32_t bdl = bbase + row * 128 + ((kcl ^ (row & 7)) << 4);
                    ldsm_x4(bl[2*p][0], bl[2*p][1], bl[2*p+1][0], bl[2*p+1][1], bdl);
                }
                #pragma unroll
                for (int mt = 0; mt < 4; mt++)
                    #pragma unroll
                    for (int nt = 0; nt < 8; nt++)
                        mma_bf16(acc[mt][nt], ah[mt], bl[nt]);
            }
        }

        if (pre) stsB(breg, (i + NSTG_TC - 1) % NSTG_TC);
    }

    #pragma unroll
    for (int mt = 0; mt < 4; mt++) {
        #pragma unroll
        for (int nt = 0; nt < 8; nt++) {
            int rbase = m0 + wm * 64 + mt * 16 + (lid >> 2);
            int col = n0 + wn * 64 + nt * 8 + (lid & 3) * 2;
            #pragma unroll
            for (int h = 0; h < 2; h++) {
                int m = rbase + h * 8;
                float v0 = acc[mt][nt][h * 2 + 0];
                float v1 = acc[mt][nt][h * 2 + 1];
                if (MODE == 0) {
                    size_t idx = (size_t)m * N + col;
                    if (residual) {
                        if (col     < N) v0 += residual[idx];
                        if (col + 1 < N) v1 += residual[idx + 1];
                    }
                    if (col     < N) Cp[idx]     = v0;
                    if (col + 1 < N) Cp[idx + 1] = v1;
                } else if (MODE == 1) {
                    if (m < M) {
                        size_t idx = (size_t)m * N + col;
                        Cp[idx]     = v0;
                        Cp[idx + 1] = v1;
                    }
                } else {
                    if (m < M) {
                        int tok = ridx[m];
                        float w = rwt[m];
                        size_t idx = (size_t)tok * N + col;
                        atomicAdd(&Cp[idx],     w * v0);
                        atomicAdd(&Cp[idx + 1], w * v1);
                    }
                }
            }
        }
    }
}

// ================= tf32 single-pass GEMM (head) =================
__global__ void __launch_bounds__(256, 1) gemm_tf32(
    const float* __restrict__ A, const float* __restrict__ B,
    float* __restrict__ C, int M, int N, int K)
{
    extern __shared__ char smem[];
    const uint32_t sb = smem_u32(smem);
    const int tid = threadIdx.x;
    const int wid = tid >> 5, lid = tid & 31;
    const int wm  = wid >> 2, wn = wid & 3;
    const int m0  = blockIdx.y * 128;
    const int n0  = blockIdx.x * 256;

    float acc[4][8][4];
    #pragma unroll
    for (int i = 0; i < 4; i++)
        #pragma unroll
        for (int j = 0; j < 8; j++)
            #pragma unroll
            for (int t = 0; t < 4; t++) acc[i][j][t] = 0.f;

    const int iters = K >> 5;

    auto fill = [&](int stage, int kit) {
        const int k0 = kit << 5;
        const uint32_t abase = sb + stage * STAGE_B;
        const uint32_t bbase = abase + A_BYTES;
        #pragma unroll
        for (int i = 0; i < 4; i++) {
            int idx = tid + i * 256;
            int r = idx >> 3, c = idx & 7;
            uint32_t dst = abase + r * 128 + ((c ^ (r & 7)) << 4);
            cp_async16(dst, A + (size_t)(m0 + r) * K + k0 + c * 4, 16);
        }
        #pragma unroll
        for (int i = 0; i < 8; i++) {
            int idx = tid + i * 256;
            int r = idx >> 3, c = idx & 7;
            uint32_t dst = bbase + r * 128 + ((c ^ (r & 7)) << 4);
            int rg = n0 + r;
            int rc = rg < N ? rg : (N - 1);
            cp_async16(dst, B + (size_t)rc * K + k0 + c * 4, rg < N ? 16 : 0);
        }
        CP_COMMIT();
    };

    #pragma unroll
    for (int s = 0; s < NSTG_TF - 1; s++) fill(s, s);

    const int grp = lid >> 3;
    const int rin = lid & 7;

    for (int i = 0; i < iters; i++) {
        const int s = i % NSTG_TF;
        asm volatile("cp.async.wait_group %0;\n" :: "n"(NSTG_TF - 2));
        __syncthreads();

        if (i + NSTG_TF - 1 < iters) fill((i + NSTG_TF - 1) % NSTG_TF, i + NSTG_TF - 1);
        else CP_COMMIT();

        const uint32_t abase = sb + s * STAGE_B;
        const uint32_t bbase = abase + A_BYTES;

        #pragma unroll
        for (int k8 = 0; k8 < 4; k8++) {
            uint32_t a[4][4], b[8][2];
            #pragma unroll
            for (int mt = 0; mt < 4; mt++) {
                int row = wm * 64 + mt * 16 + (grp & 1) * 8 + rin;
                int kc  = k8 * 2 + (grp >> 1);
                uint32_t addr = abase + row * 128 + ((kc ^ (row & 7)) << 4);
                ldsm_x4(a[mt][0], a[mt][1], a[mt][2], a[mt][3], addr);
            }
            #pragma unroll
            for (int p = 0; p < 4; p++) {
                int tile = 2 * p + (grp >> 1);
                int row  = wn * 64 + tile * 8 + rin;
                int kc   = k8 * 2 + (grp & 1);
                uint32_t addr = bbase + row * 128 + ((kc ^ (row & 7)) << 4);
                ldsm_x4(b[2*p][0], b[2*p][1], b[2*p+1][0], b[2*p+1][1], addr);
            }
            #pragma unroll
            for (int mt = 0; mt < 4; mt++)
                #pragma unroll
                for (int nt = 0; nt < 8; nt++)
                    mma_tf32(acc[mt][nt], a[mt], b[nt]);
        }
    }

    #pragma unroll
    for (int mt = 0; mt < 4; mt++) {
        #pragma unroll
        for (int nt = 0; nt < 8; nt++) {
            int rbase = m0 + wm * 64 + mt * 16 + (lid >> 2);
            int col = n0 + wn * 64 + nt * 8 + (lid & 3) * 2;
            #pragma unroll
            for (int h = 0; h < 2; h++) {
                int m = rbase + h * 8;
                size_t idx = (size_t)m * N + col;
                if (col     < N) C[idx]     = acc[mt][nt][h * 2 + 0];
                if (col + 1 < N) C[idx + 1] = acc[mt][nt][h * 2 + 1];
            }
        }
    }
}

// ---------------- embedding ----------------
__global__ void embed_kernel(const int* __restrict__ tok,
                             const float* __restrict__ emb,
                             float* __restrict__ x) {
    int t = blockIdx.x;
    int tk = tok[t];
    for (int d = threadIdx.x; d < D_MODEL; d += 256)
        x[(size_t)t*D_MODEL + d] = emb[(size_t)tk*D_MODEL + d];
}

// ---------------- RoPE ----------------
__global__ void rope_kernel(float* __restrict__ qkv) {
    int t = blockIdx.x, h = blockIdx.y, i = threadIdx.x;
    float inv = powf(10000.f, -((float)(2*i)) / 64.f);
    float ang = (float)t * inv;
    float s, c;
    sincosf(ang, &s, &c);
    size_t base = (size_t)t*QKV_STRIDE + h*HEAD_DIM + 2*i;
    float q0 = qkv[base], q1 = qkv[base+1];
    qkv[base]   = q0*c - q1*s;
    qkv[base+1] = q0*s + q1*c;
    size_t kb = base + D_MODEL;
    float k0 = qkv[kb], k1 = qkv[kb+1];
    qkv[kb]   = k0*c - k1*s;
    qkv[kb+1] = k0*s + k1*c;
}

// ---------------- blocked attention (exact ref semantics) ----------------
#define ATTN_SMEM (4 * 64 * 65 * 4)
__global__ void __launch_bounds__(256) attn_kernel(
    const float* __restrict__ qkv, float* __restrict__ o)
{
    extern __shared__ float sm[];
    float* Qs = sm;
    float* Ks = Qs + 64*65;
    float* Vs = Ks + 64*65;
    float* Ps = Vs + 64*65;
    const int ib = blockIdx.x, h = blockIdx.y;
    const int tid = threadIdx.x;
    const int qr  = tid >> 2;
    const int c0  = (tid & 3) * 16;

    for (int idx = tid; idx < 64*64; idx += 256) {
        int r = idx >> 6, c = idx & 63;
        Qs[r*65 + c] = qkv[(size_t)(ib*64+r)*QKV_STRIDE + h*HEAD_DIM + c];
    }

    float accO[16];
    #pragma unroll
    for (int i = 0; i < 16; i++) accO[i] = 0.f;
    float den = 0.f;

    for (int jb = 0; jb <= ib; jb++) {
        __syncthreads();
        for (int idx = tid; idx < 64*64; idx += 256) {
            int r = idx >> 6, c = idx & 63;
            size_t base = (size_t)(jb*64+r)*QKV_STRIDE + h*HEAD_DIM + c;
            Ks[r*65 + c] = qkv[base + D_MODEL];
            Vs[r*65 + c] = qkv[base + 2*D_MODEL];
        }
        __syncthreads();

        float s[16];
        float mx = -1e30f;
        #pragma unroll
        for (int cc = 0; cc < 16; cc++) {
            int c = c0 + cc;
            float dot = 0.f;
            #pragma unroll
            for (int d = 0; d < 64; d++)
                dot = fmaf(Qs[qr*65 + d], Ks[c*65 + d], dot);
            dot *= 0.125f;
            if (jb == ib && c > qr) dot = -1e30f;
            s[cc] = dot;
            mx = fmaxf(mx, dot);
        }
        mx = fmaxf(mx, __shfl_xor_sync(0xffffffffu, mx, 1));
        mx = fmaxf(mx, __shfl_xor_sync(0xffffffffu, mx, 2));

        #pragma unroll
        for (int cc = 0; cc < 16; cc++) {
            float p = expf(s[cc] - mx);
            Ps[qr*65 + c0 + cc] = p;
            den += p;
        }
        __syncthreads();

        #pragma unroll 8
        for (int kk = 0; kk < 64; kk++) {
            float pv = Ps[qr*65 + kk];
            #pragma unroll
            for (int d = 0; d < 16; d++)
                accO[d] = fmaf(pv, Vs[kk*65 + c0 + d], accO[d]);
        }
    }

    den += __shfl_xor_sync(0xffffffffu, den, 1);
    den += __shfl_xor_sync(0xffffffffu, den, 2);
    float invd = 1.f / (den + 1e-6f);
    #pragma unroll
    for (int d = 0; d < 16; d++)
        o[(size_t)(ib*64+qr)*D_MODEL + h*HEAD_DIM + c0 + d] = accO[d] * invd;
}

// ---------------- layernorm ----------------
__global__ void __launch_bounds__(256) ln_kernel(
    const float* __restrict__ in, const float* __restrict__ res,
    const float* __restrict__ g, const float* __restrict__ b,
    float* __restrict__ out)
{
    __shared__ float red[256];
    int t = blockIdx.x, tid = threadIdx.x;
    float v[8];
    float sum = 0.f;
    #pragma unroll
    for (int i = 0; i < 8; i++) {
        int d = i*256 + tid;
        float x = in[(size_t)t*D_MODEL + d];
        if (res) x += res[(size_t)t*D_MODEL + d];
        v[i] = x; sum += x;
    }
    red[tid] = sum; __syncthreads();
    for (int s = 128; s > 0; s >>= 1) { if (tid < s) red[tid] += red[tid+s]; __syncthreads(); }
    float mu = red[0] / D_MODEL;
    __syncthreads();
    float sq = 0.f;
    #pragma unroll
    for (int i = 0; i < 8; i++) { float d0 = v[i] - mu; sq += d0*d0; }
    red[tid] = sq; __syncthreads();
    for (int s = 128; s > 0; s >>= 1) { if (tid < s) red[tid] += red[tid+s]; __syncthreads(); }
    float rstd = rsqrtf(red[0] / D_MODEL + 1e-5f);
    #pragma unroll
    for (int i = 0; i < 8; i++) {
        int d = i*256 + tid;
        out[(size_t)t*D_MODEL + d] = (v[i] - mu) * rstd * g[d] + b[d];
    }
}

// ---------------- MoE gate ----------------
__global__ void __launch_bounds__(128) gate_kernel(
    const float* __restrict__ x, const float* __restrict__ gw,
    float* __restrict__ wts, float* __restrict__ varr)
{
    __shared__ float red[128];
    __shared__ float logit[4];
    int t = blockIdx.x, tid = threadIdx.x;
    float p[4] = {0.f, 0.f, 0.f, 0.f};
    for (int d = tid; d < D_MODEL; d += 128) {
        float xv = x[(size_t)t*D_MODEL + d];
        #pragma unroll
        for (int e = 0; e < 4; e++)
            p[e] = fmaf(xv, gw[e*D_MODEL + d], p[e]);
    }
    for (int e = 0; e < 4; e++) {
        red[tid] = p[e]; __syncthreads();
        for (int s = 64; s > 0; s >>= 1) { if (tid < s) red[tid] += red[tid+s]; __syncthreads(); }
        if (tid == 0) logit[e] = red[0];
        __syncthreads();
    }
    if (tid == 0) {
        float l[4] = {logit[0], logit[1], logit[2], logit[3]};
        float mx = fmaxf(fmaxf(l[0], l[1]), fmaxf(l[2], l[3]));
        float ex[4], ssum = 0.f;
        for (int e = 0; e < 4; e++) { ex[e] = expf(l[e] - mx); ssum += ex[e]; }
        float pr[4];
        for (int e = 0; e < 4; e++) pr[e] = ex[e] / ssum;
        int b1 = 0;
        for (int e = 1; e < 4; e++) if (pr[e] > pr[b1]) b1 = e;
        int b2 = -1;
        for (int e = 0; e < 4; e++) { if (e == b1) continue; if (b2 < 0 || pr[e] > pr[b2]) b2 = e; }
        float s2 = pr[b1] + pr[b2];
        float wv[4] = {0.f, 0.f, 0.f, 0.f};
        wv[b1] = pr[b1] / s2; wv[b2] = pr[b2] / s2;
        for (int e = 0; e < 4; e++) wts[e*SEQ + t] = wv[e];
        float mu = (l[0]+l[1]+l[2]+l[3]) * 0.25f;
        float va = ((l[0]-mu)*(l[0]-mu) + (l[1]-mu)*(l[1]-mu) +
                    (l[2]-mu)*(l[2]-mu) + (l[3]-mu)*(l[3]-mu)) / 3.f;
        varr[t] = va;
    }
}

// ---------------- routing compaction ----------------
__global__ void __launch_bounds__(1024) compact_kernel(
    const float* __restrict__ wts, int* __restrict__ cnt,
    int* __restrict__ ridx, float* __restrict__ rwt)
{
    __shared__ int sc[1024];
    int e = blockIdx.x, t = threadIdx.x;
    float w = wts[e*SEQ + t];
    int flag = (w != 0.f) ? 1 : 0;
    sc[t] = flag;
    __syncthreads();
    for (int off = 1; off < 1024; off <<= 1) {
        int v = (t >= off) ? sc[t - off] : 0;
        __syncthreads();
        sc[t] += v;
        __syncthreads();
    }
    if (flag) {
        int pos = sc[t] - 1;
        ridx[e*SEQ + pos] = t;
        rwt [e*SEQ + pos] = w;
    }
    if (t == 1023) cnt[e] = sc[1023];
}

// fused silu(h1)*h3 -> split bf16, expert-batched (blockIdx.y = expert)
__global__ void __launch_bounds__(256) silu_split_kernel(
    const float* __restrict__ h13, const int* __restrict__ cnt,
    __nv_bfloat16* __restrict__ ch, __nv_bfloat16* __restrict__ cl)
{
    int e = blockIdx.y;
    int row = blockIdx.x;
    if (row >= cnt[e]) return;
    size_t src = (size_t)e * SEQ * 2 * D_FFN + (size_t)row * (2*D_FFN);
    size_t dst = (size_t)e * SEQ * D_FFN + (size_t)row * D_FFN;
    for (int c = threadIdx.x; c < D_FFN; c += 256) {
        float a = h13[src + c];
        float v = a / (1.f + expf(-a)) * h13[src + D_FFN + c];
        __nv_bfloat16 hi = __float2bfloat16(v);
        ch[dst + c] = hi;
        cl[dst + c] = __float2bfloat16(v - __bfloat162float(hi));
    }
}

__global__ void aux_kernel(const float* __restrict__ varr, float* __restrict__ out) {
    __shared__ float red[256];
    int tid = threadIdx.x;
    float s = 0.f;
    for (int i = tid; i < SEQ; i += 256) s += varr[i];
    red[tid] = s; __syncthreads();
    for (int st = 128; st > 0; st >>= 1) { if (tid < st) red[tid] += red[tid+st]; __syncthreads(); }
    if (tid == 0) out[0] = red[0] / (float)SEQ;
}

__global__ void zero_kernel(float* __restrict__ p, int n) {
    int i = blockIdx.x * 256 + threadIdx.x;
    if (i < n) p[i] = 0.f;
}

// ---------------- driver ----------------
static inline void split(const float* src, __nv_bfloat16* hi, __nv_bfloat16* lo, long long n) {
    int n4 = (int)(n / 4);
    split_kernel<<<(n4 + 255)/256, 256>>>(src, hi, lo, n4);
}

extern "C" void kernel_launch(void* const* d_in, const int* in_sizes, int n_in,
                              void* d_out, int out_size) {
    const int*   tokens = (const int*)  d_in[0];
    const float* emb    = (const float*)d_in[1];
    const float* wq     = (const float*)d_in[2];
    const float* wk     = (const float*)d_in[3];
    const float* wv     = (const float*)d_in[4];
    const float* wo     = (const float*)d_in[5];
    const float* ln1g   = (const float*)d_in[6];
    const float* ln1b   = (const float*)d_in[7];
    const float* gatew  = (const float*)d_in[8];
    const float* w1     = (const float*)d_in[9];
    const float* w2     = (const float*)d_in[10];
    const float* w3     = (const float*)d_in[11];
    const float* ln2g   = (const float*)d_in[12];
    const float* ln2b   = (const float*)d_in[13];
    const float* fing   = (const float*)d_in[14];
    const float* finb   = (const float*)d_in[15];
    const float* headw  = (const float*)d_in[16];
    float* out = (float*)d_out;

    float *x, *qkv, *att, *y, *h13, *moe, *wts, *varr, *rwt;
    int *cnt, *ridx;
    __nv_bfloat16 *ah, *al, *ch, *cl;
    cudaGetSymbolAddress((void**)&x,    g_x);
    cudaGetSymbolAddress((void**)&qkv,  g_qkv);
    cudaGetSymbolAddress((void**)&att,  g_att);
    cudaGetSymbolAddress((void**)&y,    g_y);
    cudaGetSymbolAddress((void**)&h13,  g_h13);
    cudaGetSymbolAddress((void**)&moe,  g_moe);
    cudaGetSymbolAddress((void**)&wts,  g_wts);
    cudaGetSymbolAddress((void**)&varr, g_var);
    cudaGetSymbolAddress((void**)&cnt,  g_cnt);
    cudaGetSymbolAddress((void**)&ridx, g_ridx);
    cudaGetSymbolAddress((void**)&rwt,  g_rwt);
    cudaGetSymbolAddress((void**)&ah,   g_ah);
    cudaGetSymbolAddress((void**)&al,   g_al);
    cudaGetSymbolAddress((void**)&ch,   g_ch);
    cudaGetSymbolAddress((void**)&cl,   g_cl);

    cudaFuncSetAttribute(attn_kernel, cudaFuncAttributeMaxDynamicSharedMemorySize, ATTN_SMEM);
    cudaFuncSetAttribute(gemm_tc<0>, cudaFuncAttributeMaxDynamicSharedMemorySize, GEMM_SMEM_TC);
    cudaFuncSetAttribute(gemm_tc<1>, cudaFuncAttributeMaxDynamicSharedMemorySize, GEMM_SMEM_TC);
    cudaFuncSetAttribute(gemm_tc<2>, cudaFuncAttributeMaxDynamicSharedMemorySize, GEMM_SMEM_TC);
    cudaFuncSetAttribute(gemm_tf32, cudaFuncAttributeMaxDynamicSharedMemorySize, GEMM_SMEM_TF);

    // 1) embed + split x
    embed_kernel<<<SEQ, 256>>>(tokens, emb, x);
    split(x, ah, al, (long long)SEQ * D_MODEL);

    // 2) fused QKV (N=6144) — weights fp32 direct
    dim3 gQKV(3*D_MODEL/256, SEQ/128);
    gemm_tc<0><<<gQKV, 256, GEMM_SMEM_TC>>>(ah, al, wq, wk, wv, D_MODEL,
                                            qkv, SEQ, 3*D_MODEL, D_MODEL,
                                            nullptr, nullptr, nullptr, nullptr, 0, 0, 0);

    // 3) RoPE + attention
    rope_kernel<<<dim3(SEQ, N_HEADS), 32>>>(qkv);
    attn_kernel<<<dim3(NB, N_HEADS), 256, ATTN_SMEM>>>(qkv, att);

    // 4) output proj + residual
    dim3 gA(D_MODEL/256, SEQ/128);
    split(att, ah, al, (long long)SEQ * D_MODEL);
    gemm_tc<0><<<gA, 256, GEMM_SMEM_TC>>>(ah, al, wo, wo, wo, D_MODEL,
                                          y, SEQ, D_MODEL, D_MODEL,
                                          x, nullptr, nullptr, nullptr, 0, 0, 0);

    // 5) LN1 -> x, split for MoE
    ln_kernel<<<SEQ, 256>>>(y, nullptr, ln1g, ln1b, x);
    split(x, ah, al, (long long)SEQ * D_MODEL);

    // 6) gate + routing
    gate_kernel<<<SEQ, 128>>>(x, gatew, wts, varr);
    compact_kernel<<<NEXP, 1024>>>(wts, cnt, ridx, rwt);

    // 7) MoE — expert-batched (3 launches total)
    zero_kernel<<<(SEQ*D_MODEL + 255)/256, 256>>>(moe, SEQ*D_MODEL);
    const long long FD = (long long)D_FFN * D_MODEL;
    dim3 gUp(2*D_FFN/256, SEQ/128, NEXP);
    gemm_tc<1><<<gUp, 256, GEMM_SMEM_TC>>>(ah, al, w1, w3, nullptr, D_FFN,
                                           h13, 0, 2*D_FFN, D_MODEL,
                                           nullptr, cnt, ridx, nullptr,
                                           0, FD, (long long)SEQ*2*D_FFN);
    silu_split_kernel<<<dim3(SEQ, NEXP), 256>>>(h13, cnt, ch, cl);
    dim3 gDn(D_MODEL/256, SEQ/128, NEXP*4);
    gemm_tc<2><<<gDn, 256, GEMM_SMEM_TC>>>(ch, cl, w2, nullptr, nullptr, D_MODEL,
                                           moe, 0, D_MODEL, D_FFN,
                                           nullptr, cnt, ridx, rwt,
                                           (long long)SEQ*D_FFN, FD, 0);

    // 8) LN2 + final LN
    ln_kernel<<<SEQ, 256>>>(moe, x, ln2g, ln2b, y);
    ln_kernel<<<SEQ, 256>>>(y, nullptr, fing, finb, x);

    // 9) head (tf32 single-pass)
    dim3 gH((VOCAB + 255)/256, SEQ/128);
    gemm_tf32<<<gH, 256, GEMM_SMEM_TF>>>(x, headw, out, SEQ, VOCAB, D_MODEL);

    // 10) aux
    long long nlog = (long long)SEQ * VOCAB;
    if ((long long)out_size > nlog)
        aux_kernel<<<1, 256>>>(varr, out + nlog);
}

// round 10
// speedup vs baseline: 4.2411x; 1.0139x over previous
#include <cuda_runtime.h>
#include <cuda_bf16.h>
#include <math.h>
#include <stdint.h>

#define D_MODEL 2048
#define SEQ     1024
#define N_HEADS 32
#define HEAD_DIM 64
#define NB      (SEQ/64)
#define D_FFN   8192
#define VOCAB   50257
#define NEXP    4
#define QKV_STRIDE (3*D_MODEL)

// ---------------- scratch ----------------
__device__ float g_x  [SEQ*D_MODEL];
__device__ float g_qkv[SEQ*3*D_MODEL];
__device__ float g_y  [SEQ*D_MODEL];
__device__ float g_moe[SEQ*D_MODEL];
__device__ float g_wts[NEXP*SEQ];
__device__ float g_var[SEQ];

// routing
__device__ int   g_cnt[NEXP];
__device__ int   g_ridx[NEXP*SEQ];
__device__ float g_rwt [NEXP*SEQ];

// bf16 split scratch
__device__ __nv_bfloat16 g_ah[SEQ*D_MODEL];
__device__ __nv_bfloat16 g_al[SEQ*D_MODEL];
__device__ __nv_bfloat16 g_ch[(size_t)NEXP*SEQ*D_FFN];
__device__ __nv_bfloat16 g_cl[(size_t)NEXP*SEQ*D_FFN];

// ---------------- PTX helpers ----------------
__device__ __forceinline__ uint32_t smem_u32(const void* p) {
    uint32_t a;
    asm("{ .reg .u64 t; cvta.to.shared.u64 t, %1; cvt.u32.u64 %0, t; }" : "=r"(a) : "l"(p));
    return a;
}
__device__ __forceinline__ void cp_async16(uint32_t dst, const void* src, int src_bytes) {
    asm volatile("cp.async.cg.shared.global [%0], [%1], 16, %2;\n"
                 :: "r"(dst), "l"(src), "r"(src_bytes) : "memory");
}
#define CP_COMMIT() asm volatile("cp.async.commit_group;\n" ::: "memory")

#define STS128(addr, a, b, c, d) \
    asm volatile("st.shared.v4.b32 [%0], {%1,%2,%3,%4};" \
                 :: "r"(addr), "r"(a), "r"(b), "r"(c), "r"(d) : "memory")

__device__ __forceinline__ void ldsm_x4(uint32_t& r0, uint32_t& r1, uint32_t& r2, uint32_t& r3,
                                        uint32_t addr) {
    asm volatile("ldmatrix.sync.aligned.m8n8.x4.shared.b16 {%0,%1,%2,%3}, [%4];"
                 : "=r"(r0), "=r"(r1), "=r"(r2), "=r"(r3) : "r"(addr));
}
__device__ __forceinline__ void mma_bf16(float* c, const uint32_t* a, const uint32_t* b) {
    asm volatile(
        "mma.sync.aligned.m16n8k16.row.col.f32.bf16.bf16.f32 "
        "{%0,%1,%2,%3}, {%4,%5,%6,%7}, {%8,%9}, {%0,%1,%2,%3};"
        : "+f"(c[0]), "+f"(c[1]), "+f"(c[2]), "+f"(c[3])
        : "r"(a[0]), "r"(a[1]), "r"(a[2]), "r"(a[3]), "r"(b[0]), "r"(b[1]));
}
__device__ __forceinline__ void mma_tf32(float* c, const uint32_t* a, const uint32_t* b) {
    asm volatile(
        "mma.sync.aligned.m16n8k8.row.col.f32.tf32.tf32.f32 "
        "{%0,%1,%2,%3}, {%4,%5,%6,%7}, {%8,%9}, {%0,%1,%2,%3};"
        : "+f"(c[0]), "+f"(c[1]), "+f"(c[2]), "+f"(c[3])
        : "r"(a[0]), "r"(a[1]), "r"(a[2]), "r"(a[3]), "r"(b[0]), "r"(b[1]));
}

__device__ __forceinline__ void split2(float a, float b, uint32_t& hi, uint32_t& lo) {
    __nv_bfloat16 ha = __float2bfloat16(a), hb = __float2bfloat16(b);
    __nv_bfloat162 h; h.x = ha; h.y = hb;
    __nv_bfloat162 l;
    l.x = __float2bfloat16(a - __bfloat162float(ha));
    l.y = __float2bfloat16(b - __bfloat162float(hb));
    hi = *(uint32_t*)&h;
    lo = *(uint32_t*)&l;
}

// ================= bf16x3 GEMM: CTA 128x256, 8 warps (2Mx4N), warp 64x64 =================
#define NSTG_TC 3
#define A_BYTES (128*128)
#define B_BYTES (256*128)
#define STAGE_B (A_BYTES + B_BYTES)
#define GEMM_SMEM_TC (NSTG_TC * STAGE_B)
#define NSTG_TF 4
#define GEMM_SMEM_TF (NSTG_TF * STAGE_B)

// MODE 0: dense. C[m,n]=val(+residual). B rows: <rPB->B0, <2rPB->B1, else B2.
// MODE 1: expert-batched up + FUSED silu·mul + bf16 split. e=blockIdx.z. A rows via ridx[e].
//         B rows interleaved: even->w1 row rc/2 (B0+e*sB), odd->w3 row rc/2 (B1+e*sB).
//         Epilogue: pair (col,col+1)=(h1_j,h3_j); CH/CL[e*SEQ*D_FFN + m*D_FFN + j] = split(silu(h1)*h3).
// MODE 2: expert-batched down + split-K4. atomicAdd(C[ridx[e][m]*N+n], rwt[e][m]*val).
template<int MODE>
__global__ void __launch_bounds__(256, 1) gemm_tc(
    const __nv_bfloat16* __restrict__ Ah, const __nv_bfloat16* __restrict__ Al,
    const float* __restrict__ B0, const float* __restrict__ B1, const float* __restrict__ B2,
    int rPB,
    float* __restrict__ C, int M_in, int N, int K,
    const float* __restrict__ residual,
    const int* __restrict__ cntArr, const int* __restrict__ ridxAll,
    const float* __restrict__ rwtAll,
    long long sA, long long sB,
    __nv_bfloat16* __restrict__ CH, __nv_bfloat16* __restrict__ CL)
{
    const int tid = threadIdx.x;
    const int m0  = blockIdx.y * 128;
    const int n0  = blockIdx.x * 256;

    int M = M_in;
    int e = 0, kbase = 0, Kc = K;
    const int* ridx = ridxAll;
    const float* rwt = rwtAll;
    const float* b0p = B0; const float* b1p = B1; const float* b2p = B2;
    const __nv_bfloat16* ahp = Ah; const __nv_bfloat16* alp = Al;
    float* Cp = C;

    if (MODE == 1) {
        e = blockIdx.z;
        M = cntArr[e];
        if (m0 >= M) return;
        ridx = ridxAll + e * SEQ;
        b0p = B0 + (size_t)e * sB;
        b1p = B1 + (size_t)e * sB;
    } else if (MODE == 2) {
        e = blockIdx.z >> 2;
        int ks = blockIdx.z & 3;
        M = cntArr[e];
        if (m0 >= M) return;
        ridx = ridxAll + e * SEQ;
        rwt  = rwtAll + e * SEQ;
        ahp = Ah + (size_t)e * sA;
        alp = Al + (size_t)e * sA;
        b0p = B0 + (size_t)e * sB;
        Kc = K >> 2;
        kbase = ks * Kc;
    }

    int arow[4];
    #pragma unroll
    for (int i = 0; i < 4; i++) {
        int r = (tid + i * 256) >> 3;
        int rg = m0 + r;
        if (MODE == 0)      arow[i] = rg;
        else {
            rg = rg < M ? rg : (M - 1);
            arow[i] = (MODE == 1) ? ridx[rg] : rg;
        }
    }

    extern __shared__ char smem[];
    const uint32_t sb = smem_u32(smem);
    const int wid = tid >> 5, lid = tid & 31;
    const int wm  = wid >> 2, wn = wid & 3;

    float acc[4][8][4];
    #pragma unroll
    for (int i = 0; i < 4; i++)
        #pragma unroll
        for (int j = 0; j < 8; j++)
            #pragma unroll
            for (int t = 0; t < 4; t++) acc[i][j][t] = 0.f;

    const int iters = Kc >> 5;

    auto fillA = [&](int stage, int kit) {
        const int k0 = kbase + (kit << 5);
        const uint32_t abase = sb + stage * STAGE_B;
        #pragma unroll
        for (int i = 0; i < 4; i++) {
            int idx = tid + i * 256;
            int r = idx >> 3, c = idx & 7;
            uint32_t dst = abase + r * 128 + ((c ^ (r & 7)) << 4);
            const __nv_bfloat16* src = (c < 4)
                ? ahp + (size_t)arow[i] * K + k0 + c * 8
                : alp + (size_t)arow[i] * K + k0 + (c - 4) * 8;
            cp_async16(dst, src, 16);
        }
        CP_COMMIT();
    };

    auto ldgB = [&](float4* breg, int kit) {
        const int k0 = kbase + (kit << 5);
        #pragma unroll
        for (int i = 0; i < 4; i++) {
            int idx = tid + i * 256;
            int r = idx >> 2, c2 = idx & 3;
            int rg = n0 + r;
            int rc = rg < N ? rg : (N - 1);
            const float* Bp; int rr;
            if (MODE == 2)          { Bp = b0p; rr = rc; }
            else if (MODE == 1)     { Bp = (rc & 1) ? b1p : b0p; rr = rc >> 1; }
            else if (rc < rPB)      { Bp = b0p; rr = rc; }
            else if (rc < 2 * rPB)  { Bp = b1p; rr = rc - rPB; }
            else                    { Bp = b2p; rr = rc - 2 * rPB; }
            const float4* s4 = (const float4*)(Bp + (size_t)rr * K + k0 + c2 * 8);
            breg[i*2]     = s4[0];
            breg[i*2 + 1] = s4[1];
        }
    };

    auto stsB = [&](const float4* breg, int stage) {
        const uint32_t bbase = sb + stage * STAGE_B + A_BYTES;
        #pragma unroll
        for (int i = 0; i < 4; i++) {
            int idx = tid + i * 256;
            int r = idx >> 2, c2 = idx & 3;
            float4 v0 = breg[i*2], v1 = breg[i*2 + 1];
            uint32_t h0, h1, h2, h3, l0, l1, l2, l3;
            split2(v0.x, v0.y, h0, l0);
            split2(v0.z, v0.w, h1, l1);
            split2(v1.x, v1.y, h2, l2);
            split2(v1.z, v1.w, h3, l3);
            uint32_t ha = bbase + r * 128 + ((c2 ^ (r & 7)) << 4);
            uint32_t la = bbase + r * 128 + (((c2 + 4) ^ (r & 7)) << 4);
            STS128(ha, h0, h1, h2, h3);
            STS128(la, l0, l1, l2, l3);
        }
    };

    {
        float4 pb[8];
        #pragma unroll
        for (int s = 0; s < NSTG_TC - 1; s++) {
            fillA(s, s);
            ldgB(pb, s);
            stsB(pb, s);
        }
    }

    const int grp = lid >> 3;
    const int rin = lid & 7;
    float4 breg[8];

    for (int i = 0; i < iters; i++) {
        const int s = i % NSTG_TC;
        const bool pre = (i + NSTG_TC - 1 < iters);
        if (pre) ldgB(breg, i + NSTG_TC - 1);

        asm volatile("cp.async.wait_group %0;\n" :: "n"(NSTG_TC - 2));
        __syncthreads();

        if (pre) fillA((i + NSTG_TC - 1) % NSTG_TC, i + NSTG_TC - 1);
        else CP_COMMIT();

        const uint32_t abase = sb + s * STAGE_B;
        const uint32_t bbase = abase + A_BYTES;

        #pragma unroll
        for (int g = 0; g < 2; g++) {
            uint32_t ah[4][4], bh[8][2];
            #pragma unroll
            for (int mt = 0; mt < 4; mt++) {
                int row = wm * 64 + mt * 16 + (grp & 1) * 8 + rin;
                int kch = 2 * g + (grp >> 1);
                uint32_t ad = abase + row * 128 + ((kch ^ (row & 7)) << 4);
                ldsm_x4(ah[mt][0], ah[mt][1], ah[mt][2], ah[mt][3], ad);
            }
            #pragma unroll
            for (int p = 0; p < 4; p++) {
                int tile = 2 * p + (grp >> 1);
                int row  = wn * 64 + tile * 8 + rin;
                int kch  = 2 * g + (grp & 1);
                uint32_t bd = bbase + row * 128 + ((kch ^ (row & 7)) << 4);
                ldsm_x4(bh[2*p][0], bh[2*p][1], bh[2*p+1][0], bh[2*p+1][1], bd);
            }
            #pragma unroll
            for (int mt = 0; mt < 4; mt++)
                #pragma unroll
                for (int nt = 0; nt < 8; nt++)
                    mma_bf16(acc[mt][nt], ah[mt], bh[nt]);
            {
                uint32_t al[4][4];
                #pragma unroll
                for (int mt = 0; mt < 4; mt++) {
                    int row = wm * 64 + mt * 16 + (grp & 1) * 8 + rin;
                    int kcl = 4 + 2 * g + (grp >> 1);
                    uint32_t adl = abase + row * 128 + ((kcl ^ (row & 7)) << 4);
                    ldsm_x4(al[mt][0], al[mt][1], al[mt][2], al[mt][3], adl);
                }
                #pragma unroll
                for (int mt = 0; mt < 4; mt++)
                    #pragma unroll
                    for (int nt = 0; nt < 8; nt++)
                        mma_bf16(acc[mt][nt], al[mt], bh[nt]);
            }
            {
                uint32_t bl[8][2];
                #pragma unroll
                for (int p = 0; p < 4; p++) {
                    int tile = 2 * p + (grp >> 1);
                    int row  = wn * 64 + tile * 8 + rin;
                    int kcl  = 4 + 2 * g + (grp & 1);
                    uint32_t bdl = bbase + row * 128 + ((kcl ^ (row & 7)) << 4);
                    ldsm_x4(bl[2*p][0], bl[2*p][1], bl[2*p+1][0], bl[2*p+1][1], bdl);
                }
                #pragma unroll
                for (int mt = 0; mt < 4; mt++)
                    #pragma unroll
                    for (int nt = 0; nt < 8; nt++)
                        mma_bf16(acc[mt][nt], ah[mt], bl[nt]);
            }
        }

        if (pre) stsB(breg, (i + NSTG_TC - 1) % NSTG_TC);
    }

    #pragma unroll
    for (int mt = 0; mt < 4; mt++) {
        #pragma unroll
        for (int nt = 0; nt < 8; nt++) {
            int rbase = m0 + wm * 64 + mt * 16 + (lid >> 2);
            int col = n0 + wn * 64 + nt * 8 + (lid & 3) * 2;
            #pragma unroll
            for (int h = 0; h < 2; h++) {
                int m = rbase + h * 8;
                float v0 = acc[mt][nt][h * 2 + 0];
                float v1 = acc[mt][nt][h * 2 + 1];
                if (MODE == 0) {
                    size_t idx = (size_t)m * N + col;
                    if (residual) {
                        if (col     < N) v0 += residual[idx];
                        if (col + 1 < N) v1 += residual[idx + 1];
                    }
                    if (col     < N) Cp[idx]     = v0;
                    if (col + 1 < N) Cp[idx + 1] = v1;
                } else if (MODE == 1) {
                    if (m < M) {
                        // (v0, v1) = (h1_j, h3_j), j = col/2 — fused silu·mul + split
                        int j = col >> 1;
                        float r = v0 / (1.f + expf(-v0)) * v1;
                        __nv_bfloat16 hi = __float2bfloat16(r);
                        size_t o = (size_t)e * SEQ * D_FFN + (size_t)m * D_FFN + j;
                        CH[o] = hi;
                        CL[o] = __float2bfloat16(r - __bfloat162float(hi));
                    }
                } else {
                    if (m < M) {
                        int tok = ridx[m];
                        float w = rwt[m];
                        size_t idx = (size_t)tok * N + col;
                        atomicAdd(&Cp[idx],     w * v0);
                        atomicAdd(&Cp[idx + 1], w * v1);
                    }
                }
            }
        }
    }
}

// ================= tf32 single-pass GEMM (head) =================
__global__ void __launch_bounds__(256, 1) gemm_tf32(
    const float* __restrict__ A, const float* __restrict__ B,
    float* __restrict__ C, int M, int N, int K)
{
    extern __shared__ char smem[];
    const uint32_t sb = smem_u32(smem);
    const int tid = threadIdx.x;
    const int wid = tid >> 5, lid = tid & 31;
    const int wm  = wid >> 2, wn = wid & 3;
    const int m0  = blockIdx.y * 128;
    const int n0  = blockIdx.x * 256;

    float acc[4][8][4];
    #pragma unroll
    for (int i = 0; i < 4; i++)
        #pragma unroll
        for (int j = 0; j < 8; j++)
            #pragma unroll
            for (int t = 0; t < 4; t++) acc[i][j][t] = 0.f;

    const int iters = K >> 5;

    auto fill = [&](int stage, int kit) {
        const int k0 = kit << 5;
        const uint32_t abase = sb + stage * STAGE_B;
        const uint32_t bbase = abase + A_BYTES;
        #pragma unroll
        for (int i = 0; i < 4; i++) {
            int idx = tid + i * 256;
            int r = idx >> 3, c = idx & 7;
            uint32_t dst = abase + r * 128 + ((c ^ (r & 7)) << 4);
            cp_async16(dst, A + (size_t)(m0 + r) * K + k0 + c * 4, 16);
        }
        #pragma unroll
        for (int i = 0; i < 8; i++) {
            int idx = tid + i * 256;
            int r = idx >> 3, c = idx & 7;
            uint32_t dst = bbase + r * 128 + ((c ^ (r & 7)) << 4);
            int rg = n0 + r;
            int rc = rg < N ? rg : (N - 1);
            cp_async16(dst, B + (size_t)rc * K + k0 + c * 4, rg < N ? 16 : 0);
        }
        CP_COMMIT();
    };

    #pragma unroll
    for (int s = 0; s < NSTG_TF - 1; s++) fill(s, s);

    const int grp = lid >> 3;
    const int rin = lid & 7;

    for (int i = 0; i < iters; i++) {
        const int s = i % NSTG_TF;
        asm volatile("cp.async.wait_group %0;\n" :: "n"(NSTG_TF - 2));
        __syncthreads();

        if (i + NSTG_TF - 1 < iters) fill((i + NSTG_TF - 1) % NSTG_TF, i + NSTG_TF - 1);
        else CP_COMMIT();

        const uint32_t abase = sb + s * STAGE_B;
        const uint32_t bbase = abase + A_BYTES;

        #pragma unroll
        for (int k8 = 0; k8 < 4; k8++) {
            uint32_t a[4][4], b[8][2];
            #pragma unroll
            for (int mt = 0; mt < 4; mt++) {
                int row = wm * 64 + mt * 16 + (grp & 1) * 8 + rin;
                int kc  = k8 * 2 + (grp >> 1);
                uint32_t addr = abase + row * 128 + ((kc ^ (row & 7)) << 4);
                ldsm_x4(a[mt][0], a[mt][1], a[mt][2], a[mt][3], addr);
            }
            #pragma unroll
            for (int p = 0; p < 4; p++) {
                int tile = 2 * p + (grp >> 1);
                int row  = wn * 64 + tile * 8 + rin;
                int kc   = k8 * 2 + (grp & 1);
                uint32_t addr = bbase + row * 128 + ((kc ^ (row & 7)) << 4);
                ldsm_x4(b[2*p][0], b[2*p][1], b[2*p+1][0], b[2*p+1][1], addr);
            }
            #pragma unroll
            for (int mt = 0; mt < 4; mt++)
                #pragma unroll
                for (int nt = 0; nt < 8; nt++)
                    mma_tf32(acc[mt][nt], a[mt], b[nt]);
        }
    }

    #pragma unroll
    for (int mt = 0; mt < 4; mt++) {
        #pragma unroll
        for (int nt = 0; nt < 8; nt++) {
            int rbase = m0 + wm * 64 + mt * 16 + (lid >> 2);
            int col = n0 + wn * 64 + nt * 8 + (lid & 3) * 2;
            #pragma unroll
            for (int h = 0; h < 2; h++) {
                int m = rbase + h * 8;
                size_t idx = (size_t)m * N + col;
                if (col     < N) C[idx]     = acc[mt][nt][h * 2 + 0];
                if (col + 1 < N) C[idx + 1] = acc[mt][nt][h * 2 + 1];
            }
        }
    }
}

// ---------------- embedding (+ fused split) ----------------
__global__ void embed_kernel(const int* __restrict__ tok,
                             const float* __restrict__ emb,
                             float* __restrict__ x,
                             __nv_bfloat16* __restrict__ ah,
                             __nv_bfloat16* __restrict__ al) {
    int t = blockIdx.x;
    int tk = tok[t];
    const float2* src = (const float2*)(emb + (size_t)tk * D_MODEL);
    float2* dst = (float2*)(x + (size_t)t * D_MODEL);
    uint32_t* hd = (uint32_t*)(ah + (size_t)t * D_MODEL);
    uint32_t* ld = (uint32_t*)(al + (size_t)t * D_MODEL);
    for (int p = threadIdx.x; p < D_MODEL/2; p += 256) {
        float2 v = src[p];
        dst[p] = v;
        uint32_t h, l;
        split2(v.x, v.y, h, l);
        hd[p] = h;
        ld[p] = l;
    }
}

// ---------------- RoPE ----------------
__global__ void rope_kernel(float* __restrict__ qkv) {
    int t = blockIdx.x, h = blockIdx.y, i = threadIdx.x;
    float inv = powf(10000.f, -((float)(2*i)) / 64.f);
    float ang = (float)t * inv;
    float s, c;
    sincosf(ang, &s, &c);
    size_t base = (size_t)t*QKV_STRIDE + h*HEAD_DIM + 2*i;
    float q0 = qkv[base], q1 = qkv[base+1];
    qkv[base]   = q0*c - q1*s;
    qkv[base+1] = q0*s + q1*c;
    size_t kb = base + D_MODEL;
    float k0 = qkv[kb], k1 = qkv[kb+1];
    qkv[kb]   = k0*c - k1*s;
    qkv[kb+1] = k0*s + k1*c;
}

// ---------------- blocked attention (exact ref semantics), K transposed, split output ----------------
#define ATTN_SMEM (4 * 64 * 68 * 4)
__global__ void __launch_bounds__(256) attn_kernel(
    const float* __restrict__ qkv,
    __nv_bfloat16* __restrict__ oh, __nv_bfloat16* __restrict__ ol)
{
    extern __shared__ float sm[];
    float* Qs  = sm;               // [64][68] token-major
    float* Kst = Qs + 64*68;       // [68*dim? no: [dim][token]] => Kst[d*68 + tok]
    float* Vs  = Kst + 64*68;      // [tok][dim]
    float* Ps  = Vs + 64*68;       // [qrow][tok]
    const int ib = blockIdx.x, h = blockIdx.y;
    const int tid = threadIdx.x;
    const int qr  = tid >> 2;
    const int c0  = (tid & 3) * 16;

    for (int idx = tid; idx < 64*64; idx += 256) {
        int r = idx >> 6, c = idx & 63;
        Qs[r*68 + c] = qkv[(size_t)(ib*64+r)*QKV_STRIDE + h*HEAD_DIM + c];
    }

    float accO[16];
    #pragma unroll
    for (int i = 0; i < 16; i++) accO[i] = 0.f;
    float den = 0.f;

    for (int jb = 0; jb <= ib; jb++) {
        __syncthreads();
        for (int idx = tid; idx < 64*64; idx += 256) {
            int r = idx >> 6, c = idx & 63;
            size_t base = (size_t)(jb*64+r)*QKV_STRIDE + h*HEAD_DIM + c;
            Kst[c*68 + r] = qkv[base + D_MODEL];      // transposed
            Vs [r*68 + c] = qkv[base + 2*D_MODEL];
        }
        __syncthreads();

        float s[16];
        #pragma unroll
        for (int cc = 0; cc < 16; cc++) s[cc] = 0.f;
        #pragma unroll 4
        for (int d = 0; d < 64; d++) {
            float qd = Qs[qr*68 + d];
            const float4* kr = (const float4*)&Kst[d*68 + c0];
            float4 k0v = kr[0], k1v = kr[1], k2v = kr[2], k3v = kr[3];
            s[0]  = fmaf(qd, k0v.x, s[0]);  s[1]  = fmaf(qd, k0v.y, s[1]);
            s[2]  = fmaf(qd, k0v.z, s[2]);  s[3]  = fmaf(qd, k0v.w, s[3]);
            s[4]  = fmaf(qd, k1v.x, s[4]);  s[5]  = fmaf(qd, k1v.y, s[5]);
            s[6]  = fmaf(qd, k1v.z, s[6]);  s[7]  = fmaf(qd, k1v.w, s[7]);
            s[8]  = fmaf(qd, k2v.x, s[8]);  s[9]  = fmaf(qd, k2v.y, s[9]);
            s[10] = fmaf(qd, k2v.z, s[10]); s[11] = fmaf(qd, k2v.w, s[11]);
            s[12] = fmaf(qd, k3v.x, s[12]); s[13] = fmaf(qd, k3v.y, s[13]);
            s[14] = fmaf(qd, k3v.z, s[14]); s[15] = fmaf(qd, k3v.w, s[15]);
        }

        float mx = -1e30f;
        #pragma unroll
        for (int cc = 0; cc < 16; cc++) {
            int c = c0 + cc;
            float dot = s[cc] * 0.125f;
            if (jb == ib && c > qr) dot = -1e30f;
            s[cc] = dot;
            mx = fmaxf(mx, dot);
        }
        mx = fmaxf(mx, __shfl_xor_sync(0xffffffffu, mx, 1));
        mx = fmaxf(mx, __shfl_xor_sync(0xffffffffu, mx, 2));

        #pragma unroll
        for (int cc = 0; cc < 16; cc++) {
            float p = expf(s[cc] - mx);
            Ps[qr*68 + c0 + cc] = p;
            den += p;
        }
        __syncthreads();

        #pragma unroll 4
        for (int kk = 0; kk < 64; kk++) {
            float pv = Ps[qr*68 + kk];
            const float4* vr = (const float4*)&Vs[kk*68 + c0];
            float4 v0 = vr[0], v1 = vr[1], v2 = vr[2], v3 = vr[3];
            accO[0]  = fmaf(pv, v0.x, accO[0]);  accO[1]  = fmaf(pv, v0.y, accO[1]);
            accO[2]  = fmaf(pv, v0.z, accO[2]);  accO[3]  = fmaf(pv, v0.w, accO[3]);
            accO[4]  = fmaf(pv, v1.x, accO[4]);  accO[5]  = fmaf(pv, v1.y, accO[5]);
            accO[6]  = fmaf(pv, v1.z, accO[6]);  accO[7]  = fmaf(pv, v1.w, accO[7]);
            accO[8]  = fmaf(pv, v2.x, accO[8]);  accO[9]  = fmaf(pv, v2.y, accO[9]);
            accO[10] = fmaf(pv, v2.z, accO[10]); accO[11] = fmaf(pv, v2.w, accO[11]);
            accO[12] = fmaf(pv, v3.x, accO[12]); accO[13] = fmaf(pv, v3.y, accO[13]);
            accO[14] = fmaf(pv, v3.z, accO[14]); accO[15] = fmaf(pv, v3.w, accO[15]);
        }
    }

    den += __shfl_xor_sync(0xffffffffu, den, 1);
    den += __shfl_xor_sync(0xffffffffu, den, 2);
    float invd = 1.f / (den + 1e-6f);

    size_t obase = (size_t)(ib*64+qr)*D_MODEL + h*HEAD_DIM + c0;
    uint32_t* hd = (uint32_t*)(oh + obase);
    uint32_t* ld = (uint32_t*)(ol + obase);
    #pragma unroll
    for (int u = 0; u < 8; u++) {
        uint32_t hv, lv;
        split2(accO[2*u] * invd, accO[2*u+1] * invd, hv, lv);
        hd[u] = hv;
        ld[u] = lv;
    }
}

// ---------------- layernorm (optional residual, optional split output) ----------------
__global__ void __launch_bounds__(256) ln_kernel(
    const float* __restrict__ in, const float* __restrict__ res,
    const float* __restrict__ g, const float* __restrict__ b,
    float* __restrict__ out,
    __nv_bfloat16* __restrict__ hi, __nv_bfloat16* __restrict__ lo)
{
    __shared__ float red[256];
    int t = blockIdx.x, tid = threadIdx.x;
    float v[8];
    float sum = 0.f;
    #pragma unroll
    for (int i = 0; i < 8; i++) {
        int d = i*256 + tid;
        float x = in[(size_t)t*D_MODEL + d];
        if (res) x += res[(size_t)t*D_MODEL + d];
        v[i] = x; sum += x;
    }
    red[tid] = sum; __syncthreads();
    for (int s = 128; s > 0; s >>= 1) { if (tid < s) red[tid] += red[tid+s]; __syncthreads(); }
    float mu = red[0] / D_MODEL;
    __syncthreads();
    float sq = 0.f;
    #pragma unroll
    for (int i = 0; i < 8; i++) { float d0 = v[i] - mu; sq += d0*d0; }
    red[tid] = sq; __syncthreads();
    for (int s = 128; s > 0; s >>= 1) { if (tid < s) red[tid] += red[tid+s]; __syncthreads(); }
    float rstd = rsqrtf(red[0] / D_MODEL + 1e-5f);
    #pragma unroll
    for (int i = 0; i < 8; i++) {
        int d = i*256 + tid;
        float val = (v[i] - mu) * rstd * g[d] + b[d];
        out[(size_t)t*D_MODEL + d] = val;
        if (hi) {
            __nv_bfloat16 hv = __float2bfloat16(val);
            hi[(size_t)t*D_MODEL + d] = hv;
            lo[(size_t)t*D_MODEL + d] = __float2bfloat16(val - __bfloat162float(hv));
        }
    }
}

// ---------------- fused double layernorm: out = LNf(LN2(in+res)) ----------------
__global__ void __launch_bounds__(256) ln2_kernel(
    const float* __restrict__ in, const float* __restrict__ res,
    const float* __restrict__ g2, const float* __restrict__ b2,
    const float* __restrict__ gf, const float* __restrict__ bf,
    float* __restrict__ out)
{
    __shared__ float red[256];
    int t = blockIdx.x, tid = threadIdx.x;
    float v[8];
    float sum = 0.f;
    #pragma unroll
    for (int i = 0; i < 8; i++) {
        int d = i*256 + tid;
        float x = in[(size_t)t*D_MODEL + d] + res[(size_t)t*D_MODEL + d];
        v[i] = x; sum += x;
    }
    red[tid] = sum; __syncthreads();
    for (int s = 128; s > 0; s >>= 1) { if (tid < s) red[tid] += red[tid+s]; __syncthreads(); }
    float mu = red[0] / D_MODEL;
    __syncthreads();
    float sq = 0.f;
    #pragma unroll
    for (int i = 0; i < 8; i++) { float d0 = v[i] - mu; sq += d0*d0; }
    red[tid] = sq; __syncthreads();
    for (int s = 128; s > 0; s >>= 1) { if (tid < s) red[tid] += red[tid+s]; __syncthreads(); }
    float rstd = rsqrtf(red[0] / D_MODEL + 1e-5f);
    __syncthreads();
    // second LN
    float sum2 = 0.f;
    #pragma unroll
    for (int i = 0; i < 8; i++) {
        int d = i*256 + tid;
        v[i] = (v[i] - mu) * rstd * g2[d] + b2[d];
        sum2 += v[i];
    }
    red[tid] = sum2; __syncthreads();
    for (int s = 128; s > 0; s >>= 1) { if (tid < s) red[tid] += red[tid+s]; __syncthreads(); }
    float mu2 = red[0] / D_MODEL;
    __syncthreads();
    float sq2 = 0.f;
    #pragma unroll
    for (int i = 0; i < 8; i++) { float d0 = v[i] - mu2; sq2 += d0*d0; }
    red[tid] = sq2; __syncthreads();
    for (int s = 128; s > 0; s >>= 1) { if (tid < s) red[tid] += red[tid+s]; __syncthreads(); }
    float rstd2 = rsqrtf(red[0] / D_MODEL + 1e-5f);
    #pragma unroll
    for (int i = 0; i < 8; i++) {
        int d = i*256 + tid;
        out[(size_t)t*D_MODEL + d] = (v[i] - mu2) * rstd2 * gf[d] + bf[d];
    }
}

// ---------------- MoE gate ----------------
__global__ void __launch_bounds__(128) gate_kernel(
    const float* __restrict__ x, const float* __restrict__ gw,
    float* __restrict__ wts, float* __restrict__ varr)
{
    __shared__ float red[128];
    __shared__ float logit[4];
    int t = blockIdx.x, tid = threadIdx.x;
    float p[4] = {0.f, 0.f, 0.f, 0.f};
    for (int d = tid; d < D_MODEL; d += 128) {
        float xv = x[(size_t)t*D_MODEL + d];
        #pragma unroll
        for (int e = 0; e < 4; e++)
            p[e] = fmaf(xv, gw[e*D_MODEL + d], p[e]);
    }
    for (int e = 0; e < 4; e++) {
        red[tid] = p[e]; __syncthreads();
        for (int s = 64; s > 0; s >>= 1) { if (tid < s) red[tid] += red[tid+s]; __syncthreads(); }
        if (tid == 0) logit[e] = red[0];
        __syncthreads();
    }
    if (tid == 0) {
        float l[4] = {logit[0], logit[1], logit[2], logit[3]};
        float mx = fmaxf(fmaxf(l[0], l[1]), fmaxf(l[2], l[3]));
        float ex[4], ssum = 0.f;
        for (int e = 0; e < 4; e++) { ex[e] = expf(l[e] - mx); ssum += ex[e]; }
        float pr[4];
        for (int e = 0; e < 4; e++) pr[e] = ex[e] / ssum;
        int b1 = 0;
        for (int e = 1; e < 4; e++) if (pr[e] > pr[b1]) b1 = e;
        int b2 = -1;
        for (int e = 0; e < 4; e++) { if (e == b1) continue; if (b2 < 0 || pr[e] > pr[b2]) b2 = e; }
        float s2 = pr[b1] + pr[b2];
        float wv[4] = {0.f, 0.f, 0.f, 0.f};
        wv[b1] = pr[b1] / s2; wv[b2] = pr[b2] / s2;
        for (int e = 0; e < 4; e++) wts[e*SEQ + t] = wv[e];
        float mu = (l[0]+l[1]+l[2]+l[3]) * 0.25f;
        float va = ((l[0]-mu)*(l[0]-mu) + (l[1]-mu)*(l[1]-mu) +
                    (l[2]-mu)*(l[2]-mu) + (l[3]-mu)*(l[3]-mu)) / 3.f;
        varr[t] = va;
    }
}

// ---------------- routing compaction ----------------
__global__ void __launch_bounds__(1024) compact_kernel(
    const float* __restrict__ wts, int* __restrict__ cnt,
    int* __restrict__ ridx, float* __restrict__ rwt)
{
    __shared__ int sc[1024];
    int e = blockIdx.x, t = threadIdx.x;
    float w = wts[e*SEQ + t];
    int flag = (w != 0.f) ? 1 : 0;
    sc[t] = flag;
    __syncthreads();
    for (int off = 1; off < 1024; off <<= 1) {
        int v = (t >= off) ? sc[t - off] : 0;
        __syncthreads();
        sc[t] += v;
        __syncthreads();
    }
    if (flag) {
        int pos = sc[t] - 1;
        ridx[e*SEQ + pos] = t;
        rwt [e*SEQ + pos] = w;
    }
    if (t == 1023) cnt[e] = sc[1023];
}

__global__ void aux_kernel(const float* __restrict__ varr, float* __restrict__ out) {
    __shared__ float red[256];
    int tid = threadIdx.x;
    float s = 0.f;
    for (int i = tid; i < SEQ; i += 256) s += varr[i];
    red[tid] = s; __syncthreads();
    for (int st = 128; st > 0; st >>= 1) { if (tid < st) red[tid] += red[tid+st]; __syncthreads(); }
    if (tid == 0) out[0] = red[0] / (float)SEQ;
}

__global__ void zero_kernel(float* __restrict__ p, int n) {
    int i = blockIdx.x * 256 + threadIdx.x;
    if (i < n) p[i] = 0.f;
}

// ---------------- driver ----------------
extern "C" void kernel_launch(void* const* d_in, const int* in_sizes, int n_in,
                              void* d_out, int out_size) {
    const int*   tokens = (const int*)  d_in[0];
    const float* emb    = (const float*)d_in[1];
    const float* wq     = (const float*)d_in[2];
    const float* wk     = (const float*)d_in[3];
    const float* wv     = (const float*)d_in[4];
    const float* wo     = (const float*)d_in[5];
    const float* ln1g   = (const float*)d_in[6];
    const float* ln1b   = (const float*)d_in[7];
    const float* gatew  = (const float*)d_in[8];
    const float* w1     = (const float*)d_in[9];
    const float* w2     = (const float*)d_in[10];
    const float* w3     = (const float*)d_in[11];
    const float* ln2g   = (const float*)d_in[12];
    const float* ln2b   = (const float*)d_in[13];
    const float* fing   = (const float*)d_in[14];
    const float* finb   = (const float*)d_in[15];
    const float* headw  = (const float*)d_in[16];
    float* out = (float*)d_out;

    float *x, *qkv, *y, *moe, *wts, *varr, *rwt;
    int *cnt, *ridx;
    __nv_bfloat16 *ah, *al, *ch, *cl;
    cudaGetSymbolAddress((void**)&x,    g_x);
    cudaGetSymbolAddress((void**)&qkv,  g_qkv);
    cudaGetSymbolAddress((void**)&y,    g_y);
    cudaGetSymbolAddress((void**)&moe,  g_moe);
    cudaGetSymbolAddress((void**)&wts,  g_wts);
    cudaGetSymbolAddress((void**)&varr, g_var);
    cudaGetSymbolAddress((void**)&cnt,  g_cnt);
    cudaGetSymbolAddress((void**)&ridx, g_ridx);
    cudaGetSymbolAddress((void**)&rwt,  g_rwt);
    cudaGetSymbolAddress((void**)&ah,   g_ah);
    cudaGetSymbolAddress((void**)&al,   g_al);
    cudaGetSymbolAddress((void**)&ch,   g_ch);
    cudaGetSymbolAddress((void**)&cl,   g_cl);

    cudaFuncSetAttribute(attn_kernel, cudaFuncAttributeMaxDynamicSharedMemorySize, ATTN_SMEM);
    cudaFuncSetAttribute(gemm_tc<0>, cudaFuncAttributeMaxDynamicSharedMemorySize, GEMM_SMEM_TC);
    cudaFuncSetAttribute(gemm_tc<1>, cudaFuncAttributeMaxDynamicSharedMemorySize, GEMM_SMEM_TC);
    cudaFuncSetAttribute(gemm_tc<2>, cudaFuncAttributeMaxDynamicSharedMemorySize, GEMM_SMEM_TC);
    cudaFuncSetAttribute(gemm_tf32, cudaFuncAttributeMaxDynamicSharedMemorySize, GEMM_SMEM_TF);

    // 1) embed (+ fused split)
    embed_kernel<<<SEQ, 256>>>(tokens, emb, x, ah, al);

    // 2) fused QKV (N=6144)
    dim3 gQKV(3*D_MODEL/256, SEQ/128);
    gemm_tc<0><<<gQKV, 256, GEMM_SMEM_TC>>>(ah, al, wq, wk, wv, D_MODEL,
                                            qkv, SEQ, 3*D_MODEL, D_MODEL,
                                            nullptr, nullptr, nullptr, nullptr, 0, 0,
                                            nullptr, nullptr);

    // 3) RoPE + attention (attention emits pre-split ah/al)
    rope_kernel<<<dim3(SEQ, N_HEADS), 32>>>(qkv);
    attn_kernel<<<dim3(NB, N_HEADS), 256, ATTN_SMEM>>>(qkv, ah, al);

    // 4) output proj + residual -> y
    dim3 gA(D_MODEL/256, SEQ/128);
    gemm_tc<0><<<gA, 256, GEMM_SMEM_TC>>>(ah, al, wo, wo, wo, D_MODEL,
                                          y, SEQ, D_MODEL, D_MODEL,
                                          x, nullptr, nullptr, nullptr, 0, 0,
                                          nullptr, nullptr);

    // 5) LN1 -> x (+ fused split to ah/al)
    ln_kernel<<<SEQ, 256>>>(y, nullptr, ln1g, ln1b, x, ah, al);

    // 6) gate + routing
    gate_kernel<<<SEQ, 128>>>(x, gatew, wts, varr);
    compact_kernel<<<NEXP, 1024>>>(wts, cnt, ridx, rwt);

    // 7) MoE — up (fused silu+split) then down (atomic scatter)
    zero_kernel<<<(SEQ*D_MODEL + 255)/256, 256>>>(moe, SEQ*D_MODEL);
    const long long FD = (long long)D_FFN * D_MODEL;
    dim3 gUp(2*D_FFN/256, SEQ/128, NEXP);
    gemm_tc<1><<<gUp, 256, GEMM_SMEM_TC>>>(ah, al, w1, w3, nullptr, 0,
                                           nullptr, 0, 2*D_FFN, D_MODEL,
                                           nullptr, cnt, ridx, nullptr,
                                           0, FD, ch, cl);
    dim3 gDn(D_MODEL/256, SEQ/128, NEXP*4);
    gemm_tc<2><<<gDn, 256, GEMM_SMEM_TC>>>(ch, cl, w2, nullptr, nullptr, 0,
                                           moe, 0, D_MODEL, D_FFN,
                                           nullptr, cnt, ridx, rwt,
                                           (long long)SEQ*D_FFN, FD, nullptr, nullptr);

    // 8) fused LN2 + final LN
    ln2_kernel<<<SEQ, 256>>>(moe, x, ln2g, ln2b, fing, finb, y);

    // 9) head (tf32 single-pass)
    dim3 gH((VOCAB + 255)/256, SEQ/128);
    gemm_tf32<<<gH, 256, GEMM_SMEM_TF>>>(y, headw, out, SEQ, VOCAB, D_MODEL);

    // 10) aux
    long long nlog = (long long)SEQ * VOCAB;
    if ((long long)out_size > nlog)
        aux_kernel<<<1, 256>>>(varr, out + nlog);
}

// round 11
// speedup vs baseline: 4.8404x; 1.1413x over previous
#include <cuda_runtime.h>
#include <cuda_bf16.h>
#include <math.h>
#include <stdint.h>

#define D_MODEL 2048
#define SEQ     1024
#define N_HEADS 32
#define HEAD_DIM 64
#define NB      (SEQ/64)
#define D_FFN   8192
#define VOCAB   50257
#define NEXP    4
#define QKV_STRIDE (3*D_MODEL)

// ---------------- scratch ----------------
__device__ float g_x  [SEQ*D_MODEL];
__device__ float g_qkv[SEQ*3*D_MODEL];
__device__ float g_y  [SEQ*D_MODEL];
__device__ float g_moe[SEQ*D_MODEL];
__device__ float g_wts[NEXP*SEQ];
__device__ float g_var[SEQ];

// routing
__device__ int   g_cnt[NEXP];
__device__ int   g_ridx[NEXP*SEQ];
__device__ float g_rwt [NEXP*SEQ];

// bf16 split scratch
__device__ __nv_bfloat16 g_ah[SEQ*D_MODEL];
__device__ __nv_bfloat16 g_al[SEQ*D_MODEL];
__device__ __nv_bfloat16 g_ch[(size_t)NEXP*SEQ*D_FFN];
__device__ __nv_bfloat16 g_cl[(size_t)NEXP*SEQ*D_FFN];

// ---------------- PTX helpers ----------------
__device__ __forceinline__ uint32_t smem_u32(const void* p) {
    uint32_t a;
    asm("{ .reg .u64 t; cvta.to.shared.u64 t, %1; cvt.u32.u64 %0, t; }" : "=r"(a) : "l"(p));
    return a;
}
__device__ __forceinline__ void cp_async16(uint32_t dst, const void* src, int src_bytes) {
    asm volatile("cp.async.cg.shared.global [%0], [%1], 16, %2;\n"
                 :: "r"(dst), "l"(src), "r"(src_bytes) : "memory");
}
#define CP_COMMIT() asm volatile("cp.async.commit_group;\n" ::: "memory")

#define STS128(addr, a, b, c, d) \
    asm volatile("st.shared.v4.b32 [%0], {%1,%2,%3,%4};" \
                 :: "r"(addr), "r"(a), "r"(b), "r"(c), "r"(d) : "memory")

__device__ __forceinline__ void ldsm_x4(uint32_t& r0, uint32_t& r1, uint32_t& r2, uint32_t& r3,
                                        uint32_t addr) {
    asm volatile("ldmatrix.sync.aligned.m8n8.x4.shared.b16 {%0,%1,%2,%3}, [%4];"
                 : "=r"(r0), "=r"(r1), "=r"(r2), "=r"(r3) : "r"(addr));
}
__device__ __forceinline__ void mma_bf16(float* c, const uint32_t* a, const uint32_t* b) {
    asm volatile(
        "mma.sync.aligned.m16n8k16.row.col.f32.bf16.bf16.f32 "
        "{%0,%1,%2,%3}, {%4,%5,%6,%7}, {%8,%9}, {%0,%1,%2,%3};"
        : "+f"(c[0]), "+f"(c[1]), "+f"(c[2]), "+f"(c[3])
        : "r"(a[0]), "r"(a[1]), "r"(a[2]), "r"(a[3]), "r"(b[0]), "r"(b[1]));
}
__device__ __forceinline__ void mma_tf32(float* c, const uint32_t* a, const uint32_t* b) {
    asm volatile(
        "mma.sync.aligned.m16n8k8.row.col.f32.tf32.tf32.f32 "
        "{%0,%1,%2,%3}, {%4,%5,%6,%7}, {%8,%9}, {%0,%1,%2,%3};"
        : "+f"(c[0]), "+f"(c[1]), "+f"(c[2]), "+f"(c[3])
        : "r"(a[0]), "r"(a[1]), "r"(a[2]), "r"(a[3]), "r"(b[0]), "r"(b[1]));
}

__device__ __forceinline__ void split2(float a, float b, uint32_t& hi, uint32_t& lo) {
    __nv_bfloat16 ha = __float2bfloat16(a), hb = __float2bfloat16(b);
    __nv_bfloat162 h; h.x = ha; h.y = hb;
    __nv_bfloat162 l;
    l.x = __float2bfloat16(a - __bfloat162float(ha));
    l.y = __float2bfloat16(b - __bfloat162float(hb));
    hi = *(uint32_t*)&h;
    lo = *(uint32_t*)&l;
}

// ================= bf16x3 GEMM: CTA 128x256, 8 warps (2Mx4N), warp 64x64 =================
#define NSTG_TC 3
#define A_BYTES (128*128)
#define B_BYTES (256*128)
#define STAGE_B (A_BYTES + B_BYTES)
#define GEMM_SMEM_TC (NSTG_TC * STAGE_B)
#define NSTG_TF 4
#define GEMM_SMEM_TF (NSTG_TF * STAGE_B)

// MODE 0: dense. C[m,n]=val(+residual). B rows: <rPB->B0, <2rPB->B1, else B2.
// MODE 1: expert-batched up + FUSED silu·mul + bf16 split.
// MODE 2: expert-batched down + split-K4, atomic scatter.
template<int MODE>
__global__ void __launch_bounds__(256, 1) gemm_tc(
    const __nv_bfloat16* __restrict__ Ah, const __nv_bfloat16* __restrict__ Al,
    const float* __restrict__ B0, const float* __restrict__ B1, const float* __restrict__ B2,
    int rPB,
    float* __restrict__ C, int M_in, int N, int K,
    const float* __restrict__ residual,
    const int* __restrict__ cntArr, const int* __restrict__ ridxAll,
    const float* __restrict__ rwtAll,
    long long sA, long long sB,
    __nv_bfloat16* __restrict__ CH, __nv_bfloat16* __restrict__ CL)
{
    const int tid = threadIdx.x;
    const int m0  = blockIdx.y * 128;
    const int n0  = blockIdx.x * 256;

    int M = M_in;
    int e = 0, kbase = 0, Kc = K;
    const int* ridx = ridxAll;
    const float* rwt = rwtAll;
    const float* b0p = B0; const float* b1p = B1; const float* b2p = B2;
    const __nv_bfloat16* ahp = Ah; const __nv_bfloat16* alp = Al;
    float* Cp = C;

    if (MODE == 1) {
        e = blockIdx.z;
        M = cntArr[e];
        if (m0 >= M) return;
        ridx = ridxAll + e * SEQ;
        b0p = B0 + (size_t)e * sB;
        b1p = B1 + (size_t)e * sB;
    } else if (MODE == 2) {
        e = blockIdx.z >> 2;
        int ks = blockIdx.z & 3;
        M = cntArr[e];
        if (m0 >= M) return;
        ridx = ridxAll + e * SEQ;
        rwt  = rwtAll + e * SEQ;
        ahp = Ah + (size_t)e * sA;
        alp = Al + (size_t)e * sA;
        b0p = B0 + (size_t)e * sB;
        Kc = K >> 2;
        kbase = ks * Kc;
    }

    int arow[4];
    #pragma unroll
    for (int i = 0; i < 4; i++) {
        int r = (tid + i * 256) >> 3;
        int rg = m0 + r;
        if (MODE == 0)      arow[i] = rg;
        else {
            rg = rg < M ? rg : (M - 1);
            arow[i] = (MODE == 1) ? ridx[rg] : rg;
        }
    }

    extern __shared__ char smem[];
    const uint32_t sb = smem_u32(smem);
    const int wid = tid >> 5, lid = tid & 31;
    const int wm  = wid >> 2, wn = wid & 3;

    float acc[4][8][4];
    #pragma unroll
    for (int i = 0; i < 4; i++)
        #pragma unroll
        for (int j = 0; j < 8; j++)
            #pragma unroll
            for (int t = 0; t < 4; t++) acc[i][j][t] = 0.f;

    const int iters = Kc >> 5;

    auto fillA = [&](int stage, int kit) {
        const int k0 = kbase + (kit << 5);
        const uint32_t abase = sb + stage * STAGE_B;
        #pragma unroll
        for (int i = 0; i < 4; i++) {
            int idx = tid + i * 256;
            int r = idx >> 3, c = idx & 7;
            uint32_t dst = abase + r * 128 + ((c ^ (r & 7)) << 4);
            const __nv_bfloat16* src = (c < 4)
                ? ahp + (size_t)arow[i] * K + k0 + c * 8
                : alp + (size_t)arow[i] * K + k0 + (c - 4) * 8;
            cp_async16(dst, src, 16);
        }
        CP_COMMIT();
    };

    auto ldgB = [&](float4* breg, int kit) {
        const int k0 = kbase + (kit << 5);
        #pragma unroll
        for (int i = 0; i < 4; i++) {
            int idx = tid + i * 256;
            int r = idx >> 2, c2 = idx & 3;
            int rg = n0 + r;
            int rc = rg < N ? rg : (N - 1);
            const float* Bp; int rr;
            if (MODE == 2)          { Bp = b0p; rr = rc; }
            else if (MODE == 1)     { Bp = (rc & 1) ? b1p : b0p; rr = rc >> 1; }
            else if (rc < rPB)      { Bp = b0p; rr = rc; }
            else if (rc < 2 * rPB)  { Bp = b1p; rr = rc - rPB; }
            else                    { Bp = b2p; rr = rc - 2 * rPB; }
            const float4* s4 = (const float4*)(Bp + (size_t)rr * K + k0 + c2 * 8);
            breg[i*2]     = s4[0];
            breg[i*2 + 1] = s4[1];
        }
    };

    auto stsB = [&](const float4* breg, int stage) {
        const uint32_t bbase = sb + stage * STAGE_B + A_BYTES;
        #pragma unroll
        for (int i = 0; i < 4; i++) {
            int idx = tid + i * 256;
            int r = idx >> 2, c2 = idx & 3;
            float4 v0 = breg[i*2], v1 = breg[i*2 + 1];
            uint32_t h0, h1, h2, h3, l0, l1, l2, l3;
            split2(v0.x, v0.y, h0, l0);
            split2(v0.z, v0.w, h1, l1);
            split2(v1.x, v1.y, h2, l2);
            split2(v1.z, v1.w, h3, l3);
            uint32_t ha = bbase + r * 128 + ((c2 ^ (r & 7)) << 4);
            uint32_t la = bbase + r * 128 + (((c2 + 4) ^ (r & 7)) << 4);
            STS128(ha, h0, h1, h2, h3);
            STS128(la, l0, l1, l2, l3);
        }
    };

    {
        float4 pb[8];
        #pragma unroll
        for (int s = 0; s < NSTG_TC - 1; s++) {
            fillA(s, s);
            ldgB(pb, s);
            stsB(pb, s);
        }
    }

    const int grp = lid >> 3;
    const int rin = lid & 7;
    float4 breg[8];

    for (int i = 0; i < iters; i++) {
        const int s = i % NSTG_TC;
        const bool pre = (i + NSTG_TC - 1 < iters);
        if (pre) ldgB(breg, i + NSTG_TC - 1);

        asm volatile("cp.async.wait_group %0;\n" :: "n"(NSTG_TC - 2));
        __syncthreads();

        if (pre) fillA((i + NSTG_TC - 1) % NSTG_TC, i + NSTG_TC - 1);
        else CP_COMMIT();

        const uint32_t abase = sb + s * STAGE_B;
        const uint32_t bbase = abase + A_BYTES;

        #pragma unroll
        for (int g = 0; g < 2; g++) {
            uint32_t ah[4][4], bh[8][2];
            #pragma unroll
            for (int mt = 0; mt < 4; mt++) {
                int row = wm * 64 + mt * 16 + (grp & 1) * 8 + rin;
                int kch = 2 * g + (grp >> 1);
                uint32_t ad = abase + row * 128 + ((kch ^ (row & 7)) << 4);
                ldsm_x4(ah[mt][0], ah[mt][1], ah[mt][2], ah[mt][3], ad);
            }
            #pragma unroll
            for (int p = 0; p < 4; p++) {
                int tile = 2 * p + (grp >> 1);
                int row  = wn * 64 + tile * 8 + rin;
                int kch  = 2 * g + (grp & 1);
                uint32_t bd = bbase + row * 128 + ((kch ^ (row & 7)) << 4);
                ldsm_x4(bh[2*p][0], bh[2*p][1], bh[2*p+1][0], bh[2*p+1][1], bd);
            }
            #pragma unroll
            for (int mt = 0; mt < 4; mt++)
                #pragma unroll
                for (int nt = 0; nt < 8; nt++)
                    mma_bf16(acc[mt][nt], ah[mt], bh[nt]);
            {
                uint32_t al[4][4];
                #pragma unroll
                for (int mt = 0; mt < 4; mt++) {
                    int row = wm * 64 + mt * 16 + (grp & 1) * 8 + rin;
                    int kcl = 4 + 2 * g + (grp >> 1);
                    uint32_t adl = abase + row * 128 + ((kcl ^ (row & 7)) << 4);
                    ldsm_x4(al[mt][0], al[mt][1], al[mt][2], al[mt][3], adl);
                }
                #pragma unroll
                for (int mt = 0; mt < 4; mt++)
                    #pragma unroll
                    for (int nt = 0; nt < 8; nt++)
                        mma_bf16(acc[mt][nt], al[mt], bh[nt]);
            }
            {
                uint32_t bl[8][2];
                #pragma unroll
                for (int p = 0; p < 4; p++) {
                    int tile = 2 * p + (grp >> 1);
                    int row  = wn * 64 + tile * 8 + rin;
                    int kcl  = 4 + 2 * g + (grp & 1);
                    uint32_t bdl = bbase + row * 128 + ((kcl ^ (row & 7)) << 4);
                    ldsm_x4(bl[2*p][0], bl[2*p][1], bl[2*p+1][0], bl[2*p+1][1], bdl);
                }
                #pragma unroll
                for (int mt = 0; mt < 4; mt++)
                    #pragma unroll
                    for (int nt = 0; nt < 8; nt++)
                        mma_bf16(acc[mt][nt], ah[mt], bl[nt]);
            }
        }

        if (pre) stsB(breg, (i + NSTG_TC - 1) % NSTG_TC);
    }

    #pragma unroll
    for (int mt = 0; mt < 4; mt++) {
        #pragma unroll
        for (int nt = 0; nt < 8; nt++) {
            int rbase = m0 + wm * 64 + mt * 16 + (lid >> 2);
            int col = n0 + wn * 64 + nt * 8 + (lid & 3) * 2;
            #pragma unroll
            for (int h = 0; h < 2; h++) {
                int m = rbase + h * 8;
                float v0 = acc[mt][nt][h * 2 + 0];
                float v1 = acc[mt][nt][h * 2 + 1];
                if (MODE == 0) {
                    size_t idx = (size_t)m * N + col;
                    if (residual) {
                        if (col     < N) v0 += residual[idx];
                        if (col + 1 < N) v1 += residual[idx + 1];
                    }
                    if (col     < N) Cp[idx]     = v0;
                    if (col + 1 < N) Cp[idx + 1] = v1;
                } else if (MODE == 1) {
                    if (m < M) {
                        int j = col >> 1;
                        float r = v0 / (1.f + expf(-v0)) * v1;
                        __nv_bfloat16 hi = __float2bfloat16(r);
                        size_t o = (size_t)e * SEQ * D_FFN + (size_t)m * D_FFN + j;
                        CH[o] = hi;
                        CL[o] = __float2bfloat16(r - __bfloat162float(hi));
                    }
                } else {
                    if (m < M) {
                        int tok = ridx[m];
                        float w = rwt[m];
                        size_t idx = (size_t)tok * N + col;
                        atomicAdd(&Cp[idx],     w * v0);
                        atomicAdd(&Cp[idx + 1], w * v1);
                    }
                }
            }
        }
    }
}

// ================= tf32 single-pass GEMM (head) =================
__global__ void __launch_bounds__(256, 1) gemm_tf32(
    const float* __restrict__ A, const float* __restrict__ B,
    float* __restrict__ C, int M, int N, int K)
{
    extern __shared__ char smem[];
    const uint32_t sb = smem_u32(smem);
    const int tid = threadIdx.x;
    const int wid = tid >> 5, lid = tid & 31;
    const int wm  = wid >> 2, wn = wid & 3;
    const int m0  = blockIdx.y * 128;
    const int n0  = blockIdx.x * 256;

    float acc[4][8][4];
    #pragma unroll
    for (int i = 0; i < 4; i++)
        #pragma unroll
        for (int j = 0; j < 8; j++)
            #pragma unroll
            for (int t = 0; t < 4; t++) acc[i][j][t] = 0.f;

    const int iters = K >> 5;

    auto fill = [&](int stage, int kit) {
        const int k0 = kit << 5;
        const uint32_t abase = sb + stage * STAGE_B;
        const uint32_t bbase = abase + A_BYTES;
        #pragma unroll
        for (int i = 0; i < 4; i++) {
            int idx = tid + i * 256;
            int r = idx >> 3, c = idx & 7;
            uint32_t dst = abase + r * 128 + ((c ^ (r & 7)) << 4);
            cp_async16(dst, A + (size_t)(m0 + r) * K + k0 + c * 4, 16);
        }
        #pragma unroll
        for (int i = 0; i < 8; i++) {
            int idx = tid + i * 256;
            int r = idx >> 3, c = idx & 7;
            uint32_t dst = bbase + r * 128 + ((c ^ (r & 7)) << 4);
            int rg = n0 + r;
            int rc = rg < N ? rg : (N - 1);
            cp_async16(dst, B + (size_t)rc * K + k0 + c * 4, rg < N ? 16 : 0);
        }
        CP_COMMIT();
    };

    #pragma unroll
    for (int s = 0; s < NSTG_TF - 1; s++) fill(s, s);

    const int grp = lid >> 3;
    const int rin = lid & 7;

    for (int i = 0; i < iters; i++) {
        const int s = i % NSTG_TF;
        asm volatile("cp.async.wait_group %0;\n" :: "n"(NSTG_TF - 2));
        __syncthreads();

        if (i + NSTG_TF - 1 < iters) fill((i + NSTG_TF - 1) % NSTG_TF, i + NSTG_TF - 1);
        else CP_COMMIT();

        const uint32_t abase = sb + s * STAGE_B;
        const uint32_t bbase = abase + A_BYTES;

        #pragma unroll
        for (int k8 = 0; k8 < 4; k8++) {
            uint32_t a[4][4], b[8][2];
            #pragma unroll
            for (int mt = 0; mt < 4; mt++) {
                int row = wm * 64 + mt * 16 + (grp & 1) * 8 + rin;
                int kc  = k8 * 2 + (grp >> 1);
                uint32_t addr = abase + row * 128 + ((kc ^ (row & 7)) << 4);
                ldsm_x4(a[mt][0], a[mt][1], a[mt][2], a[mt][3], addr);
            }
            #pragma unroll
            for (int p = 0; p < 4; p++) {
                int tile = 2 * p + (grp >> 1);
                int row  = wn * 64 + tile * 8 + rin;
                int kc   = k8 * 2 + (grp & 1);
                uint32_t addr = bbase + row * 128 + ((kc ^ (row & 7)) << 4);
                ldsm_x4(b[2*p][0], b[2*p][1], b[2*p+1][0], b[2*p+1][1], addr);
            }
            #pragma unroll
            for (int mt = 0; mt < 4; mt++)
                #pragma unroll
                for (int nt = 0; nt < 8; nt++)
                    mma_tf32(acc[mt][nt], a[mt], b[nt]);
        }
    }

    #pragma unroll
    for (int mt = 0; mt < 4; mt++) {
        #pragma unroll
        for (int nt = 0; nt < 8; nt++) {
            int rbase = m0 + wm * 64 + mt * 16 + (lid >> 2);
            int col = n0 + wn * 64 + nt * 8 + (lid & 3) * 2;
            #pragma unroll
            for (int h = 0; h < 2; h++) {
                int m = rbase + h * 8;
                size_t idx = (size_t)m * N + col;
                if (col     < N) C[idx]     = acc[mt][nt][h * 2 + 0];
                if (col + 1 < N) C[idx + 1] = acc[mt][nt][h * 2 + 1];
            }
        }
    }
}

// ---------------- embedding (+ fused split) ----------------
__global__ void embed_kernel(const int* __restrict__ tok,
                             const float* __restrict__ emb,
                             float* __restrict__ x,
                             __nv_bfloat16* __restrict__ ah,
                             __nv_bfloat16* __restrict__ al) {
    int t = blockIdx.x;
    int tk = tok[t];
    const float2* src = (const float2*)(emb + (size_t)tk * D_MODEL);
    float2* dst = (float2*)(x + (size_t)t * D_MODEL);
    uint32_t* hd = (uint32_t*)(ah + (size_t)t * D_MODEL);
    uint32_t* ld = (uint32_t*)(al + (size_t)t * D_MODEL);
    for (int p = threadIdx.x; p < D_MODEL/2; p += 256) {
        float2 v = src[p];
        dst[p] = v;
        uint32_t h, l;
        split2(v.x, v.y, h, l);
        hd[p] = h;
        ld[p] = l;
    }
}

// ---------------- RoPE ----------------
__global__ void rope_kernel(float* __restrict__ qkv) {
    int t = blockIdx.x, h = blockIdx.y, i = threadIdx.x;
    float inv = powf(10000.f, -((float)(2*i)) / 64.f);
    float ang = (float)t * inv;
    float s, c;
    sincosf(ang, &s, &c);
    size_t base = (size_t)t*QKV_STRIDE + h*HEAD_DIM + 2*i;
    float q0 = qkv[base], q1 = qkv[base+1];
    qkv[base]   = q0*c - q1*s;
    qkv[base+1] = q0*s + q1*c;
    size_t kb = base + D_MODEL;
    float k0 = qkv[kb], k1 = qkv[kb+1];
    qkv[kb]   = k0*c - k1*s;
    qkv[kb+1] = k0*s + k1*c;
}

// ---------------- blocked attention: 4x4 register tiles, Q/K/P transposed ----------------
#define ATTN_SMEM (4 * 64 * 68 * 4)
__global__ void __launch_bounds__(256) attn_kernel(
    const float* __restrict__ qkv,
    __nv_bfloat16* __restrict__ oh, __nv_bfloat16* __restrict__ ol)
{
    extern __shared__ float sm[];
    float* Qst = sm;               // [d][qr]  stride 68
    float* Kst = Qst + 64*68;      // [d][tok] stride 68
    float* Vs  = Kst + 64*68;      // [tok][dim] stride 68
    float* Pst = Vs + 64*68;       // [tok][qr]  stride 68
    const int ib = blockIdx.x, h = blockIdx.y;
    const int tid = threadIdx.x;
    const int qg  = tid >> 4;      // 0..15
    const int cg  = tid & 15;      // 0..15
    const int qr0 = qg * 4;
    const int c0  = cg * 4;

    // load Q transposed: Qst[d][qr]
    for (int idx = tid; idx < 64*64; idx += 256) {
        int r = idx >> 6, c = idx & 63;
        Qst[c*68 + r] = qkv[(size_t)(ib*64+r)*QKV_STRIDE + h*HEAD_DIM + c];
    }

    float accO[4][4];
    #pragma unroll
    for (int i = 0; i < 4; i++)
        #pragma unroll
        for (int j = 0; j < 4; j++) accO[i][j] = 0.f;
    float den[4] = {0.f, 0.f, 0.f, 0.f};

    for (int jb = 0; jb <= ib; jb++) {
        __syncthreads();
        for (int idx = tid; idx < 64*64; idx += 256) {
            int r = idx >> 6, c = idx & 63;
            size_t base = (size_t)(jb*64+r)*QKV_STRIDE + h*HEAD_DIM + c;
            Kst[c*68 + r] = qkv[base + D_MODEL];     // [d][tok]
            Vs [r*68 + c] = qkv[base + 2*D_MODEL];   // [tok][dim]
        }
        __syncthreads();

        // scores: 4 q-rows x 4 cols per thread
        float s4[4][4];
        #pragma unroll
        for (int i = 0; i < 4; i++)
            #pragma unroll
            for (int j = 0; j < 4; j++) s4[i][j] = 0.f;

        #pragma unroll 4
        for (int d = 0; d < 64; d++) {
            float4 qv = *(const float4*)&Qst[d*68 + qr0];
            float4 kv = *(const float4*)&Kst[d*68 + c0];
            s4[0][0] = fmaf(qv.x, kv.x, s4[0][0]); s4[0][1] = fmaf(qv.x, kv.y, s4[0][1]);
            s4[0][2] = fmaf(qv.x, kv.z, s4[0][2]); s4[0][3] = fmaf(qv.x, kv.w, s4[0][3]);
            s4[1][0] = fmaf(qv.y, kv.x, s4[1][0]); s4[1][1] = fmaf(qv.y, kv.y, s4[1][1]);
            s4[1][2] = fmaf(qv.y, kv.z, s4[1][2]); s4[1][3] = fmaf(qv.y, kv.w, s4[1][3]);
            s4[2][0] = fmaf(qv.z, kv.x, s4[2][0]); s4[2][1] = fmaf(qv.z, kv.y, s4[2][1]);
            s4[2][2] = fmaf(qv.z, kv.z, s4[2][2]); s4[2][3] = fmaf(qv.z, kv.w, s4[2][3]);
            s4[3][0] = fmaf(qv.w, kv.x, s4[3][0]); s4[3][1] = fmaf(qv.w, kv.y, s4[3][1]);
            s4[3][2] = fmaf(qv.w, kv.z, s4[3][2]); s4[3][3] = fmaf(qv.w, kv.w, s4[3][3]);
        }

        // scale + mask + per-row block max
        float mx[4];
        #pragma unroll
        for (int i = 0; i < 4; i++) {
            mx[i] = -1e30f;
            int q = qr0 + i;
            #pragma unroll
            for (int j = 0; j < 4; j++) {
                int c = c0 + j;
                float v = s4[i][j] * 0.125f;
                if (jb == ib && c > q) v = -1e30f;
                s4[i][j] = v;
                mx[i] = fmaxf(mx[i], v);
            }
        }
        #pragma unroll
        for (int o = 1; o < 16; o <<= 1) {
            #pragma unroll
            for (int i = 0; i < 4; i++)
                mx[i] = fmaxf(mx[i], __shfl_xor_sync(0xffffffffu, mx[i], o));
        }

        // exp + den + store P transposed [tok][qr]
        #pragma unroll
        for (int j = 0; j < 4; j++) {
            float p0 = expf(s4[0][j] - mx[0]);
            float p1 = expf(s4[1][j] - mx[1]);
            float p2 = expf(s4[2][j] - mx[2]);
            float p3 = expf(s4[3][j] - mx[3]);
            den[0] += p0; den[1] += p1; den[2] += p2; den[3] += p3;
            *(float4*)&Pst[(c0 + j)*68 + qr0] = make_float4(p0, p1, p2, p3);
        }
        __syncthreads();

        // O += P @ V : 4 q-rows x 4 dims (dims = c0..c0+3)
        #pragma unroll 4
        for (int kk = 0; kk < 64; kk++) {
            float4 pv = *(const float4*)&Pst[kk*68 + qr0];
            float4 vv = *(const float4*)&Vs [kk*68 + c0];
            accO[0][0] = fmaf(pv.x, vv.x, accO[0][0]); accO[0][1] = fmaf(pv.x, vv.y, accO[0][1]);
            accO[0][2] = fmaf(pv.x, vv.z, accO[0][2]); accO[0][3] = fmaf(pv.x, vv.w, accO[0][3]);
            accO[1][0] = fmaf(pv.y, vv.x, accO[1][0]); accO[1][1] = fmaf(pv.y, vv.y, accO[1][1]);
            accO[1][2] = fmaf(pv.y, vv.z, accO[1][2]); accO[1][3] = fmaf(pv.y, vv.w, accO[1][3]);
            accO[2][0] = fmaf(pv.z, vv.x, accO[2][0]); accO[2][1] = fmaf(pv.z, vv.y, accO[2][1]);
            accO[2][2] = fmaf(pv.z, vv.z, accO[2][2]); accO[2][3] = fmaf(pv.z, vv.w, accO[2][3]);
            accO[3][0] = fmaf(pv.w, vv.x, accO[3][0]); accO[3][1] = fmaf(pv.w, vv.y, accO[3][1]);
            accO[3][2] = fmaf(pv.w, vv.z, accO[3][2]); accO[3][3] = fmaf(pv.w, vv.w, accO[3][3]);
        }
    }

    // global denominator per q-row (sum over all 16 col-groups)
    #pragma unroll
    for (int o = 1; o < 16; o <<= 1) {
        #pragma unroll
        for (int i = 0; i < 4; i++)
            den[i] += __shfl_xor_sync(0xffffffffu, den[i], o);
    }

    #pragma unroll
    for (int i = 0; i < 4; i++) {
        float invd = 1.f / (den[i] + 1e-6f);
        size_t obase = (size_t)(ib*64 + qr0 + i)*D_MODEL + h*HEAD_DIM + c0;
        uint32_t h0, l0, h1, l1;
        split2(accO[i][0]*invd, accO[i][1]*invd, h0, l0);
        split2(accO[i][2]*invd, accO[i][3]*invd, h1, l1);
        uint32_t* hd = (uint32_t*)(oh + obase);
        uint32_t* ld = (uint32_t*)(ol + obase);
        hd[0] = h0; hd[1] = h1;
        ld[0] = l0; ld[1] = l1;
    }
}

// ---------------- layernorm (optional residual, optional split output) ----------------
__global__ void __launch_bounds__(256) ln_kernel(
    const float* __restrict__ in, const float* __restrict__ res,
    const float* __restrict__ g, const float* __restrict__ b,
    float* __restrict__ out,
    __nv_bfloat16* __restrict__ hi, __nv_bfloat16* __restrict__ lo)
{
    __shared__ float red[256];
    int t = blockIdx.x, tid = threadIdx.x;
    float v[8];
    float sum = 0.f;
    #pragma unroll
    for (int i = 0; i < 8; i++) {
        int d = i*256 + tid;
        float x = in[(size_t)t*D_MODEL + d];
        if (res) x += res[(size_t)t*D_MODEL + d];
        v[i] = x; sum += x;
    }
    red[tid] = sum; __syncthreads();
    for (int s = 128; s > 0; s >>= 1) { if (tid < s) red[tid] += red[tid+s]; __syncthreads(); }
    float mu = red[0] / D_MODEL;
    __syncthreads();
    float sq = 0.f;
    #pragma unroll
    for (int i = 0; i < 8; i++) { float d0 = v[i] - mu; sq += d0*d0; }
    red[tid] = sq; __syncthreads();
    for (int s = 128; s > 0; s >>= 1) { if (tid < s) red[tid] += red[tid+s]; __syncthreads(); }
    float rstd = rsqrtf(red[0] / D_MODEL + 1e-5f);
    #pragma unroll
    for (int i = 0; i < 8; i++) {
        int d = i*256 + tid;
        float val = (v[i] - mu) * rstd * g[d] + b[d];
        out[(size_t)t*D_MODEL + d] = val;
        if (hi) {
            __nv_bfloat16 hv = __float2bfloat16(val);
            hi[(size_t)t*D_MODEL + d] = hv;
            lo[(size_t)t*D_MODEL + d] = __float2bfloat16(val - __bfloat162float(hv));
        }
    }
}

// ---------------- fused double layernorm: out = LNf(LN2(in+res)) ----------------
__global__ void __launch_bounds__(256) ln2_kernel(
    const float* __restrict__ in, const float* __restrict__ res,
    const float* __restrict__ g2, const float* __restrict__ b2,
    const float* __restrict__ gf, const float* __restrict__ bf,
    float* __restrict__ out)
{
    __shared__ float red[256];
    int t = blockIdx.x, tid = threadIdx.x;
    float v[8];
    float sum = 0.f;
    #pragma unroll
    for (int i = 0; i < 8; i++) {
        int d = i*256 + tid;
        float x = in[(size_t)t*D_MODEL + d] + res[(size_t)t*D_MODEL + d];
        v[i] = x; sum += x;
    }
    red[tid] = sum; __syncthreads();
    for (int s = 128; s > 0; s >>= 1) { if (tid < s) red[tid] += red[tid+s]; __syncthreads(); }
    float mu = red[0] / D_MODEL;
    __syncthreads();
    float sq = 0.f;
    #pragma unroll
    for (int i = 0; i < 8; i++) { float d0 = v[i] - mu; sq += d0*d0; }
    red[tid] = sq; __syncthreads();
    for (int s = 128; s > 0; s >>= 1) { if (tid < s) red[tid] += red[tid+s]; __syncthreads(); }
    float rstd = rsqrtf(red[0] / D_MODEL + 1e-5f);
    __syncthreads();
    float sum2 = 0.f;
    #pragma unroll
    for (int i = 0; i < 8; i++) {
        int d = i*256 + tid;
        v[i] = (v[i] - mu) * rstd * g2[d] + b2[d];
        sum2 += v[i];
    }
    red[tid] = sum2; __syncthreads();
    for (int s = 128; s > 0; s >>= 1) { if (tid < s) red[tid] += red[tid+s]; __syncthreads(); }
    float mu2 = red[0] / D_MODEL;
    __syncthreads();
    float sq2 = 0.f;
    #pragma unroll
    for (int i = 0; i < 8; i++) { float d0 = v[i] - mu2; sq2 += d0*d0; }
    red[tid] = sq2; __syncthreads();
    for (int s = 128; s > 0; s >>= 1) { if (tid < s) red[tid] += red[tid+s]; __syncthreads(); }
    float rstd2 = rsqrtf(red[0] / D_MODEL + 1e-5f);
    #pragma unroll
    for (int i = 0; i < 8; i++) {
        int d = i*256 + tid;
        out[(size_t)t*D_MODEL + d] = (v[i] - mu2) * rstd2 * gf[d] + bf[d];
    }
}

// ---------------- MoE gate ----------------
__global__ void __launch_bounds__(128) gate_kernel(
    const float* __restrict__ x, const float* __restrict__ gw,
    float* __restrict__ wts, float* __restrict__ varr)
{
    __shared__ float red[128];
    __shared__ float logit[4];
    int t = blockIdx.x, tid = threadIdx.x;
    float p[4] = {0.f, 0.f, 0.f, 0.f};
    for (int d = tid; d < D_MODEL; d += 128) {
        float xv = x[(size_t)t*D_MODEL + d];
        #pragma unroll
        for (int e = 0; e < 4; e++)
            p[e] = fmaf(xv, gw[e*D_MODEL + d], p[e]);
    }
    for (int e = 0; e < 4; e++) {
        red[tid] = p[e]; __syncthreads();
        for (int s = 64; s > 0; s >>= 1) { if (tid < s) red[tid] += red[tid+s]; __syncthreads(); }
        if (tid == 0) logit[e] = red[0];
        __syncthreads();
    }
    if (tid == 0) {
        float l[4] = {logit[0], logit[1], logit[2], logit[3]};
        float mx = fmaxf(fmaxf(l[0], l[1]), fmaxf(l[2], l[3]));
        float ex[4], ssum = 0.f;
        for (int e = 0; e < 4; e++) { ex[e] = expf(l[e] - mx); ssum += ex[e]; }
        float pr[4];
        for (int e = 0; e < 4; e++) pr[e] = ex[e] / ssum;
        int b1 = 0;
        for (int e = 1; e < 4; e++) if (pr[e] > pr[b1]) b1 = e;
        int b2 = -1;
        for (int e = 0; e < 4; e++) { if (e == b1) continue; if (b2 < 0 || pr[e] > pr[b2]) b2 = e; }
        float s2 = pr[b1] + pr[b2];
        float wv[4] = {0.f, 0.f, 0.f, 0.f};
        wv[b1] = pr[b1] / s2; wv[b2] = pr[b2] / s2;
        for (int e = 0; e < 4; e++) wts[e*SEQ + t] = wv[e];
        float mu = (l[0]+l[1]+l[2]+l[3]) * 0.25f;
        float va = ((l[0]-mu)*(l[0]-mu) + (l[1]-mu)*(l[1]-mu) +
                    (l[2]-mu)*(l[2]-mu) + (l[3]-mu)*(l[3]-mu)) / 3.f;
        varr[t] = va;
    }
}

// ---------------- routing compaction ----------------
__global__ void __launch_bounds__(1024) compact_kernel(
    const float* __restrict__ wts, int* __restrict__ cnt,
    int* __restrict__ ridx, float* __restrict__ rwt)
{
    __shared__ int sc[1024];
    int e = blockIdx.x, t = threadIdx.x;
    float w = wts[e*SEQ + t];
    int flag = (w != 0.f) ? 1 : 0;
    sc[t] = flag;
    __syncthreads();
    for (int off = 1; off < 1024; off <<= 1) {
        int v = (t >= off) ? sc[t - off] : 0;
        __syncthreads();
        sc[t] += v;
        __syncthreads();
    }
    if (flag) {
        int pos = sc[t] - 1;
        ridx[e*SEQ + pos] = t;
        rwt [e*SEQ + pos] = w;
    }
    if (t == 1023) cnt[e] = sc[1023];
}

__global__ void aux_kernel(const float* __restrict__ varr, float* __restrict__ out) {
    __shared__ float red[256];
    int tid = threadIdx.x;
    float s = 0.f;
    for (int i = tid; i < SEQ; i += 256) s += varr[i];
    red[tid] = s; __syncthreads();
    for (int st = 128; st > 0; st >>= 1) { if (tid < st) red[tid] += red[tid+st]; __syncthreads(); }
    if (tid == 0) out[0] = red[0] / (float)SEQ;
}

__global__ void zero_kernel(float* __restrict__ p, int n) {
    int i = blockIdx.x * 256 + threadIdx.x;
    if (i < n) p[i] = 0.f;
}

// ---------------- driver ----------------
extern "C" void kernel_launch(void* const* d_in, const int* in_sizes, int n_in,
                              void* d_out, int out_size) {
    const int*   tokens = (const int*)  d_in[0];
    const float* emb    = (const float*)d_in[1];
    const float* wq     = (const float*)d_in[2];
    const float* wk     = (const float*)d_in[3];
    const float* wv     = (const float*)d_in[4];
    const float* wo     = (const float*)d_in[5];
    const float* ln1g   = (const float*)d_in[6];
    const float* ln1b   = (const float*)d_in[7];
    const float* gatew  = (const float*)d_in[8];
    const float* w1     = (const float*)d_in[9];
    const float* w2     = (const float*)d_in[10];
    const float* w3     = (const float*)d_in[11];
    const float* ln2g   = (const float*)d_in[12];
    const float* ln2b   = (const float*)d_in[13];
    const float* fing   = (const float*)d_in[14];
    const float* finb   = (const float*)d_in[15];
    const float* headw  = (const float*)d_in[16];
    float* out = (float*)d_out;

    float *x, *qkv, *y, *moe, *wts, *varr, *rwt;
    int *cnt, *ridx;
    __nv_bfloat16 *ah, *al, *ch, *cl;
    cudaGetSymbolAddress((void**)&x,    g_x);
    cudaGetSymbolAddress((void**)&qkv,  g_qkv);
    cudaGetSymbolAddress((void**)&y,    g_y);
    cudaGetSymbolAddress((void**)&moe,  g_moe);
    cudaGetSymbolAddress((void**)&wts,  g_wts);
    cudaGetSymbolAddress((void**)&varr, g_var);
    cudaGetSymbolAddress((void**)&cnt,  g_cnt);
    cudaGetSymbolAddress((void**)&ridx, g_ridx);
    cudaGetSymbolAddress((void**)&rwt,  g_rwt);
    cudaGetSymbolAddress((void**)&ah,   g_ah);
    cudaGetSymbolAddress((void**)&al,   g_al);
    cudaGetSymbolAddress((void**)&ch,   g_ch);
    cudaGetSymbolAddress((void**)&cl,   g_cl);

    cudaFuncSetAttribute(attn_kernel, cudaFuncAttributeMaxDynamicSharedMemorySize, ATTN_SMEM);
    cudaFuncSetAttribute(gemm_tc<0>, cudaFuncAttributeMaxDynamicSharedMemorySize, GEMM_SMEM_TC);
    cudaFuncSetAttribute(gemm_tc<1>, cudaFuncAttributeMaxDynamicSharedMemorySize, GEMM_SMEM_TC);
    cudaFuncSetAttribute(gemm_tc<2>, cudaFuncAttributeMaxDynamicSharedMemorySize, GEMM_SMEM_TC);
    cudaFuncSetAttribute(gemm_tf32, cudaFuncAttributeMaxDynamicSharedMemorySize, GEMM_SMEM_TF);

    // 1) embed (+ fused split)
    embed_kernel<<<SEQ, 256>>>(tokens, emb, x, ah, al);

    // 2) fused QKV (N=6144)
    dim3 gQKV(3*D_MODEL/256, SEQ/128);
    gemm_tc<0><<<gQKV, 256, GEMM_SMEM_TC>>>(ah, al, wq, wk, wv, D_MODEL,
                                            qkv, SEQ, 3*D_MODEL, D_MODEL,
                                            nullptr, nullptr, nullptr, nullptr, 0, 0,
                                            nullptr, nullptr);

    // 3) RoPE + attention (emits pre-split ah/al)
    rope_kernel<<<dim3(SEQ, N_HEADS), 32>>>(qkv);
    attn_kernel<<<dim3(NB, N_HEADS), 256, ATTN_SMEM>>>(qkv, ah, al);

    // 4) output proj + residual -> y
    dim3 gA(D_MODEL/256, SEQ/128);
    gemm_tc<0><<<gA, 256, GEMM_SMEM_TC>>>(ah, al, wo, wo, wo, D_MODEL,
                                          y, SEQ, D_MODEL, D_MODEL,
                                          x, nullptr, nullptr, nullptr, 0, 0,
                                          nullptr, nullptr);

    // 5) LN1 -> x (+ fused split to ah/al)
    ln_kernel<<<SEQ, 256>>>(y, nullptr, ln1g, ln1b, x, ah, al);

    // 6) gate + routing
    gate_kernel<<<SEQ, 128>>>(x, gatew, wts, varr);
    compact_kernel<<<NEXP, 1024>>>(wts, cnt, ridx, rwt);

    // 7) MoE — up (fused silu+split) then down (atomic scatter)
    zero_kernel<<<(SEQ*D_MODEL + 255)/256, 256>>>(moe, SEQ*D_MODEL);
    const long long FD = (long long)D_FFN * D_MODEL;
    dim3 gUp(2*D_FFN/256, SEQ/128, NEXP);
    gemm_tc<1><<<gUp, 256, GEMM_SMEM_TC>>>(ah, al, w1, w3, nullptr, 0,
                                           nullptr, 0, 2*D_FFN, D_MODEL,
                                           nullptr, cnt, ridx, nullptr,
                                           0, FD, ch, cl);
    dim3 gDn(D_MODEL/256, SEQ/128, NEXP*4);
    gemm_tc<2><<<gDn, 256, GEMM_SMEM_TC>>>(ch, cl, w2, nullptr, nullptr, 0,
                                           moe, 0, D_MODEL, D_FFN,
                                           nullptr, cnt, ridx, rwt,
                                           (long long)SEQ*D_FFN, FD, nullptr, nullptr);

    // 8) fused LN2 + final LN
    ln2_kernel<<<SEQ, 256>>>(moe, x, ln2g, ln2b, fing, finb, y);

    // 9) head (tf32 single-pass)
    dim3 gH((VOCAB + 255)/256, SEQ/128);
    gemm_tf32<<<gH, 256, GEMM_SMEM_TF>>>(y, headw, out, SEQ, VOCAB, D_MODEL);

    // 10) aux
    long long nlog = (long long)SEQ * VOCAB;
    if ((long long)out_size > nlog)
        aux_kernel<<<1, 256>>>(varr, out + nlog);
}

// round 12
// speedup vs baseline: 4.8481x; 1.0016x over previous
#include <cuda_runtime.h>
#include <cuda_bf16.h>
#include <math.h>
#include <stdint.h>

#define D_MODEL 2048
#define SEQ     1024
#define N_HEADS 32
#define HEAD_DIM 64
#define NB      (SEQ/64)
#define D_FFN   8192
#define VOCAB   50257
#define NEXP    4
#define QKV_STRIDE (3*D_MODEL)

// ---------------- scratch ----------------
__device__ float g_x  [SEQ*D_MODEL];
__device__ float g_qkv[SEQ*3*D_MODEL];
__device__ float g_y  [SEQ*D_MODEL];
__device__ float g_moe[SEQ*D_MODEL];
__device__ float g_wts[NEXP*SEQ];
__device__ float g_var[SEQ];

// routing
__device__ int   g_cnt[NEXP];
__device__ int   g_ridx[NEXP*SEQ];
__device__ float g_rwt [NEXP*SEQ];

// bf16 split scratch
__device__ __nv_bfloat16 g_ah[SEQ*D_MODEL];
__device__ __nv_bfloat16 g_al[SEQ*D_MODEL];
__device__ __nv_bfloat16 g_ch[(size_t)NEXP*SEQ*D_FFN];
__device__ __nv_bfloat16 g_cl[(size_t)NEXP*SEQ*D_FFN];

// ---------------- PTX helpers ----------------
__device__ __forceinline__ uint32_t smem_u32(const void* p) {
    uint32_t a;
    asm("{ .reg .u64 t; cvta.to.shared.u64 t, %1; cvt.u32.u64 %0, t; }" : "=r"(a) : "l"(p));
    return a;
}
__device__ __forceinline__ void cp_async16(uint32_t dst, const void* src, int src_bytes) {
    asm volatile("cp.async.cg.shared.global [%0], [%1], 16, %2;\n"
                 :: "r"(dst), "l"(src), "r"(src_bytes) : "memory");
}
#define CP_COMMIT() asm volatile("cp.async.commit_group;\n" ::: "memory")

#define STS128(addr, a, b, c, d) \
    asm volatile("st.shared.v4.b32 [%0], {%1,%2,%3,%4};" \
                 :: "r"(addr), "r"(a), "r"(b), "r"(c), "r"(d) : "memory")

__device__ __forceinline__ void ldsm_x4(uint32_t& r0, uint32_t& r1, uint32_t& r2, uint32_t& r3,
                                        uint32_t addr) {
    asm volatile("ldmatrix.sync.aligned.m8n8.x4.shared.b16 {%0,%1,%2,%3}, [%4];"
                 : "=r"(r0), "=r"(r1), "=r"(r2), "=r"(r3) : "r"(addr));
}
__device__ __forceinline__ void mma_bf16(float* c, const uint32_t* a, const uint32_t* b) {
    asm volatile(
        "mma.sync.aligned.m16n8k16.row.col.f32.bf16.bf16.f32 "
        "{%0,%1,%2,%3}, {%4,%5,%6,%7}, {%8,%9}, {%0,%1,%2,%3};"
        : "+f"(c[0]), "+f"(c[1]), "+f"(c[2]), "+f"(c[3])
        : "r"(a[0]), "r"(a[1]), "r"(a[2]), "r"(a[3]), "r"(b[0]), "r"(b[1]));
}
__device__ __forceinline__ void mma_tf32(float* c, const uint32_t* a, const uint32_t* b) {
    asm volatile(
        "mma.sync.aligned.m16n8k8.row.col.f32.tf32.tf32.f32 "
        "{%0,%1,%2,%3}, {%4,%5,%6,%7}, {%8,%9}, {%0,%1,%2,%3};"
        : "+f"(c[0]), "+f"(c[1]), "+f"(c[2]), "+f"(c[3])
        : "r"(a[0]), "r"(a[1]), "r"(a[2]), "r"(a[3]), "r"(b[0]), "r"(b[1]));
}

__device__ __forceinline__ void split2(float a, float b, uint32_t& hi, uint32_t& lo) {
    __nv_bfloat16 ha = __float2bfloat16(a), hb = __float2bfloat16(b);
    __nv_bfloat162 h; h.x = ha; h.y = hb;
    __nv_bfloat162 l;
    l.x = __float2bfloat16(a - __bfloat162float(ha));
    l.y = __float2bfloat16(b - __bfloat162float(hb));
    hi = *(uint32_t*)&h;
    lo = *(uint32_t*)&l;
}

// ================= bf16x3 GEMM: CTA 128x256, 8 warps (2Mx4N), warp 64x64 =================
// Grid mapping: blockIdx.x = M-tile (few), blockIdx.y = N-tile (many) -> consecutive CTAs
// share the same B tile, so B is fetched from DRAM once and reused via L2.
#define NSTG_TC 3
#define A_BYTES (128*128)
#define B_BYTES (256*128)
#define STAGE_B (A_BYTES + B_BYTES)
#define GEMM_SMEM_TC (NSTG_TC * STAGE_B)
#define NSTG_TF 4
#define GEMM_SMEM_TF (NSTG_TF * STAGE_B)

// MODE 0: dense. C[m,n]=val(+residual). B rows: <rPB->B0, <2rPB->B1, else B2.
// MODE 1: expert-batched up + FUSED silu·mul + bf16 split.
// MODE 2: expert-batched down + split-K4, atomic scatter.
template<int MODE>
__global__ void __launch_bounds__(256, 1) gemm_tc(
    const __nv_bfloat16* __restrict__ Ah, const __nv_bfloat16* __restrict__ Al,
    const float* __restrict__ B0, const float* __restrict__ B1, const float* __restrict__ B2,
    int rPB,
    float* __restrict__ C, int M_in, int N, int K,
    const float* __restrict__ residual,
    const int* __restrict__ cntArr, const int* __restrict__ ridxAll,
    const float* __restrict__ rwtAll,
    long long sA, long long sB,
    __nv_bfloat16* __restrict__ CH, __nv_bfloat16* __restrict__ CL)
{
    const int tid = threadIdx.x;
    const int m0  = blockIdx.x * 128;     // m-tile on x (fast dim)
    const int n0  = blockIdx.y * 256;     // n-tile on y

    int M = M_in;
    int e = 0, kbase = 0, Kc = K;
    const int* ridx = ridxAll;
    const float* rwt = rwtAll;
    const float* b0p = B0; const float* b1p = B1; const float* b2p = B2;
    const __nv_bfloat16* ahp = Ah; const __nv_bfloat16* alp = Al;
    float* Cp = C;

    if (MODE == 1) {
        e = blockIdx.z;
        M = cntArr[e];
        if (m0 >= M) return;
        ridx = ridxAll + e * SEQ;
        b0p = B0 + (size_t)e * sB;
        b1p = B1 + (size_t)e * sB;
    } else if (MODE == 2) {
        e = blockIdx.z >> 2;
        int ks = blockIdx.z & 3;
        M = cntArr[e];
        if (m0 >= M) return;
        ridx = ridxAll + e * SEQ;
        rwt  = rwtAll + e * SEQ;
        ahp = Ah + (size_t)e * sA;
        alp = Al + (size_t)e * sA;
        b0p = B0 + (size_t)e * sB;
        Kc = K >> 2;
        kbase = ks * Kc;
    }

    int arow[4];
    #pragma unroll
    for (int i = 0; i < 4; i++) {
        int r = (tid + i * 256) >> 3;
        int rg = m0 + r;
        if (MODE == 0)      arow[i] = rg;
        else {
            rg = rg < M ? rg : (M - 1);
            arow[i] = (MODE == 1) ? ridx[rg] : rg;
        }
    }

    extern __shared__ char smem[];
    const uint32_t sb = smem_u32(smem);
    const int wid = tid >> 5, lid = tid & 31;
    const int wm  = wid >> 2, wn = wid & 3;

    float acc[4][8][4];
    #pragma unroll
    for (int i = 0; i < 4; i++)
        #pragma unroll
        for (int j = 0; j < 8; j++)
            #pragma unroll
            for (int t = 0; t < 4; t++) acc[i][j][t] = 0.f;

    const int iters = Kc >> 5;

    auto fillA = [&](int stage, int kit) {
        const int k0 = kbase + (kit << 5);
        const uint32_t abase = sb + stage * STAGE_B;
        #pragma unroll
        for (int i = 0; i < 4; i++) {
            int idx = tid + i * 256;
            int r = idx >> 3, c = idx & 7;
            uint32_t dst = abase + r * 128 + ((c ^ (r & 7)) << 4);
            const __nv_bfloat16* src = (c < 4)
                ? ahp + (size_t)arow[i] * K + k0 + c * 8
                : alp + (size_t)arow[i] * K + k0 + (c - 4) * 8;
            cp_async16(dst, src, 16);
        }
        CP_COMMIT();
    };

    auto ldgB = [&](float4* breg, int kit) {
        const int k0 = kbase + (kit << 5);
        #pragma unroll
        for (int i = 0; i < 4; i++) {
            int idx = tid + i * 256;
            int r = idx >> 2, c2 = idx & 3;
            int rg = n0 + r;
            int rc = rg < N ? rg : (N - 1);
            const float* Bp; int rr;
            if (MODE == 2)          { Bp = b0p; rr = rc; }
            else if (MODE == 1)     { Bp = (rc & 1) ? b1p : b0p; rr = rc >> 1; }
            else if (rc < rPB)      { Bp = b0p; rr = rc; }
            else if (rc < 2 * rPB)  { Bp = b1p; rr = rc - rPB; }
            else                    { Bp = b2p; rr = rc - 2 * rPB; }
            const float4* s4 = (const float4*)(Bp + (size_t)rr * K + k0 + c2 * 8);
            breg[i*2]     = s4[0];
            breg[i*2 + 1] = s4[1];
        }
    };

    auto stsB = [&](const float4* breg, int stage) {
        const uint32_t bbase = sb + stage * STAGE_B + A_BYTES;
        #pragma unroll
        for (int i = 0; i < 4; i++) {
            int idx = tid + i * 256;
            int r = idx >> 2, c2 = idx & 3;
            float4 v0 = breg[i*2], v1 = breg[i*2 + 1];
            uint32_t h0, h1, h2, h3, l0, l1, l2, l3;
            split2(v0.x, v0.y, h0, l0);
            split2(v0.z, v0.w, h1, l1);
            split2(v1.x, v1.y, h2, l2);
            split2(v1.z, v1.w, h3, l3);
            uint32_t ha = bbase + r * 128 + ((c2 ^ (r & 7)) << 4);
            uint32_t la = bbase + r * 128 + (((c2 + 4) ^ (r & 7)) << 4);
            STS128(ha, h0, h1, h2, h3);
            STS128(la, l0, l1, l2, l3);
        }
    };

    {
        float4 pb[8];
        #pragma unroll
        for (int s = 0; s < NSTG_TC - 1; s++) {
            fillA(s, s);
            ldgB(pb, s);
            stsB(pb, s);
        }
    }

    const int grp = lid >> 3;
    const int rin = lid & 7;
    float4 breg[8];

    for (int i = 0; i < iters; i++) {
        const int s = i % NSTG_TC;
        const bool pre = (i + NSTG_TC - 1 < iters);
        if (pre) ldgB(breg, i + NSTG_TC - 1);

        asm volatile("cp.async.wait_group %0;\n" :: "n"(NSTG_TC - 2));
        __syncthreads();

        if (pre) fillA((i + NSTG_TC - 1) % NSTG_TC, i + NSTG_TC - 1);
        else CP_COMMIT();

        const uint32_t abase = sb + s * STAGE_B;
        const uint32_t bbase = abase + A_BYTES;

        #pragma unroll
        for (int g = 0; g < 2; g++) {
            uint32_t ah[4][4], bh[8][2];
            #pragma unroll
            for (int mt = 0; mt < 4; mt++) {
                int row = wm * 64 + mt * 16 + (grp & 1) * 8 + rin;
                int kch = 2 * g + (grp >> 1);
                uint32_t ad = abase + row * 128 + ((kch ^ (row & 7)) << 4);
                ldsm_x4(ah[mt][0], ah[mt][1], ah[mt][2], ah[mt][3], ad);
            }
            #pragma unroll
            for (int p = 0; p < 4; p++) {
                int tile = 2 * p + (grp >> 1);
                int row  = wn * 64 + tile * 8 + rin;
                int kch  = 2 * g + (grp & 1);
                uint32_t bd = bbase + row * 128 + ((kch ^ (row & 7)) << 4);
                ldsm_x4(bh[2*p][0], bh[2*p][1], bh[2*p+1][0], bh[2*p+1][1], bd);
            }
            #pragma unroll
            for (int mt = 0; mt < 4; mt++)
                #pragma unroll
                for (int nt = 0; nt < 8; nt++)
                    mma_bf16(acc[mt][nt], ah[mt], bh[nt]);
            {
                uint32_t al[4][4];
                #pragma unroll
                for (int mt = 0; mt < 4; mt++) {
                    int row = wm * 64 + mt * 16 + (grp & 1) * 8 + rin;
                    int kcl = 4 + 2 * g + (grp >> 1);
                    uint32_t adl = abase + row * 128 + ((kcl ^ (row & 7)) << 4);
                    ldsm_x4(al[mt][0], al[mt][1], al[mt][2], al[mt][3], adl);
                }
                #pragma unroll
                for (int mt = 0; mt < 4; mt++)
                    #pragma unroll
                    for (int nt = 0; nt < 8; nt++)
                        mma_bf16(acc[mt][nt], al[mt], bh[nt]);
            }
            {
                uint32_t bl[8][2];
                #pragma unroll
                for (int p = 0; p < 4; p++) {
                    int tile = 2 * p + (grp >> 1);
                    int row  = wn * 64 + tile * 8 + rin;
                    int kcl  = 4 + 2 * g + (grp & 1);
                    uint32_t bdl = bbase + row * 128 + ((kcl ^ (row & 7)) << 4);
                    ldsm_x4(bl[2*p][0], bl[2*p][1], bl[2*p+1][0], bl[2*p+1][1], bdl);
                }
                #pragma unroll
                for (int mt = 0; mt < 4; mt++)
                    #pragma unroll
                    for (int nt = 0; nt < 8; nt++)
                        mma_bf16(acc[mt][nt], ah[mt], bl[nt]);
            }
        }

        if (pre) stsB(breg, (i + NSTG_TC - 1) % NSTG_TC);
    }

    #pragma unroll
    for (int mt = 0; mt < 4; mt++) {
        #pragma unroll
        for (int nt = 0; nt < 8; nt++) {
            int rbase = m0 + wm * 64 + mt * 16 + (lid >> 2);
            int col = n0 + wn * 64 + nt * 8 + (lid & 3) * 2;
            #pragma unroll
            for (int h = 0; h < 2; h++) {
                int m = rbase + h * 8;
                float v0 = acc[mt][nt][h * 2 + 0];
                float v1 = acc[mt][nt][h * 2 + 1];
                if (MODE == 0) {
                    size_t idx = (size_t)m * N + col;
                    if (residual) {
                        if (col     < N) v0 += residual[idx];
                        if (col + 1 < N) v1 += residual[idx + 1];
                    }
                    if (col     < N) Cp[idx]     = v0;
                    if (col + 1 < N) Cp[idx + 1] = v1;
                } else if (MODE == 1) {
                    if (m < M) {
                        int j = col >> 1;
                        float r = v0 / (1.f + expf(-v0)) * v1;
                        __nv_bfloat16 hi = __float2bfloat16(r);
                        size_t o = (size_t)e * SEQ * D_FFN + (size_t)m * D_FFN + j;
                        CH[o] = hi;
                        CL[o] = __float2bfloat16(r - __bfloat162float(hi));
                    }
                } else {
                    if (m < M) {
                        int tok = ridx[m];
                        float w = rwt[m];
                        size_t idx = (size_t)tok * N + col;
                        atomicAdd(&Cp[idx],     w * v0);
                        atomicAdd(&Cp[idx + 1], w * v1);
                    }
                }
            }
        }
    }
}

// ================= tf32 single-pass GEMM (head), m-tile on x =================
__global__ void __launch_bounds__(256, 1) gemm_tf32(
    const float* __restrict__ A, const float* __restrict__ B,
    float* __restrict__ C, int M, int N, int K)
{
    extern __shared__ char smem[];
    const uint32_t sb = smem_u32(smem);
    const int tid = threadIdx.x;
    const int wid = tid >> 5, lid = tid & 31;
    const int wm  = wid >> 2, wn = wid & 3;
    const int m0  = blockIdx.x * 128;     // m on x (fast)
    const int n0  = blockIdx.y * 256;     // n on y

    float acc[4][8][4];
    #pragma unroll
    for (int i = 0; i < 4; i++)
        #pragma unroll
        for (int j = 0; j < 8; j++)
            #pragma unroll
            for (int t = 0; t < 4; t++) acc[i][j][t] = 0.f;

    const int iters = K >> 5;

    auto fill = [&](int stage, int kit) {
        const int k0 = kit << 5;
        const uint32_t abase = sb + stage * STAGE_B;
        const uint32_t bbase = abase + A_BYTES;
        #pragma unroll
        for (int i = 0; i < 4; i++) {
            int idx = tid + i * 256;
            int r = idx >> 3, c = idx & 7;
            uint32_t dst = abase + r * 128 + ((c ^ (r & 7)) << 4);
            cp_async16(dst, A + (size_t)(m0 + r) * K + k0 + c * 4, 16);
        }
        #pragma unroll
        for (int i = 0; i < 8; i++) {
            int idx = tid + i * 256;
            int r = idx >> 3, c = idx & 7;
            uint32_t dst = bbase + r * 128 + ((c ^ (r & 7)) << 4);
            int rg = n0 + r;
            int rc = rg < N ? rg : (N - 1);
            cp_async16(dst, B + (size_t)rc * K + k0 + c * 4, rg < N ? 16 : 0);
        }
        CP_COMMIT();
    };

    #pragma unroll
    for (int s = 0; s < NSTG_TF - 1; s++) fill(s, s);

    const int grp = lid >> 3;
    const int rin = lid & 7;

    for (int i = 0; i < iters; i++) {
        const int s = i % NSTG_TF;
        asm volatile("cp.async.wait_group %0;\n" :: "n"(NSTG_TF - 2));
        __syncthreads();

        if (i + NSTG_TF - 1 < iters) fill((i + NSTG_TF - 1) % NSTG_TF, i + NSTG_TF - 1);
        else CP_COMMIT();

        const uint32_t abase = sb + s * STAGE_B;
        const uint32_t bbase = abase + A_BYTES;

        #pragma unroll
        for (int k8 = 0; k8 < 4; k8++) {
            uint32_t a[4][4], b[8][2];
            #pragma unroll
            for (int mt = 0; mt < 4; mt++) {
                int row = wm * 64 + mt * 16 + (grp & 1) * 8 + rin;
                int kc  = k8 * 2 + (grp >> 1);
                uint32_t addr = abase + row * 128 + ((kc ^ (row & 7)) << 4);
                ldsm_x4(a[mt][0], a[mt][1], a[mt][2], a[mt][3], addr);
            }
            #pragma unroll
            for (int p = 0; p < 4; p++) {
                int tile = 2 * p + (grp >> 1);
                int row  = wn * 64 + tile * 8 + rin;
                int kc   = k8 * 2 + (grp & 1);
                uint32_t addr = bbase + row * 128 + ((kc ^ (row & 7)) << 4);
                ldsm_x4(b[2*p][0], b[2*p][1], b[2*p+1][0], b[2*p+1][1], addr);
            }
            #pragma unroll
            for (int mt = 0; mt < 4; mt++)
                #pragma unroll
                for (int nt = 0; nt < 8; nt++)
                    mma_tf32(acc[mt][nt], a[mt], b[nt]);
        }
    }

    #pragma unroll
    for (int mt = 0; mt < 4; mt++) {
        #pragma unroll
        for (int nt = 0; nt < 8; nt++) {
            int rbase = m0 + wm * 64 + mt * 16 + (lid >> 2);
            int col = n0 + wn * 64 + nt * 8 + (lid & 3) * 2;
            #pragma unroll
            for (int h = 0; h < 2; h++) {
                int m = rbase + h * 8;
                size_t idx = (size_t)m * N + col;
                if (col     < N) C[idx]     = acc[mt][nt][h * 2 + 0];
                if (col + 1 < N) C[idx + 1] = acc[mt][nt][h * 2 + 1];
            }
        }
    }
}

// ---------------- embedding (+ fused split) ----------------
__global__ void embed_kernel(const int* __restrict__ tok,
                             const float* __restrict__ emb,
                             float* __restrict__ x,
                             __nv_bfloat16* __restrict__ ah,
                             __nv_bfloat16* __restrict__ al) {
    int t = blockIdx.x;
    int tk = tok[t];
    const float2* src = (const float2*)(emb + (size_t)tk * D_MODEL);
    float2* dst = (float2*)(x + (size_t)t * D_MODEL);
    uint32_t* hd = (uint32_t*)(ah + (size_t)t * D_MODEL);
    uint32_t* ld = (uint32_t*)(al + (size_t)t * D_MODEL);
    for (int p = threadIdx.x; p < D_MODEL/2; p += 256) {
        float2 v = src[p];
        dst[p] = v;
        uint32_t h, l;
        split2(v.x, v.y, h, l);
        hd[p] = h;
        ld[p] = l;
    }
}

// ---------------- RoPE ----------------
__global__ void rope_kernel(float* __restrict__ qkv) {
    int t = blockIdx.x, h = blockIdx.y, i = threadIdx.x;
    float inv = powf(10000.f, -((float)(2*i)) / 64.f);
    float ang = (float)t * inv;
    float s, c;
    sincosf(ang, &s, &c);
    size_t base = (size_t)t*QKV_STRIDE + h*HEAD_DIM + 2*i;
    float q0 = qkv[base], q1 = qkv[base+1];
    qkv[base]   = q0*c - q1*s;
    qkv[base+1] = q0*s + q1*c;
    size_t kb = base + D_MODEL;
    float k0 = qkv[kb], k1 = qkv[kb+1];
    qkv[kb]   = k0*c - k1*s;
    qkv[kb+1] = k0*s + k1*c;
}

// ---------------- blocked attention: 4x4 register tiles, Q/K/P transposed ----------------
#define ATTN_SMEM (4 * 64 * 68 * 4)
__global__ void __launch_bounds__(256) attn_kernel(
    const float* __restrict__ qkv,
    __nv_bfloat16* __restrict__ oh, __nv_bfloat16* __restrict__ ol)
{
    extern __shared__ float sm[];
    float* Qst = sm;
    float* Kst = Qst + 64*68;
    float* Vs  = Kst + 64*68;
    float* Pst = Vs + 64*68;
    const int ib = blockIdx.x, h = blockIdx.y;
    const int tid = threadIdx.x;
    const int qg  = tid >> 4;
    const int cg  = tid & 15;
    const int qr0 = qg * 4;
    const int c0  = cg * 4;

    for (int idx = tid; idx < 64*64; idx += 256) {
        int r = idx >> 6, c = idx & 63;
        Qst[c*68 + r] = qkv[(size_t)(ib*64+r)*QKV_STRIDE + h*HEAD_DIM + c];
    }

    float accO[4][4];
    #pragma unroll
    for (int i = 0; i < 4; i++)
        #pragma unroll
        for (int j = 0; j < 4; j++) accO[i][j] = 0.f;
    float den[4] = {0.f, 0.f, 0.f, 0.f};

    for (int jb = 0; jb <= ib; jb++) {
        __syncthreads();
        for (int idx = tid; idx < 64*64; idx += 256) {
            int r = idx >> 6, c = idx & 63;
            size_t base = (size_t)(jb*64+r)*QKV_STRIDE + h*HEAD_DIM + c;
            Kst[c*68 + r] = qkv[base + D_MODEL];
            Vs [r*68 + c] = qkv[base + 2*D_MODEL];
        }
        __syncthreads();

        float s4[4][4];
        #pragma unroll
        for (int i = 0; i < 4; i++)
            #pragma unroll
            for (int j = 0; j < 4; j++) s4[i][j] = 0.f;

        #pragma unroll 4
        for (int d = 0; d < 64; d++) {
            float4 qv = *(const float4*)&Qst[d*68 + qr0];
            float4 kv = *(const float4*)&Kst[d*68 + c0];
            s4[0][0] = fmaf(qv.x, kv.x, s4[0][0]); s4[0][1] = fmaf(qv.x, kv.y, s4[0][1]);
            s4[0][2] = fmaf(qv.x, kv.z, s4[0][2]); s4[0][3] = fmaf(qv.x, kv.w, s4[0][3]);
            s4[1][0] = fmaf(qv.y, kv.x, s4[1][0]); s4[1][1] = fmaf(qv.y, kv.y, s4[1][1]);
            s4[1][2] = fmaf(qv.y, kv.z, s4[1][2]); s4[1][3] = fmaf(qv.y, kv.w, s4[1][3]);
            s4[2][0] = fmaf(qv.z, kv.x, s4[2][0]); s4[2][1] = fmaf(qv.z, kv.y, s4[2][1]);
            s4[2][2] = fmaf(qv.z, kv.z, s4[2][2]); s4[2][3] = fmaf(qv.z, kv.w, s4[2][3]);
            s4[3][0] = fmaf(qv.w, kv.x, s4[3][0]); s4[3][1] = fmaf(qv.w, kv.y, s4[3][1]);
            s4[3][2] = fmaf(qv.w, kv.z, s4[3][2]); s4[3][3] = fmaf(qv.w, kv.w, s4[3][3]);
        }

        float mx[4];
        #pragma unroll
        for (int i = 0; i < 4; i++) {
            mx[i] = -1e30f;
            int q = qr0 + i;
            #pragma unroll
            for (int j = 0; j < 4; j++) {
                int c = c0 + j;
                float v = s4[i][j] * 0.125f;
                if (jb == ib && c > q) v = -1e30f;
                s4[i][j] = v;
                mx[i] = fmaxf(mx[i], v);
            }
        }
        #pragma unroll
        for (int o = 1; o < 16; o <<= 1) {
            #pragma unroll
            for (int i = 0; i < 4; i++)
                mx[i] = fmaxf(mx[i], __shfl_xor_sync(0xffffffffu, mx[i], o));
        }

        #pragma unroll
        for (int j = 0; j < 4; j++) {
            float p0 = expf(s4[0][j] - mx[0]);
            float p1 = expf(s4[1][j] - mx[1]);
            float p2 = expf(s4[2][j] - mx[2]);
            float p3 = expf(s4[3][j] - mx[3]);
            den[0] += p0; den[1] += p1; den[2] += p2; den[3] += p3;
            *(float4*)&Pst[(c0 + j)*68 + qr0] = make_float4(p0, p1, p2, p3);
        }
        __syncthreads();

        #pragma unroll 4
        for (int kk = 0; kk < 64; kk++) {
            float4 pv = *(const float4*)&Pst[kk*68 + qr0];
            float4 vv = *(const float4*)&Vs [kk*68 + c0];
            accO[0][0] = fmaf(pv.x, vv.x, accO[0][0]); accO[0][1] = fmaf(pv.x, vv.y, accO[0][1]);
            accO[0][2] = fmaf(pv.x, vv.z, accO[0][2]); accO[0][3] = fmaf(pv.x, vv.w, accO[0][3]);
            accO[1][0] = fmaf(pv.y, vv.x, accO[1][0]); accO[1][1] = fmaf(pv.y, vv.y, accO[1][1]);
            accO[1][2] = fmaf(pv.y, vv.z, accO[1][2]); accO[1][3] = fmaf(pv.y, vv.w, accO[1][3]);
            accO[2][0] = fmaf(pv.z, vv.x, accO[2][0]); accO[2][1] = fmaf(pv.z, vv.y, accO[2][1]);
            accO[2][2] = fmaf(pv.z, vv.z, accO[2][2]); accO[2][3] = fmaf(pv.z, vv.w, accO[2][3]);
            accO[3][0] = fmaf(pv.w, vv.x, accO[3][0]); accO[3][1] = fmaf(pv.w, vv.y, accO[3][1]);
            accO[3][2] = fmaf(pv.w, vv.z, accO[3][2]); accO[3][3] = fmaf(pv.w, vv.w, accO[3][3]);
        }
    }

    #pragma unroll
    for (int o = 1; o < 16; o <<= 1) {
        #pragma unroll
        for (int i = 0; i < 4; i++)
            den[i] += __shfl_xor_sync(0xffffffffu, den[i], o);
    }

    #pragma unroll
    for (int i = 0; i < 4; i++) {
        float invd = 1.f / (den[i] + 1e-6f);
        size_t obase = (size_t)(ib*64 + qr0 + i)*D_MODEL + h*HEAD_DIM + c0;
        uint32_t h0, l0, h1, l1;
        split2(accO[i][0]*invd, accO[i][1]*invd, h0, l0);
        split2(accO[i][2]*invd, accO[i][3]*invd, h1, l1);
        uint32_t* hd = (uint32_t*)(oh + obase);
        uint32_t* ld = (uint32_t*)(ol + obase);
        hd[0] = h0; hd[1] = h1;
        ld[0] = l0; ld[1] = l1;
    }
}

// ---------------- layernorm (optional residual, optional split output) ----------------
__global__ void __launch_bounds__(256) ln_kernel(
    const float* __restrict__ in, const float* __restrict__ res,
    const float* __restrict__ g, const float* __restrict__ b,
    float* __restrict__ out,
    __nv_bfloat16* __restrict__ hi, __nv_bfloat16* __restrict__ lo)
{
    __shared__ float red[256];
    int t = blockIdx.x, tid = threadIdx.x;
    float v[8];
    float sum = 0.f;
    #pragma unroll
    for (int i = 0; i < 8; i++) {
        int d = i*256 + tid;
        float x = in[(size_t)t*D_MODEL + d];
        if (res) x += res[(size_t)t*D_MODEL + d];
        v[i] = x; sum += x;
    }
    red[tid] = sum; __syncthreads();
    for (int s = 128; s > 0; s >>= 1) { if (tid < s) red[tid] += red[tid+s]; __syncthreads(); }
    float mu = red[0] / D_MODEL;
    __syncthreads();
    float sq = 0.f;
    #pragma unroll
    for (int i = 0; i < 8; i++) { float d0 = v[i] - mu; sq += d0*d0; }
    red[tid] = sq; __syncthreads();
    for (int s = 128; s > 0; s >>= 1) { if (tid < s) red[tid] += red[tid+s]; __syncthreads(); }
    float rstd = rsqrtf(red[0] / D_MODEL + 1e-5f);
    #pragma unroll
    for (int i = 0; i < 8; i++) {
        int d = i*256 + tid;
        float val = (v[i] - mu) * rstd * g[d] + b[d];
        out[(size_t)t*D_MODEL + d] = val;
        if (hi) {
            __nv_bfloat16 hv = __float2bfloat16(val);
            hi[(size_t)t*D_MODEL + d] = hv;
            lo[(size_t)t*D_MODEL + d] = __float2bfloat16(val - __bfloat162float(hv));
        }
    }
}

// ---------------- fused double layernorm: out = LNf(LN2(in+res)) ----------------
__global__ void __launch_bounds__(256) ln2_kernel(
    const float* __restrict__ in, const float* __restrict__ res,
    const float* __restrict__ g2, const float* __restrict__ b2,
    const float* __restrict__ gf, const float* __restrict__ bf,
    float* __restrict__ out)
{
    __shared__ float red[256];
    int t = blockIdx.x, tid = threadIdx.x;
    float v[8];
    float sum = 0.f;
    #pragma unroll
    for (int i = 0; i < 8; i++) {
        int d = i*256 + tid;
        float x = in[(size_t)t*D_MODEL + d] + res[(size_t)t*D_MODEL + d];
        v[i] = x; sum += x;
    }
    red[tid] = sum; __syncthreads();
    for (int s = 128; s > 0; s >>= 1) { if (tid < s) red[tid] += red[tid+s]; __syncthreads(); }
    float mu = red[0] / D_MODEL;
    __syncthreads();
    float sq = 0.f;
    #pragma unroll
    for (int i = 0; i < 8; i++) { float d0 = v[i] - mu; sq += d0*d0; }
    red[tid] = sq; __syncthreads();
    for (int s = 128; s > 0; s >>= 1) { if (tid < s) red[tid] += red[tid+s]; __syncthreads(); }
    float rstd = rsqrtf(red[0] / D_MODEL + 1e-5f);
    __syncthreads();
    float sum2 = 0.f;
    #pragma unroll
    for (int i = 0; i < 8; i++) {
        int d = i*256 + tid;
        v[i] = (v[i] - mu) * rstd * g2[d] + b2[d];
        sum2 += v[i];
    }
    red[tid] = sum2; __syncthreads();
    for (int s = 128; s > 0; s >>= 1) { if (tid < s) red[tid] += red[tid+s]; __syncthreads(); }
    float mu2 = red[0] / D_MODEL;
    __syncthreads();
    float sq2 = 0.f;
    #pragma unroll
    for (int i = 0; i < 8; i++) { float d0 = v[i] - mu2; sq2 += d0*d0; }
    red[tid] = sq2; __syncthreads();
    for (int s = 128; s > 0; s >>= 1) { if (tid < s) red[tid] += red[tid+s]; __syncthreads(); }
    float rstd2 = rsqrtf(red[0] / D_MODEL + 1e-5f);
    #pragma unroll
    for (int i = 0; i < 8; i++) {
        int d = i*256 + tid;
        out[(size_t)t*D_MODEL + d] = (v[i] - mu2) * rstd2 * gf[d] + bf[d];
    }
}

// ---------------- MoE gate ----------------
__global__ void __launch_bounds__(128) gate_kernel(
    const float* __restrict__ x, const float* __restrict__ gw,
    float* __restrict__ wts, float* __restrict__ varr)
{
    __shared__ float red[128];
    __shared__ float logit[4];
    int t = blockIdx.x, tid = threadIdx.x;
    float p[4] = {0.f, 0.f, 0.f, 0.f};
    for (int d = tid; d < D_MODEL; d += 128) {
        float xv = x[(size_t)t*D_MODEL + d];
        #pragma unroll
        for (int e = 0; e < 4; e++)
            p[e] = fmaf(xv, gw[e*D_MODEL + d], p[e]);
    }
    for (int e = 0; e < 4; e++) {
        red[tid] = p[e]; __syncthreads();
        for (int s = 64; s > 0; s >>= 1) { if (tid < s) red[tid] += red[tid+s]; __syncthreads(); }
        if (tid == 0) logit[e] = red[0];
        __syncthreads();
    }
    if (tid == 0) {
        float l[4] = {logit[0], logit[1], logit[2], logit[3]};
        float mx = fmaxf(fmaxf(l[0], l[1]), fmaxf(l[2], l[3]));
        float ex[4], ssum = 0.f;
        for (int e = 0; e < 4; e++) { ex[e] = expf(l[e] - mx); ssum += ex[e]; }
        float pr[4];
        for (int e = 0; e < 4; e++) pr[e] = ex[e] / ssum;
        int b1 = 0;
        for (int e = 1; e < 4; e++) if (pr[e] > pr[b1]) b1 = e;
        int b2 = -1;
        for (int e = 0; e < 4; e++) { if (e == b1) continue; if (b2 < 0 || pr[e] > pr[b2]) b2 = e; }
        float s2 = pr[b1] + pr[b2];
        float wv[4] = {0.f, 0.f, 0.f, 0.f};
        wv[b1] = pr[b1] / s2; wv[b2] = pr[b2] / s2;
        for (int e = 0; e < 4; e++) wts[e*SEQ + t] = wv[e];
        float mu = (l[0]+l[1]+l[2]+l[3]) * 0.25f;
        float va = ((l[0]-mu)*(l[0]-mu) + (l[1]-mu)*(l[1]-mu) +
                    (l[2]-mu)*(l[2]-mu) + (l[3]-mu)*(l[3]-mu)) / 3.f;
        varr[t] = va;
    }
}

// ---------------- routing compaction ----------------
__global__ void __launch_bounds__(1024) compact_kernel(
    const float* __restrict__ wts, int* __restrict__ cnt,
    int* __restrict__ ridx, float* __restrict__ rwt)
{
    __shared__ int sc[1024];
    int e = blockIdx.x, t = threadIdx.x;
    float w = wts[e*SEQ + t];
    int flag = (w != 0.f) ? 1 : 0;
    sc[t] = flag;
    __syncthreads();
    for (int off = 1; off < 1024; off <<= 1) {
        int v = (t >= off) ? sc[t - off] : 0;
        __syncthreads();
        sc[t] += v;
        __syncthreads();
    }
    if (flag) {
        int pos = sc[t] - 1;
        ridx[e*SEQ + pos] = t;
        rwt [e*SEQ + pos] = w;
    }
    if (t == 1023) cnt[e] = sc[1023];
}

__global__ void aux_kernel(const float* __restrict__ varr, float* __restrict__ out) {
    __shared__ float red[256];
    int tid = threadIdx.x;
    float s = 0.f;
    for (int i = tid; i < SEQ; i += 256) s += varr[i];
    red[tid] = s; __syncthreads();
    for (int st = 128; st > 0; st >>= 1) { if (tid < st) red[tid] += red[tid+st]; __syncthreads(); }
    if (tid == 0) out[0] = red[0] / (float)SEQ;
}

__global__ void zero_kernel(float* __restrict__ p, int n) {
    int i = blockIdx.x * 256 + threadIdx.x;
    if (i < n) p[i] = 0.f;
}

// ---------------- driver ----------------
extern "C" void kernel_launch(void* const* d_in, const int* in_sizes, int n_in,
                              void* d_out, int out_size) {
    const int*   tokens = (const int*)  d_in[0];
    const float* emb    = (const float*)d_in[1];
    const float* wq     = (const float*)d_in[2];
    const float* wk     = (const float*)d_in[3];
    const float* wv     = (const float*)d_in[4];
    const float* wo     = (const float*)d_in[5];
    const float* ln1g   = (const float*)d_in[6];
    const float* ln1b   = (const float*)d_in[7];
    const float* gatew  = (const float*)d_in[8];
    const float* w1     = (const float*)d_in[9];
    const float* w2     = (const float*)d_in[10];
    const float* w3     = (const float*)d_in[11];
    const float* ln2g   = (const float*)d_in[12];
    const float* ln2b   = (const float*)d_in[13];
    const float* fing   = (const float*)d_in[14];
    const float* finb   = (const float*)d_in[15];
    const float* headw  = (const float*)d_in[16];
    float* out = (float*)d_out;

    float *x, *qkv, *y, *moe, *wts, *varr, *rwt;
    int *cnt, *ridx;
    __nv_bfloat16 *ah, *al, *ch, *cl;
    cudaGetSymbolAddress((void**)&x,    g_x);
    cudaGetSymbolAddress((void**)&qkv,  g_qkv);
    cudaGetSymbolAddress((void**)&y,    g_y);
    cudaGetSymbolAddress((void**)&moe,  g_moe);
    cudaGetSymbolAddress((void**)&wts,  g_wts);
    cudaGetSymbolAddress((void**)&varr, g_var);
    cudaGetSymbolAddress((void**)&cnt,  g_cnt);
    cudaGetSymbolAddress((void**)&ridx, g_ridx);
    cudaGetSymbolAddress((void**)&rwt,  g_rwt);
    cudaGetSymbolAddress((void**)&ah,   g_ah);
    cudaGetSymbolAddress((void**)&al,   g_al);
    cudaGetSymbolAddress((void**)&ch,   g_ch);
    cudaGetSymbolAddress((void**)&cl,   g_cl);

    cudaFuncSetAttribute(attn_kernel, cudaFuncAttributeMaxDynamicSharedMemorySize, ATTN_SMEM);
    cudaFuncSetAttribute(gemm_tc<0>, cudaFuncAttributeMaxDynamicSharedMemorySize, GEMM_SMEM_TC);
    cudaFuncSetAttribute(gemm_tc<1>, cudaFuncAttributeMaxDynamicSharedMemorySize, GEMM_SMEM_TC);
    cudaFuncSetAttribute(gemm_tc<2>, cudaFuncAttributeMaxDynamicSharedMemorySize, GEMM_SMEM_TC);
    cudaFuncSetAttribute(gemm_tf32, cudaFuncAttributeMaxDynamicSharedMemorySize, GEMM_SMEM_TF);

    // 1) embed (+ fused split)
    embed_kernel<<<SEQ, 256>>>(tokens, emb, x, ah, al);

    // 2) fused QKV (N=6144) — grid: (m-tiles, n-tiles)
    dim3 gQKV(SEQ/128, 3*D_MODEL/256);
    gemm_tc<0><<<gQKV, 256, GEMM_SMEM_TC>>>(ah, al, wq, wk, wv, D_MODEL,
                                            qkv, SEQ, 3*D_MODEL, D_MODEL,
                                            nullptr, nullptr, nullptr, nullptr, 0, 0,
                                            nullptr, nullptr);

    // 3) RoPE + attention (emits pre-split ah/al)
    rope_kernel<<<dim3(SEQ, N_HEADS), 32>>>(qkv);
    attn_kernel<<<dim3(NB, N_HEADS), 256, ATTN_SMEM>>>(qkv, ah, al);

    // 4) output proj + residual -> y
    dim3 gA(SEQ/128, D_MODEL/256);
    gemm_tc<0><<<gA, 256, GEMM_SMEM_TC>>>(ah, al, wo, wo, wo, D_MODEL,
                                          y, SEQ, D_MODEL, D_MODEL,
                                          x, nullptr, nullptr, nullptr, 0, 0,
                                          nullptr, nullptr);

    // 5) LN1 -> x (+ fused split to ah/al)
    ln_kernel<<<SEQ, 256>>>(y, nullptr, ln1g, ln1b, x, ah, al);

    // 6) gate + routing
    gate_kernel<<<SEQ, 128>>>(x, gatew, wts, varr);
    compact_kernel<<<NEXP, 1024>>>(wts, cnt, ridx, rwt);

    // 7) MoE — up (fused silu+split) then down (atomic scatter)
    zero_kernel<<<(SEQ*D_MODEL + 255)/256, 256>>>(moe, SEQ*D_MODEL);
    const long long FD = (long long)D_FFN * D_MODEL;
    dim3 gUp(SEQ/128, 2*D_FFN/256, NEXP);
    gemm_tc<1><<<gUp, 256, GEMM_SMEM_TC>>>(ah, al, w1, w3, nullptr, 0,
                                           nullptr, 0, 2*D_FFN, D_MODEL,
                                           nullptr, cnt, ridx, nullptr,
                                           0, FD, ch, cl);
    dim3 gDn(SEQ/128, D_MODEL/256, NEXP*4);
    gemm_tc<2><<<gDn, 256, GEMM_SMEM_TC>>>(ch, cl, w2, nullptr, nullptr, 0,
                                           moe, 0, D_MODEL, D_FFN,
                                           nullptr, cnt, ridx, rwt,
                                           (long long)SEQ*D_FFN, FD, nullptr, nullptr);

    // 8) fused LN2 + final LN
    ln2_kernel<<<SEQ, 256>>>(moe, x, ln2g, ln2b, fing, finb, y);

    // 9) head (tf32 single-pass) — grid: (m-tiles, n-tiles)
    dim3 gH(SEQ/128, (VOCAB + 255)/256);
    gemm_tf32<<<gH, 256, GEMM_SMEM_TF>>>(y, headw, out, SEQ, VOCAB, D_MODEL);

    // 10) aux
    long long nlog = (long long)SEQ * VOCAB;
    if ((long long)out_size > nlog)
        aux_kernel<<<1, 256>>>(varr, out + nlog);
}

// round 13
// speedup vs baseline: 5.3273x; 1.0988x over previous
#include <cuda_runtime.h>
#include <cuda_bf16.h>
#include <math.h>
#include <stdint.h>

#define D_MODEL 2048
#define SEQ     1024
#define N_HEADS 32
#define HEAD_DIM 64
#define NB      (SEQ/64)
#define D_FFN   8192
#define VOCAB   50257
#define NEXP    4
#define QKV_STRIDE (3*D_MODEL)

// ---------------- scratch ----------------
__device__ float g_x  [SEQ*D_MODEL];
__device__ float g_qkv[SEQ*3*D_MODEL];
__device__ float g_y  [SEQ*D_MODEL];
__device__ float g_moe[SEQ*D_MODEL];
__device__ float g_wts[NEXP*SEQ];
__device__ float g_var[SEQ];
__device__ float g_h  [(size_t)NEXP*SEQ*D_FFN];   // fp32 silu(h1)*h3 per expert

// routing
__device__ int   g_cnt[NEXP];
__device__ int   g_ridx[NEXP*SEQ];
__device__ float g_rwt [NEXP*SEQ];

// bf16 split scratch (d_model activations)
__device__ __nv_bfloat16 g_ah[SEQ*D_MODEL];
__device__ __nv_bfloat16 g_al[SEQ*D_MODEL];

// ---------------- PTX helpers ----------------
__device__ __forceinline__ uint32_t smem_u32(const void* p) {
    uint32_t a;
    asm("{ .reg .u64 t; cvta.to.shared.u64 t, %1; cvt.u32.u64 %0, t; }" : "=r"(a) : "l"(p));
    return a;
}
__device__ __forceinline__ void cp_async16(uint32_t dst, const void* src, int src_bytes) {
    asm volatile("cp.async.cg.shared.global [%0], [%1], 16, %2;\n"
                 :: "r"(dst), "l"(src), "r"(src_bytes) : "memory");
}
#define CP_COMMIT() asm volatile("cp.async.commit_group;\n" ::: "memory")

#define STS128(addr, a, b, c, d) \
    asm volatile("st.shared.v4.b32 [%0], {%1,%2,%3,%4};" \
                 :: "r"(addr), "r"(a), "r"(b), "r"(c), "r"(d) : "memory")

__device__ __forceinline__ void ldsm_x4(uint32_t& r0, uint32_t& r1, uint32_t& r2, uint32_t& r3,
                                        uint32_t addr) {
    asm volatile("ldmatrix.sync.aligned.m8n8.x4.shared.b16 {%0,%1,%2,%3}, [%4];"
                 : "=r"(r0), "=r"(r1), "=r"(r2), "=r"(r3) : "r"(addr));
}
__device__ __forceinline__ void mma_bf16(float* c, const uint32_t* a, const uint32_t* b) {
    asm volatile(
        "mma.sync.aligned.m16n8k16.row.col.f32.bf16.bf16.f32 "
        "{%0,%1,%2,%3}, {%4,%5,%6,%7}, {%8,%9}, {%0,%1,%2,%3};"
        : "+f"(c[0]), "+f"(c[1]), "+f"(c[2]), "+f"(c[3])
        : "r"(a[0]), "r"(a[1]), "r"(a[2]), "r"(a[3]), "r"(b[0]), "r"(b[1]));
}
__device__ __forceinline__ void mma_tf32(float* c, const uint32_t* a, const uint32_t* b) {
    asm volatile(
        "mma.sync.aligned.m16n8k8.row.col.f32.tf32.tf32.f32 "
        "{%0,%1,%2,%3}, {%4,%5,%6,%7}, {%8,%9}, {%0,%1,%2,%3};"
        : "+f"(c[0]), "+f"(c[1]), "+f"(c[2]), "+f"(c[3])
        : "r"(a[0]), "r"(a[1]), "r"(a[2]), "r"(a[3]), "r"(b[0]), "r"(b[1]));
}

__device__ __forceinline__ void split2(float a, float b, uint32_t& hi, uint32_t& lo) {
    __nv_bfloat16 ha = __float2bfloat16(a), hb = __float2bfloat16(b);
    __nv_bfloat162 h; h.x = ha; h.y = hb;
    __nv_bfloat162 l;
    l.x = __float2bfloat16(a - __bfloat162float(ha));
    l.y = __float2bfloat16(b - __bfloat162float(hb));
    hi = *(uint32_t*)&h;
    lo = *(uint32_t*)&l;
}

// ================= bf16x3 GEMM: CTA 128x256, 8 warps (2Mx4N), warp 64x64 =================
#define NSTG_TC 3
#define A_BYTES (128*128)
#define B_BYTES (256*128)
#define STAGE_B (A_BYTES + B_BYTES)
#define GEMM_SMEM_TC (NSTG_TC * STAGE_B)
#define NSTG_TF 4
#define GEMM_SMEM_TF (NSTG_TF * STAGE_B)

// MODE 1: expert-batched up + FUSED silu·mul -> fp32 H. e=blockIdx.z, A rows via ridx[e],
//         B rows interleaved even->B0(w1) odd->B1(w3) (per-expert slab via sB).
// MODE 3: dense rows, split-K via gridDim.z, atomicAdd into zeroed C. B rows: <rPB->B0,<2rPB->B1,else B2.
template<int MODE>
__global__ void __launch_bounds__(256, 1) gemm_tc(
    const __nv_bfloat16* __restrict__ Ah, const __nv_bfloat16* __restrict__ Al,
    const float* __restrict__ B0, const float* __restrict__ B1, const float* __restrict__ B2,
    int rPB,
    float* __restrict__ C, int N, int K,
    const int* __restrict__ cntArr, const int* __restrict__ ridxAll,
    long long sB, float* __restrict__ Hout)
{
    const int tid = threadIdx.x;
    const int m0  = blockIdx.x * 128;
    const int n0  = blockIdx.y * 256;

    int M = SEQ;
    int e = 0, kbase = 0, Kc = K;
    const int* ridx = ridxAll;
    const float* b0p = B0; const float* b1p = B1; const float* b2p = B2;

    if (MODE == 1) {
        e = blockIdx.z;
        M = cntArr[e];
        if (m0 >= M) return;
        ridx = ridxAll + e * SEQ;
        b0p = B0 + (size_t)e * sB;
        b1p = B1 + (size_t)e * sB;
    } else { // MODE 3
        Kc = K / (int)gridDim.z;
        kbase = (int)blockIdx.z * Kc;
    }

    int arow[4];
    #pragma unroll
    for (int i = 0; i < 4; i++) {
        int r = (tid + i * 256) >> 3;
        int rg = m0 + r;
        if (MODE == 3) arow[i] = rg;
        else {
            rg = rg < M ? rg : (M - 1);
            arow[i] = ridx[rg];
        }
    }

    extern __shared__ char smem[];
    const uint32_t sb = smem_u32(smem);
    const int wid = tid >> 5, lid = tid & 31;
    const int wm  = wid >> 2, wn = wid & 3;

    float acc[4][8][4];
    #pragma unroll
    for (int i = 0; i < 4; i++)
        #pragma unroll
        for (int j = 0; j < 8; j++)
            #pragma unroll
            for (int t = 0; t < 4; t++) acc[i][j][t] = 0.f;

    const int iters = Kc >> 5;

    auto fillA = [&](int stage, int kit) {
        const int k0 = kbase + (kit << 5);
        const uint32_t abase = sb + stage * STAGE_B;
        #pragma unroll
        for (int i = 0; i < 4; i++) {
            int idx = tid + i * 256;
            int r = idx >> 3, c = idx & 7;
            uint32_t dst = abase + r * 128 + ((c ^ (r & 7)) << 4);
            const __nv_bfloat16* src = (c < 4)
                ? Ah + (size_t)arow[i] * K + k0 + c * 8
                : Al + (size_t)arow[i] * K + k0 + (c - 4) * 8;
            cp_async16(dst, src, 16);
        }
        CP_COMMIT();
    };

    auto ldgB = [&](float4* breg, int kit) {
        const int k0 = kbase + (kit << 5);
        #pragma unroll
        for (int i = 0; i < 4; i++) {
            int idx = tid + i * 256;
            int r = idx >> 2, c2 = idx & 3;
            int rg = n0 + r;
            int rc = rg < N ? rg : (N - 1);
            const float* Bp; int rr;
            if (MODE == 1)          { Bp = (rc & 1) ? b1p : b0p; rr = rc >> 1; }
            else if (rc < rPB)      { Bp = b0p; rr = rc; }
            else if (rc < 2 * rPB)  { Bp = b1p; rr = rc - rPB; }
            else                    { Bp = b2p; rr = rc - 2 * rPB; }
            const float4* s4 = (const float4*)(Bp + (size_t)rr * K + k0 + c2 * 8);
            breg[i*2]     = s4[0];
            breg[i*2 + 1] = s4[1];
        }
    };

    auto stsB = [&](const float4* breg, int stage) {
        const uint32_t bbase = sb + stage * STAGE_B + A_BYTES;
        #pragma unroll
        for (int i = 0; i < 4; i++) {
            int idx = tid + i * 256;
            int r = idx >> 2, c2 = idx & 3;
            float4 v0 = breg[i*2], v1 = breg[i*2 + 1];
            uint32_t h0, h1, h2, h3, l0, l1, l2, l3;
            split2(v0.x, v0.y, h0, l0);
            split2(v0.z, v0.w, h1, l1);
            split2(v1.x, v1.y, h2, l2);
            split2(v1.z, v1.w, h3, l3);
            uint32_t ha = bbase + r * 128 + ((c2 ^ (r & 7)) << 4);
            uint32_t la = bbase + r * 128 + (((c2 + 4) ^ (r & 7)) << 4);
            STS128(ha, h0, h1, h2, h3);
            STS128(la, l0, l1, l2, l3);
        }
    };

    {
        float4 pb[8];
        #pragma unroll
        for (int s = 0; s < NSTG_TC - 1; s++) {
            fillA(s, s);
            ldgB(pb, s);
            stsB(pb, s);
        }
    }

    const int grp = lid >> 3;
    const int rin = lid & 7;
    float4 breg[8];

    for (int i = 0; i < iters; i++) {
        const int s = i % NSTG_TC;
        const bool pre = (i + NSTG_TC - 1 < iters);
        if (pre) ldgB(breg, i + NSTG_TC - 1);

        asm volatile("cp.async.wait_group %0;\n" :: "n"(NSTG_TC - 2));
        __syncthreads();

        if (pre) fillA((i + NSTG_TC - 1) % NSTG_TC, i + NSTG_TC - 1);
        else CP_COMMIT();

        const uint32_t abase = sb + s * STAGE_B;
        const uint32_t bbase = abase + A_BYTES;

        #pragma unroll
        for (int g = 0; g < 2; g++) {
            uint32_t ah[4][4], bh[8][2];
            #pragma unroll
            for (int mt = 0; mt < 4; mt++) {
                int row = wm * 64 + mt * 16 + (grp & 1) * 8 + rin;
                int kch = 2 * g + (grp >> 1);
                uint32_t ad = abase + row * 128 + ((kch ^ (row & 7)) << 4);
                ldsm_x4(ah[mt][0], ah[mt][1], ah[mt][2], ah[mt][3], ad);
            }
            #pragma unroll
            for (int p = 0; p < 4; p++) {
                int tile = 2 * p + (grp >> 1);
                int row  = wn * 64 + tile * 8 + rin;
                int kch  = 2 * g + (grp & 1);
                uint32_t bd = bbase + row * 128 + ((kch ^ (row & 7)) << 4);
                ldsm_x4(bh[2*p][0], bh[2*p][1], bh[2*p+1][0], bh[2*p+1][1], bd);
            }
            #pragma unroll
            for (int mt = 0; mt < 4; mt++)
                #pragma unroll
                for (int nt = 0; nt < 8; nt++)
                    mma_bf16(acc[mt][nt], ah[mt], bh[nt]);
            {
                uint32_t al[4][4];
                #pragma unroll
                for (int mt = 0; mt < 4; mt++) {
                    int row = wm * 64 + mt * 16 + (grp & 1) * 8 + rin;
                    int kcl = 4 + 2 * g + (grp >> 1);
                    uint32_t adl = abase + row * 128 + ((kcl ^ (row & 7)) << 4);
                    ldsm_x4(al[mt][0], al[mt][1], al[mt][2], al[mt][3], adl);
                }
                #pragma unroll
                for (int mt = 0; mt < 4; mt++)
                    #pragma unroll
                    for (int nt = 0; nt < 8; nt++)
                        mma_bf16(acc[mt][nt], al[mt], bh[nt]);
            }
            {
                uint32_t bl[8][2];
                #pragma unroll
                for (int p = 0; p < 4; p++) {
                    int tile = 2 * p + (grp >> 1);
                    int row  = wn * 64 + tile * 8 + rin;
                    int kcl  = 4 + 2 * g + (grp & 1);
                    uint32_t bdl = bbase + row * 128 + ((kcl ^ (row & 7)) << 4);
                    ldsm_x4(bl[2*p][0], bl[2*p][1], bl[2*p+1][0], bl[2*p+1][1], bdl);
                }
                #pragma unroll
                for (int mt = 0; mt < 4; mt++)
                    #pragma unroll
                    for (int nt = 0; nt < 8; nt++)
                        mma_bf16(acc[mt][nt], ah[mt], bl[nt]);
            }
        }

        if (pre) stsB(breg, (i + NSTG_TC - 1) % NSTG_TC);
    }

    #pragma unroll
    for (int mt = 0; mt < 4; mt++) {
        #pragma unroll
        for (int nt = 0; nt < 8; nt++) {
            int rbase = m0 + wm * 64 + mt * 16 + (lid >> 2);
            int col = n0 + wn * 64 + nt * 8 + (lid & 3) * 2;
            #pragma unroll
            for (int h = 0; h < 2; h++) {
                int m = rbase + h * 8;
                float v0 = acc[mt][nt][h * 2 + 0];
                float v1 = acc[mt][nt][h * 2 + 1];
                if (MODE == 1) {
                    if (m < M) {
                        int j = col >> 1;  // (v0,v1) = (h1_j, h3_j)
                        float r = v0 / (1.f + expf(-v0)) * v1;
                        Hout[(size_t)e * SEQ * D_FFN + (size_t)m * D_FFN + j] = r;
                    }
                } else { // MODE 3: split-K atomic accumulate
                    size_t idx = (size_t)m * N + col;
                    if (col     < N) atomicAdd(&C[idx],     v0);
                    if (col + 1 < N) atomicAdd(&C[idx + 1], v1);
                }
            }
        }
    }
}

// ================= tf32 single-pass GEMM (head) =================
__global__ void __launch_bounds__(256, 1) gemm_tf32(
    const float* __restrict__ A, const float* __restrict__ B,
    float* __restrict__ C, int M, int N, int K)
{
    extern __shared__ char smem[];
    const uint32_t sb = smem_u32(smem);
    const int tid = threadIdx.x;
    const int wid = tid >> 5, lid = tid & 31;
    const int wm  = wid >> 2, wn = wid & 3;
    const int m0  = blockIdx.x * 128;
    const int n0  = blockIdx.y * 256;

    float acc[4][8][4];
    #pragma unroll
    for (int i = 0; i < 4; i++)
        #pragma unroll
        for (int j = 0; j < 8; j++)
            #pragma unroll
            for (int t = 0; t < 4; t++) acc[i][j][t] = 0.f;

    const int iters = K >> 5;

    auto fill = [&](int stage, int kit) {
        const int k0 = kit << 5;
        const uint32_t abase = sb + stage * STAGE_B;
        const uint32_t bbase = abase + A_BYTES;
        #pragma unroll
        for (int i = 0; i < 4; i++) {
            int idx = tid + i * 256;
            int r = idx >> 3, c = idx & 7;
            uint32_t dst = abase + r * 128 + ((c ^ (r & 7)) << 4);
            cp_async16(dst, A + (size_t)(m0 + r) * K + k0 + c * 4, 16);
        }
        #pragma unroll
        for (int i = 0; i < 8; i++) {
            int idx = tid + i * 256;
            int r = idx >> 3, c = idx & 7;
            uint32_t dst = bbase + r * 128 + ((c ^ (r & 7)) << 4);
            int rg = n0 + r;
            int rc = rg < N ? rg : (N - 1);
            cp_async16(dst, B + (size_t)rc * K + k0 + c * 4, rg < N ? 16 : 0);
        }
        CP_COMMIT();
    };

    #pragma unroll
    for (int s = 0; s < NSTG_TF - 1; s++) fill(s, s);

    const int grp = lid >> 3;
    const int rin = lid & 7;

    for (int i = 0; i < iters; i++) {
        const int s = i % NSTG_TF;
        asm volatile("cp.async.wait_group %0;\n" :: "n"(NSTG_TF - 2));
        __syncthreads();

        if (i + NSTG_TF - 1 < iters) fill((i + NSTG_TF - 1) % NSTG_TF, i + NSTG_TF - 1);
        else CP_COMMIT();

        const uint32_t abase = sb + s * STAGE_B;
        const uint32_t bbase = abase + A_BYTES;

        #pragma unroll
        for (int k8 = 0; k8 < 4; k8++) {
            uint32_t a[4][4], b[8][2];
            #pragma unroll
            for (int mt = 0; mt < 4; mt++) {
                int row = wm * 64 + mt * 16 + (grp & 1) * 8 + rin;
                int kc  = k8 * 2 + (grp >> 1);
                uint32_t addr = abase + row * 128 + ((kc ^ (row & 7)) << 4);
                ldsm_x4(a[mt][0], a[mt][1], a[mt][2], a[mt][3], addr);
            }
            #pragma unroll
            for (int p = 0; p < 4; p++) {
                int tile = 2 * p + (grp >> 1);
                int row  = wn * 64 + tile * 8 + rin;
                int kc   = k8 * 2 + (grp & 1);
                uint32_t addr = bbase + row * 128 + ((kc ^ (row & 7)) << 4);
                ldsm_x4(b[2*p][0], b[2*p][1], b[2*p+1][0], b[2*p+1][1], addr);
            }
            #pragma unroll
            for (int mt = 0; mt < 4; mt++)
                #pragma unroll
                for (int nt = 0; nt < 8; nt++)
                    mma_tf32(acc[mt][nt], a[mt], b[nt]);
        }
    }

    #pragma unroll
    for (int mt = 0; mt < 4; mt++) {
        #pragma unroll
        for (int nt = 0; nt < 8; nt++) {
            int rbase = m0 + wm * 64 + mt * 16 + (lid >> 2);
            int col = n0 + wn * 64 + nt * 8 + (lid & 3) * 2;
            #pragma unroll
            for (int h = 0; h < 2; h++) {
                int m = rbase + h * 8;
                size_t idx = (size_t)m * N + col;
                if (col     < N) C[idx]     = acc[mt][nt][h * 2 + 0];
                if (col + 1 < N) C[idx + 1] = acc[mt][nt][h * 2 + 1];
            }
        }
    }
}

// ================= tf32 MoE down-proj: expert slab + split-K4 + weighted atomic scatter =========
__global__ void __launch_bounds__(256, 1) gemm_tf32_moe(
    const float* __restrict__ H, const float* __restrict__ W2,
    float* __restrict__ C, int N, int K,
    const int* __restrict__ cntArr, const int* __restrict__ ridxAll,
    const float* __restrict__ rwtAll)
{
    const int tid = threadIdx.x;
    const int m0  = blockIdx.x * 128;
    const int n0  = blockIdx.y * 256;
    const int e   = blockIdx.z >> 2;
    const int ks  = blockIdx.z & 3;
    const int M   = cntArr[e];
    if (m0 >= M) return;
    const int* ridx = ridxAll + e * SEQ;
    const float* rwt = rwtAll + e * SEQ;
    const float* A = H  + (size_t)e * SEQ * D_FFN;
    const float* B = W2 + (size_t)e * D_FFN * D_MODEL;
    const int Kc    = K >> 2;
    const int kbase = ks * Kc;

    int arow[4];
    #pragma unroll
    for (int i = 0; i < 4; i++) {
        int r = (tid + i * 256) >> 3;
        int rg = m0 + r;
        arow[i] = rg < M ? rg : (M - 1);
    }

    extern __shared__ char smem[];
    const uint32_t sb = smem_u32(smem);
    const int wid = tid >> 5, lid = tid & 31;
    const int wm  = wid >> 2, wn = wid & 3;

    float acc[4][8][4];
    #pragma unroll
    for (int i = 0; i < 4; i++)
        #pragma unroll
        for (int j = 0; j < 8; j++)
            #pragma unroll
            for (int t = 0; t < 4; t++) acc[i][j][t] = 0.f;

    const int iters = Kc >> 5;

    auto fill = [&](int stage, int kit) {
        const int k0 = kbase + (kit << 5);
        const uint32_t abase = sb + stage * STAGE_B;
        const uint32_t bbase = abase + A_BYTES;
        #pragma unroll
        for (int i = 0; i < 4; i++) {
            int idx = tid + i * 256;
            int r = idx >> 3, c = idx & 7;
            uint32_t dst = abase + r * 128 + ((c ^ (r & 7)) << 4);
            cp_async16(dst, A + (size_t)arow[i] * K + k0 + c * 4, 16);
        }
        #pragma unroll
        for (int i = 0; i < 8; i++) {
            int idx = tid + i * 256;
            int r = idx >> 3, c = idx & 7;
            uint32_t dst = bbase + r * 128 + ((c ^ (r & 7)) << 4);
            int rg = n0 + r;
            int rc = rg < N ? rg : (N - 1);
            cp_async16(dst, B + (size_t)rc * K + k0 + c * 4, rg < N ? 16 : 0);
        }
        CP_COMMIT();
    };

    #pragma unroll
    for (int s = 0; s < NSTG_TF - 1; s++) fill(s, s);

    const int grp = lid >> 3;
    const int rin = lid & 7;

    for (int i = 0; i < iters; i++) {
        const int s = i % NSTG_TF;
        asm volatile("cp.async.wait_group %0;\n" :: "n"(NSTG_TF - 2));
        __syncthreads();

        if (i + NSTG_TF - 1 < iters) fill((i + NSTG_TF - 1) % NSTG_TF, i + NSTG_TF - 1);
        else CP_COMMIT();

        const uint32_t abase = sb + s * STAGE_B;
        const uint32_t bbase = abase + A_BYTES;

        #pragma unroll
        for (int k8 = 0; k8 < 4; k8++) {
            uint32_t a[4][4], b[8][2];
            #pragma unroll
            for (int mt = 0; mt < 4; mt++) {
                int row = wm * 64 + mt * 16 + (grp & 1) * 8 + rin;
                int kc  = k8 * 2 + (grp >> 1);
                uint32_t addr = abase + row * 128 + ((kc ^ (row & 7)) << 4);
                ldsm_x4(a[mt][0], a[mt][1], a[mt][2], a[mt][3], addr);
            }
            #pragma unroll
            for (int p = 0; p < 4; p++) {
                int tile = 2 * p + (grp >> 1);
                int row  = wn * 64 + tile * 8 + rin;
                int kc   = k8 * 2 + (grp & 1);
                uint32_t addr = bbase + row * 128 + ((kc ^ (row & 7)) << 4);
                ldsm_x4(b[2*p][0], b[2*p][1], b[2*p+1][0], b[2*p+1][1], addr);
            }
            #pragma unroll
            for (int mt = 0; mt < 4; mt++)
                #pragma unroll
                for (int nt = 0; nt < 8; nt++)
                    mma_tf32(acc[mt][nt], a[mt], b[nt]);
        }
    }

    #pragma unroll
    for (int mt = 0; mt < 4; mt++) {
        #pragma unroll
        for (int nt = 0; nt < 8; nt++) {
            int rbase = m0 + wm * 64 + mt * 16 + (lid >> 2);
            int col = n0 + wn * 64 + nt * 8 + (lid & 3) * 2;
            #pragma unroll
            for (int h = 0; h < 2; h++) {
                int m = rbase + h * 8;
                if (m < M) {
                    int tok = ridx[m];
                    float w = rwt[m];
                    size_t idx = (size_t)tok * N + col;
                    atomicAdd(&C[idx],     w * acc[mt][nt][h * 2 + 0]);
                    atomicAdd(&C[idx + 1], w * acc[mt][nt][h * 2 + 1]);
                }
            }
        }
    }
}

// ---------------- embedding (+ fused split) ----------------
__global__ void embed_kernel(const int* __restrict__ tok,
                             const float* __restrict__ emb,
                             float* __restrict__ x,
                             __nv_bfloat16* __restrict__ ah,
                             __nv_bfloat16* __restrict__ al) {
    int t = blockIdx.x;
    int tk = tok[t];
    const float2* src = (const float2*)(emb + (size_t)tk * D_MODEL);
    float2* dst = (float2*)(x + (size_t)t * D_MODEL);
    uint32_t* hd = (uint32_t*)(ah + (size_t)t * D_MODEL);
    uint32_t* ld = (uint32_t*)(al + (size_t)t * D_MODEL);
    for (int p = threadIdx.x; p < D_MODEL/2; p += 256) {
        float2 v = src[p];
        dst[p] = v;
        uint32_t h, l;
        split2(v.x, v.y, h, l);
        hd[p] = h;
        ld[p] = l;
    }
}

// ---------------- RoPE ----------------
__global__ void rope_kernel(float* __restrict__ qkv) {
    int t = blockIdx.x, h = blockIdx.y, i = threadIdx.x;
    float inv = powf(10000.f, -((float)(2*i)) / 64.f);
    float ang = (float)t * inv;
    float s, c;
    sincosf(ang, &s, &c);
    size_t base = (size_t)t*QKV_STRIDE + h*HEAD_DIM + 2*i;
    float q0 = qkv[base], q1 = qkv[base+1];
    qkv[base]   = q0*c - q1*s;
    qkv[base+1] = q0*s + q1*c;
    size_t kb = base + D_MODEL;
    float k0 = qkv[kb], k1 = qkv[kb+1];
    qkv[kb]   = k0*c - k1*s;
    qkv[kb+1] = k0*s + k1*c;
}

// ---------------- blocked attention: 4x4 register tiles, Q/K/P transposed ----------------
#define ATTN_SMEM (4 * 64 * 68 * 4)
__global__ void __launch_bounds__(256) attn_kernel(
    const float* __restrict__ qkv,
    __nv_bfloat16* __restrict__ oh, __nv_bfloat16* __restrict__ ol)
{
    extern __shared__ float sm[];
    float* Qst = sm;
    float* Kst = Qst + 64*68;
    float* Vs  = Kst + 64*68;
    float* Pst = Vs + 64*68;
    const int ib = blockIdx.x, h = blockIdx.y;
    const int tid = threadIdx.x;
    const int qg  = tid >> 4;
    const int cg  = tid & 15;
    const int qr0 = qg * 4;
    const int c0  = cg * 4;

    for (int idx = tid; idx < 64*64; idx += 256) {
        int r = idx >> 6, c = idx & 63;
        Qst[c*68 + r] = qkv[(size_t)(ib*64+r)*QKV_STRIDE + h*HEAD_DIM + c];
    }

    float accO[4][4];
    #pragma unroll
    for (int i = 0; i < 4; i++)
        #pragma unroll
        for (int j = 0; j < 4; j++) accO[i][j] = 0.f;
    float den[4] = {0.f, 0.f, 0.f, 0.f};

    for (int jb = 0; jb <= ib; jb++) {
        __syncthreads();
        for (int idx = tid; idx < 64*64; idx += 256) {
            int r = idx >> 6, c = idx & 63;
            size_t base = (size_t)(jb*64+r)*QKV_STRIDE + h*HEAD_DIM + c;
            Kst[c*68 + r] = qkv[base + D_MODEL];
            Vs [r*68 + c] = qkv[base + 2*D_MODEL];
        }
        __syncthreads();

        float s4[4][4];
        #pragma unroll
        for (int i = 0; i < 4; i++)
            #pragma unroll
            for (int j = 0; j < 4; j++) s4[i][j] = 0.f;

        #pragma unroll 4
        for (int d = 0; d < 64; d++) {
            float4 qv = *(const float4*)&Qst[d*68 + qr0];
            float4 kv = *(const float4*)&Kst[d*68 + c0];
            s4[0][0] = fmaf(qv.x, kv.x, s4[0][0]); s4[0][1] = fmaf(qv.x, kv.y, s4[0][1]);
            s4[0][2] = fmaf(qv.x, kv.z, s4[0][2]); s4[0][3] = fmaf(qv.x, kv.w, s4[0][3]);
            s4[1][0] = fmaf(qv.y, kv.x, s4[1][0]); s4[1][1] = fmaf(qv.y, kv.y, s4[1][1]);
            s4[1][2] = fmaf(qv.y, kv.z, s4[1][2]); s4[1][3] = fmaf(qv.y, kv.w, s4[1][3]);
            s4[2][0] = fmaf(qv.z, kv.x, s4[2][0]); s4[2][1] = fmaf(qv.z, kv.y, s4[2][1]);
            s4[2][2] = fmaf(qv.z, kv.z, s4[2][2]); s4[2][3] = fmaf(qv.z, kv.w, s4[2][3]);
            s4[3][0] = fmaf(qv.w, kv.x, s4[3][0]); s4[3][1] = fmaf(qv.w, kv.y, s4[3][1]);
            s4[3][2] = fmaf(qv.w, kv.z, s4[3][2]); s4[3][3] = fmaf(qv.w, kv.w, s4[3][3]);
        }

        float mx[4];
        #pragma unroll
        for (int i = 0; i < 4; i++) {
            mx[i] = -1e30f;
            int q = qr0 + i;
            #pragma unroll
            for (int j = 0; j < 4; j++) {
                int c = c0 + j;
                float v = s4[i][j] * 0.125f;
                if (jb == ib && c > q) v = -1e30f;
                s4[i][j] = v;
                mx[i] = fmaxf(mx[i], v);
            }
        }
        #pragma unroll
        for (int o = 1; o < 16; o <<= 1) {
            #pragma unroll
            for (int i = 0; i < 4; i++)
                mx[i] = fmaxf(mx[i], __shfl_xor_sync(0xffffffffu, mx[i], o));
        }

        #pragma unroll
        for (int j = 0; j < 4; j++) {
            float p0 = expf(s4[0][j] - mx[0]);
            float p1 = expf(s4[1][j] - mx[1]);
            float p2 = expf(s4[2][j] - mx[2]);
            float p3 = expf(s4[3][j] - mx[3]);
            den[0] += p0; den[1] += p1; den[2] += p2; den[3] += p3;
            *(float4*)&Pst[(c0 + j)*68 + qr0] = make_float4(p0, p1, p2, p3);
        }
        __syncthreads();

        #pragma unroll 4
        for (int kk = 0; kk < 64; kk++) {
            float4 pv = *(const float4*)&Pst[kk*68 + qr0];
            float4 vv = *(const float4*)&Vs [kk*68 + c0];
            accO[0][0] = fmaf(pv.x, vv.x, accO[0][0]); accO[0][1] = fmaf(pv.x, vv.y, accO[0][1]);
            accO[0][2] = fmaf(pv.x, vv.z, accO[0][2]); accO[0][3] = fmaf(pv.x, vv.w, accO[0][3]);
            accO[1][0] = fmaf(pv.y, vv.x, accO[1][0]); accO[1][1] = fmaf(pv.y, vv.y, accO[1][1]);
            accO[1][2] = fmaf(pv.y, vv.z, accO[1][2]); accO[1][3] = fmaf(pv.y, vv.w, accO[1][3]);
            accO[2][0] = fmaf(pv.z, vv.x, accO[2][0]); accO[2][1] = fmaf(pv.z, vv.y, accO[2][1]);
            accO[2][2] = fmaf(pv.z, vv.z, accO[2][2]); accO[2][3] = fmaf(pv.z, vv.w, accO[2][3]);
            accO[3][0] = fmaf(pv.w, vv.x, accO[3][0]); accO[3][1] = fmaf(pv.w, vv.y, accO[3][1]);
            accO[3][2] = fmaf(pv.w, vv.z, accO[3][2]); accO[3][3] = fmaf(pv.w, vv.w, accO[3][3]);
        }
    }

    #pragma unroll
    for (int o = 1; o < 16; o <<= 1) {
        #pragma unroll
        for (int i = 0; i < 4; i++)
            den[i] += __shfl_xor_sync(0xffffffffu, den[i], o);
    }

    #pragma unroll
    for (int i = 0; i < 4; i++) {
        float invd = 1.f / (den[i] + 1e-6f);
        size_t obase = (size_t)(ib*64 + qr0 + i)*D_MODEL + h*HEAD_DIM + c0;
        uint32_t h0, l0, h1, l1;
        split2(accO[i][0]*invd, accO[i][1]*invd, h0, l0);
        split2(accO[i][2]*invd, accO[i][3]*invd, h1, l1);
        uint32_t* hd = (uint32_t*)(oh + obase);
        uint32_t* ld = (uint32_t*)(ol + obase);
        hd[0] = h0; hd[1] = h1;
        ld[0] = l0; ld[1] = l1;
    }
}

// ---------------- layernorm (optional residual, optional split output) ----------------
__global__ void __launch_bounds__(256) ln_kernel(
    const float* __restrict__ in, const float* __restrict__ res,
    const float* __restrict__ g, const float* __restrict__ b,
    float* __restrict__ out,
    __nv_bfloat16* __restrict__ hi, __nv_bfloat16* __restrict__ lo)
{
    __shared__ float red[256];
    int t = blockIdx.x, tid = threadIdx.x;
    float v[8];
    float sum = 0.f;
    #pragma unroll
    for (int i = 0; i < 8; i++) {
        int d = i*256 + tid;
        float x = in[(size_t)t*D_MODEL + d];
        if (res) x += res[(size_t)t*D_MODEL + d];
        v[i] = x; sum += x;
    }
    red[tid] = sum; __syncthreads();
    for (int s = 128; s > 0; s >>= 1) { if (tid < s) red[tid] += red[tid+s]; __syncthreads(); }
    float mu = red[0] / D_MODEL;
    __syncthreads();
    float sq = 0.f;
    #pragma unroll
    for (int i = 0; i < 8; i++) { float d0 = v[i] - mu; sq += d0*d0; }
    red[tid] = sq; __syncthreads();
    for (int s = 128; s > 0; s >>= 1) { if (tid < s) red[tid] += red[tid+s]; __syncthreads(); }
    float rstd = rsqrtf(red[0] / D_MODEL + 1e-5f);
    #pragma unroll
    for (int i = 0; i < 8; i++) {
        int d = i*256 + tid;
        float val = (v[i] - mu) * rstd * g[d] + b[d];
        out[(size_t)t*D_MODEL + d] = val;
        if (hi) {
            __nv_bfloat16 hv = __float2bfloat16(val);
            hi[(size_t)t*D_MODEL + d] = hv;
            lo[(size_t)t*D_MODEL + d] = __float2bfloat16(val - __bfloat162float(hv));
        }
    }
}

// ---------------- fused double layernorm: out = LNf(LN2(in+res)) ----------------
__global__ void __launch_bounds__(256) ln2_kernel(
    const float* __restrict__ in, const float* __restrict__ res,
    const float* __restrict__ g2, const float* __restrict__ b2,
    const float* __restrict__ gf, const float* __restrict__ bf,
    float* __restrict__ out)
{
    __shared__ float red[256];
    int t = blockIdx.x, tid = threadIdx.x;
    float v[8];
    float sum = 0.f;
    #pragma unroll
    for (int i = 0; i < 8; i++) {
        int d = i*256 + tid;
        float x = in[(size_t)t*D_MODEL + d] + res[(size_t)t*D_MODEL + d];
        v[i] = x; sum += x;
    }
    red[tid] = sum; __syncthreads();
    for (int s = 128; s > 0; s >>= 1) { if (tid < s) red[tid] += red[tid+s]; __syncthreads(); }
    float mu = red[0] / D_MODEL;
    __syncthreads();
    float sq = 0.f;
    #pragma unroll
    for (int i = 0; i < 8; i++) { float d0 = v[i] - mu; sq += d0*d0; }
    red[tid] = sq; __syncthreads();
    for (int s = 128; s > 0; s >>= 1) { if (tid < s) red[tid] += red[tid+s]; __syncthreads(); }
    float rstd = rsqrtf(red[0] / D_MODEL + 1e-5f);
    __syncthreads();
    float sum2 = 0.f;
    #pragma unroll
    for (int i = 0; i < 8; i++) {
        int d = i*256 + tid;
        v[i] = (v[i] - mu) * rstd * g2[d] + b2[d];
        sum2 += v[i];
    }
    red[tid] = sum2; __syncthreads();
    for (int s = 128; s > 0; s >>= 1) { if (tid < s) red[tid] += red[tid+s]; __syncthreads(); }
    float mu2 = red[0] / D_MODEL;
    __syncthreads();
    float sq2 = 0.f;
    #pragma unroll
    for (int i = 0; i < 8; i++) { float d0 = v[i] - mu2; sq2 += d0*d0; }
    red[tid] = sq2; __syncthreads();
    for (int s = 128; s > 0; s >>= 1) { if (tid < s) red[tid] += red[tid+s]; __syncthreads(); }
    float rstd2 = rsqrtf(red[0] / D_MODEL + 1e-5f);
    #pragma unroll
    for (int i = 0; i < 8; i++) {
        int d = i*256 + tid;
        out[(size_t)t*D_MODEL + d] = (v[i] - mu2) * rstd2 * gf[d] + bf[d];
    }
}

// ---------------- MoE gate ----------------
__global__ void __launch_bounds__(128) gate_kernel(
    const float* __restrict__ x, const float* __restrict__ gw,
    float* __restrict__ wts, float* __restrict__ varr)
{
    __shared__ float red[128];
    __shared__ float logit[4];
    int t = blockIdx.x, tid = threadIdx.x;
    float p[4] = {0.f, 0.f, 0.f, 0.f};
    for (int d = tid; d < D_MODEL; d += 128) {
        float xv = x[(size_t)t*D_MODEL + d];
        #pragma unroll
        for (int e = 0; e < 4; e++)
            p[e] = fmaf(xv, gw[e*D_MODEL + d], p[e]);
    }
    for (int e = 0; e < 4; e++) {
        red[tid] = p[e]; __syncthreads();
        for (int s = 64; s > 0; s >>= 1) { if (tid < s) red[tid] += red[tid+s]; __syncthreads(); }
        if (tid == 0) logit[e] = red[0];
        __syncthreads();
    }
    if (tid == 0) {
        float l[4] = {logit[0], logit[1], logit[2], logit[3]};
        float mx = fmaxf(fmaxf(l[0], l[1]), fmaxf(l[2], l[3]));
        float ex[4], ssum = 0.f;
        for (int e = 0; e < 4; e++) { ex[e] = expf(l[e] - mx); ssum += ex[e]; }
        float pr[4];
        for (int e = 0; e < 4; e++) pr[e] = ex[e] / ssum;
        int b1 = 0;
        for (int e = 1; e < 4; e++) if (pr[e] > pr[b1]) b1 = e;
        int b2 = -1;
        for (int e = 0; e < 4; e++) { if (e == b1) continue; if (b2 < 0 || pr[e] > pr[b2]) b2 = e; }
        float s2 = pr[b1] + pr[b2];
        float wv[4] = {0.f, 0.f, 0.f, 0.f};
        wv[b1] = pr[b1] / s2; wv[b2] = pr[b2] / s2;
        for (int e = 0; e < 4; e++) wts[e*SEQ + t] = wv[e];
        float mu = (l[0]+l[1]+l[2]+l[3]) * 0.25f;
        float va = ((l[0]-mu)*(l[0]-mu) + (l[1]-mu)*(l[1]-mu) +
                    (l[2]-mu)*(l[2]-mu) + (l[3]-mu)*(l[3]-mu)) / 3.f;
        varr[t] = va;
    }
}

// ---------------- routing compaction ----------------
__global__ void __launch_bounds__(1024) compact_kernel(
    const float* __restrict__ wts, int* __restrict__ cnt,
    int* __restrict__ ridx, float* __restrict__ rwt)
{
    __shared__ int sc[1024];
    int e = blockIdx.x, t = threadIdx.x;
    float w = wts[e*SEQ + t];
    int flag = (w != 0.f) ? 1 : 0;
    sc[t] = flag;
    __syncthreads();
    for (int off = 1; off < 1024; off <<= 1) {
        int v = (t >= off) ? sc[t - off] : 0;
        __syncthreads();
        sc[t] += v;
        __syncthreads();
    }
    if (flag) {
        int pos = sc[t] - 1;
        ridx[e*SEQ + pos] = t;
        rwt [e*SEQ + pos] = w;
    }
    if (t == 1023) cnt[e] = sc[1023];
}

__global__ void aux_kernel(const float* __restrict__ varr, float* __restrict__ out) {
    __shared__ float red[256];
    int tid = threadIdx.x;
    float s = 0.f;
    for (int i = tid; i < SEQ; i += 256) s += varr[i];
    red[tid] = s; __syncthreads();
    for (int st = 128; st > 0; st >>= 1) { if (tid < st) red[tid] += red[tid+st]; __syncthreads(); }
    if (tid == 0) out[0] = red[0] / (float)SEQ;
}

__global__ void zero_kernel(float* __restrict__ p, int n) {
    int i = blockIdx.x * 256 + threadIdx.x;
    if (i < n) p[i] = 0.f;
}

// ---------------- driver ----------------
extern "C" void kernel_launch(void* const* d_in, const int* in_sizes, int n_in,
                              void* d_out, int out_size) {
    const int*   tokens = (const int*)  d_in[0];
    const float* emb    = (const float*)d_in[1];
    const float* wq     = (const float*)d_in[2];
    const float* wk     = (const float*)d_in[3];
    const float* wv     = (const float*)d_in[4];
    const float* wo     = (const float*)d_in[5];
    const float* ln1g   = (const float*)d_in[6];
    const float* ln1b   = (const float*)d_in[7];
    const float* gatew  = (const float*)d_in[8];
    const float* w1     = (const float*)d_in[9];
    const float* w2     = (const float*)d_in[10];
    const float* w3     = (const float*)d_in[11];
    const float* ln2g   = (const float*)d_in[12];
    const float* ln2b   = (const float*)d_in[13];
    const float* fing   = (const float*)d_in[14];
    const float* finb   = (const float*)d_in[15];
    const float* headw  = (const float*)d_in[16];
    float* out = (float*)d_out;

    float *x, *qkv, *y, *moe, *wts, *varr, *rwt, *hbuf;
    int *cnt, *ridx;
    __nv_bfloat16 *ah, *al;
    cudaGetSymbolAddress((void**)&x,    g_x);
    cudaGetSymbolAddress((void**)&qkv,  g_qkv);
    cudaGetSymbolAddress((void**)&y,    g_y);
    cudaGetSymbolAddress((void**)&moe,  g_moe);
    cudaGetSymbolAddress((void**)&wts,  g_wts);
    cudaGetSymbolAddress((void**)&varr, g_var);
    cudaGetSymbolAddress((void**)&hbuf, g_h);
    cudaGetSymbolAddress((void**)&cnt,  g_cnt);
    cudaGetSymbolAddress((void**)&ridx, g_ridx);
    cudaGetSymbolAddress((void**)&rwt,  g_rwt);
    cudaGetSymbolAddress((void**)&ah,   g_ah);
    cudaGetSymbolAddress((void**)&al,   g_al);

    cudaFuncSetAttribute(attn_kernel, cudaFuncAttributeMaxDynamicSharedMemorySize, ATTN_SMEM);
    cudaFuncSetAttribute(gemm_tc<1>, cudaFuncAttributeMaxDynamicSharedMemorySize, GEMM_SMEM_TC);
    cudaFuncSetAttribute(gemm_tc<3>, cudaFuncAttributeMaxDynamicSharedMemorySize, GEMM_SMEM_TC);
    cudaFuncSetAttribute(gemm_tf32, cudaFuncAttributeMaxDynamicSharedMemorySize, GEMM_SMEM_TF);
    cudaFuncSetAttribute(gemm_tf32_moe, cudaFuncAttributeMaxDynamicSharedMemorySize, GEMM_SMEM_TF);

    // 1) embed (+ fused split)
    embed_kernel<<<SEQ, 256>>>(tokens, emb, x, ah, al);

    // 2) fused QKV (N=6144), split-K2 atomic
    zero_kernel<<<(SEQ*3*D_MODEL + 255)/256, 256>>>(qkv, SEQ*3*D_MODEL);
    dim3 gQKV(SEQ/128, 3*D_MODEL/256, 2);
    gemm_tc<3><<<gQKV, 256, GEMM_SMEM_TC>>>(ah, al, wq, wk, wv, D_MODEL,
                                            qkv, 3*D_MODEL, D_MODEL,
                                            nullptr, nullptr, 0, nullptr);

    // 3) RoPE + attention (emits pre-split ah/al)
    rope_kernel<<<dim3(SEQ, N_HEADS), 32>>>(qkv);
    attn_kernel<<<dim3(NB, N_HEADS), 256, ATTN_SMEM>>>(qkv, ah, al);

    // 4) output proj, split-K4 atomic -> y ; residual folded into LN1
    zero_kernel<<<(SEQ*D_MODEL + 255)/256, 256>>>(y, SEQ*D_MODEL);
    dim3 gA(SEQ/128, D_MODEL/256, 4);
    gemm_tc<3><<<gA, 256, GEMM_SMEM_TC>>>(ah, al, wo, wo, wo, D_MODEL,
                                          y, D_MODEL, D_MODEL,
                                          nullptr, nullptr, 0, nullptr);

    // 5) LN1(y + x) -> x (+ fused split to ah/al)
    ln_kernel<<<SEQ, 256>>>(y, x, ln1g, ln1b, x, ah, al);

    // 6) gate + routing
    gate_kernel<<<SEQ, 128>>>(x, gatew, wts, varr);
    compact_kernel<<<NEXP, 1024>>>(wts, cnt, ridx, rwt);

    // 7) MoE — up (fused silu, fp32 H) then tf32 down (weighted atomic scatter)
    zero_kernel<<<(SEQ*D_MODEL + 255)/256, 256>>>(moe, SEQ*D_MODEL);
    const long long FD = (long long)D_FFN * D_MODEL;
    dim3 gUp(SEQ/128, 2*D_FFN/256, NEXP);
    gemm_tc<1><<<gUp, 256, GEMM_SMEM_TC>>>(ah, al, w1, w3, nullptr, 0,
                                           nullptr, 2*D_FFN, D_MODEL,
                                           cnt, ridx, FD, hbuf);
    dim3 gDn(SEQ/128, D_MODEL/256, NEXP*4);
    gemm_tf32_moe<<<gDn, 256, GEMM_SMEM_TF>>>(hbuf, w2, moe, D_MODEL, D_FFN,
                                              cnt, ridx, rwt);

    // 8) fused LN2 + final LN
    ln2_kernel<<<SEQ, 256>>>(moe, x, ln2g, ln2b, fing, finb, y);

    // 9) head (tf32 single-pass)
    dim3 gH(SEQ/128, (VOCAB + 255)/256);
    gemm_tf32<<<gH, 256, GEMM_SMEM_TF>>>(y, headw, out, SEQ, VOCAB, D_MODEL);

    // 10) aux
    long long nlog = (long long)SEQ * VOCAB;
    if ((long long)out_size > nlog)
        aux_kernel<<<1, 256>>>(varr, out + nlog);
}

// round 14
// speedup vs baseline: 5.4370x; 1.0206x over previous
#include <cuda_runtime.h>
#include <cuda_bf16.h>
#include <math.h>
#include <stdint.h>

#define D_MODEL 2048
#define SEQ     1024
#define N_HEADS 32
#define HEAD_DIM 64
#define NB      (SEQ/64)
#define D_FFN   8192
#define VOCAB   50257
#define NEXP    4
#define QKV_STRIDE (3*D_MODEL)

// ---------------- scratch ----------------
__device__ float g_x  [SEQ*D_MODEL];
__device__ float g_qkv[SEQ*3*D_MODEL];
__device__ float g_y  [SEQ*D_MODEL];
__device__ float g_moe[SEQ*D_MODEL];
__device__ float g_wts[NEXP*SEQ];
__device__ float g_var[SEQ];
__device__ float g_h  [(size_t)NEXP*SEQ*D_FFN];   // fp32 silu(h1)*h3 per expert

// routing
__device__ int   g_cnt[NEXP];
__device__ int   g_ridx[NEXP*SEQ];
__device__ float g_rwt [NEXP*SEQ];

// bf16 split scratch (d_model activations)
__device__ __nv_bfloat16 g_ah[SEQ*D_MODEL];
__device__ __nv_bfloat16 g_al[SEQ*D_MODEL];

// ---------------- PTX helpers ----------------
__device__ __forceinline__ uint32_t smem_u32(const void* p) {
    uint32_t a;
    asm("{ .reg .u64 t; cvta.to.shared.u64 t, %1; cvt.u32.u64 %0, t; }" : "=r"(a) : "l"(p));
    return a;
}
__device__ __forceinline__ void cp_async16(uint32_t dst, const void* src, int src_bytes) {
    asm volatile("cp.async.cg.shared.global [%0], [%1], 16, %2;\n"
                 :: "r"(dst), "l"(src), "r"(src_bytes) : "memory");
}
#define CP_COMMIT() asm volatile("cp.async.commit_group;\n" ::: "memory")

#define STS128(addr, a, b, c, d) \
    asm volatile("st.shared.v4.b32 [%0], {%1,%2,%3,%4};" \
                 :: "r"(addr), "r"(a), "r"(b), "r"(c), "r"(d) : "memory")

__device__ __forceinline__ void ldsm_x4(uint32_t& r0, uint32_t& r1, uint32_t& r2, uint32_t& r3,
                                        uint32_t addr) {
    asm volatile("ldmatrix.sync.aligned.m8n8.x4.shared.b16 {%0,%1,%2,%3}, [%4];"
                 : "=r"(r0), "=r"(r1), "=r"(r2), "=r"(r3) : "r"(addr));
}
__device__ __forceinline__ void mma_bf16(float* c, const uint32_t* a, const uint32_t* b) {
    asm volatile(
        "mma.sync.aligned.m16n8k16.row.col.f32.bf16.bf16.f32 "
        "{%0,%1,%2,%3}, {%4,%5,%6,%7}, {%8,%9}, {%0,%1,%2,%3};"
        : "+f"(c[0]), "+f"(c[1]), "+f"(c[2]), "+f"(c[3])
        : "r"(a[0]), "r"(a[1]), "r"(a[2]), "r"(a[3]), "r"(b[0]), "r"(b[1]));
}
__device__ __forceinline__ void mma_tf32(float* c, const uint32_t* a, const uint32_t* b) {
    asm volatile(
        "mma.sync.aligned.m16n8k8.row.col.f32.tf32.tf32.f32 "
        "{%0,%1,%2,%3}, {%4,%5,%6,%7}, {%8,%9}, {%0,%1,%2,%3};"
        : "+f"(c[0]), "+f"(c[1]), "+f"(c[2]), "+f"(c[3])
        : "r"(a[0]), "r"(a[1]), "r"(a[2]), "r"(a[3]), "r"(b[0]), "r"(b[1]));
}

__device__ __forceinline__ void split2(float a, float b, uint32_t& hi, uint32_t& lo) {
    __nv_bfloat16 ha = __float2bfloat16(a), hb = __float2bfloat16(b);
    __nv_bfloat162 h; h.x = ha; h.y = hb;
    __nv_bfloat162 l;
    l.x = __float2bfloat16(a - __bfloat162float(ha));
    l.y = __float2bfloat16(b - __bfloat162float(hb));
    hi = *(uint32_t*)&h;
    lo = *(uint32_t*)&l;
}

// ================= bf16x3 GEMM: CTA 128x256, 8 warps (2Mx4N), warp 64x64 =================
#define NSTG_TC 3
#define A_BYTES (128*128)
#define B_BYTES (256*128)
#define STAGE_B (A_BYTES + B_BYTES)
#define GEMM_SMEM_TC (NSTG_TC * STAGE_B)
#define NSTG_TF 4
#define GEMM_SMEM_TF (NSTG_TF * STAGE_B)

// MODE 1: expert-batched up + FUSED silu·mul -> fp32 H. e=blockIdx.z, A rows via ridx[e],
//         B rows interleaved even->B0(w1) odd->B1(w3) (per-expert slab via sB).
// MODE 3: dense rows, split-K via gridDim.z, atomicAdd into zeroed C. B rows: <rPB->B0,<2rPB->B1,else B2.
template<int MODE>
__global__ void __launch_bounds__(256, 1) gemm_tc(
    const __nv_bfloat16* __restrict__ Ah, const __nv_bfloat16* __restrict__ Al,
    const float* __restrict__ B0, const float* __restrict__ B1, const float* __restrict__ B2,
    int rPB,
    float* __restrict__ C, int N, int K,
    const int* __restrict__ cntArr, const int* __restrict__ ridxAll,
    long long sB, float* __restrict__ Hout)
{
    const int tid = threadIdx.x;
    const int m0  = blockIdx.x * 128;
    const int n0  = blockIdx.y * 256;

    int M = SEQ;
    int e = 0, kbase = 0, Kc = K;
    const int* ridx = ridxAll;
    const float* b0p = B0; const float* b1p = B1; const float* b2p = B2;

    if (MODE == 1) {
        e = blockIdx.z;
        M = cntArr[e];
        if (m0 >= M) return;
        ridx = ridxAll + e * SEQ;
        b0p = B0 + (size_t)e * sB;
        b1p = B1 + (size_t)e * sB;
    } else { // MODE 3
        Kc = K / (int)gridDim.z;
        kbase = (int)blockIdx.z * Kc;
    }

    int arow[4];
    #pragma unroll
    for (int i = 0; i < 4; i++) {
        int r = (tid + i * 256) >> 3;
        int rg = m0 + r;
        if (MODE == 3) arow[i] = rg;
        else {
            rg = rg < M ? rg : (M - 1);
            arow[i] = ridx[rg];
        }
    }

    extern __shared__ char smem[];
    const uint32_t sb = smem_u32(smem);
    const int wid = tid >> 5, lid = tid & 31;
    const int wm  = wid >> 2, wn = wid & 3;

    float acc[4][8][4];
    #pragma unroll
    for (int i = 0; i < 4; i++)
        #pragma unroll
        for (int j = 0; j < 8; j++)
            #pragma unroll
            for (int t = 0; t < 4; t++) acc[i][j][t] = 0.f;

    const int iters = Kc >> 5;

    auto fillA = [&](int stage, int kit) {
        const int k0 = kbase + (kit << 5);
        const uint32_t abase = sb + stage * STAGE_B;
        #pragma unroll
        for (int i = 0; i < 4; i++) {
            int idx = tid + i * 256;
            int r = idx >> 3, c = idx & 7;
            uint32_t dst = abase + r * 128 + ((c ^ (r & 7)) << 4);
            const __nv_bfloat16* src = (c < 4)
                ? Ah + (size_t)arow[i] * K + k0 + c * 8
                : Al + (size_t)arow[i] * K + k0 + (c - 4) * 8;
            cp_async16(dst, src, 16);
        }
        CP_COMMIT();
    };

    auto ldgB = [&](float4* breg, int kit) {
        const int k0 = kbase + (kit << 5);
        #pragma unroll
        for (int i = 0; i < 4; i++) {
            int idx = tid + i * 256;
            int r = idx >> 2, c2 = idx & 3;
            int rg = n0 + r;
            int rc = rg < N ? rg : (N - 1);
            const float* Bp; int rr;
            if (MODE == 1)          { Bp = (rc & 1) ? b1p : b0p; rr = rc >> 1; }
            else if (rc < rPB)      { Bp = b0p; rr = rc; }
            else if (rc < 2 * rPB)  { Bp = b1p; rr = rc - rPB; }
            else                    { Bp = b2p; rr = rc - 2 * rPB; }
            const float4* s4 = (const float4*)(Bp + (size_t)rr * K + k0 + c2 * 8);
            breg[i*2]     = s4[0];
            breg[i*2 + 1] = s4[1];
        }
    };

    auto stsB = [&](const float4* breg, int stage) {
        const uint32_t bbase = sb + stage * STAGE_B + A_BYTES;
        #pragma unroll
        for (int i = 0; i < 4; i++) {
            int idx = tid + i * 256;
            int r = idx >> 2, c2 = idx & 3;
            float4 v0 = breg[i*2], v1 = breg[i*2 + 1];
            uint32_t h0, h1, h2, h3, l0, l1, l2, l3;
            split2(v0.x, v0.y, h0, l0);
            split2(v0.z, v0.w, h1, l1);
            split2(v1.x, v1.y, h2, l2);
            split2(v1.z, v1.w, h3, l3);
            uint32_t ha = bbase + r * 128 + ((c2 ^ (r & 7)) << 4);
            uint32_t la = bbase + r * 128 + (((c2 + 4) ^ (r & 7)) << 4);
            STS128(ha, h0, h1, h2, h3);
            STS128(la, l0, l1, l2, l3);
        }
    };

    {
        float4 pb[8];
        #pragma unroll
        for (int s = 0; s < NSTG_TC - 1; s++) {
            fillA(s, s);
            ldgB(pb, s);
            stsB(pb, s);
        }
    }

    const int grp = lid >> 3;
    const int rin = lid & 7;
    float4 breg[8];

    for (int i = 0; i < iters; i++) {
        const int s = i % NSTG_TC;
        const bool pre = (i + NSTG_TC - 1 < iters);
        if (pre) ldgB(breg, i + NSTG_TC - 1);

        asm volatile("cp.async.wait_group %0;\n" :: "n"(NSTG_TC - 2));
        __syncthreads();

        if (pre) fillA((i + NSTG_TC - 1) % NSTG_TC, i + NSTG_TC - 1);
        else CP_COMMIT();

        const uint32_t abase = sb + s * STAGE_B;
        const uint32_t bbase = abase + A_BYTES;

        #pragma unroll
        for (int g = 0; g < 2; g++) {
            uint32_t ah[4][4], bh[8][2];
            #pragma unroll
            for (int mt = 0; mt < 4; mt++) {
                int row = wm * 64 + mt * 16 + (grp & 1) * 8 + rin;
                int kch = 2 * g + (grp >> 1);
                uint32_t ad = abase + row * 128 + ((kch ^ (row & 7)) << 4);
                ldsm_x4(ah[mt][0], ah[mt][1], ah[mt][2], ah[mt][3], ad);
            }
            #pragma unroll
            for (int p = 0; p < 4; p++) {
                int tile = 2 * p + (grp >> 1);
                int row  = wn * 64 + tile * 8 + rin;
                int kch  = 2 * g + (grp & 1);
                uint32_t bd = bbase + row * 128 + ((kch ^ (row & 7)) << 4);
                ldsm_x4(bh[2*p][0], bh[2*p][1], bh[2*p+1][0], bh[2*p+1][1], bd);
            }
            #pragma unroll
            for (int mt = 0; mt < 4; mt++)
                #pragma unroll
                for (int nt = 0; nt < 8; nt++)
                    mma_bf16(acc[mt][nt], ah[mt], bh[nt]);
            {
                uint32_t al[4][4];
                #pragma unroll
                for (int mt = 0; mt < 4; mt++) {
                    int row = wm * 64 + mt * 16 + (grp & 1) * 8 + rin;
                    int kcl = 4 + 2 * g + (grp >> 1);
                    uint32_t adl = abase + row * 128 + ((kcl ^ (row & 7)) << 4);
                    ldsm_x4(al[mt][0], al[mt][1], al[mt][2], al[mt][3], adl);
                }
                #pragma unroll
                for (int mt = 0; mt < 4; mt++)
                    #pragma unroll
                    for (int nt = 0; nt < 8; nt++)
                        mma_bf16(acc[mt][nt], al[mt], bh[nt]);
            }
            {
                uint32_t bl[8][2];
                #pragma unroll
                for (int p = 0; p < 4; p++) {
                    int tile = 2 * p + (grp >> 1);
                    int row  = wn * 64 + tile * 8 + rin;
                    int kcl  = 4 + 2 * g + (grp & 1);
                    uint32_t bdl = bbase + row * 128 + ((kcl ^ (row & 7)) << 4);
                    ldsm_x4(bl[2*p][0], bl[2*p][1], bl[2*p+1][0], bl[2*p+1][1], bdl);
                }
                #pragma unroll
                for (int mt = 0; mt < 4; mt++)
                    #pragma unroll
                    for (int nt = 0; nt < 8; nt++)
                        mma_bf16(acc[mt][nt], ah[mt], bl[nt]);
            }
        }

        if (pre) stsB(breg, (i + NSTG_TC - 1) % NSTG_TC);
    }

    #pragma unroll
    for (int mt = 0; mt < 4; mt++) {
        #pragma unroll
        for (int nt = 0; nt < 8; nt++) {
            int rbase = m0 + wm * 64 + mt * 16 + (lid >> 2);
            int col = n0 + wn * 64 + nt * 8 + (lid & 3) * 2;
            #pragma unroll
            for (int h = 0; h < 2; h++) {
                int m = rbase + h * 8;
                float v0 = acc[mt][nt][h * 2 + 0];
                float v1 = acc[mt][nt][h * 2 + 1];
                if (MODE == 1) {
                    if (m < M) {
                        int j = col >> 1;  // (v0,v1) = (h1_j, h3_j)
                        float r = v0 / (1.f + expf(-v0)) * v1;
                        Hout[(size_t)e * SEQ * D_FFN + (size_t)m * D_FFN + j] = r;
                    }
                } else { // MODE 3: split-K atomic accumulate
                    size_t idx = (size_t)m * N + col;
                    if (col     < N) atomicAdd(&C[idx],     v0);
                    if (col + 1 < N) atomicAdd(&C[idx + 1], v1);
                }
            }
        }
    }
}

// ================= tf32 single-pass GEMM (head) =================
__global__ void __launch_bounds__(256, 1) gemm_tf32(
    const float* __restrict__ A, const float* __restrict__ B,
    float* __restrict__ C, int M, int N, int K)
{
    extern __shared__ char smem[];
    const uint32_t sb = smem_u32(smem);
    const int tid = threadIdx.x;
    const int wid = tid >> 5, lid = tid & 31;
    const int wm  = wid >> 2, wn = wid & 3;
    const int m0  = blockIdx.x * 128;
    const int n0  = blockIdx.y * 256;

    float acc[4][8][4];
    #pragma unroll
    for (int i = 0; i < 4; i++)
        #pragma unroll
        for (int j = 0; j < 8; j++)
            #pragma unroll
            for (int t = 0; t < 4; t++) acc[i][j][t] = 0.f;

    const int iters = K >> 5;

    auto fill = [&](int stage, int kit) {
        const int k0 = kit << 5;
        const uint32_t abase = sb + stage * STAGE_B;
        const uint32_t bbase = abase + A_BYTES;
        #pragma unroll
        for (int i = 0; i < 4; i++) {
            int idx = tid + i * 256;
            int r = idx >> 3, c = idx & 7;
            uint32_t dst = abase + r * 128 + ((c ^ (r & 7)) << 4);
            cp_async16(dst, A + (size_t)(m0 + r) * K + k0 + c * 4, 16);
        }
        #pragma unroll
        for (int i = 0; i < 8; i++) {
            int idx = tid + i * 256;
            int r = idx >> 3, c = idx & 7;
            uint32_t dst = bbase + r * 128 + ((c ^ (r & 7)) << 4);
            int rg = n0 + r;
            int rc = rg < N ? rg : (N - 1);
            cp_async16(dst, B + (size_t)rc * K + k0 + c * 4, rg < N ? 16 : 0);
        }
        CP_COMMIT();
    };

    #pragma unroll
    for (int s = 0; s < NSTG_TF - 1; s++) fill(s, s);

    const int grp = lid >> 3;
    const int rin = lid & 7;

    for (int i = 0; i < iters; i++) {
        const int s = i % NSTG_TF;
        asm volatile("cp.async.wait_group %0;\n" :: "n"(NSTG_TF - 2));
        __syncthreads();

        if (i + NSTG_TF - 1 < iters) fill((i + NSTG_TF - 1) % NSTG_TF, i + NSTG_TF - 1);
        else CP_COMMIT();

        const uint32_t abase = sb + s * STAGE_B;
        const uint32_t bbase = abase + A_BYTES;

        #pragma unroll
        for (int k8 = 0; k8 < 4; k8++) {
            uint32_t a[4][4], b[8][2];
            #pragma unroll
            for (int mt = 0; mt < 4; mt++) {
                int row = wm * 64 + mt * 16 + (grp & 1) * 8 + rin;
                int kc  = k8 * 2 + (grp >> 1);
                uint32_t addr = abase + row * 128 + ((kc ^ (row & 7)) << 4);
                ldsm_x4(a[mt][0], a[mt][1], a[mt][2], a[mt][3], addr);
            }
            #pragma unroll
            for (int p = 0; p < 4; p++) {
                int tile = 2 * p + (grp >> 1);
                int row  = wn * 64 + tile * 8 + rin;
                int kc   = k8 * 2 + (grp & 1);
                uint32_t addr = bbase + row * 128 + ((kc ^ (row & 7)) << 4);
                ldsm_x4(b[2*p][0], b[2*p][1], b[2*p+1][0], b[2*p+1][1], addr);
            }
            #pragma unroll
            for (int mt = 0; mt < 4; mt++)
                #pragma unroll
                for (int nt = 0; nt < 8; nt++)
                    mma_tf32(acc[mt][nt], a[mt], b[nt]);
        }
    }

    #pragma unroll
    for (int mt = 0; mt < 4; mt++) {
        #pragma unroll
        for (int nt = 0; nt < 8; nt++) {
            int rbase = m0 + wm * 64 + mt * 16 + (lid >> 2);
            int col = n0 + wn * 64 + nt * 8 + (lid & 3) * 2;
            #pragma unroll
            for (int h = 0; h < 2; h++) {
                int m = rbase + h * 8;
                size_t idx = (size_t)m * N + col;
                if (col     < N) C[idx]     = acc[mt][nt][h * 2 + 0];
                if (col + 1 < N) C[idx + 1] = acc[mt][nt][h * 2 + 1];
            }
        }
    }
}

// ================= tf32 MoE down-proj: expert slab + split-K4 + weighted atomic scatter =========
__global__ void __launch_bounds__(256, 1) gemm_tf32_moe(
    const float* __restrict__ H, const float* __restrict__ W2,
    float* __restrict__ C, int N, int K,
    const int* __restrict__ cntArr, const int* __restrict__ ridxAll,
    const float* __restrict__ rwtAll)
{
    const int tid = threadIdx.x;
    const int m0  = blockIdx.x * 128;
    const int n0  = blockIdx.y * 256;
    const int e   = blockIdx.z >> 2;
    const int ks  = blockIdx.z & 3;
    const int M   = cntArr[e];
    if (m0 >= M) return;
    const int* ridx = ridxAll + e * SEQ;
    const float* rwt = rwtAll + e * SEQ;
    const float* A = H  + (size_t)e * SEQ * D_FFN;
    const float* B = W2 + (size_t)e * D_FFN * D_MODEL;
    const int Kc    = K >> 2;
    const int kbase = ks * Kc;

    int arow[4];
    #pragma unroll
    for (int i = 0; i < 4; i++) {
        int r = (tid + i * 256) >> 3;
        int rg = m0 + r;
        arow[i] = rg < M ? rg : (M - 1);
    }

    extern __shared__ char smem[];
    const uint32_t sb = smem_u32(smem);
    const int wid = tid >> 5, lid = tid & 31;
    const int wm  = wid >> 2, wn = wid & 3;

    float acc[4][8][4];
    #pragma unroll
    for (int i = 0; i < 4; i++)
        #pragma unroll
        for (int j = 0; j < 8; j++)
            #pragma unroll
            for (int t = 0; t < 4; t++) acc[i][j][t] = 0.f;

    const int iters = Kc >> 5;

    auto fill = [&](int stage, int kit) {
        const int k0 = kbase + (kit << 5);
        const uint32_t abase = sb + stage * STAGE_B;
        const uint32_t bbase = abase + A_BYTES;
        #pragma unroll
        for (int i = 0; i < 4; i++) {
            int idx = tid + i * 256;
            int r = idx >> 3, c = idx & 7;
            uint32_t dst = abase + r * 128 + ((c ^ (r & 7)) << 4);
            cp_async16(dst, A + (size_t)arow[i] * K + k0 + c * 4, 16);
        }
        #pragma unroll
        for (int i = 0; i < 8; i++) {
            int idx = tid + i * 256;
            int r = idx >> 3, c = idx & 7;
            uint32_t dst = bbase + r * 128 + ((c ^ (r & 7)) << 4);
            int rg = n0 + r;
            int rc = rg < N ? rg : (N - 1);
            cp_async16(dst, B + (size_t)rc * K + k0 + c * 4, rg < N ? 16 : 0);
        }
        CP_COMMIT();
    };

    #pragma unroll
    for (int s = 0; s < NSTG_TF - 1; s++) fill(s, s);

    const int grp = lid >> 3;
    const int rin = lid & 7;

    for (int i = 0; i < iters; i++) {
        const int s = i % NSTG_TF;
        asm volatile("cp.async.wait_group %0;\n" :: "n"(NSTG_TF - 2));
        __syncthreads();

        if (i + NSTG_TF - 1 < iters) fill((i + NSTG_TF - 1) % NSTG_TF, i + NSTG_TF - 1);
        else CP_COMMIT();

        const uint32_t abase = sb + s * STAGE_B;
        const uint32_t bbase = abase + A_BYTES;

        #pragma unroll
        for (int k8 = 0; k8 < 4; k8++) {
            uint32_t a[4][4], b[8][2];
            #pragma unroll
            for (int mt = 0; mt < 4; mt++) {
                int row = wm * 64 + mt * 16 + (grp & 1) * 8 + rin;
                int kc  = k8 * 2 + (grp >> 1);
                uint32_t addr = abase + row * 128 + ((kc ^ (row & 7)) << 4);
                ldsm_x4(a[mt][0], a[mt][1], a[mt][2], a[mt][3], addr);
            }
            #pragma unroll
            for (int p = 0; p < 4; p++) {
                int tile = 2 * p + (grp >> 1);
                int row  = wn * 64 + tile * 8 + rin;
                int kc   = k8 * 2 + (grp & 1);
                uint32_t addr = bbase + row * 128 + ((kc ^ (row & 7)) << 4);
                ldsm_x4(b[2*p][0], b[2*p][1], b[2*p+1][0], b[2*p+1][1], addr);
            }
            #pragma unroll
            for (int mt = 0; mt < 4; mt++)
                #pragma unroll
                for (int nt = 0; nt < 8; nt++)
                    mma_tf32(acc[mt][nt], a[mt], b[nt]);
        }
    }

    #pragma unroll
    for (int mt = 0; mt < 4; mt++) {
        #pragma unroll
        for (int nt = 0; nt < 8; nt++) {
            int rbase = m0 + wm * 64 + mt * 16 + (lid >> 2);
            int col = n0 + wn * 64 + nt * 8 + (lid & 3) * 2;
            #pragma unroll
            for (int h = 0; h < 2; h++) {
                int m = rbase + h * 8;
                if (m < M) {
                    int tok = ridx[m];
                    float w = rwt[m];
                    size_t idx = (size_t)tok * N + col;
                    atomicAdd(&C[idx],     w * acc[mt][nt][h * 2 + 0]);
                    atomicAdd(&C[idx + 1], w * acc[mt][nt][h * 2 + 1]);
                }
            }
        }
    }
}

// ---------------- embedding (+ fused split) ----------------
__global__ void embed_kernel(const int* __restrict__ tok,
                             const float* __restrict__ emb,
                             float* __restrict__ x,
                             __nv_bfloat16* __restrict__ ah,
                             __nv_bfloat16* __restrict__ al) {
    int t = blockIdx.x;
    int tk = tok[t];
    const float2* src = (const float2*)(emb + (size_t)tk * D_MODEL);
    float2* dst = (float2*)(x + (size_t)t * D_MODEL);
    uint32_t* hd = (uint32_t*)(ah + (size_t)t * D_MODEL);
    uint32_t* ld = (uint32_t*)(al + (size_t)t * D_MODEL);
    for (int p = threadIdx.x; p < D_MODEL/2; p += 256) {
        float2 v = src[p];
        dst[p] = v;
        uint32_t h, l;
        split2(v.x, v.y, h, l);
        hd[p] = h;
        ld[p] = l;
    }
}

// ---------------- RoPE ----------------
__global__ void rope_kernel(float* __restrict__ qkv) {
    int t = blockIdx.x, h = blockIdx.y, i = threadIdx.x;
    float inv = powf(10000.f, -((float)(2*i)) / 64.f);
    float ang = (float)t * inv;
    float s, c;
    sincosf(ang, &s, &c);
    size_t base = (size_t)t*QKV_STRIDE + h*HEAD_DIM + 2*i;
    float q0 = qkv[base], q1 = qkv[base+1];
    qkv[base]   = q0*c - q1*s;
    qkv[base+1] = q0*s + q1*c;
    size_t kb = base + D_MODEL;
    float k0 = qkv[kb], k1 = qkv[kb+1];
    qkv[kb]   = k0*c - k1*s;
    qkv[kb+1] = k0*s + k1*c;
}

// ---------------- blocked attention: 4x4 register tiles, Q/K/P transposed ----------------
#define ATTN_SMEM (4 * 64 * 68 * 4)
__global__ void __launch_bounds__(256) attn_kernel(
    const float* __restrict__ qkv,
    __nv_bfloat16* __restrict__ oh, __nv_bfloat16* __restrict__ ol)
{
    extern __shared__ float sm[];
    float* Qst = sm;
    float* Kst = Qst + 64*68;
    float* Vs  = Kst + 64*68;
    float* Pst = Vs + 64*68;
    const int ib = blockIdx.x, h = blockIdx.y;
    const int tid = threadIdx.x;
    const int qg  = tid >> 4;
    const int cg  = tid & 15;
    const int qr0 = qg * 4;
    const int c0  = cg * 4;

    for (int idx = tid; idx < 64*64; idx += 256) {
        int r = idx >> 6, c = idx & 63;
        Qst[c*68 + r] = qkv[(size_t)(ib*64+r)*QKV_STRIDE + h*HEAD_DIM + c];
    }

    float accO[4][4];
    #pragma unroll
    for (int i = 0; i < 4; i++)
        #pragma unroll
        for (int j = 0; j < 4; j++) accO[i][j] = 0.f;
    float den[4] = {0.f, 0.f, 0.f, 0.f};

    for (int jb = 0; jb <= ib; jb++) {
        __syncthreads();
        for (int idx = tid; idx < 64*64; idx += 256) {
            int r = idx >> 6, c = idx & 63;
            size_t base = (size_t)(jb*64+r)*QKV_STRIDE + h*HEAD_DIM + c;
            Kst[c*68 + r] = qkv[base + D_MODEL];
            Vs [r*68 + c] = qkv[base + 2*D_MODEL];
        }
        __syncthreads();

        float s4[4][4];
        #pragma unroll
        for (int i = 0; i < 4; i++)
            #pragma unroll
            for (int j = 0; j < 4; j++) s4[i][j] = 0.f;

        #pragma unroll 4
        for (int d = 0; d < 64; d++) {
            float4 qv = *(const float4*)&Qst[d*68 + qr0];
            float4 kv = *(const float4*)&Kst[d*68 + c0];
            s4[0][0] = fmaf(qv.x, kv.x, s4[0][0]); s4[0][1] = fmaf(qv.x, kv.y, s4[0][1]);
            s4[0][2] = fmaf(qv.x, kv.z, s4[0][2]); s4[0][3] = fmaf(qv.x, kv.w, s4[0][3]);
            s4[1][0] = fmaf(qv.y, kv.x, s4[1][0]); s4[1][1] = fmaf(qv.y, kv.y, s4[1][1]);
            s4[1][2] = fmaf(qv.y, kv.z, s4[1][2]); s4[1][3] = fmaf(qv.y, kv.w, s4[1][3]);
            s4[2][0] = fmaf(qv.z, kv.x, s4[2][0]); s4[2][1] = fmaf(qv.z, kv.y, s4[2][1]);
            s4[2][2] = fmaf(qv.z, kv.z, s4[2][2]); s4[2][3] = fmaf(qv.z, kv.w, s4[2][3]);
            s4[3][0] = fmaf(qv.w, kv.x, s4[3][0]); s4[3][1] = fmaf(qv.w, kv.y, s4[3][1]);
            s4[3][2] = fmaf(qv.w, kv.z, s4[3][2]); s4[3][3] = fmaf(qv.w, kv.w, s4[3][3]);
        }

        float mx[4];
        #pragma unroll
        for (int i = 0; i < 4; i++) {
            mx[i] = -1e30f;
            int q = qr0 + i;
            #pragma unroll
            for (int j = 0; j < 4; j++) {
                int c = c0 + j;
                float v = s4[i][j] * 0.125f;
                if (jb == ib && c > q) v = -1e30f;
                s4[i][j] = v;
                mx[i] = fmaxf(mx[i], v);
            }
        }
        #pragma unroll
        for (int o = 1; o < 16; o <<= 1) {
            #pragma unroll
            for (int i = 0; i < 4; i++)
                mx[i] = fmaxf(mx[i], __shfl_xor_sync(0xffffffffu, mx[i], o));
        }

        #pragma unroll
        for (int j = 0; j < 4; j++) {
            float p0 = expf(s4[0][j] - mx[0]);
            float p1 = expf(s4[1][j] - mx[1]);
            float p2 = expf(s4[2][j] - mx[2]);
            float p3 = expf(s4[3][j] - mx[3]);
            den[0] += p0; den[1] += p1; den[2] += p2; den[3] += p3;
            *(float4*)&Pst[(c0 + j)*68 + qr0] = make_float4(p0, p1, p2, p3);
        }
        __syncthreads();

        #pragma unroll 4
        for (int kk = 0; kk < 64; kk++) {
            float4 pv = *(const float4*)&Pst[kk*68 + qr0];
            float4 vv = *(const float4*)&Vs [kk*68 + c0];
            accO[0][0] = fmaf(pv.x, vv.x, accO[0][0]); accO[0][1] = fmaf(pv.x, vv.y, accO[0][1]);
            accO[0][2] = fmaf(pv.x, vv.z, accO[0][2]); accO[0][3] = fmaf(pv.x, vv.w, accO[0][3]);
            accO[1][0] = fmaf(pv.y, vv.x, accO[1][0]); accO[1][1] = fmaf(pv.y, vv.y, accO[1][1]);
            accO[1][2] = fmaf(pv.y, vv.z, accO[1][2]); accO[1][3] = fmaf(pv.y, vv.w, accO[1][3]);
            accO[2][0] = fmaf(pv.z, vv.x, accO[2][0]); accO[2][1] = fmaf(pv.z, vv.y, accO[2][1]);
            accO[2][2] = fmaf(pv.z, vv.z, accO[2][2]); accO[2][3] = fmaf(pv.z, vv.w, accO[2][3]);
            accO[3][0] = fmaf(pv.w, vv.x, accO[3][0]); accO[3][1] = fmaf(pv.w, vv.y, accO[3][1]);
            accO[3][2] = fmaf(pv.w, vv.z, accO[3][2]); accO[3][3] = fmaf(pv.w, vv.w, accO[3][3]);
        }
    }

    #pragma unroll
    for (int o = 1; o < 16; o <<= 1) {
        #pragma unroll
        for (int i = 0; i < 4; i++)
            den[i] += __shfl_xor_sync(0xffffffffu, den[i], o);
    }

    #pragma unroll
    for (int i = 0; i < 4; i++) {
        float invd = 1.f / (den[i] + 1e-6f);
        size_t obase = (size_t)(ib*64 + qr0 + i)*D_MODEL + h*HEAD_DIM + c0;
        uint32_t h0, l0, h1, l1;
        split2(accO[i][0]*invd, accO[i][1]*invd, h0, l0);
        split2(accO[i][2]*invd, accO[i][3]*invd, h1, l1);
        uint32_t* hd = (uint32_t*)(oh + obase);
        uint32_t* ld = (uint32_t*)(ol + obase);
        hd[0] = h0; hd[1] = h1;
        ld[0] = l0; ld[1] = l1;
    }
}

// ---------------- layernorm (optional residual, optional split output) ----------------
__global__ void __launch_bounds__(256) ln_kernel(
    const float* __restrict__ in, const float* __restrict__ res,
    const float* __restrict__ g, const float* __restrict__ b,
    float* __restrict__ out,
    __nv_bfloat16* __restrict__ hi, __nv_bfloat16* __restrict__ lo)
{
    __shared__ float red[256];
    int t = blockIdx.x, tid = threadIdx.x;
    float v[8];
    float sum = 0.f;
    #pragma unroll
    for (int i = 0; i < 8; i++) {
        int d = i*256 + tid;
        float x = in[(size_t)t*D_MODEL + d];
        if (res) x += res[(size_t)t*D_MODEL + d];
        v[i] = x; sum += x;
    }
    red[tid] = sum; __syncthreads();
    for (int s = 128; s > 0; s >>= 1) { if (tid < s) red[tid] += red[tid+s]; __syncthreads(); }
    float mu = red[0] / D_MODEL;
    __syncthreads();
    float sq = 0.f;
    #pragma unroll
    for (int i = 0; i < 8; i++) { float d0 = v[i] - mu; sq += d0*d0; }
    red[tid] = sq; __syncthreads();
    for (int s = 128; s > 0; s >>= 1) { if (tid < s) red[tid] += red[tid+s]; __syncthreads(); }
    float rstd = rsqrtf(red[0] / D_MODEL + 1e-5f);
    #pragma unroll
    for (int i = 0; i < 8; i++) {
        int d = i*256 + tid;
        float val = (v[i] - mu) * rstd * g[d] + b[d];
        out[(size_t)t*D_MODEL + d] = val;
        if (hi) {
            __nv_bfloat16 hv = __float2bfloat16(val);
            hi[(size_t)t*D_MODEL + d] = hv;
            lo[(size_t)t*D_MODEL + d] = __float2bfloat16(val - __bfloat162float(hv));
        }
    }
}

// ---------------- fused double layernorm: out = LNf(LN2(in+res)) ----------------
__global__ void __launch_bounds__(256) ln2_kernel(
    const float* __restrict__ in, const float* __restrict__ res,
    const float* __restrict__ g2, const float* __restrict__ b2,
    const float* __restrict__ gf, const float* __restrict__ bf,
    float* __restrict__ out)
{
    __shared__ float red[256];
    int t = blockIdx.x, tid = threadIdx.x;
    float v[8];
    float sum = 0.f;
    #pragma unroll
    for (int i = 0; i < 8; i++) {
        int d = i*256 + tid;
        float x = in[(size_t)t*D_MODEL + d] + res[(size_t)t*D_MODEL + d];
        v[i] = x; sum += x;
    }
    red[tid] = sum; __syncthreads();
    for (int s = 128; s > 0; s >>= 1) { if (tid < s) red[tid] += red[tid+s]; __syncthreads(); }
    float mu = red[0] / D_MODEL;
    __syncthreads();
    float sq = 0.f;
    #pragma unroll
    for (int i = 0; i < 8; i++) { float d0 = v[i] - mu; sq += d0*d0; }
    red[tid] = sq; __syncthreads();
    for (int s = 128; s > 0; s >>= 1) { if (tid < s) red[tid] += red[tid+s]; __syncthreads(); }
    float rstd = rsqrtf(red[0] / D_MODEL + 1e-5f);
    __syncthreads();
    float sum2 = 0.f;
    #pragma unroll
    for (int i = 0; i < 8; i++) {
        int d = i*256 + tid;
        v[i] = (v[i] - mu) * rstd * g2[d] + b2[d];
        sum2 += v[i];
    }
    red[tid] = sum2; __syncthreads();
    for (int s = 128; s > 0; s >>= 1) { if (tid < s) red[tid] += red[tid+s]; __syncthreads(); }
    float mu2 = red[0] / D_MODEL;
    __syncthreads();
    float sq2 = 0.f;
    #pragma unroll
    for (int i = 0; i < 8; i++) { float d0 = v[i] - mu2; sq2 += d0*d0; }
    red[tid] = sq2; __syncthreads();
    for (int s = 128; s > 0; s >>= 1) { if (tid < s) red[tid] += red[tid+s]; __syncthreads(); }
    float rstd2 = rsqrtf(red[0] / D_MODEL + 1e-5f);
    #pragma unroll
    for (int i = 0; i < 8; i++) {
        int d = i*256 + tid;
        out[(size_t)t*D_MODEL + d] = (v[i] - mu2) * rstd2 * gf[d] + bf[d];
    }
}

// ---------------- MoE gate ----------------
__global__ void __launch_bounds__(128) gate_kernel(
    const float* __restrict__ x, const float* __restrict__ gw,
    float* __restrict__ wts, float* __restrict__ varr)
{
    __shared__ float red[128];
    __shared__ float logit[4];
    int t = blockIdx.x, tid = threadIdx.x;
    float p[4] = {0.f, 0.f, 0.f, 0.f};
    for (int d = tid; d < D_MODEL; d += 128) {
        float xv = x[(size_t)t*D_MODEL + d];
        #pragma unroll
        for (int e = 0; e < 4; e++)
            p[e] = fmaf(xv, gw[e*D_MODEL + d], p[e]);
    }
    for (int e = 0; e < 4; e++) {
        red[tid] = p[e]; __syncthreads();
        for (int s = 64; s > 0; s >>= 1) { if (tid < s) red[tid] += red[tid+s]; __syncthreads(); }
        if (tid == 0) logit[e] = red[0];
        __syncthreads();
    }
    if (tid == 0) {
        float l[4] = {logit[0], logit[1], logit[2], logit[3]};
        float mx = fmaxf(fmaxf(l[0], l[1]), fmaxf(l[2], l[3]));
        float ex[4], ssum = 0.f;
        for (int e = 0; e < 4; e++) { ex[e] = expf(l[e] - mx); ssum += ex[e]; }
        float pr[4];
        for (int e = 0; e < 4; e++) pr[e] = ex[e] / ssum;
        int b1 = 0;
        for (int e = 1; e < 4; e++) if (pr[e] > pr[b1]) b1 = e;
        int b2 = -1;
        for (int e = 0; e < 4; e++) { if (e == b1) continue; if (b2 < 0 || pr[e] > pr[b2]) b2 = e; }
        float s2 = pr[b1] + pr[b2];
        float wv[4] = {0.f, 0.f, 0.f, 0.f};
        wv[b1] = pr[b1] / s2; wv[b2] = pr[b2] / s2;
        for (int e = 0; e < 4; e++) wts[e*SEQ + t] = wv[e];
        float mu = (l[0]+l[1]+l[2]+l[3]) * 0.25f;
        float va = ((l[0]-mu)*(l[0]-mu) + (l[1]-mu)*(l[1]-mu) +
                    (l[2]-mu)*(l[2]-mu) + (l[3]-mu)*(l[3]-mu)) / 3.f;
        varr[t] = va;
    }
}

// ---------------- routing compaction ----------------
__global__ void __launch_bounds__(1024) compact_kernel(
    const float* __restrict__ wts, int* __restrict__ cnt,
    int* __restrict__ ridx, float* __restrict__ rwt)
{
    __shared__ int sc[1024];
    int e = blockIdx.x, t = threadIdx.x;
    float w = wts[e*SEQ + t];
    int flag = (w != 0.f) ? 1 : 0;
    sc[t] = flag;
    __syncthreads();
    for (int off = 1; off < 1024; off <<= 1) {
        int v = (t >= off) ? sc[t - off] : 0;
        __syncthreads();
        sc[t] += v;
        __syncthreads();
    }
    if (flag) {
        int pos = sc[t] - 1;
        ridx[e*SEQ + pos] = t;
        rwt [e*SEQ + pos] = w;
    }
    if (t == 1023) cnt[e] = sc[1023];
}

__global__ void aux_kernel(const float* __restrict__ varr, float* __restrict__ out) {
    __shared__ float red[256];
    int tid = threadIdx.x;
    float s = 0.f;
    for (int i = tid; i < SEQ; i += 256) s += varr[i];
    red[tid] = s; __syncthreads();
    for (int st = 128; st > 0; st >>= 1) { if (tid < st) red[tid] += red[tid+st]; __syncthreads(); }
    if (tid == 0) out[0] = red[0] / (float)SEQ;
}

__global__ void zero_kernel(float* __restrict__ p, int n) {
    int i = blockIdx.x * 256 + threadIdx.x;
    if (i < n) p[i] = 0.f;
}

// ---------------- driver ----------------
extern "C" void kernel_launch(void* const* d_in, const int* in_sizes, int n_in,
                              void* d_out, int out_size) {
    const int*   tokens = (const int*)  d_in[0];
    const float* emb    = (const float*)d_in[1];
    const float* wq     = (const float*)d_in[2];
    const float* wk     = (const float*)d_in[3];
    const float* wv     = (const float*)d_in[4];
    const float* wo     = (const float*)d_in[5];
    const float* ln1g   = (const float*)d_in[6];
    const float* ln1b   = (const float*)d_in[7];
    const float* gatew  = (const float*)d_in[8];
    const float* w1     = (const float*)d_in[9];
    const float* w2     = (const float*)d_in[10];
    const float* w3     = (const float*)d_in[11];
    const float* ln2g   = (const float*)d_in[12];
    const float* ln2b   = (const float*)d_in[13];
    const float* fing   = (const float*)d_in[14];
    const float* finb   = (const float*)d_in[15];
    const float* headw  = (const float*)d_in[16];
    float* out = (float*)d_out;

    float *x, *qkv, *y, *moe, *wts, *varr, *rwt, *hbuf;
    int *cnt, *ridx;
    __nv_bfloat16 *ah, *al;
    cudaGetSymbolAddress((void**)&x,    g_x);
    cudaGetSymbolAddress((void**)&qkv,  g_qkv);
    cudaGetSymbolAddress((void**)&y,    g_y);
    cudaGetSymbolAddress((void**)&moe,  g_moe);
    cudaGetSymbolAddress((void**)&wts,  g_wts);
    cudaGetSymbolAddress((void**)&varr, g_var);
    cudaGetSymbolAddress((void**)&hbuf, g_h);
    cudaGetSymbolAddress((void**)&cnt,  g_cnt);
    cudaGetSymbolAddress((void**)&ridx, g_ridx);
    cudaGetSymbolAddress((void**)&rwt,  g_rwt);
    cudaGetSymbolAddress((void**)&ah,   g_ah);
    cudaGetSymbolAddress((void**)&al,   g_al);

    cudaFuncSetAttribute(attn_kernel, cudaFuncAttributeMaxDynamicSharedMemorySize, ATTN_SMEM);
    cudaFuncSetAttribute(gemm_tc<1>, cudaFuncAttributeMaxDynamicSharedMemorySize, GEMM_SMEM_TC);
    cudaFuncSetAttribute(gemm_tc<3>, cudaFuncAttributeMaxDynamicSharedMemorySize, GEMM_SMEM_TC);
    cudaFuncSetAttribute(gemm_tf32, cudaFuncAttributeMaxDynamicSharedMemorySize, GEMM_SMEM_TF);
    cudaFuncSetAttribute(gemm_tf32_moe, cudaFuncAttributeMaxDynamicSharedMemorySize, GEMM_SMEM_TF);

    // 1) embed (+ fused split)
    embed_kernel<<<SEQ, 256>>>(tokens, emb, x, ah, al);

    // 2) fused QKV (N=6144), split-K2 atomic
    zero_kernel<<<(SEQ*3*D_MODEL + 255)/256, 256>>>(qkv, SEQ*3*D_MODEL);
    dim3 gQKV(SEQ/128, 3*D_MODEL/256, 2);
    gemm_tc<3><<<gQKV, 256, GEMM_SMEM_TC>>>(ah, al, wq, wk, wv, D_MODEL,
                                            qkv, 3*D_MODEL, D_MODEL,
                                            nullptr, nullptr, 0, nullptr);

    // 3) RoPE + attention (emits pre-split ah/al)
    rope_kernel<<<dim3(SEQ, N_HEADS), 32>>>(qkv);
    attn_kernel<<<dim3(NB, N_HEADS), 256, ATTN_SMEM>>>(qkv, ah, al);

    // 4) output proj, split-K4 atomic -> y ; residual folded into LN1
    zero_kernel<<<(SEQ*D_MODEL + 255)/256, 256>>>(y, SEQ*D_MODEL);
    dim3 gA(SEQ/128, D_MODEL/256, 4);
    gemm_tc<3><<<gA, 256, GEMM_SMEM_TC>>>(ah, al, wo, wo, wo, D_MODEL,
                                          y, D_MODEL, D_MODEL,
                                          nullptr, nullptr, 0, nullptr);

    // 5) LN1(y + x) -> x (+ fused split to ah/al)
    ln_kernel<<<SEQ, 256>>>(y, x, ln1g, ln1b, x, ah, al);

    // 6) gate + routing
    gate_kernel<<<SEQ, 128>>>(x, gatew, wts, varr);
    compact_kernel<<<NEXP, 1024>>>(wts, cnt, ridx, rwt);

    // 7) MoE — up (fused silu, fp32 H) then tf32 down (weighted atomic scatter)
    zero_kernel<<<(SEQ*D_MODEL + 255)/256, 256>>>(moe, SEQ*D_MODEL);
    const long long FD = (long long)D_FFN * D_MODEL;
    dim3 gUp(SEQ/128, 2*D_FFN/256, NEXP);
    gemm_tc<1><<<gUp, 256, GEMM_SMEM_TC>>>(ah, al, w1, w3, nullptr, 0,
                                           nullptr, 2*D_FFN, D_MODEL,
                                           cnt, ridx, FD, hbuf);
    dim3 gDn(SEQ/128, D_MODEL/256, NEXP*4);
    gemm_tf32_moe<<<gDn, 256, GEMM_SMEM_TF>>>(hbuf, w2, moe, D_MODEL, D_FFN,
                                              cnt, ridx, rwt);

    // 8) fused LN2 + final LN
    ln2_kernel<<<SEQ, 256>>>(moe, x, ln2g, ln2b, fing, finb, y);

    // 9) head (tf32 single-pass)
    dim3 gH(SEQ/128, (VOCAB + 255)/256);
    gemm_tf32<<<gH, 256, GEMM_SMEM_TF>>>(y, headw, out, SEQ, VOCAB, D_MODEL);

    // 10) aux
    long long nlog = (long long)SEQ * VOCAB;
    if ((long long)out_size > nlog)
        aux_kernel<<<1, 256>>>(varr, out + nlog);
}